// round 9
// baseline (speedup 1.0000x reference)
#include <cuda_runtime.h>
#include <math.h>
#include <stdint.h>

// Problem capacities (fixed shapes per reference)
#define NMAXN 50000
#define EMAXE 200000
#define ETOTMAX (EMAXE + NMAXN)
#define GMAXG 1000

// ---------------- scratch (static device memory; no allocations allowed) ----
__device__ float g_bufA[(size_t)NMAXN * 1024];
__device__ float g_bufB[(size_t)NMAXN * 1024];
__device__ float g_bufC[(size_t)NMAXN * 1024];
__device__ float g_alS[NMAXN * 4];
__device__ float g_alD[NMAXN * 4];
__device__ float g_u[512 * 4];
__device__ float g_v[512 * 4];
__device__ int   g_degi[NMAXN];
__device__ int   g_rowptr[NMAXN + 1];
__device__ int   g_cursor[NMAXN];
__device__ int   g_csrsrc[ETOTMAX];
__device__ float g_dinv[NMAXN];
__device__ int   g_gstart[GMAXG + 1];
__device__ float g_bnsum[1024];
__device__ float g_bnsq[1024];
__device__ float g_bnscale[1024];
__device__ float g_bnshift[1024];
__device__ float g_z[GMAXG * 640];
__device__ float g_zf[GMAXG * 128];

// ---------------- CSR build -------------------------------------------------
__global__ void deg_build(const int* __restrict__ ei, int E, int Etot,
                          int* __restrict__ degi)
{
    int e = blockIdx.x * blockDim.x + threadIdx.x;
    if (e >= Etot) return;
    int d = (e < E) ? ei[E + e] : (e - E);
    atomicAdd(degi + d, 1);
}

__global__ void scan_kernel(const int* __restrict__ degi, int* __restrict__ rowptr,
                            int* __restrict__ cursor, int n)
{
    __shared__ int sm[32];
    __shared__ int s_carry;
    int tid = threadIdx.x;
    int lane = tid & 31, w = tid >> 5;
    if (tid == 0) s_carry = 0;
    __syncthreads();
    for (int base = 0; base < n; base += 1024) {
        int i = base + tid;
        int v = (i < n) ? degi[i] : 0;
        int x = v;
#pragma unroll
        for (int o = 1; o < 32; o <<= 1) {
            int y = __shfl_up_sync(0xFFFFFFFFu, x, o);
            if (lane >= o) x += y;
        }
        if (lane == 31) sm[w] = x;
        __syncthreads();
        if (w == 0) {
            int y = sm[lane];
#pragma unroll
            for (int o = 1; o < 32; o <<= 1) {
                int z = __shfl_up_sync(0xFFFFFFFFu, y, o);
                if (lane >= o) y += z;
            }
            sm[lane] = y;
        }
        __syncthreads();
        int incl = x + (w ? sm[w - 1] : 0);
        int excl = incl - v;
        int carry = s_carry;
        if (i < n) { rowptr[i] = carry + excl; cursor[i] = carry + excl; }
        __syncthreads();
        if (tid == 1023) s_carry = carry + incl;
        __syncthreads();
    }
    if (tid == 0) rowptr[n] = s_carry;
}

__global__ void csr_scatter(const int* __restrict__ ei, int E, int Etot,
                            int* __restrict__ cursor, int* __restrict__ csrsrc)
{
    int e = blockIdx.x * blockDim.x + threadIdx.x;
    if (e >= Etot) return;
    int s, d;
    if (e < E) { s = ei[e]; d = ei[E + e]; }
    else       { s = e - E; d = e - E; }
    int pos = atomicAdd(cursor + d, 1);
    csrsrc[pos] = s;
}

__global__ void dinv_kernel(const int* __restrict__ rowptr, float* __restrict__ dinv,
                            int n)
{
    int i = blockIdx.x * blockDim.x + threadIdx.x;
    if (i >= n) return;
    float deg = (float)(rowptr[i + 1] - rowptr[i]);
    dinv[i] = rsqrtf(fmaxf(deg, 1.0f));
}

// graph boundaries from sorted batch
__global__ void gstart_build(const int* __restrict__ batch, int n, int G,
                             int* __restrict__ gstart)
{
    int i = blockIdx.x * blockDim.x + threadIdx.x;
    if (i < n) {
        int b = batch[i];
        int bp = (i > 0) ? batch[i - 1] : -1;
        for (int g = bp + 1; g <= b; g++) gstart[g] = i;
    } else if (i == n) {
        int bl = batch[n - 1];
        for (int g = bl + 1; g <= G; g++) gstart[g] = n;
    }
}

// ---------------- u/v vectors: u[k,h] = sum_c W[k,hC+c]*a[h,c] ---------------
__global__ void uv_build(const float* __restrict__ W, const float* __restrict__ aS,
                         const float* __restrict__ aD, int K, int C,
                         float* __restrict__ u, float* __restrict__ v)
{
    int idx = blockIdx.x * blockDim.x + threadIdx.x;
    int warp = idx >> 5, lane = idx & 31;
    if (warp >= K * 4) return;
    int k = warp >> 2, h = warp & 3;
    const float* wrow = W + (size_t)k * (4 * C) + h * C;
    const float* as = aS + h * C;
    const float* ad = aD + h * C;
    float s = 0.f, d = 0.f;
    for (int c = lane; c < C; c += 32) {
        float wv = wrow[c];
        s += wv * as[c];
        d += wv * ad[c];
    }
#pragma unroll
    for (int o = 16; o; o >>= 1) {
        s += __shfl_xor_sync(0xFFFFFFFFu, s, o);
        d += __shfl_xor_sync(0xFFFFFFFFu, d, o);
    }
    if (lane == 0) { u[k * 4 + h] = s; v[k * 4 + h] = d; }
}

// ---------------- skinny alpha GEMM (layer 1, K=64, fp32 exact) --------------
__global__ __launch_bounds__(256) void alpha_gemm64(
    const float* __restrict__ in, int n,
    const float* __restrict__ u, const float* __restrict__ v,
    float* __restrict__ alS, float* __restrict__ alD)
{
    __shared__ float su[64][4];
    __shared__ float sv[64][4];
    int tid = threadIdx.x;
    if (tid < 64 * 4) { su[tid >> 2][tid & 3] = u[tid]; sv[tid >> 2][tid & 3] = v[tid]; }
    __syncthreads();

    int warp = tid >> 5, lane = tid & 31;
    for (int node = blockIdx.x * 8 + warp; node < n; node += gridDim.x * 8) {
        const float* row = in + (size_t)node * 64;
        float x0 = row[lane], x1 = row[lane + 32];
        float as[4], ad[4];
#pragma unroll
        for (int h = 0; h < 4; h++) {
            as[h] = x0 * su[lane][h] + x1 * su[lane + 32][h];
            ad[h] = x0 * sv[lane][h] + x1 * sv[lane + 32][h];
        }
#pragma unroll
        for (int h = 0; h < 4; h++) {
#pragma unroll
            for (int o = 16; o; o >>= 1) {
                as[h] += __shfl_xor_sync(0xFFFFFFFFu, as[h], o);
                ad[h] += __shfl_xor_sync(0xFFFFFFFFu, ad[h], o);
            }
        }
        if (lane == 0) {
            *(float4*)(alS + (size_t)node * 4) = make_float4(as[0], as[1], as[2], as[3]);
            *(float4*)(alD + (size_t)node * 4) = make_float4(ad[0], ad[1], ad[2], ad[3]);
        }
    }
}

// ---------------- TF32 tensor-core GEMM (cp.async double-buffered, R6) -------
__device__ __forceinline__ void mma_tf32(float c[4], const float a[4], const float b[2]) {
    asm volatile(
        "mma.sync.aligned.m16n8k8.row.col.f32.tf32.tf32.f32 "
        "{%0,%1,%2,%3}, {%4,%5,%6,%7}, {%8,%9}, {%0,%1,%2,%3};"
        : "+f"(c[0]), "+f"(c[1]), "+f"(c[2]), "+f"(c[3])
        : "r"(__float_as_uint(a[0])), "r"(__float_as_uint(a[1])),
          "r"(__float_as_uint(a[2])), "r"(__float_as_uint(a[3])),
          "r"(__float_as_uint(b[0])), "r"(__float_as_uint(b[1])));
}

__device__ __forceinline__ void cp_async16(float* smem_dst, const float* gmem_src,
                                           bool pred) {
    uint32_t saddr = (uint32_t)__cvta_generic_to_shared(smem_dst);
    int sz = pred ? 16 : 0;
    asm volatile("cp.async.cg.shared.global [%0], [%1], 16, %2;\n"
                 :: "r"(saddr), "l"(gmem_src), "r"(sz));
}

#define ABUF 4608
#define BBUF 4352
#define SMEM_FLOATS (2 * ABUF + 2 * BBUF)

// C[M,Nc] = op(A)[M,K] @ B[K,Nc]; op = relu(bn) if BNRELU.
// GROUP: A base shifts by (blockN/128)*K columns (head-blocked input).
// ALPHA: accumulates alS/alD[row*4+head] += sum_col C*aS/aD.
template <bool BNRELU, bool ALPHA, bool GROUP>
__global__ __launch_bounds__(256, 2) void tf32gemm(
    const float* __restrict__ A, const float* __restrict__ B,
    float* __restrict__ C, int M, int Nc, int K,
    int lda, int ldb, int ldc,
    const float* __restrict__ scale, const float* __restrict__ shift,
    const float* __restrict__ aS, const float* __restrict__ aD, int Chead,
    float* __restrict__ alS, float* __restrict__ alD)
{
    extern __shared__ float smem[];

    int tid = threadIdx.x;
    int lane = tid & 31;
    int wid = tid >> 5;
    int warpM = (wid >> 2) * 64;
    int warpN = (wid & 3) * 32;
    int r = lane >> 2;
    int cq = lane & 3;

    int blockM = blockIdx.y * 128;
    int blockN = blockIdx.x * 128;

    if (GROUP) A += (size_t)(blockN >> 7) * K;

    int acol = (tid & 7) * 4;
    int arow0 = tid >> 3;
    int bcol = (tid & 31) * 4;
    int brow0 = tid >> 5;

    float acc[4][4][4];
#pragma unroll
    for (int mt = 0; mt < 4; mt++)
#pragma unroll
        for (int nt = 0; nt < 4; nt++)
#pragma unroll
            for (int i = 0; i < 4; i++) acc[mt][nt][i] = 0.0f;

    int nk = K >> 5;

    auto load_tile = [&](int k0, int buf) {
        float* As = smem + buf * ABUF;
        float* Bs = smem + 2 * ABUF + buf * BBUF;
#pragma unroll
        for (int i = 0; i < 4; i++) {
            int row = blockM + arow0 + i * 32;
            cp_async16(&As[(arow0 + i * 32) * 36 + acol],
                       A + (size_t)row * lda + k0 + acol, row < M);
        }
#pragma unroll
        for (int i = 0; i < 4; i++) {
            int kr = brow0 + i * 8;
            cp_async16(&Bs[kr * 136 + bcol],
                       B + (size_t)(k0 + kr) * ldb + blockN + bcol, true);
        }
        asm volatile("cp.async.commit_group;\n");
    };

    load_tile(0, 0);

    for (int kt = 0; kt < nk; kt++) {
        if (kt + 1 < nk) {
            load_tile((kt + 1) << 5, (kt + 1) & 1);
            asm volatile("cp.async.wait_group 1;\n");
        } else {
            asm volatile("cp.async.wait_group 0;\n");
        }
        __syncthreads();

        const float* As = smem + (kt & 1) * ABUF;
        const float* Bs = smem + 2 * ABUF + (kt & 1) * BBUF;
        int k0 = kt << 5;

        float scv[8], shv[8];
        if (BNRELU) {
#pragma unroll
            for (int kk = 0; kk < 4; kk++) {
                scv[kk]     = scale[k0 + kk * 8 + cq];
                scv[kk + 4] = scale[k0 + kk * 8 + cq + 4];
                shv[kk]     = shift[k0 + kk * 8 + cq];
                shv[kk + 4] = shift[k0 + kk * 8 + cq + 4];
            }
        }

#pragma unroll
        for (int kk = 0; kk < 4; kk++) {
            int kb = kk * 8;
            float a[4][4], b[4][2];
#pragma unroll
            for (int mt = 0; mt < 4; mt++) {
                int m = warpM + mt * 16 + r;
                float a0 = As[m * 36 + kb + cq];
                float a1 = As[(m + 8) * 36 + kb + cq];
                float a2 = As[m * 36 + kb + cq + 4];
                float a3 = As[(m + 8) * 36 + kb + cq + 4];
                if (BNRELU) {
                    a0 = fmaxf(fmaf(a0, scv[kk], shv[kk]), 0.f);
                    a1 = fmaxf(fmaf(a1, scv[kk], shv[kk]), 0.f);
                    a2 = fmaxf(fmaf(a2, scv[kk + 4], shv[kk + 4]), 0.f);
                    a3 = fmaxf(fmaf(a3, scv[kk + 4], shv[kk + 4]), 0.f);
                }
                a[mt][0] = a0; a[mt][1] = a1; a[mt][2] = a2; a[mt][3] = a3;
            }
#pragma unroll
            for (int nt = 0; nt < 4; nt++) {
                int nn = warpN + nt * 8 + r;
                b[nt][0] = Bs[(kb + cq) * 136 + nn];
                b[nt][1] = Bs[(kb + cq + 4) * 136 + nn];
            }
#pragma unroll
            for (int mt = 0; mt < 4; mt++)
#pragma unroll
                for (int nt = 0; nt < 4; nt++)
                    mma_tf32(acc[mt][nt], a[mt], b[nt]);
        }
        __syncthreads();
    }

#pragma unroll
    for (int mt = 0; mt < 4; mt++) {
        int row0 = blockM + warpM + mt * 16 + r;
#pragma unroll
        for (int nt = 0; nt < 4; nt++) {
            int col = blockN + warpN + nt * 8 + cq * 2;
            if (row0 < M)
                *(float2*)(C + (size_t)row0 * ldc + col) =
                    make_float2(acc[mt][nt][0], acc[mt][nt][1]);
            if (row0 + 8 < M)
                *(float2*)(C + (size_t)(row0 + 8) * ldc + col) =
                    make_float2(acc[mt][nt][2], acc[mt][nt][3]);
        }
    }

    if (ALPHA) {
        int head = blockN / Chead;
        float ws[4][2], wd[4][2];
#pragma unroll
        for (int nt = 0; nt < 4; nt++) {
            int col = blockN + warpN + nt * 8 + cq * 2;
            int c = col - head * Chead;
            ws[nt][0] = aS[head * Chead + c];
            ws[nt][1] = aS[head * Chead + c + 1];
            wd[nt][0] = aD[head * Chead + c];
            wd[nt][1] = aD[head * Chead + c + 1];
        }
#pragma unroll
        for (int mt = 0; mt < 4; mt++) {
            float ps0 = 0.f, pd0 = 0.f, ps1 = 0.f, pd1 = 0.f;
#pragma unroll
            for (int nt = 0; nt < 4; nt++) {
                ps0 += acc[mt][nt][0] * ws[nt][0] + acc[mt][nt][1] * ws[nt][1];
                pd0 += acc[mt][nt][0] * wd[nt][0] + acc[mt][nt][1] * wd[nt][1];
                ps1 += acc[mt][nt][2] * ws[nt][0] + acc[mt][nt][3] * ws[nt][1];
                pd1 += acc[mt][nt][2] * wd[nt][0] + acc[mt][nt][3] * wd[nt][1];
            }
#pragma unroll
            for (int o = 1; o < 4; o <<= 1) {
                ps0 += __shfl_xor_sync(0xFFFFFFFFu, ps0, o);
                pd0 += __shfl_xor_sync(0xFFFFFFFFu, pd0, o);
                ps1 += __shfl_xor_sync(0xFFFFFFFFu, ps1, o);
                pd1 += __shfl_xor_sync(0xFFFFFFFFu, pd1, o);
            }
            if (cq == 0) {
                int row0 = blockM + warpM + mt * 16 + r;
                if (row0 < M) {
                    atomicAdd(alS + (size_t)row0 * 4 + head, ps0);
                    atomicAdd(alD + (size_t)row0 * 4 + head, pd0);
                }
                if (row0 + 8 < M) {
                    atomicAdd(alS + (size_t)(row0 + 8) * 4 + head, ps1);
                    atomicAdd(alD + (size_t)(row0 + 8) * 4 + head, pd1);
                }
            }
        }
    }
}

// ---------------- fp32 SGEMM (small head GEMMs) ------------------------------
template <bool RELU>
__global__ __launch_bounds__(256) void sgemm(
    const float* __restrict__ A, const float* __restrict__ B,
    const float* __restrict__ bias, float* __restrict__ C,
    int M, int Nc, int K, int lda, int ldc)
{
    __shared__ float As[8][128];
    __shared__ float Bs[8][128];

    int tid = threadIdx.x;
    int bx = blockIdx.x;
    int by = blockIdx.y;

    int tx = tid % 16;
    int ty = tid / 16;

    int rowA = by * 128 + tid / 2;
    int colA = (tid % 2) * 4;
    int rowB = tid / 32;
    int colB = (tid % 32) * 4;

    float acc[8][8];
#pragma unroll
    for (int i = 0; i < 8; i++)
#pragma unroll
        for (int j = 0; j < 8; j++) acc[i][j] = 0.0f;

    for (int k0 = 0; k0 < K; k0 += 8) {
        float4 av = make_float4(0.f, 0.f, 0.f, 0.f);
        if (rowA < M)
            av = *(const float4*)(A + (size_t)rowA * lda + k0 + colA);
        As[colA + 0][tid / 2] = av.x;
        As[colA + 1][tid / 2] = av.y;
        As[colA + 2][tid / 2] = av.z;
        As[colA + 3][tid / 2] = av.w;

        float4 bv = *(const float4*)(B + (size_t)(k0 + rowB) * Nc + bx * 128 + colB);
        *(float4*)(&Bs[rowB][colB]) = bv;

        __syncthreads();

#pragma unroll
        for (int kk = 0; kk < 8; kk++) {
            float ra[8], rb[8];
#pragma unroll
            for (int i = 0; i < 8; i++) ra[i] = As[kk][ty * 8 + i];
#pragma unroll
            for (int j = 0; j < 8; j++) rb[j] = Bs[kk][tx * 8 + j];
#pragma unroll
            for (int i = 0; i < 8; i++)
#pragma unroll
                for (int j = 0; j < 8; j++) acc[i][j] = fmaf(ra[i], rb[j], acc[i][j]);
        }
        __syncthreads();
    }

#pragma unroll
    for (int i = 0; i < 8; i++) {
        int row = by * 128 + ty * 8 + i;
        if (row >= M) continue;
#pragma unroll
        for (int j = 0; j < 8; j++) {
            int col = bx * 128 + tx * 8 + j;
            float v = acc[i][j];
            if (bias) v += bias[col];
            if (RELU) v = v > 0.f ? v : 0.f;
            C[(size_t)row * ldc + col] = v;
        }
    }
}

// ---- GAT layer 1 input-space gather: agg[d, h*64+c] = sum alpha*x[src,c] ----
__global__ __launch_bounds__(64) void gat_agg_in64(
    const int* __restrict__ rowptr, const int* __restrict__ csrsrc,
    const float* __restrict__ alS, const float* __restrict__ alD,
    const float* __restrict__ in, float* __restrict__ agg)
{
    constexpr int NT = 64;
    __shared__ float s_red[8];
    __shared__ float s_bm[4];
    __shared__ float s_binv[4];
    __shared__ float s_al[16][4];
    __shared__ int   s_src[16];

    int d = blockIdx.x;
    int tid = threadIdx.x;
    int lane = tid & 31, w = tid >> 5;
    int beg = rowptr[d], end = rowptr[d + 1];

    float4 ad4 = *(const float4*)(alD + (size_t)d * 4);
    float adv[4] = {ad4.x, ad4.y, ad4.z, ad4.w};

    float mx[4] = {-INFINITY, -INFINITY, -INFINITY, -INFINITY};
    for (int i = beg + tid; i < end; i += NT) {
        int s = csrsrc[i];
        float4 as4 = *(const float4*)(alS + (size_t)s * 4);
        float l[4] = {as4.x + adv[0], as4.y + adv[1], as4.z + adv[2], as4.w + adv[3]};
#pragma unroll
        for (int hh = 0; hh < 4; hh++) {
            float t = l[hh];
            t = t > 0.f ? t : 0.2f * t;
            mx[hh] = fmaxf(mx[hh], t);
        }
    }
#pragma unroll
    for (int hh = 0; hh < 4; hh++)
#pragma unroll
        for (int o = 16; o; o >>= 1)
            mx[hh] = fmaxf(mx[hh], __shfl_xor_sync(0xFFFFFFFFu, mx[hh], o));
    if (lane == 0)
#pragma unroll
        for (int hh = 0; hh < 4; hh++) s_red[w * 4 + hh] = mx[hh];
    __syncthreads();
    if (tid < 4) s_bm[tid] = fmaxf(s_red[tid], s_red[4 + tid]);
    __syncthreads();
    float bm[4] = {s_bm[0], s_bm[1], s_bm[2], s_bm[3]};

    float sme[4] = {0.f, 0.f, 0.f, 0.f};
    for (int i = beg + tid; i < end; i += NT) {
        int s = csrsrc[i];
        float4 as4 = *(const float4*)(alS + (size_t)s * 4);
        float l[4] = {as4.x + adv[0], as4.y + adv[1], as4.z + adv[2], as4.w + adv[3]};
#pragma unroll
        for (int hh = 0; hh < 4; hh++) {
            float t = l[hh];
            t = t > 0.f ? t : 0.2f * t;
            sme[hh] += expf(t - bm[hh]);
        }
    }
#pragma unroll
    for (int hh = 0; hh < 4; hh++)
#pragma unroll
        for (int o = 16; o; o >>= 1)
            sme[hh] += __shfl_xor_sync(0xFFFFFFFFu, sme[hh], o);
    if (lane == 0)
#pragma unroll
        for (int hh = 0; hh < 4; hh++) s_red[w * 4 + hh] = sme[hh];
    __syncthreads();
    if (tid < 4) s_binv[tid] = 1.0f / fmaxf(s_red[tid] + s_red[4 + tid], 1e-16f);
    __syncthreads();

    float acc[4] = {0.f, 0.f, 0.f, 0.f};
    for (int c0 = beg; c0 < end; c0 += 16) {
        int cnt = min(16, end - c0);
        if (tid < cnt * 4) {
            int j = tid >> 2, hh = tid & 3;
            int s = csrsrc[c0 + j];
            if (hh == 0) s_src[j] = s;
            float t = alS[(size_t)s * 4 + hh] + adv[hh];
            t = t > 0.f ? t : 0.2f * t;
            s_al[j][hh] = expf(t - s_bm[hh]) * s_binv[hh];
        }
        __syncthreads();
        int j = 0;
        for (; j + 4 <= cnt; j += 4) {
            // batch 4 independent random row loads (MLP=4)
            float v0 = in[(size_t)s_src[j + 0] * 64 + tid];
            float v1 = in[(size_t)s_src[j + 1] * 64 + tid];
            float v2 = in[(size_t)s_src[j + 2] * 64 + tid];
            float v3 = in[(size_t)s_src[j + 3] * 64 + tid];
#pragma unroll
            for (int hh = 0; hh < 4; hh++) {
                acc[hh] = fmaf(s_al[j + 0][hh], v0, acc[hh]);
                acc[hh] = fmaf(s_al[j + 1][hh], v1, acc[hh]);
                acc[hh] = fmaf(s_al[j + 2][hh], v2, acc[hh]);
                acc[hh] = fmaf(s_al[j + 3][hh], v3, acc[hh]);
            }
        }
        for (; j < cnt; j++) {
            float v = in[(size_t)s_src[j] * 64 + tid];
#pragma unroll
            for (int hh = 0; hh < 4; hh++)
                acc[hh] = fmaf(s_al[j][hh], v, acc[hh]);
        }
        __syncthreads();
    }

#pragma unroll
    for (int hh = 0; hh < 4; hh++)
        agg[(size_t)d * 256 + hh * 64 + tid] = acc[hh];
}

// ---- fused per-destination GAT softmax + gather (output space) --------------
// HC=1024, SPLIT=2: two blocks per node, each handling a 512-channel half.
// Requires HC/SPLIT == 4*NT (one float4 per thread).
template <int HC, int SPLIT>
__global__ __launch_bounds__(128) void gat_gather(
    const int* __restrict__ rowptr, const int* __restrict__ csrsrc,
    const float* __restrict__ alS, const float* __restrict__ alD,
    const float* __restrict__ h, float* __restrict__ out)
{
    constexpr int NT = 128;
    constexpr int HCW = HC / SPLIT;
    static_assert(HCW == 4 * NT, "one float4 per thread");
    constexpr int CPH = HC / 4;

    __shared__ float s_red[16];
    __shared__ float s_bm[4];
    __shared__ float s_binv[4];
    __shared__ float s_al[32][4];
    __shared__ int   s_src[32];

    int d = blockIdx.x;
    int half = (SPLIT > 1) ? blockIdx.y : 0;
    int coff = half * HCW;
    int tid = threadIdx.x;
    int lane = tid & 31, w = tid >> 5;
    int beg = rowptr[d], end = rowptr[d + 1];

    float4 ad4 = *(const float4*)(alD + (size_t)d * 4);
    float adv[4] = {ad4.x, ad4.y, ad4.z, ad4.w};

    float mx[4] = {-INFINITY, -INFINITY, -INFINITY, -INFINITY};
    for (int i = beg + tid; i < end; i += NT) {
        int s = csrsrc[i];
        float4 as4 = *(const float4*)(alS + (size_t)s * 4);
        float l[4] = {as4.x + adv[0], as4.y + adv[1], as4.z + adv[2], as4.w + adv[3]};
#pragma unroll
        for (int hh = 0; hh < 4; hh++) {
            float t = l[hh];
            t = t > 0.f ? t : 0.2f * t;
            mx[hh] = fmaxf(mx[hh], t);
        }
    }
#pragma unroll
    for (int hh = 0; hh < 4; hh++)
#pragma unroll
        for (int o = 16; o; o >>= 1)
            mx[hh] = fmaxf(mx[hh], __shfl_xor_sync(0xFFFFFFFFu, mx[hh], o));
    if (lane == 0)
#pragma unroll
        for (int hh = 0; hh < 4; hh++) s_red[w * 4 + hh] = mx[hh];
    __syncthreads();
    if (tid < 4) {
        float r = fmaxf(fmaxf(s_red[tid], s_red[4 + tid]),
                        fmaxf(s_red[8 + tid], s_red[12 + tid]));
        s_bm[tid] = r;
    }
    __syncthreads();
    float bm[4] = {s_bm[0], s_bm[1], s_bm[2], s_bm[3]};

    float sme[4] = {0.f, 0.f, 0.f, 0.f};
    for (int i = beg + tid; i < end; i += NT) {
        int s = csrsrc[i];
        float4 as4 = *(const float4*)(alS + (size_t)s * 4);
        float l[4] = {as4.x + adv[0], as4.y + adv[1], as4.z + adv[2], as4.w + adv[3]};
#pragma unroll
        for (int hh = 0; hh < 4; hh++) {
            float t = l[hh];
            t = t > 0.f ? t : 0.2f * t;
            sme[hh] += expf(t - bm[hh]);
        }
    }
#pragma unroll
    for (int hh = 0; hh < 4; hh++)
#pragma unroll
        for (int o = 16; o; o >>= 1)
            sme[hh] += __shfl_xor_sync(0xFFFFFFFFu, sme[hh], o);
    if (lane == 0)
#pragma unroll
        for (int hh = 0; hh < 4; hh++) s_red[w * 4 + hh] = sme[hh];
    __syncthreads();
    if (tid < 4) {
        float r = s_red[tid] + s_red[4 + tid] + s_red[8 + tid] + s_red[12 + tid];
        s_binv[tid] = 1.0f / fmaxf(r, 1e-16f);
    }
    __syncthreads();

    float4 acc = make_float4(0.f, 0.f, 0.f, 0.f);
    int hof = (coff + tid * 4) / CPH;   // head of this thread's float4

    for (int c0 = beg; c0 < end; c0 += 32) {
        int cnt = min(32, end - c0);
        if (tid < cnt * 4) {
            int j = tid >> 2, hh = tid & 3;
            int s = csrsrc[c0 + j];
            if (hh == 0) s_src[j] = s;
            float t = alS[(size_t)s * 4 + hh] + adv[hh];
            t = t > 0.f ? t : 0.2f * t;
            s_al[j][hh] = expf(t - s_bm[hh]) * s_binv[hh];
        }
        __syncthreads();
        int j = 0;
        for (; j + 4 <= cnt; j += 4) {
            // batch 4 independent random row loads (MLP=4)
            const float4* p0 = (const float4*)(h + (size_t)s_src[j + 0] * HC + coff);
            const float4* p1 = (const float4*)(h + (size_t)s_src[j + 1] * HC + coff);
            const float4* p2 = (const float4*)(h + (size_t)s_src[j + 2] * HC + coff);
            const float4* p3 = (const float4*)(h + (size_t)s_src[j + 3] * HC + coff);
            float4 v0 = p0[tid];
            float4 v1 = p1[tid];
            float4 v2 = p2[tid];
            float4 v3 = p3[tid];
            float a0 = s_al[j + 0][hof];
            float a1 = s_al[j + 1][hof];
            float a2 = s_al[j + 2][hof];
            float a3 = s_al[j + 3][hof];
            acc.x = fmaf(a0, v0.x, acc.x); acc.y = fmaf(a0, v0.y, acc.y);
            acc.z = fmaf(a0, v0.z, acc.z); acc.w = fmaf(a0, v0.w, acc.w);
            acc.x = fmaf(a1, v1.x, acc.x); acc.y = fmaf(a1, v1.y, acc.y);
            acc.z = fmaf(a1, v1.z, acc.z); acc.w = fmaf(a1, v1.w, acc.w);
            acc.x = fmaf(a2, v2.x, acc.x); acc.y = fmaf(a2, v2.y, acc.y);
            acc.z = fmaf(a2, v2.z, acc.z); acc.w = fmaf(a2, v2.w, acc.w);
            acc.x = fmaf(a3, v3.x, acc.x); acc.y = fmaf(a3, v3.y, acc.y);
            acc.z = fmaf(a3, v3.z, acc.z); acc.w = fmaf(a3, v3.w, acc.w);
        }
        for (; j < cnt; j++) {
            const float4* hp = (const float4*)(h + (size_t)s_src[j] * HC + coff);
            float a = s_al[j][hof];
            float4 hv = hp[tid];
            acc.x = fmaf(a, hv.x, acc.x);
            acc.y = fmaf(a, hv.y, acc.y);
            acc.z = fmaf(a, hv.z, acc.z);
            acc.w = fmaf(a, hv.w, acc.w);
        }
        __syncthreads();
    }

    float4* op = (float4*)(out + (size_t)d * HC + coff);
    op[tid] = acc;
}

// ---------------- GCN gather (4-way edge unroll, MLP=4) ----------------------
__global__ __launch_bounds__(64) void gcn_gather(
    const int* __restrict__ rowptr, const int* __restrict__ csrsrc,
    const float* __restrict__ dinv, const float* __restrict__ h,
    float* __restrict__ out)
{
    int d = blockIdx.x;
    int tid = threadIdx.x;
    int beg = rowptr[d], end = rowptr[d + 1];
    float dd = dinv[d];

    float4 acc = make_float4(0.f, 0.f, 0.f, 0.f);
    int i = beg;
    for (; i + 4 <= end; i += 4) {
        int s0 = csrsrc[i + 0], s1 = csrsrc[i + 1];
        int s2 = csrsrc[i + 2], s3 = csrsrc[i + 3];
        float n0 = dinv[s0] * dd, n1 = dinv[s1] * dd;
        float n2 = dinv[s2] * dd, n3 = dinv[s3] * dd;
        float4 v0 = *(const float4*)(h + (size_t)s0 * 256 + tid * 4);
        float4 v1 = *(const float4*)(h + (size_t)s1 * 256 + tid * 4);
        float4 v2 = *(const float4*)(h + (size_t)s2 * 256 + tid * 4);
        float4 v3 = *(const float4*)(h + (size_t)s3 * 256 + tid * 4);
        acc.x = fmaf(n0, v0.x, acc.x); acc.y = fmaf(n0, v0.y, acc.y);
        acc.z = fmaf(n0, v0.z, acc.z); acc.w = fmaf(n0, v0.w, acc.w);
        acc.x = fmaf(n1, v1.x, acc.x); acc.y = fmaf(n1, v1.y, acc.y);
        acc.z = fmaf(n1, v1.z, acc.z); acc.w = fmaf(n1, v1.w, acc.w);
        acc.x = fmaf(n2, v2.x, acc.x); acc.y = fmaf(n2, v2.y, acc.y);
        acc.z = fmaf(n2, v2.z, acc.z); acc.w = fmaf(n2, v2.w, acc.w);
        acc.x = fmaf(n3, v3.x, acc.x); acc.y = fmaf(n3, v3.y, acc.y);
        acc.z = fmaf(n3, v3.z, acc.z); acc.w = fmaf(n3, v3.w, acc.w);
    }
    for (; i < end; i++) {
        int s = csrsrc[i];
        float nrm = dinv[s] * dd;
        float4 v = *(const float4*)(h + (size_t)s * 256 + tid * 4);
        acc.x = fmaf(nrm, v.x, acc.x);
        acc.y = fmaf(nrm, v.y, acc.y);
        acc.z = fmaf(nrm, v.z, acc.z);
        acc.w = fmaf(nrm, v.w, acc.w);
    }
    *(float4*)(out + (size_t)d * 256 + tid * 4) = acc;
}

// ---------------- BatchNorm -------------------------------------------------
__global__ void bn_stats(const float* __restrict__ x, int rows, int K,
                         float* __restrict__ sum, float* __restrict__ sq)
{
    int col = blockIdx.x * blockDim.x + threadIdx.x;
    float s = 0.f, q = 0.f;
    for (int r = blockIdx.y; r < rows; r += gridDim.y) {
        float v = x[(size_t)r * K + col];
        s += v;
        q += v * v;
    }
    atomicAdd(sum + col, s);
    atomicAdd(sq + col, q);
}

__global__ void bn_finalize(const float* __restrict__ sum, const float* __restrict__ sq,
                            const float* __restrict__ g, const float* __restrict__ b,
                            int rows, int K, float* __restrict__ scale,
                            float* __restrict__ shift)
{
    int c = blockIdx.x * blockDim.x + threadIdx.x;
    if (c >= K) return;
    float inv_n = 1.0f / (float)rows;
    float mu = sum[c] * inv_n;
    float var = sq[c] * inv_n - mu * mu;
    float sc = g[c] * rsqrtf(var + 1e-5f);
    scale[c] = sc;
    shift[c] = b[c] - mu * sc;
}

__global__ void bn_apply_relu(float* __restrict__ x, const float* __restrict__ scale,
                              const float* __restrict__ shift, size_t total, int K)
{
    for (size_t i = (size_t)blockIdx.x * blockDim.x + threadIdx.x; i < total;
         i += (size_t)gridDim.x * blockDim.x) {
        int c = (int)(i % K);
        float v = x[i] * scale[c] + shift[c];
        x[i] = v > 0.f ? v : 0.f;
    }
}

// ---------------- Pooling: one block per graph (batch sorted, no atomics) ----
__global__ __launch_bounds__(256) void pool_graph(
    const float* __restrict__ h, const int* __restrict__ gstart,
    const float* __restrict__ scale, const float* __restrict__ shift,
    float* __restrict__ z)
{
    int g = blockIdx.x;
    int c = threadIdx.x;
    int beg = gstart[g], end = gstart[g + 1];
    float sc = scale[c], sh = shift[c];
    float sum = 0.f, mx = 0.f;
    for (int r = beg; r < end; r++) {
        float v = fmaxf(fmaf(h[(size_t)r * 256 + c], sc, sh), 0.f);
        sum += v;
        mx = fmaxf(mx, v);
    }
    float cnt = (float)(end - beg);
    z[(size_t)g * 640 + c] = sum / fmaxf(cnt, 1.0f);
    z[(size_t)g * 640 + 256 + c] = mx;
}

// ---------------- Head -------------------------------------------------------
__global__ void head_final(const float* __restrict__ zf, const float* __restrict__ Wf2,
                           const float* __restrict__ bf2, float* __restrict__ out)
{
    int g = blockIdx.x;
    int t = threadIdx.x;
    float v = zf[(size_t)g * 128 + t] * Wf2[t];
#pragma unroll
    for (int o = 16; o; o >>= 1) v += __shfl_down_sync(0xFFFFFFFFu, v, o);
    __shared__ float sm[4];
    if ((t & 31) == 0) sm[t >> 5] = v;
    __syncthreads();
    if (t == 0) {
        float s = sm[0] + sm[1] + sm[2] + sm[3] + bf2[0];
        out[g] = 1.0f / (1.0f + expf(-s));
    }
}

// ---------------- launch ------------------------------------------------------
extern "C" void kernel_launch(void* const* d_in, const int* in_sizes, int n_in,
                              void* d_out, int out_size)
{
    const float* x    = (const float*)d_in[0];
    const int*   ei   = (const int*)d_in[1];
    const int*   batch= (const int*)d_in[2];
    const float* fp   = (const float*)d_in[3];
    const float* W1   = (const float*)d_in[4];
    const float* a1s  = (const float*)d_in[5];
    const float* a1d  = (const float*)d_in[6];
    const float* bn1g = (const float*)d_in[8];
    const float* bn1b = (const float*)d_in[9];
    const float* W2   = (const float*)d_in[10];
    const float* a2s  = (const float*)d_in[11];
    const float* a2d  = (const float*)d_in[12];
    const float* bn2g = (const float*)d_in[14];
    const float* bn2b = (const float*)d_in[15];
    const float* Wg   = (const float*)d_in[16];
    const float* bn3g = (const float*)d_in[18];
    const float* bn3b = (const float*)d_in[19];
    const float* Ws   = (const float*)d_in[20];
    const float* bs   = (const float*)d_in[21];
    const float* Wf1  = (const float*)d_in[22];
    const float* bnfg = (const float*)d_in[24];
    const float* bnfb = (const float*)d_in[25];
    const float* Wf2  = (const float*)d_in[26];
    const float* bf2  = (const float*)d_in[27];
    float* out = (float*)d_out;

    int n    = in_sizes[0] / 64;
    int E    = in_sizes[1] / 2;
    int Etot = E + n;
    int G    = in_sizes[3] / 128;

    float *bufA, *bufB, *bufC, *alS, *alD, *dinv, *uu, *vv;
    float *bnsum, *bnsq, *bnscale, *bnshift, *z, *zf;
    int *degi, *rowptr, *cursor, *csrsrc, *gstart;
    cudaGetSymbolAddress((void**)&bufA, g_bufA);
    cudaGetSymbolAddress((void**)&bufB, g_bufB);
    cudaGetSymbolAddress((void**)&bufC, g_bufC);
    cudaGetSymbolAddress((void**)&alS, g_alS);
    cudaGetSymbolAddress((void**)&alD, g_alD);
    cudaGetSymbolAddress((void**)&uu, g_u);
    cudaGetSymbolAddress((void**)&vv, g_v);
    cudaGetSymbolAddress((void**)&degi, g_degi);
    cudaGetSymbolAddress((void**)&rowptr, g_rowptr);
    cudaGetSymbolAddress((void**)&cursor, g_cursor);
    cudaGetSymbolAddress((void**)&csrsrc, g_csrsrc);
    cudaGetSymbolAddress((void**)&dinv, g_dinv);
    cudaGetSymbolAddress((void**)&gstart, g_gstart);
    cudaGetSymbolAddress((void**)&bnsum, g_bnsum);
    cudaGetSymbolAddress((void**)&bnsq, g_bnsq);
    cudaGetSymbolAddress((void**)&bnscale, g_bnscale);
    cudaGetSymbolAddress((void**)&bnshift, g_bnshift);
    cudaGetSymbolAddress((void**)&z, g_z);
    cudaGetSymbolAddress((void**)&zf, g_zf);

    size_t smem_bytes = SMEM_FLOATS * sizeof(float);
    static bool attr_done = false;
    if (!attr_done) {
        cudaFuncSetAttribute(tf32gemm<false, false, true>,
                             cudaFuncAttributeMaxDynamicSharedMemorySize, (int)smem_bytes);
        cudaFuncSetAttribute(tf32gemm<true, true, false>,
                             cudaFuncAttributeMaxDynamicSharedMemorySize, (int)smem_bytes);
        cudaFuncSetAttribute(tf32gemm<true, false, false>,
                             cudaFuncAttributeMaxDynamicSharedMemorySize, (int)smem_bytes);
        attr_done = true;
    }

    auto gemm = [&](const float* A, const float* B, const float* bias, float* C,
                    int M, int Nc, int K, int lda, int ldc, bool relu) {
        dim3 grid(Nc / 128, (M + 127) / 128);
        if (relu) sgemm<true><<<grid, 256>>>(A, B, bias, C, M, Nc, K, lda, ldc);
        else      sgemm<false><<<grid, 256>>>(A, B, bias, C, M, Nc, K, lda, ldc);
    };

    auto bnstats = [&](const float* Xp, int rows, int K, const float* gg,
                       const float* bb) {
        cudaMemsetAsync(bnsum, 0, K * sizeof(float));
        cudaMemsetAsync(bnsq, 0, K * sizeof(float));
        dim3 g1(K / 128, 128);
        bn_stats<<<g1, 128>>>(Xp, rows, K, bnsum, bnsq);
        bn_finalize<<<(K + 127) / 128, 128>>>(bnsum, bnsq, gg, bb, rows, K,
                                              bnscale, bnshift);
    };

    // ---- CSR build (dst-sorted), reused by GAT1/GAT2/GCN; graph boundaries
    cudaMemsetAsync(degi, 0, n * sizeof(int));
    deg_build<<<(Etot + 255) / 256, 256>>>(ei, E, Etot, degi);
    scan_kernel<<<1, 1024>>>(degi, rowptr, cursor, n);
    csr_scatter<<<(Etot + 255) / 256, 256>>>(ei, E, Etot, cursor, csrsrc);
    dinv_kernel<<<(n + 255) / 256, 256>>>(rowptr, dinv, n);
    gstart_build<<<(n + 256) / 256, 256>>>(batch, n, G, gstart);

    // ---- GAT layer 1 (input-space): alphas exact via u=W1·a; gather x; GEMM
    uv_build<<<(64 * 4 * 32 + 255) / 256, 256>>>(W1, a1s, a1d, 64, 128, uu, vv);
    alpha_gemm64<<<(n + 7) / 8, 256>>>(x, n, uu, vv, alS, alD);
    gat_agg_in64<<<n, 64>>>(rowptr, csrsrc, alS, alD, x, bufA);
    {
        dim3 grid(4, (n + 127) / 128);
        tf32gemm<false, false, true><<<grid, 256, smem_bytes>>>(
            bufA, W1, bufB, n, 512, 64, 256, 512, 512,
            nullptr, nullptr, nullptr, nullptr, 128, nullptr, nullptr);
    }
    bnstats(bufB, n, 512, bn1g, bn1b);

    // ---- GAT layer 2: bufC = relu(bn(bufB))@W2 (+ fused alphas); gather -> bufA
    cudaMemsetAsync(alS, 0, (size_t)n * 4 * sizeof(float));
    cudaMemsetAsync(alD, 0, (size_t)n * 4 * sizeof(float));
    {
        dim3 grid(8, (n + 127) / 128);
        tf32gemm<true, true, false><<<grid, 256, smem_bytes>>>(
            bufB, W2, bufC, n, 1024, 512, 512, 1024, 1024,
            bnscale, bnshift, a2s, a2d, 256, alS, alD);
    }
    {
        dim3 grid(n, 2);
        gat_gather<1024, 2><<<grid, 128>>>(rowptr, csrsrc, alS, alD, bufC, bufA);
    }
    bnstats(bufA, n, 1024, bn2g, bn2b);

    // ---- GCN: bufB[N,256] = relu(bn(bufA))@Wg; gather -> bufC; BN stats
    {
        dim3 grid(2, (n + 127) / 128);
        tf32gemm<true, false, false><<<grid, 256, smem_bytes>>>(
            bufA, Wg, bufB, n, 256, 1024, 1024, 256, 256,
            bnscale, bnshift, nullptr, nullptr, 256, nullptr, nullptr);
    }
    gcn_gather<<<n, 64>>>(rowptr, csrsrc, dinv, bufB, bufC);
    bnstats(bufC, n, 256, bn3g, bn3b);

    // ---- Pooling into z[G,640] (block per graph; BN+relu on the fly)
    pool_graph<<<G, 256>>>(bufC, gstart, bnscale, bnshift, z);

    // ---- solvent MLP: relu(fp @ Ws + bs) -> z[:,512:640]
    gemm(fp, Ws, bs, z + 512, G, 128, 128, 128, 640, true);

    // ---- head: zf = z @ Wf1 (bf1 cancels under BN); BN; relu; sigmoid
    gemm(z, Wf1, nullptr, zf, G, 128, 640, 640, 128, false);
    {
        cudaMemsetAsync(bnsum, 0, 128 * sizeof(float));
        cudaMemsetAsync(bnsq, 0, 128 * sizeof(float));
        dim3 g1(1, 128);
        bn_stats<<<g1, 128>>>(zf, G, 128, bnsum, bnsq);
        bn_finalize<<<1, 128>>>(bnsum, bnsq, bnfg, bnfb, G, 128, bnscale, bnshift);
        bn_apply_relu<<<((size_t)G * 128 + 255) / 256, 256>>>(zf, bnscale, bnshift,
                                                              (size_t)G * 128, 128);
    }
    head_final<<<G, 128>>>(zf, Wf2, bf2, out);
}

// round 10
// speedup vs baseline: 1.0954x; 1.0954x over previous
#include <cuda_runtime.h>
#include <math.h>
#include <stdint.h>

// Problem capacities (fixed shapes per reference)
#define NMAXN 50000
#define EMAXE 200000
#define ETOTMAX (EMAXE + NMAXN)
#define GMAXG 1000

// ---------------- scratch (static device memory; no allocations allowed) ----
__device__ float g_bufA[(size_t)NMAXN * 1024];
__device__ float g_bufB[(size_t)NMAXN * 1024];
__device__ float g_bufC[(size_t)NMAXN * 1024];
__device__ float g_alS[NMAXN * 4];
__device__ float g_alD[NMAXN * 4];
__device__ float g_u[512 * 4];
__device__ float g_v[512 * 4];
__device__ int   g_degi[NMAXN];
__device__ int   g_incl[NMAXN];
__device__ int   g_part[128];
__device__ int   g_rowptr[NMAXN + 1];
__device__ int   g_cursor[NMAXN];
__device__ int   g_csrsrc[ETOTMAX];
__device__ float g_dinv[NMAXN];
__device__ int   g_gstart[GMAXG + 1];
__device__ float g_bnsum[1024];
__device__ float g_bnsq[1024];
__device__ float g_bnscale[1024];
__device__ float g_bnshift[1024];
__device__ float g_z[GMAXG * 640];
__device__ float g_zf[GMAXG * 128];

// ---------------- CSR build -------------------------------------------------
__global__ void deg_build(const int* __restrict__ ei, int E, int Etot,
                          int* __restrict__ degi)
{
    int e = blockIdx.x * blockDim.x + threadIdx.x;
    if (e >= Etot) return;
    int d = (e < E) ? ei[E + e] : (e - E);
    atomicAdd(degi + d, 1);
}

// phase 1: per-block inclusive scan of 1024 elements; block totals to part[]
__global__ __launch_bounds__(1024) void scan_partial(
    const int* __restrict__ degi, int n, int* __restrict__ incl,
    int* __restrict__ part)
{
    __shared__ int sm[32];
    int tid = threadIdx.x;
    int lane = tid & 31, w = tid >> 5;
    int i = blockIdx.x * 1024 + tid;
    int v = (i < n) ? degi[i] : 0;
    int x = v;
#pragma unroll
    for (int o = 1; o < 32; o <<= 1) {
        int y = __shfl_up_sync(0xFFFFFFFFu, x, o);
        if (lane >= o) x += y;
    }
    if (lane == 31) sm[w] = x;
    __syncthreads();
    if (w == 0) {
        int y = sm[lane];
#pragma unroll
        for (int o = 1; o < 32; o <<= 1) {
            int z = __shfl_up_sync(0xFFFFFFFFu, y, o);
            if (lane >= o) y += z;
        }
        sm[lane] = y;
    }
    __syncthreads();
    int inclv = x + (w ? sm[w - 1] : 0);
    if (i < n) incl[i] = inclv;
    if (tid == 1023) part[blockIdx.x] = inclv;
}

// phase 2: exclusive scan of block totals (nb <= 128, trivial)
__global__ void scan_roots(int* __restrict__ part, int nb)
{
    __shared__ int sm[128];
    int t = threadIdx.x;
    sm[t] = (t < nb) ? part[t] : 0;
    __syncthreads();
    if (t == 0) {
        int run = 0;
        for (int i = 0; i < nb; i++) { int v = sm[i]; sm[i] = run; run += v; }
    }
    __syncthreads();
    if (t < nb) part[t] = sm[t];
}

// phase 3: finalize rowptr/cursor, compute dinv, write rowptr[n]
__global__ void scan_add(const int* __restrict__ incl, const int* __restrict__ degi,
                         const int* __restrict__ part, int n, int Etot,
                         int* __restrict__ rowptr, int* __restrict__ cursor,
                         float* __restrict__ dinv)
{
    int i = blockIdx.x * blockDim.x + threadIdx.x;
    if (i == 0) rowptr[n] = Etot;
    if (i >= n) return;
    int dg = degi[i];
    int exc = incl[i] + part[i >> 10] - dg;
    rowptr[i] = exc;
    cursor[i] = exc;
    dinv[i] = rsqrtf(fmaxf((float)dg, 1.0f));
}

__global__ void csr_scatter(const int* __restrict__ ei, int E, int Etot,
                            int* __restrict__ cursor, int* __restrict__ csrsrc)
{
    int e = blockIdx.x * blockDim.x + threadIdx.x;
    if (e >= Etot) return;
    int s, d;
    if (e < E) { s = ei[e]; d = ei[E + e]; }
    else       { s = e - E; d = e - E; }
    int pos = atomicAdd(cursor + d, 1);
    csrsrc[pos] = s;
}

// graph boundaries from sorted batch
__global__ void gstart_build(const int* __restrict__ batch, int n, int G,
                             int* __restrict__ gstart)
{
    int i = blockIdx.x * blockDim.x + threadIdx.x;
    if (i < n) {
        int b = batch[i];
        int bp = (i > 0) ? batch[i - 1] : -1;
        for (int g = bp + 1; g <= b; g++) gstart[g] = i;
    } else if (i == n) {
        int bl = batch[n - 1];
        for (int g = bl + 1; g <= G; g++) gstart[g] = n;
    }
}

// ---------------- u/v vectors: u[k,h] = sum_c W[k,hC+c]*a[h,c] ---------------
__global__ void uv_build(const float* __restrict__ W, const float* __restrict__ aS,
                         const float* __restrict__ aD, int K, int C,
                         float* __restrict__ u, float* __restrict__ v)
{
    int idx = blockIdx.x * blockDim.x + threadIdx.x;
    int warp = idx >> 5, lane = idx & 31;
    if (warp >= K * 4) return;
    int k = warp >> 2, h = warp & 3;
    const float* wrow = W + (size_t)k * (4 * C) + h * C;
    const float* as = aS + h * C;
    const float* ad = aD + h * C;
    float s = 0.f, d = 0.f;
    for (int c = lane; c < C; c += 32) {
        float wv = wrow[c];
        s += wv * as[c];
        d += wv * ad[c];
    }
#pragma unroll
    for (int o = 16; o; o >>= 1) {
        s += __shfl_xor_sync(0xFFFFFFFFu, s, o);
        d += __shfl_xor_sync(0xFFFFFFFFu, d, o);
    }
    if (lane == 0) { u[k * 4 + h] = s; v[k * 4 + h] = d; }
}

// ---------------- skinny alpha GEMM (layer 1, K=64, fp32 exact) --------------
__global__ __launch_bounds__(256) void alpha_gemm64(
    const float* __restrict__ in, int n,
    const float* __restrict__ u, const float* __restrict__ v,
    float* __restrict__ alS, float* __restrict__ alD)
{
    __shared__ float su[64][4];
    __shared__ float sv[64][4];
    int tid = threadIdx.x;
    if (tid < 64 * 4) { su[tid >> 2][tid & 3] = u[tid]; sv[tid >> 2][tid & 3] = v[tid]; }
    __syncthreads();

    int warp = tid >> 5, lane = tid & 31;
    for (int node = blockIdx.x * 8 + warp; node < n; node += gridDim.x * 8) {
        const float* row = in + (size_t)node * 64;
        float x0 = row[lane], x1 = row[lane + 32];
        float as[4], ad[4];
#pragma unroll
        for (int h = 0; h < 4; h++) {
            as[h] = x0 * su[lane][h] + x1 * su[lane + 32][h];
            ad[h] = x0 * sv[lane][h] + x1 * sv[lane + 32][h];
        }
#pragma unroll
        for (int h = 0; h < 4; h++) {
#pragma unroll
            for (int o = 16; o; o >>= 1) {
                as[h] += __shfl_xor_sync(0xFFFFFFFFu, as[h], o);
                ad[h] += __shfl_xor_sync(0xFFFFFFFFu, ad[h], o);
            }
        }
        if (lane == 0) {
            *(float4*)(alS + (size_t)node * 4) = make_float4(as[0], as[1], as[2], as[3]);
            *(float4*)(alD + (size_t)node * 4) = make_float4(ad[0], ad[1], ad[2], ad[3]);
        }
    }
}

// ---------------- TF32 tensor-core GEMM (cp.async double-buffered) -----------
__device__ __forceinline__ void mma_tf32(float c[4], const float a[4], const float b[2]) {
    asm volatile(
        "mma.sync.aligned.m16n8k8.row.col.f32.tf32.tf32.f32 "
        "{%0,%1,%2,%3}, {%4,%5,%6,%7}, {%8,%9}, {%0,%1,%2,%3};"
        : "+f"(c[0]), "+f"(c[1]), "+f"(c[2]), "+f"(c[3])
        : "r"(__float_as_uint(a[0])), "r"(__float_as_uint(a[1])),
          "r"(__float_as_uint(a[2])), "r"(__float_as_uint(a[3])),
          "r"(__float_as_uint(b[0])), "r"(__float_as_uint(b[1])));
}

__device__ __forceinline__ void cp_async16(float* smem_dst, const float* gmem_src,
                                           bool pred) {
    uint32_t saddr = (uint32_t)__cvta_generic_to_shared(smem_dst);
    int sz = pred ? 16 : 0;
    asm volatile("cp.async.cg.shared.global [%0], [%1], 16, %2;\n"
                 :: "r"(saddr), "l"(gmem_src), "r"(sz));
}

#define ABUF 4608
#define BBUF 4352
#define SMEM_FLOATS (2 * ABUF + 2 * BBUF)

// C[M,Nc] = op(A)[M,K] @ B[K,Nc]; op = relu(bn) if BNRELU.
// GROUP: A base shifts by (blockN/128)*K columns (head-blocked input).
// ALPHA: accumulates alS/alD[row*4+head] += sum_col C*aS/aD.
template <bool BNRELU, bool ALPHA, bool GROUP>
__global__ __launch_bounds__(256, 2) void tf32gemm(
    const float* __restrict__ A, const float* __restrict__ B,
    float* __restrict__ C, int M, int Nc, int K,
    int lda, int ldb, int ldc,
    const float* __restrict__ scale, const float* __restrict__ shift,
    const float* __restrict__ aS, const float* __restrict__ aD, int Chead,
    float* __restrict__ alS, float* __restrict__ alD)
{
    extern __shared__ float smem[];

    int tid = threadIdx.x;
    int lane = tid & 31;
    int wid = tid >> 5;
    int warpM = (wid >> 2) * 64;
    int warpN = (wid & 3) * 32;
    int r = lane >> 2;
    int cq = lane & 3;

    int blockM = blockIdx.y * 128;
    int blockN = blockIdx.x * 128;

    if (GROUP) A += (size_t)(blockN >> 7) * K;

    int acol = (tid & 7) * 4;
    int arow0 = tid >> 3;
    int bcol = (tid & 31) * 4;
    int brow0 = tid >> 5;

    float acc[4][4][4];
#pragma unroll
    for (int mt = 0; mt < 4; mt++)
#pragma unroll
        for (int nt = 0; nt < 4; nt++)
#pragma unroll
            for (int i = 0; i < 4; i++) acc[mt][nt][i] = 0.0f;

    int nk = K >> 5;

    auto load_tile = [&](int k0, int buf) {
        float* As = smem + buf * ABUF;
        float* Bs = smem + 2 * ABUF + buf * BBUF;
#pragma unroll
        for (int i = 0; i < 4; i++) {
            int row = blockM + arow0 + i * 32;
            cp_async16(&As[(arow0 + i * 32) * 36 + acol],
                       A + (size_t)row * lda + k0 + acol, row < M);
        }
#pragma unroll
        for (int i = 0; i < 4; i++) {
            int kr = brow0 + i * 8;
            cp_async16(&Bs[kr * 136 + bcol],
                       B + (size_t)(k0 + kr) * ldb + blockN + bcol, true);
        }
        asm volatile("cp.async.commit_group;\n");
    };

    load_tile(0, 0);

    for (int kt = 0; kt < nk; kt++) {
        if (kt + 1 < nk) {
            load_tile((kt + 1) << 5, (kt + 1) & 1);
            asm volatile("cp.async.wait_group 1;\n");
        } else {
            asm volatile("cp.async.wait_group 0;\n");
        }
        __syncthreads();

        const float* As = smem + (kt & 1) * ABUF;
        const float* Bs = smem + 2 * ABUF + (kt & 1) * BBUF;
        int k0 = kt << 5;

        float scv[8], shv[8];
        if (BNRELU) {
#pragma unroll
            for (int kk = 0; kk < 4; kk++) {
                scv[kk]     = scale[k0 + kk * 8 + cq];
                scv[kk + 4] = scale[k0 + kk * 8 + cq + 4];
                shv[kk]     = shift[k0 + kk * 8 + cq];
                shv[kk + 4] = shift[k0 + kk * 8 + cq + 4];
            }
        }

#pragma unroll
        for (int kk = 0; kk < 4; kk++) {
            int kb = kk * 8;
            float a[4][4], b[4][2];
#pragma unroll
            for (int mt = 0; mt < 4; mt++) {
                int m = warpM + mt * 16 + r;
                float a0 = As[m * 36 + kb + cq];
                float a1 = As[(m + 8) * 36 + kb + cq];
                float a2 = As[m * 36 + kb + cq + 4];
                float a3 = As[(m + 8) * 36 + kb + cq + 4];
                if (BNRELU) {
                    a0 = fmaxf(fmaf(a0, scv[kk], shv[kk]), 0.f);
                    a1 = fmaxf(fmaf(a1, scv[kk], shv[kk]), 0.f);
                    a2 = fmaxf(fmaf(a2, scv[kk + 4], shv[kk + 4]), 0.f);
                    a3 = fmaxf(fmaf(a3, scv[kk + 4], shv[kk + 4]), 0.f);
                }
                a[mt][0] = a0; a[mt][1] = a1; a[mt][2] = a2; a[mt][3] = a3;
            }
#pragma unroll
            for (int nt = 0; nt < 4; nt++) {
                int nn = warpN + nt * 8 + r;
                b[nt][0] = Bs[(kb + cq) * 136 + nn];
                b[nt][1] = Bs[(kb + cq + 4) * 136 + nn];
            }
#pragma unroll
            for (int mt = 0; mt < 4; mt++)
#pragma unroll
                for (int nt = 0; nt < 4; nt++)
                    mma_tf32(acc[mt][nt], a[mt], b[nt]);
        }
        __syncthreads();
    }

#pragma unroll
    for (int mt = 0; mt < 4; mt++) {
        int row0 = blockM + warpM + mt * 16 + r;
#pragma unroll
        for (int nt = 0; nt < 4; nt++) {
            int col = blockN + warpN + nt * 8 + cq * 2;
            if (row0 < M)
                *(float2*)(C + (size_t)row0 * ldc + col) =
                    make_float2(acc[mt][nt][0], acc[mt][nt][1]);
            if (row0 + 8 < M)
                *(float2*)(C + (size_t)(row0 + 8) * ldc + col) =
                    make_float2(acc[mt][nt][2], acc[mt][nt][3]);
        }
    }

    if (ALPHA) {
        int head = blockN / Chead;
        float ws[4][2], wd[4][2];
#pragma unroll
        for (int nt = 0; nt < 4; nt++) {
            int col = blockN + warpN + nt * 8 + cq * 2;
            int c = col - head * Chead;
            ws[nt][0] = aS[head * Chead + c];
            ws[nt][1] = aS[head * Chead + c + 1];
            wd[nt][0] = aD[head * Chead + c];
            wd[nt][1] = aD[head * Chead + c + 1];
        }
#pragma unroll
        for (int mt = 0; mt < 4; mt++) {
            float ps0 = 0.f, pd0 = 0.f, ps1 = 0.f, pd1 = 0.f;
#pragma unroll
            for (int nt = 0; nt < 4; nt++) {
                ps0 += acc[mt][nt][0] * ws[nt][0] + acc[mt][nt][1] * ws[nt][1];
                pd0 += acc[mt][nt][0] * wd[nt][0] + acc[mt][nt][1] * wd[nt][1];
                ps1 += acc[mt][nt][2] * ws[nt][0] + acc[mt][nt][3] * ws[nt][1];
                pd1 += acc[mt][nt][2] * wd[nt][0] + acc[mt][nt][3] * wd[nt][1];
            }
#pragma unroll
            for (int o = 1; o < 4; o <<= 1) {
                ps0 += __shfl_xor_sync(0xFFFFFFFFu, ps0, o);
                pd0 += __shfl_xor_sync(0xFFFFFFFFu, pd0, o);
                ps1 += __shfl_xor_sync(0xFFFFFFFFu, ps1, o);
                pd1 += __shfl_xor_sync(0xFFFFFFFFu, pd1, o);
            }
            if (cq == 0) {
                int row0 = blockM + warpM + mt * 16 + r;
                if (row0 < M) {
                    atomicAdd(alS + (size_t)row0 * 4 + head, ps0);
                    atomicAdd(alD + (size_t)row0 * 4 + head, pd0);
                }
                if (row0 + 8 < M) {
                    atomicAdd(alS + (size_t)(row0 + 8) * 4 + head, ps1);
                    atomicAdd(alD + (size_t)(row0 + 8) * 4 + head, pd1);
                }
            }
        }
    }
}

// ---------------- fp32 SGEMM (solvent MLP: bias+relu) ------------------------
template <bool RELU>
__global__ __launch_bounds__(256) void sgemm(
    const float* __restrict__ A, const float* __restrict__ B,
    const float* __restrict__ bias, float* __restrict__ C,
    int M, int Nc, int K, int lda, int ldc)
{
    __shared__ float As[8][128];
    __shared__ float Bs[8][128];

    int tid = threadIdx.x;
    int bx = blockIdx.x;
    int by = blockIdx.y;

    int tx = tid % 16;
    int ty = tid / 16;

    int rowA = by * 128 + tid / 2;
    int colA = (tid % 2) * 4;
    int rowB = tid / 32;
    int colB = (tid % 32) * 4;

    float acc[8][8];
#pragma unroll
    for (int i = 0; i < 8; i++)
#pragma unroll
        for (int j = 0; j < 8; j++) acc[i][j] = 0.0f;

    for (int k0 = 0; k0 < K; k0 += 8) {
        float4 av = make_float4(0.f, 0.f, 0.f, 0.f);
        if (rowA < M)
            av = *(const float4*)(A + (size_t)rowA * lda + k0 + colA);
        As[colA + 0][tid / 2] = av.x;
        As[colA + 1][tid / 2] = av.y;
        As[colA + 2][tid / 2] = av.z;
        As[colA + 3][tid / 2] = av.w;

        float4 bv = *(const float4*)(B + (size_t)(k0 + rowB) * Nc + bx * 128 + colB);
        *(float4*)(&Bs[rowB][colB]) = bv;

        __syncthreads();

#pragma unroll
        for (int kk = 0; kk < 8; kk++) {
            float ra[8], rb[8];
#pragma unroll
            for (int i = 0; i < 8; i++) ra[i] = As[kk][ty * 8 + i];
#pragma unroll
            for (int j = 0; j < 8; j++) rb[j] = Bs[kk][tx * 8 + j];
#pragma unroll
            for (int i = 0; i < 8; i++)
#pragma unroll
                for (int j = 0; j < 8; j++) acc[i][j] = fmaf(ra[i], rb[j], acc[i][j]);
        }
        __syncthreads();
    }

#pragma unroll
    for (int i = 0; i < 8; i++) {
        int row = by * 128 + ty * 8 + i;
        if (row >= M) continue;
#pragma unroll
        for (int j = 0; j < 8; j++) {
            int col = bx * 128 + tx * 8 + j;
            float v = acc[i][j];
            if (bias) v += bias[col];
            if (RELU) v = v > 0.f ? v : 0.f;
            C[(size_t)row * ldc + col] = v;
        }
    }
}

// ---- GAT layer 1 input-space gather: agg[d, h*64+c] = sum alpha*x[src,c] ----
__global__ __launch_bounds__(64) void gat_agg_in64(
    const int* __restrict__ rowptr, const int* __restrict__ csrsrc,
    const float* __restrict__ alS, const float* __restrict__ alD,
    const float* __restrict__ in, float* __restrict__ agg)
{
    constexpr int NT = 64;
    __shared__ float s_red[8];
    __shared__ float s_bm[4];
    __shared__ float s_binv[4];
    __shared__ float s_al[16][4];
    __shared__ int   s_src[16];

    int d = blockIdx.x;
    int tid = threadIdx.x;
    int lane = tid & 31, w = tid >> 5;
    int beg = rowptr[d], end = rowptr[d + 1];

    float4 ad4 = *(const float4*)(alD + (size_t)d * 4);
    float adv[4] = {ad4.x, ad4.y, ad4.z, ad4.w};

    float mx[4] = {-INFINITY, -INFINITY, -INFINITY, -INFINITY};
    for (int i = beg + tid; i < end; i += NT) {
        int s = csrsrc[i];
        float4 as4 = *(const float4*)(alS + (size_t)s * 4);
        float l[4] = {as4.x + adv[0], as4.y + adv[1], as4.z + adv[2], as4.w + adv[3]};
#pragma unroll
        for (int hh = 0; hh < 4; hh++) {
            float t = l[hh];
            t = t > 0.f ? t : 0.2f * t;
            mx[hh] = fmaxf(mx[hh], t);
        }
    }
#pragma unroll
    for (int hh = 0; hh < 4; hh++)
#pragma unroll
        for (int o = 16; o; o >>= 1)
            mx[hh] = fmaxf(mx[hh], __shfl_xor_sync(0xFFFFFFFFu, mx[hh], o));
    if (lane == 0)
#pragma unroll
        for (int hh = 0; hh < 4; hh++) s_red[w * 4 + hh] = mx[hh];
    __syncthreads();
    if (tid < 4) s_bm[tid] = fmaxf(s_red[tid], s_red[4 + tid]);
    __syncthreads();
    float bm[4] = {s_bm[0], s_bm[1], s_bm[2], s_bm[3]};

    float sme[4] = {0.f, 0.f, 0.f, 0.f};
    for (int i = beg + tid; i < end; i += NT) {
        int s = csrsrc[i];
        float4 as4 = *(const float4*)(alS + (size_t)s * 4);
        float l[4] = {as4.x + adv[0], as4.y + adv[1], as4.z + adv[2], as4.w + adv[3]};
#pragma unroll
        for (int hh = 0; hh < 4; hh++) {
            float t = l[hh];
            t = t > 0.f ? t : 0.2f * t;
            sme[hh] += expf(t - bm[hh]);
        }
    }
#pragma unroll
    for (int hh = 0; hh < 4; hh++)
#pragma unroll
        for (int o = 16; o; o >>= 1)
            sme[hh] += __shfl_xor_sync(0xFFFFFFFFu, sme[hh], o);
    if (lane == 0)
#pragma unroll
        for (int hh = 0; hh < 4; hh++) s_red[w * 4 + hh] = sme[hh];
    __syncthreads();
    if (tid < 4) s_binv[tid] = 1.0f / fmaxf(s_red[tid] + s_red[4 + tid], 1e-16f);
    __syncthreads();

    float acc[4] = {0.f, 0.f, 0.f, 0.f};
    for (int c0 = beg; c0 < end; c0 += 16) {
        int cnt = min(16, end - c0);
        if (tid < cnt * 4) {
            int j = tid >> 2, hh = tid & 3;
            int s = csrsrc[c0 + j];
            if (hh == 0) s_src[j] = s;
            float t = alS[(size_t)s * 4 + hh] + adv[hh];
            t = t > 0.f ? t : 0.2f * t;
            s_al[j][hh] = expf(t - s_bm[hh]) * s_binv[hh];
        }
        __syncthreads();
        int j = 0;
        for (; j + 4 <= cnt; j += 4) {
            float v0 = in[(size_t)s_src[j + 0] * 64 + tid];
            float v1 = in[(size_t)s_src[j + 1] * 64 + tid];
            float v2 = in[(size_t)s_src[j + 2] * 64 + tid];
            float v3 = in[(size_t)s_src[j + 3] * 64 + tid];
#pragma unroll
            for (int hh = 0; hh < 4; hh++) {
                acc[hh] = fmaf(s_al[j + 0][hh], v0, acc[hh]);
                acc[hh] = fmaf(s_al[j + 1][hh], v1, acc[hh]);
                acc[hh] = fmaf(s_al[j + 2][hh], v2, acc[hh]);
                acc[hh] = fmaf(s_al[j + 3][hh], v3, acc[hh]);
            }
        }
        for (; j < cnt; j++) {
            float v = in[(size_t)s_src[j] * 64 + tid];
#pragma unroll
            for (int hh = 0; hh < 4; hh++)
                acc[hh] = fmaf(s_al[j][hh], v, acc[hh]);
        }
        __syncthreads();
    }

#pragma unroll
    for (int hh = 0; hh < 4; hh++)
        agg[(size_t)d * 256 + hh * 64 + tid] = acc[hh];
}

// ---- fused per-destination GAT softmax + gather (output space) --------------
template <int HC, int SPLIT>
__global__ __launch_bounds__(128) void gat_gather(
    const int* __restrict__ rowptr, const int* __restrict__ csrsrc,
    const float* __restrict__ alS, const float* __restrict__ alD,
    const float* __restrict__ h, float* __restrict__ out)
{
    constexpr int NT = 128;
    constexpr int HCW = HC / SPLIT;
    static_assert(HCW == 4 * NT, "one float4 per thread");
    constexpr int CPH = HC / 4;

    __shared__ float s_red[16];
    __shared__ float s_bm[4];
    __shared__ float s_binv[4];
    __shared__ float s_al[32][4];
    __shared__ int   s_src[32];

    int d = blockIdx.x;
    int half = (SPLIT > 1) ? blockIdx.y : 0;
    int coff = half * HCW;
    int tid = threadIdx.x;
    int lane = tid & 31, w = tid >> 5;
    int beg = rowptr[d], end = rowptr[d + 1];

    float4 ad4 = *(const float4*)(alD + (size_t)d * 4);
    float adv[4] = {ad4.x, ad4.y, ad4.z, ad4.w};

    float mx[4] = {-INFINITY, -INFINITY, -INFINITY, -INFINITY};
    for (int i = beg + tid; i < end; i += NT) {
        int s = csrsrc[i];
        float4 as4 = *(const float4*)(alS + (size_t)s * 4);
        float l[4] = {as4.x + adv[0], as4.y + adv[1], as4.z + adv[2], as4.w + adv[3]};
#pragma unroll
        for (int hh = 0; hh < 4; hh++) {
            float t = l[hh];
            t = t > 0.f ? t : 0.2f * t;
            mx[hh] = fmaxf(mx[hh], t);
        }
    }
#pragma unroll
    for (int hh = 0; hh < 4; hh++)
#pragma unroll
        for (int o = 16; o; o >>= 1)
            mx[hh] = fmaxf(mx[hh], __shfl_xor_sync(0xFFFFFFFFu, mx[hh], o));
    if (lane == 0)
#pragma unroll
        for (int hh = 0; hh < 4; hh++) s_red[w * 4 + hh] = mx[hh];
    __syncthreads();
    if (tid < 4) {
        float r = fmaxf(fmaxf(s_red[tid], s_red[4 + tid]),
                        fmaxf(s_red[8 + tid], s_red[12 + tid]));
        s_bm[tid] = r;
    }
    __syncthreads();
    float bm[4] = {s_bm[0], s_bm[1], s_bm[2], s_bm[3]};

    float sme[4] = {0.f, 0.f, 0.f, 0.f};
    for (int i = beg + tid; i < end; i += NT) {
        int s = csrsrc[i];
        float4 as4 = *(const float4*)(alS + (size_t)s * 4);
        float l[4] = {as4.x + adv[0], as4.y + adv[1], as4.z + adv[2], as4.w + adv[3]};
#pragma unroll
        for (int hh = 0; hh < 4; hh++) {
            float t = l[hh];
            t = t > 0.f ? t : 0.2f * t;
            sme[hh] += expf(t - bm[hh]);
        }
    }
#pragma unroll
    for (int hh = 0; hh < 4; hh++)
#pragma unroll
        for (int o = 16; o; o >>= 1)
            sme[hh] += __shfl_xor_sync(0xFFFFFFFFu, sme[hh], o);
    if (lane == 0)
#pragma unroll
        for (int hh = 0; hh < 4; hh++) s_red[w * 4 + hh] = sme[hh];
    __syncthreads();
    if (tid < 4) {
        float r = s_red[tid] + s_red[4 + tid] + s_red[8 + tid] + s_red[12 + tid];
        s_binv[tid] = 1.0f / fmaxf(r, 1e-16f);
    }
    __syncthreads();

    float4 acc = make_float4(0.f, 0.f, 0.f, 0.f);
    int hof = (coff + tid * 4) / CPH;

    for (int c0 = beg; c0 < end; c0 += 32) {
        int cnt = min(32, end - c0);
        if (tid < cnt * 4) {
            int j = tid >> 2, hh = tid & 3;
            int s = csrsrc[c0 + j];
            if (hh == 0) s_src[j] = s;
            float t = alS[(size_t)s * 4 + hh] + adv[hh];
            t = t > 0.f ? t : 0.2f * t;
            s_al[j][hh] = expf(t - s_bm[hh]) * s_binv[hh];
        }
        __syncthreads();
        int j = 0;
        for (; j + 4 <= cnt; j += 4) {
            const float4* p0 = (const float4*)(h + (size_t)s_src[j + 0] * HC + coff);
            const float4* p1 = (const float4*)(h + (size_t)s_src[j + 1] * HC + coff);
            const float4* p2 = (const float4*)(h + (size_t)s_src[j + 2] * HC + coff);
            const float4* p3 = (const float4*)(h + (size_t)s_src[j + 3] * HC + coff);
            float4 v0 = p0[tid];
            float4 v1 = p1[tid];
            float4 v2 = p2[tid];
            float4 v3 = p3[tid];
            float a0 = s_al[j + 0][hof];
            float a1 = s_al[j + 1][hof];
            float a2 = s_al[j + 2][hof];
            float a3 = s_al[j + 3][hof];
            acc.x = fmaf(a0, v0.x, acc.x); acc.y = fmaf(a0, v0.y, acc.y);
            acc.z = fmaf(a0, v0.z, acc.z); acc.w = fmaf(a0, v0.w, acc.w);
            acc.x = fmaf(a1, v1.x, acc.x); acc.y = fmaf(a1, v1.y, acc.y);
            acc.z = fmaf(a1, v1.z, acc.z); acc.w = fmaf(a1, v1.w, acc.w);
            acc.x = fmaf(a2, v2.x, acc.x); acc.y = fmaf(a2, v2.y, acc.y);
            acc.z = fmaf(a2, v2.z, acc.z); acc.w = fmaf(a2, v2.w, acc.w);
            acc.x = fmaf(a3, v3.x, acc.x); acc.y = fmaf(a3, v3.y, acc.y);
            acc.z = fmaf(a3, v3.z, acc.z); acc.w = fmaf(a3, v3.w, acc.w);
        }
        for (; j < cnt; j++) {
            const float4* hp = (const float4*)(h + (size_t)s_src[j] * HC + coff);
            float a = s_al[j][hof];
            float4 hv = hp[tid];
            acc.x = fmaf(a, hv.x, acc.x);
            acc.y = fmaf(a, hv.y, acc.y);
            acc.z = fmaf(a, hv.z, acc.z);
            acc.w = fmaf(a, hv.w, acc.w);
        }
        __syncthreads();
    }

    float4* op = (float4*)(out + (size_t)d * HC + coff);
    op[tid] = acc;
}

// ---------------- GCN gather (4-way edge unroll, MLP=4) ----------------------
__global__ __launch_bounds__(64) void gcn_gather(
    const int* __restrict__ rowptr, const int* __restrict__ csrsrc,
    const float* __restrict__ dinv, const float* __restrict__ h,
    float* __restrict__ out)
{
    int d = blockIdx.x;
    int tid = threadIdx.x;
    int beg = rowptr[d], end = rowptr[d + 1];
    float dd = dinv[d];

    float4 acc = make_float4(0.f, 0.f, 0.f, 0.f);
    int i = beg;
    for (; i + 4 <= end; i += 4) {
        int s0 = csrsrc[i + 0], s1 = csrsrc[i + 1];
        int s2 = csrsrc[i + 2], s3 = csrsrc[i + 3];
        float n0 = dinv[s0] * dd, n1 = dinv[s1] * dd;
        float n2 = dinv[s2] * dd, n3 = dinv[s3] * dd;
        float4 v0 = *(const float4*)(h + (size_t)s0 * 256 + tid * 4);
        float4 v1 = *(const float4*)(h + (size_t)s1 * 256 + tid * 4);
        float4 v2 = *(const float4*)(h + (size_t)s2 * 256 + tid * 4);
        float4 v3 = *(const float4*)(h + (size_t)s3 * 256 + tid * 4);
        acc.x = fmaf(n0, v0.x, acc.x); acc.y = fmaf(n0, v0.y, acc.y);
        acc.z = fmaf(n0, v0.z, acc.z); acc.w = fmaf(n0, v0.w, acc.w);
        acc.x = fmaf(n1, v1.x, acc.x); acc.y = fmaf(n1, v1.y, acc.y);
        acc.z = fmaf(n1, v1.z, acc.z); acc.w = fmaf(n1, v1.w, acc.w);
        acc.x = fmaf(n2, v2.x, acc.x); acc.y = fmaf(n2, v2.y, acc.y);
        acc.z = fmaf(n2, v2.z, acc.z); acc.w = fmaf(n2, v2.w, acc.w);
        acc.x = fmaf(n3, v3.x, acc.x); acc.y = fmaf(n3, v3.y, acc.y);
        acc.z = fmaf(n3, v3.z, acc.z); acc.w = fmaf(n3, v3.w, acc.w);
    }
    for (; i < end; i++) {
        int s = csrsrc[i];
        float nrm = dinv[s] * dd;
        float4 v = *(const float4*)(h + (size_t)s * 256 + tid * 4);
        acc.x = fmaf(nrm, v.x, acc.x);
        acc.y = fmaf(nrm, v.y, acc.y);
        acc.z = fmaf(nrm, v.z, acc.z);
        acc.w = fmaf(nrm, v.w, acc.w);
    }
    *(float4*)(out + (size_t)d * 256 + tid * 4) = acc;
}

// ---------------- BatchNorm -------------------------------------------------
__global__ void bn_stats(const float* __restrict__ x, int rows, int K,
                         float* __restrict__ sum, float* __restrict__ sq)
{
    int col = blockIdx.x * blockDim.x + threadIdx.x;
    float s = 0.f, q = 0.f;
    for (int r = blockIdx.y; r < rows; r += gridDim.y) {
        float v = x[(size_t)r * K + col];
        s += v;
        q += v * v;
    }
    atomicAdd(sum + col, s);
    atomicAdd(sq + col, q);
}

__global__ void bn_finalize(const float* __restrict__ sum, const float* __restrict__ sq,
                            const float* __restrict__ g, const float* __restrict__ b,
                            int rows, int K, float* __restrict__ scale,
                            float* __restrict__ shift)
{
    int c = blockIdx.x * blockDim.x + threadIdx.x;
    if (c >= K) return;
    float inv_n = 1.0f / (float)rows;
    float mu = sum[c] * inv_n;
    float var = sq[c] * inv_n - mu * mu;
    float sc = g[c] * rsqrtf(var + 1e-5f);
    scale[c] = sc;
    shift[c] = b[c] - mu * sc;
}

__global__ void bn_apply_relu(float* __restrict__ x, const float* __restrict__ scale,
                              const float* __restrict__ shift, size_t total, int K)
{
    for (size_t i = (size_t)blockIdx.x * blockDim.x + threadIdx.x; i < total;
         i += (size_t)gridDim.x * blockDim.x) {
        int c = (int)(i % K);
        float v = x[i] * scale[c] + shift[c];
        x[i] = v > 0.f ? v : 0.f;
    }
}

// ---------------- Pooling: one block per graph (batch sorted, no atomics) ----
__global__ __launch_bounds__(256) void pool_graph(
    const float* __restrict__ h, const int* __restrict__ gstart,
    const float* __restrict__ scale, const float* __restrict__ shift,
    float* __restrict__ z)
{
    int g = blockIdx.x;
    int c = threadIdx.x;
    int beg = gstart[g], end = gstart[g + 1];
    float sc = scale[c], sh = shift[c];
    float sum = 0.f, mx = 0.f;
    for (int r = beg; r < end; r++) {
        float v = fmaxf(fmaf(h[(size_t)r * 256 + c], sc, sh), 0.f);
        sum += v;
        mx = fmaxf(mx, v);
    }
    float cnt = (float)(end - beg);
    z[(size_t)g * 640 + c] = sum / fmaxf(cnt, 1.0f);
    z[(size_t)g * 640 + 256 + c] = mx;
}

// ---------------- Head -------------------------------------------------------
__global__ void head_final(const float* __restrict__ zf, const float* __restrict__ Wf2,
                           const float* __restrict__ bf2, float* __restrict__ out)
{
    int g = blockIdx.x;
    int t = threadIdx.x;
    float v = zf[(size_t)g * 128 + t] * Wf2[t];
#pragma unroll
    for (int o = 16; o; o >>= 1) v += __shfl_down_sync(0xFFFFFFFFu, v, o);
    __shared__ float sm[4];
    if ((t & 31) == 0) sm[t >> 5] = v;
    __syncthreads();
    if (t == 0) {
        float s = sm[0] + sm[1] + sm[2] + sm[3] + bf2[0];
        out[g] = 1.0f / (1.0f + expf(-s));
    }
}

// ---------------- launch ------------------------------------------------------
extern "C" void kernel_launch(void* const* d_in, const int* in_sizes, int n_in,
                              void* d_out, int out_size)
{
    const float* x    = (const float*)d_in[0];
    const int*   ei   = (const int*)d_in[1];
    const int*   batch= (const int*)d_in[2];
    const float* fp   = (const float*)d_in[3];
    const float* W1   = (const float*)d_in[4];
    const float* a1s  = (const float*)d_in[5];
    const float* a1d  = (const float*)d_in[6];
    const float* bn1g = (const float*)d_in[8];
    const float* bn1b = (const float*)d_in[9];
    const float* W2   = (const float*)d_in[10];
    const float* a2s  = (const float*)d_in[11];
    const float* a2d  = (const float*)d_in[12];
    const float* bn2g = (const float*)d_in[14];
    const float* bn2b = (const float*)d_in[15];
    const float* Wg   = (const float*)d_in[16];
    const float* bn3g = (const float*)d_in[18];
    const float* bn3b = (const float*)d_in[19];
    const float* Ws   = (const float*)d_in[20];
    const float* bs   = (const float*)d_in[21];
    const float* Wf1  = (const float*)d_in[22];
    const float* bnfg = (const float*)d_in[24];
    const float* bnfb = (const float*)d_in[25];
    const float* Wf2  = (const float*)d_in[26];
    const float* bf2  = (const float*)d_in[27];
    float* out = (float*)d_out;

    int n    = in_sizes[0] / 64;
    int E    = in_sizes[1] / 2;
    int Etot = E + n;
    int G    = in_sizes[3] / 128;

    float *bufA, *bufB, *bufC, *alS, *alD, *dinv, *uu, *vv;
    float *bnsum, *bnsq, *bnscale, *bnshift, *z, *zf;
    int *degi, *incl, *part, *rowptr, *cursor, *csrsrc, *gstart;
    cudaGetSymbolAddress((void**)&bufA, g_bufA);
    cudaGetSymbolAddress((void**)&bufB, g_bufB);
    cudaGetSymbolAddress((void**)&bufC, g_bufC);
    cudaGetSymbolAddress((void**)&alS, g_alS);
    cudaGetSymbolAddress((void**)&alD, g_alD);
    cudaGetSymbolAddress((void**)&uu, g_u);
    cudaGetSymbolAddress((void**)&vv, g_v);
    cudaGetSymbolAddress((void**)&degi, g_degi);
    cudaGetSymbolAddress((void**)&incl, g_incl);
    cudaGetSymbolAddress((void**)&part, g_part);
    cudaGetSymbolAddress((void**)&rowptr, g_rowptr);
    cudaGetSymbolAddress((void**)&cursor, g_cursor);
    cudaGetSymbolAddress((void**)&csrsrc, g_csrsrc);
    cudaGetSymbolAddress((void**)&dinv, g_dinv);
    cudaGetSymbolAddress((void**)&gstart, g_gstart);
    cudaGetSymbolAddress((void**)&bnsum, g_bnsum);
    cudaGetSymbolAddress((void**)&bnsq, g_bnsq);
    cudaGetSymbolAddress((void**)&bnscale, g_bnscale);
    cudaGetSymbolAddress((void**)&bnshift, g_bnshift);
    cudaGetSymbolAddress((void**)&z, g_z);
    cudaGetSymbolAddress((void**)&zf, g_zf);

    size_t smem_bytes = SMEM_FLOATS * sizeof(float);
    static bool attr_done = false;
    if (!attr_done) {
        cudaFuncSetAttribute(tf32gemm<false, false, true>,
                             cudaFuncAttributeMaxDynamicSharedMemorySize, (int)smem_bytes);
        cudaFuncSetAttribute(tf32gemm<true, true, false>,
                             cudaFuncAttributeMaxDynamicSharedMemorySize, (int)smem_bytes);
        cudaFuncSetAttribute(tf32gemm<true, false, false>,
                             cudaFuncAttributeMaxDynamicSharedMemorySize, (int)smem_bytes);
        cudaFuncSetAttribute(tf32gemm<false, false, false>,
                             cudaFuncAttributeMaxDynamicSharedMemorySize, (int)smem_bytes);
        attr_done = true;
    }

    auto gemm = [&](const float* A, const float* B, const float* bias, float* C,
                    int M, int Nc, int K, int lda, int ldc, bool relu) {
        dim3 grid(Nc / 128, (M + 127) / 128);
        if (relu) sgemm<true><<<grid, 256>>>(A, B, bias, C, M, Nc, K, lda, ldc);
        else      sgemm<false><<<grid, 256>>>(A, B, bias, C, M, Nc, K, lda, ldc);
    };

    auto bnstats = [&](const float* Xp, int rows, int K, const float* gg,
                       const float* bb) {
        cudaMemsetAsync(bnsum, 0, K * sizeof(float));
        cudaMemsetAsync(bnsq, 0, K * sizeof(float));
        dim3 g1(K / 128, 128);
        bn_stats<<<g1, 128>>>(Xp, rows, K, bnsum, bnsq);
        bn_finalize<<<(K + 127) / 128, 128>>>(bnsum, bnsq, gg, bb, rows, K,
                                              bnscale, bnshift);
    };

    // ---- CSR build (dst-sorted), multi-block scan; dinv fused into add pass
    cudaMemsetAsync(degi, 0, n * sizeof(int));
    deg_build<<<(Etot + 255) / 256, 256>>>(ei, E, Etot, degi);
    int nb = (n + 1023) / 1024;
    scan_partial<<<nb, 1024>>>(degi, n, incl, part);
    scan_roots<<<1, 128>>>(part, nb);
    scan_add<<<(n + 255) / 256, 256>>>(incl, degi, part, n, Etot,
                                       rowptr, cursor, dinv);
    csr_scatter<<<(Etot + 255) / 256, 256>>>(ei, E, Etot, cursor, csrsrc);
    gstart_build<<<(n + 256) / 256, 256>>>(batch, n, G, gstart);

    // ---- GAT layer 1 (input-space): alphas exact via u=W1·a; gather x; GEMM
    uv_build<<<(64 * 4 * 32 + 255) / 256, 256>>>(W1, a1s, a1d, 64, 128, uu, vv);
    alpha_gemm64<<<(n + 7) / 8, 256>>>(x, n, uu, vv, alS, alD);
    gat_agg_in64<<<n, 64>>>(rowptr, csrsrc, alS, alD, x, bufA);
    {
        dim3 grid(4, (n + 127) / 128);
        tf32gemm<false, false, true><<<grid, 256, smem_bytes>>>(
            bufA, W1, bufB, n, 512, 64, 256, 512, 512,
            nullptr, nullptr, nullptr, nullptr, 128, nullptr, nullptr);
    }
    bnstats(bufB, n, 512, bn1g, bn1b);

    // ---- GAT layer 2: bufC = relu(bn(bufB))@W2 (+ fused alphas); gather -> bufA
    cudaMemsetAsync(alS, 0, (size_t)n * 4 * sizeof(float));
    cudaMemsetAsync(alD, 0, (size_t)n * 4 * sizeof(float));
    {
        dim3 grid(8, (n + 127) / 128);
        tf32gemm<true, true, false><<<grid, 256, smem_bytes>>>(
            bufB, W2, bufC, n, 1024, 512, 512, 1024, 1024,
            bnscale, bnshift, a2s, a2d, 256, alS, alD);
    }
    {
        dim3 grid(n, 2);
        gat_gather<1024, 2><<<grid, 128>>>(rowptr, csrsrc, alS, alD, bufC, bufA);
    }
    bnstats(bufA, n, 1024, bn2g, bn2b);

    // ---- GCN: bufB[N,256] = relu(bn(bufA))@Wg; gather -> bufC; BN stats
    {
        dim3 grid(2, (n + 127) / 128);
        tf32gemm<true, false, false><<<grid, 256, smem_bytes>>>(
            bufA, Wg, bufB, n, 256, 1024, 1024, 256, 256,
            bnscale, bnshift, nullptr, nullptr, 256, nullptr, nullptr);
    }
    gcn_gather<<<n, 64>>>(rowptr, csrsrc, dinv, bufB, bufC);
    bnstats(bufC, n, 256, bn3g, bn3b);

    // ---- Pooling into z[G,640] (block per graph; BN+relu on the fly)
    pool_graph<<<G, 256>>>(bufC, gstart, bnscale, bnshift, z);

    // ---- solvent MLP: relu(fp @ Ws + bs) -> z[:,512:640]
    gemm(fp, Ws, bs, z + 512, G, 128, 128, 128, 640, true);

    // ---- head: zf = z @ Wf1 via tf32 (bf1 cancels under BN); BN; relu; sigmoid
    {
        dim3 grid(1, (G + 127) / 128);
        tf32gemm<false, false, false><<<grid, 256, smem_bytes>>>(
            z, Wf1, zf, G, 128, 640, 640, 128, 128,
            nullptr, nullptr, nullptr, nullptr, 128, nullptr, nullptr);
    }
    {
        cudaMemsetAsync(bnsum, 0, 128 * sizeof(float));
        cudaMemsetAsync(bnsq, 0, 128 * sizeof(float));
        dim3 g1(1, 128);
        bn_stats<<<g1, 128>>>(zf, G, 128, bnsum, bnsq);
        bn_finalize<<<1, 128>>>(bnsum, bnsq, bnfg, bnfb, G, 128, bnscale, bnshift);
        bn_apply_relu<<<((size_t)G * 128 + 255) / 256, 256>>>(zf, bnscale, bnshift,
                                                              (size_t)G * 128, 128);
    }
    head_final<<<G, 128>>>(zf, Wf2, bf2, out);
}

// round 11
// speedup vs baseline: 1.1483x; 1.0483x over previous
#include <cuda_runtime.h>
#include <cuda_fp16.h>
#include <math.h>
#include <stdint.h>

// Problem capacities (fixed shapes per reference)
#define NMAXN 50000
#define EMAXE 200000
#define ETOTMAX (EMAXE + NMAXN)
#define GMAXG 1000

// ---------------- scratch (static device memory; no allocations allowed) ----
__device__ float g_bufA[(size_t)NMAXN * 1024];
__device__ float g_bufB[(size_t)NMAXN * 1024];
__device__ float g_bufC[(size_t)NMAXN * 1024];
__device__ float g_alS[NMAXN * 4];
__device__ float g_alD[NMAXN * 4];
__device__ float g_u[512 * 4];
__device__ float g_v[512 * 4];
__device__ int   g_degi[NMAXN];
__device__ int   g_incl[NMAXN];
__device__ int   g_part[128];
__device__ int   g_rowptr[NMAXN + 1];
__device__ int   g_cursor[NMAXN];
__device__ int   g_csrsrc[ETOTMAX];
__device__ float g_dinv[NMAXN];
__device__ int   g_gstart[GMAXG + 1];
__device__ float g_bnsum[1024];
__device__ float g_bnsq[1024];
__device__ float g_bnscale[1024];
__device__ float g_bnshift[1024];
__device__ float g_z[GMAXG * 640];
__device__ float g_zf[GMAXG * 128];

// ---------------- CSR build -------------------------------------------------
__global__ void deg_build(const int* __restrict__ ei, int E, int Etot,
                          int* __restrict__ degi)
{
    int e = blockIdx.x * blockDim.x + threadIdx.x;
    if (e >= Etot) return;
    int d = (e < E) ? ei[E + e] : (e - E);
    atomicAdd(degi + d, 1);
}

__global__ __launch_bounds__(1024) void scan_partial(
    const int* __restrict__ degi, int n, int* __restrict__ incl,
    int* __restrict__ part)
{
    __shared__ int sm[32];
    int tid = threadIdx.x;
    int lane = tid & 31, w = tid >> 5;
    int i = blockIdx.x * 1024 + tid;
    int v = (i < n) ? degi[i] : 0;
    int x = v;
#pragma unroll
    for (int o = 1; o < 32; o <<= 1) {
        int y = __shfl_up_sync(0xFFFFFFFFu, x, o);
        if (lane >= o) x += y;
    }
    if (lane == 31) sm[w] = x;
    __syncthreads();
    if (w == 0) {
        int y = sm[lane];
#pragma unroll
        for (int o = 1; o < 32; o <<= 1) {
            int z = __shfl_up_sync(0xFFFFFFFFu, y, o);
            if (lane >= o) y += z;
        }
        sm[lane] = y;
    }
    __syncthreads();
    int inclv = x + (w ? sm[w - 1] : 0);
    if (i < n) incl[i] = inclv;
    if (tid == 1023) part[blockIdx.x] = inclv;
}

__global__ void scan_roots(int* __restrict__ part, int nb)
{
    __shared__ int sm[128];
    int t = threadIdx.x;
    sm[t] = (t < nb) ? part[t] : 0;
    __syncthreads();
    if (t == 0) {
        int run = 0;
        for (int i = 0; i < nb; i++) { int v = sm[i]; sm[i] = run; run += v; }
    }
    __syncthreads();
    if (t < nb) part[t] = sm[t];
}

__global__ void scan_add(const int* __restrict__ incl, const int* __restrict__ degi,
                         const int* __restrict__ part, int n, int Etot,
                         int* __restrict__ rowptr, int* __restrict__ cursor,
                         float* __restrict__ dinv)
{
    int i = blockIdx.x * blockDim.x + threadIdx.x;
    if (i == 0) rowptr[n] = Etot;
    if (i >= n) return;
    int dg = degi[i];
    int exc = incl[i] + part[i >> 10] - dg;
    rowptr[i] = exc;
    cursor[i] = exc;
    dinv[i] = rsqrtf(fmaxf((float)dg, 1.0f));
}

__global__ void csr_scatter(const int* __restrict__ ei, int E, int Etot,
                            int* __restrict__ cursor, int* __restrict__ csrsrc)
{
    int e = blockIdx.x * blockDim.x + threadIdx.x;
    if (e >= Etot) return;
    int s, d;
    if (e < E) { s = ei[e]; d = ei[E + e]; }
    else       { s = e - E; d = e - E; }
    int pos = atomicAdd(cursor + d, 1);
    csrsrc[pos] = s;
}

__global__ void gstart_build(const int* __restrict__ batch, int n, int G,
                             int* __restrict__ gstart)
{
    int i = blockIdx.x * blockDim.x + threadIdx.x;
    if (i < n) {
        int b = batch[i];
        int bp = (i > 0) ? batch[i - 1] : -1;
        for (int g = bp + 1; g <= b; g++) gstart[g] = i;
    } else if (i == n) {
        int bl = batch[n - 1];
        for (int g = bl + 1; g <= G; g++) gstart[g] = n;
    }
}

// ---------------- u/v vectors: u[k,h] = sum_c W[k,hC+c]*a[h,c] ---------------
__global__ void uv_build(const float* __restrict__ W, const float* __restrict__ aS,
                         const float* __restrict__ aD, int K, int C,
                         float* __restrict__ u, float* __restrict__ v)
{
    int idx = blockIdx.x * blockDim.x + threadIdx.x;
    int warp = idx >> 5, lane = idx & 31;
    if (warp >= K * 4) return;
    int k = warp >> 2, h = warp & 3;
    const float* wrow = W + (size_t)k * (4 * C) + h * C;
    const float* as = aS + h * C;
    const float* ad = aD + h * C;
    float s = 0.f, d = 0.f;
    for (int c = lane; c < C; c += 32) {
        float wv = wrow[c];
        s += wv * as[c];
        d += wv * ad[c];
    }
#pragma unroll
    for (int o = 16; o; o >>= 1) {
        s += __shfl_xor_sync(0xFFFFFFFFu, s, o);
        d += __shfl_xor_sync(0xFFFFFFFFu, d, o);
    }
    if (lane == 0) { u[k * 4 + h] = s; v[k * 4 + h] = d; }
}

// ---------------- skinny alpha GEMM (layer 1, K=64, fp32 exact) --------------
__global__ __launch_bounds__(256) void alpha_gemm64(
    const float* __restrict__ in, int n,
    const float* __restrict__ u, const float* __restrict__ v,
    float* __restrict__ alS, float* __restrict__ alD)
{
    __shared__ float su[64][4];
    __shared__ float sv[64][4];
    int tid = threadIdx.x;
    if (tid < 64 * 4) { su[tid >> 2][tid & 3] = u[tid]; sv[tid >> 2][tid & 3] = v[tid]; }
    __syncthreads();

    int warp = tid >> 5, lane = tid & 31;
    for (int node = blockIdx.x * 8 + warp; node < n; node += gridDim.x * 8) {
        const float* row = in + (size_t)node * 64;
        float x0 = row[lane], x1 = row[lane + 32];
        float as[4], ad[4];
#pragma unroll
        for (int h = 0; h < 4; h++) {
            as[h] = x0 * su[lane][h] + x1 * su[lane + 32][h];
            ad[h] = x0 * sv[lane][h] + x1 * sv[lane + 32][h];
        }
#pragma unroll
        for (int h = 0; h < 4; h++) {
#pragma unroll
            for (int o = 16; o; o >>= 1) {
                as[h] += __shfl_xor_sync(0xFFFFFFFFu, as[h], o);
                ad[h] += __shfl_xor_sync(0xFFFFFFFFu, ad[h], o);
            }
        }
        if (lane == 0) {
            *(float4*)(alS + (size_t)node * 4) = make_float4(as[0], as[1], as[2], as[3]);
            *(float4*)(alD + (size_t)node * 4) = make_float4(ad[0], ad[1], ad[2], ad[3]);
        }
    }
}

// ---------------- TF32 tensor-core GEMM (cp.async double-buffered) -----------
__device__ __forceinline__ void mma_tf32(float c[4], const float a[4], const float b[2]) {
    asm volatile(
        "mma.sync.aligned.m16n8k8.row.col.f32.tf32.tf32.f32 "
        "{%0,%1,%2,%3}, {%4,%5,%6,%7}, {%8,%9}, {%0,%1,%2,%3};"
        : "+f"(c[0]), "+f"(c[1]), "+f"(c[2]), "+f"(c[3])
        : "r"(__float_as_uint(a[0])), "r"(__float_as_uint(a[1])),
          "r"(__float_as_uint(a[2])), "r"(__float_as_uint(a[3])),
          "r"(__float_as_uint(b[0])), "r"(__float_as_uint(b[1])));
}

__device__ __forceinline__ void cp_async16(float* smem_dst, const float* gmem_src,
                                           bool pred) {
    uint32_t saddr = (uint32_t)__cvta_generic_to_shared(smem_dst);
    int sz = pred ? 16 : 0;
    asm volatile("cp.async.cg.shared.global [%0], [%1], 16, %2;\n"
                 :: "r"(saddr), "l"(gmem_src), "r"(sz));
}

#define ABUF 4608
#define BBUF 4352
#define SMEM_FLOATS (2 * ABUF + 2 * BBUF)

// C[M,Nc] = op(A)[M,K] @ B[K,Nc]; op = relu(bn) if BNRELU.
// GROUP: A base shifts by (blockN/128)*K columns.
// ALPHA: accumulates alS/alD[row*4+head] += sum_col C*aS/aD.
// HALF: C is written as __half (ldc in half elements).
template <bool BNRELU, bool ALPHA, bool GROUP, bool HALF>
__global__ __launch_bounds__(256, 2) void tf32gemm(
    const float* __restrict__ A, const float* __restrict__ B,
    void* __restrict__ Cout, int M, int Nc, int K,
    int lda, int ldb, int ldc,
    const float* __restrict__ scale, const float* __restrict__ shift,
    const float* __restrict__ aS, const float* __restrict__ aD, int Chead,
    float* __restrict__ alS, float* __restrict__ alD)
{
    extern __shared__ float smem[];

    int tid = threadIdx.x;
    int lane = tid & 31;
    int wid = tid >> 5;
    int warpM = (wid >> 2) * 64;
    int warpN = (wid & 3) * 32;
    int r = lane >> 2;
    int cq = lane & 3;

    int blockM = blockIdx.y * 128;
    int blockN = blockIdx.x * 128;

    if (GROUP) A += (size_t)(blockN >> 7) * K;

    int acol = (tid & 7) * 4;
    int arow0 = tid >> 3;
    int bcol = (tid & 31) * 4;
    int brow0 = tid >> 5;

    float acc[4][4][4];
#pragma unroll
    for (int mt = 0; mt < 4; mt++)
#pragma unroll
        for (int nt = 0; nt < 4; nt++)
#pragma unroll
            for (int i = 0; i < 4; i++) acc[mt][nt][i] = 0.0f;

    int nk = K >> 5;

    auto load_tile = [&](int k0, int buf) {
        float* As = smem + buf * ABUF;
        float* Bs = smem + 2 * ABUF + buf * BBUF;
#pragma unroll
        for (int i = 0; i < 4; i++) {
            int row = blockM + arow0 + i * 32;
            cp_async16(&As[(arow0 + i * 32) * 36 + acol],
                       A + (size_t)row * lda + k0 + acol, row < M);
        }
#pragma unroll
        for (int i = 0; i < 4; i++) {
            int kr = brow0 + i * 8;
            cp_async16(&Bs[kr * 136 + bcol],
                       B + (size_t)(k0 + kr) * ldb + blockN + bcol, true);
        }
        asm volatile("cp.async.commit_group;\n");
    };

    load_tile(0, 0);

    for (int kt = 0; kt < nk; kt++) {
        if (kt + 1 < nk) {
            load_tile((kt + 1) << 5, (kt + 1) & 1);
            asm volatile("cp.async.wait_group 1;\n");
        } else {
            asm volatile("cp.async.wait_group 0;\n");
        }
        __syncthreads();

        const float* As = smem + (kt & 1) * ABUF;
        const float* Bs = smem + 2 * ABUF + (kt & 1) * BBUF;
        int k0 = kt << 5;

        float scv[8], shv[8];
        if (BNRELU) {
#pragma unroll
            for (int kk = 0; kk < 4; kk++) {
                scv[kk]     = scale[k0 + kk * 8 + cq];
                scv[kk + 4] = scale[k0 + kk * 8 + cq + 4];
                shv[kk]     = shift[k0 + kk * 8 + cq];
                shv[kk + 4] = shift[k0 + kk * 8 + cq + 4];
            }
        }

#pragma unroll
        for (int kk = 0; kk < 4; kk++) {
            int kb = kk * 8;
            float a[4][4], b[4][2];
#pragma unroll
            for (int mt = 0; mt < 4; mt++) {
                int m = warpM + mt * 16 + r;
                float a0 = As[m * 36 + kb + cq];
                float a1 = As[(m + 8) * 36 + kb + cq];
                float a2 = As[m * 36 + kb + cq + 4];
                float a3 = As[(m + 8) * 36 + kb + cq + 4];
                if (BNRELU) {
                    a0 = fmaxf(fmaf(a0, scv[kk], shv[kk]), 0.f);
                    a1 = fmaxf(fmaf(a1, scv[kk], shv[kk]), 0.f);
                    a2 = fmaxf(fmaf(a2, scv[kk + 4], shv[kk + 4]), 0.f);
                    a3 = fmaxf(fmaf(a3, scv[kk + 4], shv[kk + 4]), 0.f);
                }
                a[mt][0] = a0; a[mt][1] = a1; a[mt][2] = a2; a[mt][3] = a3;
            }
#pragma unroll
            for (int nt = 0; nt < 4; nt++) {
                int nn = warpN + nt * 8 + r;
                b[nt][0] = Bs[(kb + cq) * 136 + nn];
                b[nt][1] = Bs[(kb + cq + 4) * 136 + nn];
            }
#pragma unroll
            for (int mt = 0; mt < 4; mt++)
#pragma unroll
                for (int nt = 0; nt < 4; nt++)
                    mma_tf32(acc[mt][nt], a[mt], b[nt]);
        }
        __syncthreads();
    }

#pragma unroll
    for (int mt = 0; mt < 4; mt++) {
        int row0 = blockM + warpM + mt * 16 + r;
#pragma unroll
        for (int nt = 0; nt < 4; nt++) {
            int col = blockN + warpN + nt * 8 + cq * 2;
            if (HALF) {
                __half2* Ch = (__half2*)Cout;
                if (row0 < M)
                    Ch[((size_t)row0 * ldc + col) >> 1] =
                        __floats2half2_rn(acc[mt][nt][0], acc[mt][nt][1]);
                if (row0 + 8 < M)
                    Ch[((size_t)(row0 + 8) * ldc + col) >> 1] =
                        __floats2half2_rn(acc[mt][nt][2], acc[mt][nt][3]);
            } else {
                float* C = (float*)Cout;
                if (row0 < M)
                    *(float2*)(C + (size_t)row0 * ldc + col) =
                        make_float2(acc[mt][nt][0], acc[mt][nt][1]);
                if (row0 + 8 < M)
                    *(float2*)(C + (size_t)(row0 + 8) * ldc + col) =
                        make_float2(acc[mt][nt][2], acc[mt][nt][3]);
            }
        }
    }

    if (ALPHA) {
        int head = blockN / Chead;
        float ws[4][2], wd[4][2];
#pragma unroll
        for (int nt = 0; nt < 4; nt++) {
            int col = blockN + warpN + nt * 8 + cq * 2;
            int c = col - head * Chead;
            ws[nt][0] = aS[head * Chead + c];
            ws[nt][1] = aS[head * Chead + c + 1];
            wd[nt][0] = aD[head * Chead + c];
            wd[nt][1] = aD[head * Chead + c + 1];
        }
#pragma unroll
        for (int mt = 0; mt < 4; mt++) {
            float ps0 = 0.f, pd0 = 0.f, ps1 = 0.f, pd1 = 0.f;
#pragma unroll
            for (int nt = 0; nt < 4; nt++) {
                ps0 += acc[mt][nt][0] * ws[nt][0] + acc[mt][nt][1] * ws[nt][1];
                pd0 += acc[mt][nt][0] * wd[nt][0] + acc[mt][nt][1] * wd[nt][1];
                ps1 += acc[mt][nt][2] * ws[nt][0] + acc[mt][nt][3] * ws[nt][1];
                pd1 += acc[mt][nt][2] * wd[nt][0] + acc[mt][nt][3] * wd[nt][1];
            }
#pragma unroll
            for (int o = 1; o < 4; o <<= 1) {
                ps0 += __shfl_xor_sync(0xFFFFFFFFu, ps0, o);
                pd0 += __shfl_xor_sync(0xFFFFFFFFu, pd0, o);
                ps1 += __shfl_xor_sync(0xFFFFFFFFu, ps1, o);
                pd1 += __shfl_xor_sync(0xFFFFFFFFu, pd1, o);
            }
            if (cq == 0) {
                int row0 = blockM + warpM + mt * 16 + r;
                if (row0 < M) {
                    atomicAdd(alS + (size_t)row0 * 4 + head, ps0);
                    atomicAdd(alD + (size_t)row0 * 4 + head, pd0);
                }
                if (row0 + 8 < M) {
                    atomicAdd(alS + (size_t)(row0 + 8) * 4 + head, ps1);
                    atomicAdd(alD + (size_t)(row0 + 8) * 4 + head, pd1);
                }
            }
        }
    }
}

// ---------------- fp32 SGEMM (solvent MLP: bias+relu) ------------------------
template <bool RELU>
__global__ __launch_bounds__(256) void sgemm(
    const float* __restrict__ A, const float* __restrict__ B,
    const float* __restrict__ bias, float* __restrict__ C,
    int M, int Nc, int K, int lda, int ldc)
{
    __shared__ float As[8][128];
    __shared__ float Bs[8][128];

    int tid = threadIdx.x;
    int bx = blockIdx.x;
    int by = blockIdx.y;

    int tx = tid % 16;
    int ty = tid / 16;

    int rowA = by * 128 + tid / 2;
    int colA = (tid % 2) * 4;
    int rowB = tid / 32;
    int colB = (tid % 32) * 4;

    float acc[8][8];
#pragma unroll
    for (int i = 0; i < 8; i++)
#pragma unroll
        for (int j = 0; j < 8; j++) acc[i][j] = 0.0f;

    for (int k0 = 0; k0 < K; k0 += 8) {
        float4 av = make_float4(0.f, 0.f, 0.f, 0.f);
        if (rowA < M)
            av = *(const float4*)(A + (size_t)rowA * lda + k0 + colA);
        As[colA + 0][tid / 2] = av.x;
        As[colA + 1][tid / 2] = av.y;
        As[colA + 2][tid / 2] = av.z;
        As[colA + 3][tid / 2] = av.w;

        float4 bv = *(const float4*)(B + (size_t)(k0 + rowB) * Nc + bx * 128 + colB);
        *(float4*)(&Bs[rowB][colB]) = bv;

        __syncthreads();

#pragma unroll
        for (int kk = 0; kk < 8; kk++) {
            float ra[8], rb[8];
#pragma unroll
            for (int i = 0; i < 8; i++) ra[i] = As[kk][ty * 8 + i];
#pragma unroll
            for (int j = 0; j < 8; j++) rb[j] = Bs[kk][tx * 8 + j];
#pragma unroll
            for (int i = 0; i < 8; i++)
#pragma unroll
                for (int j = 0; j < 8; j++) acc[i][j] = fmaf(ra[i], rb[j], acc[i][j]);
        }
        __syncthreads();
    }

#pragma unroll
    for (int i = 0; i < 8; i++) {
        int row = by * 128 + ty * 8 + i;
        if (row >= M) continue;
#pragma unroll
        for (int j = 0; j < 8; j++) {
            int col = bx * 128 + tx * 8 + j;
            float v = acc[i][j];
            if (bias) v += bias[col];
            if (RELU) v = v > 0.f ? v : 0.f;
            C[(size_t)row * ldc + col] = v;
        }
    }
}

// ---- GAT layer 1 input-space gather: agg[d, h*64+c] = sum alpha*x[src,c] ----
__global__ __launch_bounds__(64) void gat_agg_in64(
    const int* __restrict__ rowptr, const int* __restrict__ csrsrc,
    const float* __restrict__ alS, const float* __restrict__ alD,
    const float* __restrict__ in, float* __restrict__ agg)
{
    constexpr int NT = 64;
    __shared__ float s_red[8];
    __shared__ float s_bm[4];
    __shared__ float s_binv[4];
    __shared__ float s_al[16][4];
    __shared__ int   s_src[16];

    int d = blockIdx.x;
    int tid = threadIdx.x;
    int lane = tid & 31, w = tid >> 5;
    int beg = rowptr[d], end = rowptr[d + 1];

    float4 ad4 = *(const float4*)(alD + (size_t)d * 4);
    float adv[4] = {ad4.x, ad4.y, ad4.z, ad4.w};

    float mx[4] = {-INFINITY, -INFINITY, -INFINITY, -INFINITY};
    for (int i = beg + tid; i < end; i += NT) {
        int s = csrsrc[i];
        float4 as4 = *(const float4*)(alS + (size_t)s * 4);
        float l[4] = {as4.x + adv[0], as4.y + adv[1], as4.z + adv[2], as4.w + adv[3]};
#pragma unroll
        for (int hh = 0; hh < 4; hh++) {
            float t = l[hh];
            t = t > 0.f ? t : 0.2f * t;
            mx[hh] = fmaxf(mx[hh], t);
        }
    }
#pragma unroll
    for (int hh = 0; hh < 4; hh++)
#pragma unroll
        for (int o = 16; o; o >>= 1)
            mx[hh] = fmaxf(mx[hh], __shfl_xor_sync(0xFFFFFFFFu, mx[hh], o));
    if (lane == 0)
#pragma unroll
        for (int hh = 0; hh < 4; hh++) s_red[w * 4 + hh] = mx[hh];
    __syncthreads();
    if (tid < 4) s_bm[tid] = fmaxf(s_red[tid], s_red[4 + tid]);
    __syncthreads();
    float bm[4] = {s_bm[0], s_bm[1], s_bm[2], s_bm[3]};

    float sme[4] = {0.f, 0.f, 0.f, 0.f};
    for (int i = beg + tid; i < end; i += NT) {
        int s = csrsrc[i];
        float4 as4 = *(const float4*)(alS + (size_t)s * 4);
        float l[4] = {as4.x + adv[0], as4.y + adv[1], as4.z + adv[2], as4.w + adv[3]};
#pragma unroll
        for (int hh = 0; hh < 4; hh++) {
            float t = l[hh];
            t = t > 0.f ? t : 0.2f * t;
            sme[hh] += expf(t - bm[hh]);
        }
    }
#pragma unroll
    for (int hh = 0; hh < 4; hh++)
#pragma unroll
        for (int o = 16; o; o >>= 1)
            sme[hh] += __shfl_xor_sync(0xFFFFFFFFu, sme[hh], o);
    if (lane == 0)
#pragma unroll
        for (int hh = 0; hh < 4; hh++) s_red[w * 4 + hh] = sme[hh];
    __syncthreads();
    if (tid < 4) s_binv[tid] = 1.0f / fmaxf(s_red[tid] + s_red[4 + tid], 1e-16f);
    __syncthreads();

    float acc[4] = {0.f, 0.f, 0.f, 0.f};
    for (int c0 = beg; c0 < end; c0 += 16) {
        int cnt = min(16, end - c0);
        if (tid < cnt * 4) {
            int j = tid >> 2, hh = tid & 3;
            int s = csrsrc[c0 + j];
            if (hh == 0) s_src[j] = s;
            float t = alS[(size_t)s * 4 + hh] + adv[hh];
            t = t > 0.f ? t : 0.2f * t;
            s_al[j][hh] = expf(t - s_bm[hh]) * s_binv[hh];
        }
        __syncthreads();
        int j = 0;
        for (; j + 4 <= cnt; j += 4) {
            float v0 = in[(size_t)s_src[j + 0] * 64 + tid];
            float v1 = in[(size_t)s_src[j + 1] * 64 + tid];
            float v2 = in[(size_t)s_src[j + 2] * 64 + tid];
            float v3 = in[(size_t)s_src[j + 3] * 64 + tid];
#pragma unroll
            for (int hh = 0; hh < 4; hh++) {
                acc[hh] = fmaf(s_al[j + 0][hh], v0, acc[hh]);
                acc[hh] = fmaf(s_al[j + 1][hh], v1, acc[hh]);
                acc[hh] = fmaf(s_al[j + 2][hh], v2, acc[hh]);
                acc[hh] = fmaf(s_al[j + 3][hh], v3, acc[hh]);
            }
        }
        for (; j < cnt; j++) {
            float v = in[(size_t)s_src[j] * 64 + tid];
#pragma unroll
            for (int hh = 0; hh < 4; hh++)
                acc[hh] = fmaf(s_al[j][hh], v, acc[hh]);
        }
        __syncthreads();
    }

#pragma unroll
    for (int hh = 0; hh < 4; hh++)
        agg[(size_t)d * 256 + hh * 64 + tid] = acc[hh];
}

// ---- fused per-destination GAT softmax + gather (fp16 h rows) ---------------
// HC=1024, SPLIT=2: two blocks per node, each handles a 512-channel half.
// Each thread owns 4 channels (4 halves = 8 bytes per edge row).
template <int HC, int SPLIT>
__global__ __launch_bounds__(128) void gat_gather_h(
    const int* __restrict__ rowptr, const int* __restrict__ csrsrc,
    const float* __restrict__ alS, const float* __restrict__ alD,
    const __half* __restrict__ h, float* __restrict__ out)
{
    constexpr int NT = 128;
    constexpr int HCW = HC / SPLIT;
    static_assert(HCW == 4 * NT, "4 channels per thread");
    constexpr int CPH = HC / 4;

    __shared__ float s_red[16];
    __shared__ float s_bm[4];
    __shared__ float s_binv[4];
    __shared__ float s_al[32][4];
    __shared__ int   s_src[32];

    int d = blockIdx.x;
    int half = (SPLIT > 1) ? blockIdx.y : 0;
    int coff = half * HCW;
    int tid = threadIdx.x;
    int lane = tid & 31, w = tid >> 5;
    int beg = rowptr[d], end = rowptr[d + 1];

    float4 ad4 = *(const float4*)(alD + (size_t)d * 4);
    float adv[4] = {ad4.x, ad4.y, ad4.z, ad4.w};

    float mx[4] = {-INFINITY, -INFINITY, -INFINITY, -INFINITY};
    for (int i = beg + tid; i < end; i += NT) {
        int s = csrsrc[i];
        float4 as4 = *(const float4*)(alS + (size_t)s * 4);
        float l[4] = {as4.x + adv[0], as4.y + adv[1], as4.z + adv[2], as4.w + adv[3]};
#pragma unroll
        for (int hh = 0; hh < 4; hh++) {
            float t = l[hh];
            t = t > 0.f ? t : 0.2f * t;
            mx[hh] = fmaxf(mx[hh], t);
        }
    }
#pragma unroll
    for (int hh = 0; hh < 4; hh++)
#pragma unroll
        for (int o = 16; o; o >>= 1)
            mx[hh] = fmaxf(mx[hh], __shfl_xor_sync(0xFFFFFFFFu, mx[hh], o));
    if (lane == 0)
#pragma unroll
        for (int hh = 0; hh < 4; hh++) s_red[w * 4 + hh] = mx[hh];
    __syncthreads();
    if (tid < 4) {
        float r = fmaxf(fmaxf(s_red[tid], s_red[4 + tid]),
                        fmaxf(s_red[8 + tid], s_red[12 + tid]));
        s_bm[tid] = r;
    }
    __syncthreads();
    float bm[4] = {s_bm[0], s_bm[1], s_bm[2], s_bm[3]};

    float sme[4] = {0.f, 0.f, 0.f, 0.f};
    for (int i = beg + tid; i < end; i += NT) {
        int s = csrsrc[i];
        float4 as4 = *(const float4*)(alS + (size_t)s * 4);
        float l[4] = {as4.x + adv[0], as4.y + adv[1], as4.z + adv[2], as4.w + adv[3]};
#pragma unroll
        for (int hh = 0; hh < 4; hh++) {
            float t = l[hh];
            t = t > 0.f ? t : 0.2f * t;
            sme[hh] += expf(t - bm[hh]);
        }
    }
#pragma unroll
    for (int hh = 0; hh < 4; hh++)
#pragma unroll
        for (int o = 16; o; o >>= 1)
            sme[hh] += __shfl_xor_sync(0xFFFFFFFFu, sme[hh], o);
    if (lane == 0)
#pragma unroll
        for (int hh = 0; hh < 4; hh++) s_red[w * 4 + hh] = sme[hh];
    __syncthreads();
    if (tid < 4) {
        float r = s_red[tid] + s_red[4 + tid] + s_red[8 + tid] + s_red[12 + tid];
        s_binv[tid] = 1.0f / fmaxf(r, 1e-16f);
    }
    __syncthreads();

    float4 acc = make_float4(0.f, 0.f, 0.f, 0.f);
    int hof = (coff + tid * 4) / CPH;

    for (int c0 = beg; c0 < end; c0 += 32) {
        int cnt = min(32, end - c0);
        if (tid < cnt * 4) {
            int j = tid >> 2, hh = tid & 3;
            int s = csrsrc[c0 + j];
            if (hh == 0) s_src[j] = s;
            float t = alS[(size_t)s * 4 + hh] + adv[hh];
            t = t > 0.f ? t : 0.2f * t;
            s_al[j][hh] = expf(t - s_bm[hh]) * s_binv[hh];
        }
        __syncthreads();
        int j = 0;
        for (; j + 4 <= cnt; j += 4) {
            // batch 4 independent random 8-byte half-row loads (MLP=4)
            const uint2* p0 = (const uint2*)(h + (size_t)s_src[j + 0] * HC + coff) + tid;
            const uint2* p1 = (const uint2*)(h + (size_t)s_src[j + 1] * HC + coff) + tid;
            const uint2* p2 = (const uint2*)(h + (size_t)s_src[j + 2] * HC + coff) + tid;
            const uint2* p3 = (const uint2*)(h + (size_t)s_src[j + 3] * HC + coff) + tid;
            uint2 r0 = *p0, r1 = *p1, r2 = *p2, r3 = *p3;
            float a0 = s_al[j + 0][hof];
            float a1 = s_al[j + 1][hof];
            float a2 = s_al[j + 2][hof];
            float a3 = s_al[j + 3][hof];
            float2 f0a = __half22float2(*(__half2*)&r0.x);
            float2 f0b = __half22float2(*(__half2*)&r0.y);
            float2 f1a = __half22float2(*(__half2*)&r1.x);
            float2 f1b = __half22float2(*(__half2*)&r1.y);
            float2 f2a = __half22float2(*(__half2*)&r2.x);
            float2 f2b = __half22float2(*(__half2*)&r2.y);
            float2 f3a = __half22float2(*(__half2*)&r3.x);
            float2 f3b = __half22float2(*(__half2*)&r3.y);
            acc.x = fmaf(a0, f0a.x, acc.x); acc.y = fmaf(a0, f0a.y, acc.y);
            acc.z = fmaf(a0, f0b.x, acc.z); acc.w = fmaf(a0, f0b.y, acc.w);
            acc.x = fmaf(a1, f1a.x, acc.x); acc.y = fmaf(a1, f1a.y, acc.y);
            acc.z = fmaf(a1, f1b.x, acc.z); acc.w = fmaf(a1, f1b.y, acc.w);
            acc.x = fmaf(a2, f2a.x, acc.x); acc.y = fmaf(a2, f2a.y, acc.y);
            acc.z = fmaf(a2, f2b.x, acc.z); acc.w = fmaf(a2, f2b.y, acc.w);
            acc.x = fmaf(a3, f3a.x, acc.x); acc.y = fmaf(a3, f3a.y, acc.y);
            acc.z = fmaf(a3, f3b.x, acc.z); acc.w = fmaf(a3, f3b.y, acc.w);
        }
        for (; j < cnt; j++) {
            const uint2* p = (const uint2*)(h + (size_t)s_src[j] * HC + coff) + tid;
            uint2 rr = *p;
            float a = s_al[j][hof];
            float2 fa = __half22float2(*(__half2*)&rr.x);
            float2 fb = __half22float2(*(__half2*)&rr.y);
            acc.x = fmaf(a, fa.x, acc.x);
            acc.y = fmaf(a, fa.y, acc.y);
            acc.z = fmaf(a, fb.x, acc.z);
            acc.w = fmaf(a, fb.y, acc.w);
        }
        __syncthreads();
    }

    float4* op = (float4*)(out + (size_t)d * HC + coff);
    op[tid] = acc;
}

// ---------------- GCN gather (fp16 h rows, 4-way edge unroll) ----------------
__global__ __launch_bounds__(64) void gcn_gather_h(
    const int* __restrict__ rowptr, const int* __restrict__ csrsrc,
    const float* __restrict__ dinv, const __half* __restrict__ h,
    float* __restrict__ out)
{
    int d = blockIdx.x;
    int tid = threadIdx.x;
    int beg = rowptr[d], end = rowptr[d + 1];
    float dd = dinv[d];

    float4 acc = make_float4(0.f, 0.f, 0.f, 0.f);
    int i = beg;
    for (; i + 4 <= end; i += 4) {
        int s0 = csrsrc[i + 0], s1 = csrsrc[i + 1];
        int s2 = csrsrc[i + 2], s3 = csrsrc[i + 3];
        float n0 = dinv[s0] * dd, n1 = dinv[s1] * dd;
        float n2 = dinv[s2] * dd, n3 = dinv[s3] * dd;
        uint2 r0 = *((const uint2*)(h + (size_t)s0 * 256) + tid);
        uint2 r1 = *((const uint2*)(h + (size_t)s1 * 256) + tid);
        uint2 r2 = *((const uint2*)(h + (size_t)s2 * 256) + tid);
        uint2 r3 = *((const uint2*)(h + (size_t)s3 * 256) + tid);
        float2 f0a = __half22float2(*(__half2*)&r0.x);
        float2 f0b = __half22float2(*(__half2*)&r0.y);
        float2 f1a = __half22float2(*(__half2*)&r1.x);
        float2 f1b = __half22float2(*(__half2*)&r1.y);
        float2 f2a = __half22float2(*(__half2*)&r2.x);
        float2 f2b = __half22float2(*(__half2*)&r2.y);
        float2 f3a = __half22float2(*(__half2*)&r3.x);
        float2 f3b = __half22float2(*(__half2*)&r3.y);
        acc.x = fmaf(n0, f0a.x, acc.x); acc.y = fmaf(n0, f0a.y, acc.y);
        acc.z = fmaf(n0, f0b.x, acc.z); acc.w = fmaf(n0, f0b.y, acc.w);
        acc.x = fmaf(n1, f1a.x, acc.x); acc.y = fmaf(n1, f1a.y, acc.y);
        acc.z = fmaf(n1, f1b.x, acc.z); acc.w = fmaf(n1, f1b.y, acc.w);
        acc.x = fmaf(n2, f2a.x, acc.x); acc.y = fmaf(n2, f2a.y, acc.y);
        acc.z = fmaf(n2, f2b.x, acc.z); acc.w = fmaf(n2, f2b.y, acc.w);
        acc.x = fmaf(n3, f3a.x, acc.x); acc.y = fmaf(n3, f3a.y, acc.y);
        acc.z = fmaf(n3, f3b.x, acc.z); acc.w = fmaf(n3, f3b.y, acc.w);
    }
    for (; i < end; i++) {
        int s = csrsrc[i];
        float nrm = dinv[s] * dd;
        uint2 rr = *((const uint2*)(h + (size_t)s * 256) + tid);
        float2 fa = __half22float2(*(__half2*)&rr.x);
        float2 fb = __half22float2(*(__half2*)&rr.y);
        acc.x = fmaf(nrm, fa.x, acc.x);
        acc.y = fmaf(nrm, fa.y, acc.y);
        acc.z = fmaf(nrm, fb.x, acc.z);
        acc.w = fmaf(nrm, fb.y, acc.w);
    }
    *(float4*)(out + (size_t)d * 256 + tid * 4) = acc;
}

// ---------------- BatchNorm -------------------------------------------------
__global__ void bn_stats(const float* __restrict__ x, int rows, int K,
                         float* __restrict__ sum, float* __restrict__ sq)
{
    int col = blockIdx.x * blockDim.x + threadIdx.x;
    float s = 0.f, q = 0.f;
    for (int r = blockIdx.y; r < rows; r += gridDim.y) {
        float v = x[(size_t)r * K + col];
        s += v;
        q += v * v;
    }
    atomicAdd(sum + col, s);
    atomicAdd(sq + col, q);
}

__global__ void bn_finalize(const float* __restrict__ sum, const float* __restrict__ sq,
                            const float* __restrict__ g, const float* __restrict__ b,
                            int rows, int K, float* __restrict__ scale,
                            float* __restrict__ shift)
{
    int c = blockIdx.x * blockDim.x + threadIdx.x;
    if (c >= K) return;
    float inv_n = 1.0f / (float)rows;
    float mu = sum[c] * inv_n;
    float var = sq[c] * inv_n - mu * mu;
    float sc = g[c] * rsqrtf(var + 1e-5f);
    scale[c] = sc;
    shift[c] = b[c] - mu * sc;
}

__global__ void bn_apply_relu(float* __restrict__ x, const float* __restrict__ scale,
                              const float* __restrict__ shift, size_t total, int K)
{
    for (size_t i = (size_t)blockIdx.x * blockDim.x + threadIdx.x; i < total;
         i += (size_t)gridDim.x * blockDim.x) {
        int c = (int)(i % K);
        float v = x[i] * scale[c] + shift[c];
        x[i] = v > 0.f ? v : 0.f;
    }
}

// ---------------- Pooling: one block per graph (batch sorted, no atomics) ----
__global__ __launch_bounds__(256) void pool_graph(
    const float* __restrict__ h, const int* __restrict__ gstart,
    const float* __restrict__ scale, const float* __restrict__ shift,
    float* __restrict__ z)
{
    int g = blockIdx.x;
    int c = threadIdx.x;
    int beg = gstart[g], end = gstart[g + 1];
    float sc = scale[c], sh = shift[c];
    float sum = 0.f, mx = 0.f;
    for (int r = beg; r < end; r++) {
        float v = fmaxf(fmaf(h[(size_t)r * 256 + c], sc, sh), 0.f);
        sum += v;
        mx = fmaxf(mx, v);
    }
    float cnt = (float)(end - beg);
    z[(size_t)g * 640 + c] = sum / fmaxf(cnt, 1.0f);
    z[(size_t)g * 640 + 256 + c] = mx;
}

// ---------------- Head -------------------------------------------------------
__global__ void head_final(const float* __restrict__ zf, const float* __restrict__ Wf2,
                           const float* __restrict__ bf2, float* __restrict__ out)
{
    int g = blockIdx.x;
    int t = threadIdx.x;
    float v = zf[(size_t)g * 128 + t] * Wf2[t];
#pragma unroll
    for (int o = 16; o; o >>= 1) v += __shfl_down_sync(0xFFFFFFFFu, v, o);
    __shared__ float sm[4];
    if ((t & 31) == 0) sm[t >> 5] = v;
    __syncthreads();
    if (t == 0) {
        float s = sm[0] + sm[1] + sm[2] + sm[3] + bf2[0];
        out[g] = 1.0f / (1.0f + expf(-s));
    }
}

// ---------------- launch ------------------------------------------------------
extern "C" void kernel_launch(void* const* d_in, const int* in_sizes, int n_in,
                              void* d_out, int out_size)
{
    const float* x    = (const float*)d_in[0];
    const int*   ei   = (const int*)d_in[1];
    const int*   batch= (const int*)d_in[2];
    const float* fp   = (const float*)d_in[3];
    const float* W1   = (const float*)d_in[4];
    const float* a1s  = (const float*)d_in[5];
    const float* a1d  = (const float*)d_in[6];
    const float* bn1g = (const float*)d_in[8];
    const float* bn1b = (const float*)d_in[9];
    const float* W2   = (const float*)d_in[10];
    const float* a2s  = (const float*)d_in[11];
    const float* a2d  = (const float*)d_in[12];
    const float* bn2g = (const float*)d_in[14];
    const float* bn2b = (const float*)d_in[15];
    const float* Wg   = (const float*)d_in[16];
    const float* bn3g = (const float*)d_in[18];
    const float* bn3b = (const float*)d_in[19];
    const float* Ws   = (const float*)d_in[20];
    const float* bs   = (const float*)d_in[21];
    const float* Wf1  = (const float*)d_in[22];
    const float* bnfg = (const float*)d_in[24];
    const float* bnfb = (const float*)d_in[25];
    const float* Wf2  = (const float*)d_in[26];
    const float* bf2  = (const float*)d_in[27];
    float* out = (float*)d_out;

    int n    = in_sizes[0] / 64;
    int E    = in_sizes[1] / 2;
    int Etot = E + n;
    int G    = in_sizes[3] / 128;

    float *bufA, *bufB, *bufC, *alS, *alD, *dinv, *uu, *vv;
    float *bnsum, *bnsq, *bnscale, *bnshift, *z, *zf;
    int *degi, *incl, *part, *rowptr, *cursor, *csrsrc, *gstart;
    cudaGetSymbolAddress((void**)&bufA, g_bufA);
    cudaGetSymbolAddress((void**)&bufB, g_bufB);
    cudaGetSymbolAddress((void**)&bufC, g_bufC);
    cudaGetSymbolAddress((void**)&alS, g_alS);
    cudaGetSymbolAddress((void**)&alD, g_alD);
    cudaGetSymbolAddress((void**)&uu, g_u);
    cudaGetSymbolAddress((void**)&vv, g_v);
    cudaGetSymbolAddress((void**)&degi, g_degi);
    cudaGetSymbolAddress((void**)&incl, g_incl);
    cudaGetSymbolAddress((void**)&part, g_part);
    cudaGetSymbolAddress((void**)&rowptr, g_rowptr);
    cudaGetSymbolAddress((void**)&cursor, g_cursor);
    cudaGetSymbolAddress((void**)&csrsrc, g_csrsrc);
    cudaGetSymbolAddress((void**)&dinv, g_dinv);
    cudaGetSymbolAddress((void**)&gstart, g_gstart);
    cudaGetSymbolAddress((void**)&bnsum, g_bnsum);
    cudaGetSymbolAddress((void**)&bnsq, g_bnsq);
    cudaGetSymbolAddress((void**)&bnscale, g_bnscale);
    cudaGetSymbolAddress((void**)&bnshift, g_bnshift);
    cudaGetSymbolAddress((void**)&z, g_z);
    cudaGetSymbolAddress((void**)&zf, g_zf);

    __half* bufC_h = (__half*)bufC;   // GAT2 GEMM output (fp16)
    __half* bufB_h = (__half*)bufB;   // GCN GEMM output (fp16)

    size_t smem_bytes = SMEM_FLOATS * sizeof(float);
    static bool attr_done = false;
    if (!attr_done) {
        cudaFuncSetAttribute(tf32gemm<false, false, true, false>,
                             cudaFuncAttributeMaxDynamicSharedMemorySize, (int)smem_bytes);
        cudaFuncSetAttribute(tf32gemm<true, true, false, true>,
                             cudaFuncAttributeMaxDynamicSharedMemorySize, (int)smem_bytes);
        cudaFuncSetAttribute(tf32gemm<true, false, false, true>,
                             cudaFuncAttributeMaxDynamicSharedMemorySize, (int)smem_bytes);
        cudaFuncSetAttribute(tf32gemm<false, false, false, false>,
                             cudaFuncAttributeMaxDynamicSharedMemorySize, (int)smem_bytes);
        attr_done = true;
    }

    auto gemm = [&](const float* A, const float* B, const float* bias, float* C,
                    int M, int Nc, int K, int lda, int ldc, bool relu) {
        dim3 grid(Nc / 128, (M + 127) / 128);
        if (relu) sgemm<true><<<grid, 256>>>(A, B, bias, C, M, Nc, K, lda, ldc);
        else      sgemm<false><<<grid, 256>>>(A, B, bias, C, M, Nc, K, lda, ldc);
    };

    auto bnstats = [&](const float* Xp, int rows, int K, const float* gg,
                       const float* bb) {
        cudaMemsetAsync(bnsum, 0, K * sizeof(float));
        cudaMemsetAsync(bnsq, 0, K * sizeof(float));
        dim3 g1(K / 128, 128);
        bn_stats<<<g1, 128>>>(Xp, rows, K, bnsum, bnsq);
        bn_finalize<<<(K + 127) / 128, 128>>>(bnsum, bnsq, gg, bb, rows, K,
                                              bnscale, bnshift);
    };

    // ---- CSR build (dst-sorted), multi-block scan; dinv fused into add pass
    cudaMemsetAsync(degi, 0, n * sizeof(int));
    deg_build<<<(Etot + 255) / 256, 256>>>(ei, E, Etot, degi);
    int nb = (n + 1023) / 1024;
    scan_partial<<<nb, 1024>>>(degi, n, incl, part);
    scan_roots<<<1, 128>>>(part, nb);
    scan_add<<<(n + 255) / 256, 256>>>(incl, degi, part, n, Etot,
                                       rowptr, cursor, dinv);
    csr_scatter<<<(Etot + 255) / 256, 256>>>(ei, E, Etot, cursor, csrsrc);
    gstart_build<<<(n + 256) / 256, 256>>>(batch, n, G, gstart);

    // ---- GAT layer 1 (input-space): alphas exact via u=W1·a; gather x; GEMM
    uv_build<<<(64 * 4 * 32 + 255) / 256, 256>>>(W1, a1s, a1d, 64, 128, uu, vv);
    alpha_gemm64<<<(n + 7) / 8, 256>>>(x, n, uu, vv, alS, alD);
    gat_agg_in64<<<n, 64>>>(rowptr, csrsrc, alS, alD, x, bufA);
    {
        dim3 grid(4, (n + 127) / 128);
        tf32gemm<false, false, true, false><<<grid, 256, smem_bytes>>>(
            bufA, W1, bufB, n, 512, 64, 256, 512, 512,
            nullptr, nullptr, nullptr, nullptr, 128, nullptr, nullptr);
    }
    bnstats(bufB, n, 512, bn1g, bn1b);

    // ---- GAT layer 2: bufC(fp16) = relu(bn(bufB))@W2 (+ alphas); gather -> bufA
    cudaMemsetAsync(alS, 0, (size_t)n * 4 * sizeof(float));
    cudaMemsetAsync(alD, 0, (size_t)n * 4 * sizeof(float));
    {
        dim3 grid(8, (n + 127) / 128);
        tf32gemm<true, true, false, true><<<grid, 256, smem_bytes>>>(
            bufB, W2, bufC_h, n, 1024, 512, 512, 1024, 1024,
            bnscale, bnshift, a2s, a2d, 256, alS, alD);
    }
    {
        dim3 grid(n, 2);
        gat_gather_h<1024, 2><<<grid, 128>>>(rowptr, csrsrc, alS, alD, bufC_h, bufA);
    }
    bnstats(bufA, n, 1024, bn2g, bn2b);

    // ---- GCN: bufB(fp16) = relu(bn(bufA))@Wg; gather -> bufC(fp32); BN stats
    {
        dim3 grid(2, (n + 127) / 128);
        tf32gemm<true, false, false, true><<<grid, 256, smem_bytes>>>(
            bufA, Wg, bufB_h, n, 256, 1024, 1024, 256, 256,
            bnscale, bnshift, nullptr, nullptr, 256, nullptr, nullptr);
    }
    gcn_gather_h<<<n, 64>>>(rowptr, csrsrc, dinv, bufB_h, bufC);
    bnstats(bufC, n, 256, bn3g, bn3b);

    // ---- Pooling into z[G,640] (block per graph; BN+relu on the fly)
    pool_graph<<<G, 256>>>(bufC, gstart, bnscale, bnshift, z);

    // ---- solvent MLP: relu(fp @ Ws + bs) -> z[:,512:640]
    gemm(fp, Ws, bs, z + 512, G, 128, 128, 128, 640, true);

    // ---- head: zf = z @ Wf1 via tf32 (bf1 cancels under BN); BN; relu; sigmoid
    {
        dim3 grid(1, (G + 127) / 128);
        tf32gemm<false, false, false, false><<<grid, 256, smem_bytes>>>(
            z, Wf1, zf, G, 128, 640, 640, 128, 128,
            nullptr, nullptr, nullptr, nullptr, 128, nullptr, nullptr);
    }
    {
        cudaMemsetAsync(bnsum, 0, 128 * sizeof(float));
        cudaMemsetAsync(bnsq, 0, 128 * sizeof(float));
        dim3 g1(1, 128);
        bn_stats<<<g1, 128>>>(zf, G, 128, bnsum, bnsq);
        bn_finalize<<<1, 128>>>(bnsum, bnsq, bnfg, bnfb, G, 128, bnscale, bnshift);
        bn_apply_relu<<<((size_t)G * 128 + 255) / 256, 256>>>(zf, bnscale, bnshift,
                                                              (size_t)G * 128, 128);
    }
    head_final<<<G, 128>>>(zf, Wf2, bf2, out);
}

// round 12
// speedup vs baseline: 1.3516x; 1.1771x over previous
#include <cuda_runtime.h>
#include <cuda_fp16.h>
#include <math.h>
#include <stdint.h>

// Problem capacities (fixed shapes per reference)
#define NMAXN 50000
#define EMAXE 200000
#define ETOTMAX (EMAXE + NMAXN)
#define GMAXG 1000

// ---------------- scratch (static device memory; no allocations allowed) ----
__device__ float g_bufA[(size_t)NMAXN * 1024];
__device__ float g_bufB[(size_t)NMAXN * 1024];
__device__ float g_bufC[(size_t)NMAXN * 1024];
__device__ __half g_w1p[64 * 512];
__device__ __half g_w2p[512 * 1024];
__device__ __half g_wgp[1024 * 256];
__device__ float g_alS[NMAXN * 4];
__device__ float g_alD[NMAXN * 4];
__device__ float g_u[512 * 4];
__device__ float g_v[512 * 4];
__device__ int   g_degi[NMAXN];
__device__ int   g_incl[NMAXN];
__device__ int   g_part[128];
__device__ int   g_rowptr[NMAXN + 1];
__device__ int   g_cursor[NMAXN];
__device__ int   g_csrsrc[ETOTMAX];
__device__ float g_dinv[NMAXN];
__device__ int   g_gstart[GMAXG + 1];
__device__ float g_bnsum[1024];
__device__ float g_bnsq[1024];
__device__ float g_bnscale[1024];
__device__ float g_bnshift[1024];
__device__ float g_z[GMAXG * 640];
__device__ float g_zf[GMAXG * 128];

// ---------------- CSR build -------------------------------------------------
__global__ void deg_build(const int* __restrict__ ei, int E, int Etot,
                          int* __restrict__ degi)
{
    int e = blockIdx.x * blockDim.x + threadIdx.x;
    if (e >= Etot) return;
    int d = (e < E) ? ei[E + e] : (e - E);
    atomicAdd(degi + d, 1);
}

__global__ __launch_bounds__(1024) void scan_partial(
    const int* __restrict__ degi, int n, int* __restrict__ incl,
    int* __restrict__ part)
{
    __shared__ int sm[32];
    int tid = threadIdx.x;
    int lane = tid & 31, w = tid >> 5;
    int i = blockIdx.x * 1024 + tid;
    int v = (i < n) ? degi[i] : 0;
    int x = v;
#pragma unroll
    for (int o = 1; o < 32; o <<= 1) {
        int y = __shfl_up_sync(0xFFFFFFFFu, x, o);
        if (lane >= o) x += y;
    }
    if (lane == 31) sm[w] = x;
    __syncthreads();
    if (w == 0) {
        int y = sm[lane];
#pragma unroll
        for (int o = 1; o < 32; o <<= 1) {
            int z = __shfl_up_sync(0xFFFFFFFFu, y, o);
            if (lane >= o) y += z;
        }
        sm[lane] = y;
    }
    __syncthreads();
    int inclv = x + (w ? sm[w - 1] : 0);
    if (i < n) incl[i] = inclv;
    if (tid == 1023) part[blockIdx.x] = inclv;
}

__global__ void scan_roots(int* __restrict__ part, int nb)
{
    __shared__ int sm[128];
    int t = threadIdx.x;
    sm[t] = (t < nb) ? part[t] : 0;
    __syncthreads();
    if (t == 0) {
        int run = 0;
        for (int i = 0; i < nb; i++) { int v = sm[i]; sm[i] = run; run += v; }
    }
    __syncthreads();
    if (t < nb) part[t] = sm[t];
}

__global__ void scan_add(const int* __restrict__ incl, const int* __restrict__ degi,
                         const int* __restrict__ part, int n, int Etot,
                         int* __restrict__ rowptr, int* __restrict__ cursor,
                         float* __restrict__ dinv)
{
    int i = blockIdx.x * blockDim.x + threadIdx.x;
    if (i == 0) rowptr[n] = Etot;
    if (i >= n) return;
    int dg = degi[i];
    int exc = incl[i] + part[i >> 10] - dg;
    rowptr[i] = exc;
    cursor[i] = exc;
    dinv[i] = rsqrtf(fmaxf((float)dg, 1.0f));
}

__global__ void csr_scatter(const int* __restrict__ ei, int E, int Etot,
                            int* __restrict__ cursor, int* __restrict__ csrsrc)
{
    int e = blockIdx.x * blockDim.x + threadIdx.x;
    if (e >= Etot) return;
    int s, d;
    if (e < E) { s = ei[e]; d = ei[E + e]; }
    else       { s = e - E; d = e - E; }
    int pos = atomicAdd(cursor + d, 1);
    csrsrc[pos] = s;
}

__global__ void gstart_build(const int* __restrict__ batch, int n, int G,
                             int* __restrict__ gstart)
{
    int i = blockIdx.x * blockDim.x + threadIdx.x;
    if (i < n) {
        int b = batch[i];
        int bp = (i > 0) ? batch[i - 1] : -1;
        for (int g = bp + 1; g <= b; g++) gstart[g] = i;
    } else if (i == n) {
        int bl = batch[n - 1];
        for (int g = bl + 1; g <= G; g++) gstart[g] = n;
    }
}

// ---------------- weight packing: Wp[k/2][n][2] fp16 ------------------------
__global__ void pack_w(const float* __restrict__ W, int K, int Nc,
                       __half* __restrict__ Wp)
{
    int i = blockIdx.x * blockDim.x + threadIdx.x;
    if (i >= K * Nc) return;
    int k = i / Nc, nn = i % Nc;
    Wp[(size_t)(k >> 1) * 2 * Nc + 2 * nn + (k & 1)] = __float2half_rn(W[i]);
}

// ---------------- u/v vectors: u[k,h] = sum_c W[k,hC+c]*a[h,c] ---------------
__global__ void uv_build(const float* __restrict__ W, const float* __restrict__ aS,
                         const float* __restrict__ aD, int K, int C,
                         float* __restrict__ u, float* __restrict__ v)
{
    int idx = blockIdx.x * blockDim.x + threadIdx.x;
    int warp = idx >> 5, lane = idx & 31;
    if (warp >= K * 4) return;
    int k = warp >> 2, h = warp & 3;
    const float* wrow = W + (size_t)k * (4 * C) + h * C;
    const float* as = aS + h * C;
    const float* ad = aD + h * C;
    float s = 0.f, d = 0.f;
    for (int c = lane; c < C; c += 32) {
        float wv = wrow[c];
        s += wv * as[c];
        d += wv * ad[c];
    }
#pragma unroll
    for (int o = 16; o; o >>= 1) {
        s += __shfl_xor_sync(0xFFFFFFFFu, s, o);
        d += __shfl_xor_sync(0xFFFFFFFFu, d, o);
    }
    if (lane == 0) { u[k * 4 + h] = s; v[k * 4 + h] = d; }
}

// ---------------- skinny alpha GEMM (layer 1, K=64, fp32 exact) --------------
__global__ __launch_bounds__(256) void alpha_gemm64(
    const float* __restrict__ in, int n,
    const float* __restrict__ u, const float* __restrict__ v,
    float* __restrict__ alS, float* __restrict__ alD)
{
    __shared__ float su[64][4];
    __shared__ float sv[64][4];
    int tid = threadIdx.x;
    if (tid < 64 * 4) { su[tid >> 2][tid & 3] = u[tid]; sv[tid >> 2][tid & 3] = v[tid]; }
    __syncthreads();

    int warp = tid >> 5, lane = tid & 31;
    for (int node = blockIdx.x * 8 + warp; node < n; node += gridDim.x * 8) {
        const float* row = in + (size_t)node * 64;
        float x0 = row[lane], x1 = row[lane + 32];
        float as[4], ad[4];
#pragma unroll
        for (int h = 0; h < 4; h++) {
            as[h] = x0 * su[lane][h] + x1 * su[lane + 32][h];
            ad[h] = x0 * sv[lane][h] + x1 * sv[lane + 32][h];
        }
#pragma unroll
        for (int h = 0; h < 4; h++) {
#pragma unroll
            for (int o = 16; o; o >>= 1) {
                as[h] += __shfl_xor_sync(0xFFFFFFFFu, as[h], o);
                ad[h] += __shfl_xor_sync(0xFFFFFFFFu, ad[h], o);
            }
        }
        if (lane == 0) {
            *(float4*)(alS + (size_t)node * 4) = make_float4(as[0], as[1], as[2], as[3]);
            *(float4*)(alD + (size_t)node * 4) = make_float4(ad[0], ad[1], ad[2], ad[3]);
        }
    }
}

// ---------------- FP16 tensor-core GEMM (cp.async double-buffered) -----------
__device__ __forceinline__ void mma_f16(float c[4], const uint32_t a[4],
                                        uint32_t b0, uint32_t b1) {
    asm volatile(
        "mma.sync.aligned.m16n8k16.row.col.f32.f16.f16.f32 "
        "{%0,%1,%2,%3}, {%4,%5,%6,%7}, {%8,%9}, {%0,%1,%2,%3};"
        : "+f"(c[0]), "+f"(c[1]), "+f"(c[2]), "+f"(c[3])
        : "r"(a[0]), "r"(a[1]), "r"(a[2]), "r"(a[3]), "r"(b0), "r"(b1));
}

__device__ __forceinline__ void cp_async16(void* smem_dst, const void* gmem_src,
                                           bool pred) {
    uint32_t saddr = (uint32_t)__cvta_generic_to_shared(smem_dst);
    int sz = pred ? 16 : 0;
    asm volatile("cp.async.cg.shared.global [%0], [%1], 16, %2;\n"
                 :: "r"(saddr), "l"(gmem_src), "r"(sz));
}

__device__ __forceinline__ uint32_t bnrelu_h2(uint32_t v, float2 sc, float2 sh) {
    float2 f = __half22float2(*(__half2*)&v);
    f.x = fmaxf(fmaf(f.x, sc.x, sh.x), 0.f);
    f.y = fmaxf(fmaf(f.y, sc.y, sh.y), 0.f);
    __half2 h = __floats2half2_rn(f.x, f.y);
    return *(uint32_t*)&h;
}

// hgemm smem: A stage = 128 rows x 20 half2 (pitch 20) = 10240B,
//             B stage = 16 k2-rows x 136 half2 (pitch 136) = 8704B; 2 stages.
#define H_ASTG 10240
#define H_BSTG 8704
#define H_SMEM (2 * (H_ASTG + H_BSTG))

// C[M,Nc] = op(A)[M,K] @ B[K,Nc]; A fp16 [M,K]; Bp fp16 k-pair packed.
// op = relu(bn) if BNRELU. GROUP: A += (blockN/128)*K. ALPHA: logit partials.
// HALFOUT: C written fp16.
template <bool BNRELU, bool ALPHA, bool GROUP, bool HALFOUT>
__global__ __launch_bounds__(256, 2) void hgemm(
    const __half* __restrict__ A, const __half* __restrict__ Bp,
    void* __restrict__ Cout, int M, int Nc, int K, int lda, int ldc,
    const float* __restrict__ scale, const float* __restrict__ shift,
    const float* __restrict__ aS, const float* __restrict__ aD, int Chead,
    float* __restrict__ alS, float* __restrict__ alD)
{
    extern __shared__ char smem[];

    int tid = threadIdx.x;
    int lane = tid & 31;
    int wid = tid >> 5;
    int warpM = (wid >> 2) * 64;
    int warpN = (wid & 3) * 32;
    int r = lane >> 2;
    int cq = lane & 3;

    int blockM = blockIdx.y * 128;
    int blockN = blockIdx.x * 128;

    if (GROUP) A += (size_t)(blockN >> 7) * K;

    float acc[4][4][4];
#pragma unroll
    for (int mt = 0; mt < 4; mt++)
#pragma unroll
        for (int nt = 0; nt < 4; nt++)
#pragma unroll
            for (int i = 0; i < 4; i++) acc[mt][nt][i] = 0.0f;

    int nk = K >> 5;

    auto load_tile = [&](int kt, int buf) {
        char* As = smem + buf * H_ASTG;
        char* Bs = smem + 2 * H_ASTG + buf * H_BSTG;
#pragma unroll
        for (int i = 0; i < 2; i++) {
            int row = (tid >> 2) + i * 64;
            int grow = blockM + row;
            cp_async16(As + ((size_t)row * 20 + (tid & 3) * 4) * 4,
                       A + (size_t)grow * lda + kt * 32 + (tid & 3) * 8,
                       grow < M);
        }
#pragma unroll
        for (int i = 0; i < 2; i++) {
            int c = tid + i * 256;
            int krow = c >> 5;
            int nc4 = (c & 31) * 4;
            cp_async16(Bs + ((size_t)krow * 136 + nc4) * 4,
                       Bp + (size_t)(kt * 16 + krow) * 2 * Nc + 2 * blockN + nc4 * 2,
                       true);
        }
        asm volatile("cp.async.commit_group;\n");
    };

    load_tile(0, 0);

    for (int kt = 0; kt < nk; kt++) {
        if (kt + 1 < nk) {
            load_tile(kt + 1, (kt + 1) & 1);
            asm volatile("cp.async.wait_group 1;\n");
        } else {
            asm volatile("cp.async.wait_group 0;\n");
        }
        __syncthreads();

        const uint32_t* As2 = (const uint32_t*)(smem + (kt & 1) * H_ASTG);
        const uint32_t* Bs2 = (const uint32_t*)(smem + 2 * H_ASTG + (kt & 1) * H_BSTG);

#pragma unroll
        for (int ks = 0; ks < 2; ks++) {
            int kb2 = ks * 8;
            float2 sc01, sh01, sc23, sh23;
            if (BNRELU) {
                int kg = kt * 32 + ks * 16 + 2 * cq;
                sc01 = *(const float2*)(scale + kg);
                sh01 = *(const float2*)(shift + kg);
                sc23 = *(const float2*)(scale + kg + 8);
                sh23 = *(const float2*)(shift + kg + 8);
            }
            uint32_t a[4][4], b[4][2];
#pragma unroll
            for (int mt = 0; mt < 4; mt++) {
                int m = warpM + mt * 16 + r;
                uint32_t a0 = As2[m * 20 + kb2 + cq];
                uint32_t a1 = As2[(m + 8) * 20 + kb2 + cq];
                uint32_t a2 = As2[m * 20 + kb2 + cq + 4];
                uint32_t a3 = As2[(m + 8) * 20 + kb2 + cq + 4];
                if (BNRELU) {
                    a0 = bnrelu_h2(a0, sc01, sh01);
                    a1 = bnrelu_h2(a1, sc01, sh01);
                    a2 = bnrelu_h2(a2, sc23, sh23);
                    a3 = bnrelu_h2(a3, sc23, sh23);
                }
                a[mt][0] = a0; a[mt][1] = a1; a[mt][2] = a2; a[mt][3] = a3;
            }
#pragma unroll
            for (int nt = 0; nt < 4; nt++) {
                int nn = warpN + nt * 8 + r;
                b[nt][0] = Bs2[(kb2 + cq) * 136 + nn];
                b[nt][1] = Bs2[(kb2 + cq + 4) * 136 + nn];
            }
#pragma unroll
            for (int mt = 0; mt < 4; mt++)
#pragma unroll
                for (int nt = 0; nt < 4; nt++)
                    mma_f16(acc[mt][nt], a[mt], b[nt][0], b[nt][1]);
        }
        __syncthreads();
    }

#pragma unroll
    for (int mt = 0; mt < 4; mt++) {
        int row0 = blockM + warpM + mt * 16 + r;
#pragma unroll
        for (int nt = 0; nt < 4; nt++) {
            int col = blockN + warpN + nt * 8 + cq * 2;
            if (HALFOUT) {
                __half2* Ch = (__half2*)Cout;
                if (row0 < M)
                    Ch[((size_t)row0 * ldc + col) >> 1] =
                        __floats2half2_rn(acc[mt][nt][0], acc[mt][nt][1]);
                if (row0 + 8 < M)
                    Ch[((size_t)(row0 + 8) * ldc + col) >> 1] =
                        __floats2half2_rn(acc[mt][nt][2], acc[mt][nt][3]);
            } else {
                float* C = (float*)Cout;
                if (row0 < M)
                    *(float2*)(C + (size_t)row0 * ldc + col) =
                        make_float2(acc[mt][nt][0], acc[mt][nt][1]);
                if (row0 + 8 < M)
                    *(float2*)(C + (size_t)(row0 + 8) * ldc + col) =
                        make_float2(acc[mt][nt][2], acc[mt][nt][3]);
            }
        }
    }

    if (ALPHA) {
        int head = blockN / Chead;
        float ws[4][2], wd[4][2];
#pragma unroll
        for (int nt = 0; nt < 4; nt++) {
            int col = blockN + warpN + nt * 8 + cq * 2;
            int c = col - head * Chead;
            ws[nt][0] = aS[head * Chead + c];
            ws[nt][1] = aS[head * Chead + c + 1];
            wd[nt][0] = aD[head * Chead + c];
            wd[nt][1] = aD[head * Chead + c + 1];
        }
#pragma unroll
        for (int mt = 0; mt < 4; mt++) {
            float ps0 = 0.f, pd0 = 0.f, ps1 = 0.f, pd1 = 0.f;
#pragma unroll
            for (int nt = 0; nt < 4; nt++) {
                ps0 += acc[mt][nt][0] * ws[nt][0] + acc[mt][nt][1] * ws[nt][1];
                pd0 += acc[mt][nt][0] * wd[nt][0] + acc[mt][nt][1] * wd[nt][1];
                ps1 += acc[mt][nt][2] * ws[nt][0] + acc[mt][nt][3] * ws[nt][1];
                pd1 += acc[mt][nt][2] * wd[nt][0] + acc[mt][nt][3] * wd[nt][1];
            }
#pragma unroll
            for (int o = 1; o < 4; o <<= 1) {
                ps0 += __shfl_xor_sync(0xFFFFFFFFu, ps0, o);
                pd0 += __shfl_xor_sync(0xFFFFFFFFu, pd0, o);
                ps1 += __shfl_xor_sync(0xFFFFFFFFu, ps1, o);
                pd1 += __shfl_xor_sync(0xFFFFFFFFu, pd1, o);
            }
            if (cq == 0) {
                int row0 = blockM + warpM + mt * 16 + r;
                if (row0 < M) {
                    atomicAdd(alS + (size_t)row0 * 4 + head, ps0);
                    atomicAdd(alD + (size_t)row0 * 4 + head, pd0);
                }
                if (row0 + 8 < M) {
                    atomicAdd(alS + (size_t)(row0 + 8) * 4 + head, ps1);
                    atomicAdd(alD + (size_t)(row0 + 8) * 4 + head, pd1);
                }
            }
        }
    }
}

// ---------------- TF32 tensor-core GEMM (head z@Wf1 only) --------------------
__device__ __forceinline__ void mma_tf32(float c[4], const float a[4], const float b[2]) {
    asm volatile(
        "mma.sync.aligned.m16n8k8.row.col.f32.tf32.tf32.f32 "
        "{%0,%1,%2,%3}, {%4,%5,%6,%7}, {%8,%9}, {%0,%1,%2,%3};"
        : "+f"(c[0]), "+f"(c[1]), "+f"(c[2]), "+f"(c[3])
        : "r"(__float_as_uint(a[0])), "r"(__float_as_uint(a[1])),
          "r"(__float_as_uint(a[2])), "r"(__float_as_uint(a[3])),
          "r"(__float_as_uint(b[0])), "r"(__float_as_uint(b[1])));
}

#define ABUF 4608
#define BBUF 4352
#define SMEM_FLOATS (2 * ABUF + 2 * BBUF)

__global__ __launch_bounds__(256, 2) void tf32gemm(
    const float* __restrict__ A, const float* __restrict__ B,
    float* __restrict__ C, int M, int Nc, int K, int lda, int ldb, int ldc)
{
    extern __shared__ float smemf[];

    int tid = threadIdx.x;
    int lane = tid & 31;
    int wid = tid >> 5;
    int warpM = (wid >> 2) * 64;
    int warpN = (wid & 3) * 32;
    int r = lane >> 2;
    int cq = lane & 3;

    int blockM = blockIdx.y * 128;
    int blockN = blockIdx.x * 128;

    int acol = (tid & 7) * 4;
    int arow0 = tid >> 3;
    int bcol = (tid & 31) * 4;
    int brow0 = tid >> 5;

    float acc[4][4][4];
#pragma unroll
    for (int mt = 0; mt < 4; mt++)
#pragma unroll
        for (int nt = 0; nt < 4; nt++)
#pragma unroll
            for (int i = 0; i < 4; i++) acc[mt][nt][i] = 0.0f;

    int nk = K >> 5;

    auto load_tile = [&](int k0, int buf) {
        float* As = smemf + buf * ABUF;
        float* Bs = smemf + 2 * ABUF + buf * BBUF;
#pragma unroll
        for (int i = 0; i < 4; i++) {
            int row = blockM + arow0 + i * 32;
            cp_async16(&As[(arow0 + i * 32) * 36 + acol],
                       A + (size_t)row * lda + k0 + acol, row < M);
        }
#pragma unroll
        for (int i = 0; i < 4; i++) {
            int kr = brow0 + i * 8;
            cp_async16(&Bs[kr * 136 + bcol],
                       B + (size_t)(k0 + kr) * ldb + blockN + bcol, true);
        }
        asm volatile("cp.async.commit_group;\n");
    };

    load_tile(0, 0);

    for (int kt = 0; kt < nk; kt++) {
        if (kt + 1 < nk) {
            load_tile((kt + 1) << 5, (kt + 1) & 1);
            asm volatile("cp.async.wait_group 1;\n");
        } else {
            asm volatile("cp.async.wait_group 0;\n");
        }
        __syncthreads();

        const float* As = smemf + (kt & 1) * ABUF;
        const float* Bs = smemf + 2 * ABUF + (kt & 1) * BBUF;

#pragma unroll
        for (int kk = 0; kk < 4; kk++) {
            int kb = kk * 8;
            float a[4][4], b[4][2];
#pragma unroll
            for (int mt = 0; mt < 4; mt++) {
                int m = warpM + mt * 16 + r;
                a[mt][0] = As[m * 36 + kb + cq];
                a[mt][1] = As[(m + 8) * 36 + kb + cq];
                a[mt][2] = As[m * 36 + kb + cq + 4];
                a[mt][3] = As[(m + 8) * 36 + kb + cq + 4];
            }
#pragma unroll
            for (int nt = 0; nt < 4; nt++) {
                int nn = warpN + nt * 8 + r;
                b[nt][0] = Bs[(kb + cq) * 136 + nn];
                b[nt][1] = Bs[(kb + cq + 4) * 136 + nn];
            }
#pragma unroll
            for (int mt = 0; mt < 4; mt++)
#pragma unroll
                for (int nt = 0; nt < 4; nt++)
                    mma_tf32(acc[mt][nt], a[mt], b[nt]);
        }
        __syncthreads();
    }

#pragma unroll
    for (int mt = 0; mt < 4; mt++) {
        int row0 = blockM + warpM + mt * 16 + r;
#pragma unroll
        for (int nt = 0; nt < 4; nt++) {
            int col = blockN + warpN + nt * 8 + cq * 2;
            if (row0 < M)
                *(float2*)(C + (size_t)row0 * ldc + col) =
                    make_float2(acc[mt][nt][0], acc[mt][nt][1]);
            if (row0 + 8 < M)
                *(float2*)(C + (size_t)(row0 + 8) * ldc + col) =
                    make_float2(acc[mt][nt][2], acc[mt][nt][3]);
        }
    }
}

// ---------------- fp32 SGEMM (solvent MLP: bias+relu) ------------------------
template <bool RELU>
__global__ __launch_bounds__(256) void sgemm(
    const float* __restrict__ A, const float* __restrict__ B,
    const float* __restrict__ bias, float* __restrict__ C,
    int M, int Nc, int K, int lda, int ldc)
{
    __shared__ float As[8][128];
    __shared__ float Bs[8][128];

    int tid = threadIdx.x;
    int bx = blockIdx.x;
    int by = blockIdx.y;

    int tx = tid % 16;
    int ty = tid / 16;

    int rowA = by * 128 + tid / 2;
    int colA = (tid % 2) * 4;
    int rowB = tid / 32;
    int colB = (tid % 32) * 4;

    float acc[8][8];
#pragma unroll
    for (int i = 0; i < 8; i++)
#pragma unroll
        for (int j = 0; j < 8; j++) acc[i][j] = 0.0f;

    for (int k0 = 0; k0 < K; k0 += 8) {
        float4 av = make_float4(0.f, 0.f, 0.f, 0.f);
        if (rowA < M)
            av = *(const float4*)(A + (size_t)rowA * lda + k0 + colA);
        As[colA + 0][tid / 2] = av.x;
        As[colA + 1][tid / 2] = av.y;
        As[colA + 2][tid / 2] = av.z;
        As[colA + 3][tid / 2] = av.w;

        float4 bv = *(const float4*)(B + (size_t)(k0 + rowB) * Nc + bx * 128 + colB);
        *(float4*)(&Bs[rowB][colB]) = bv;

        __syncthreads();

#pragma unroll
        for (int kk = 0; kk < 8; kk++) {
            float ra[8], rb[8];
#pragma unroll
            for (int i = 0; i < 8; i++) ra[i] = As[kk][ty * 8 + i];
#pragma unroll
            for (int j = 0; j < 8; j++) rb[j] = Bs[kk][tx * 8 + j];
#pragma unroll
            for (int i = 0; i < 8; i++)
#pragma unroll
                for (int j = 0; j < 8; j++) acc[i][j] = fmaf(ra[i], rb[j], acc[i][j]);
        }
        __syncthreads();
    }

#pragma unroll
    for (int i = 0; i < 8; i++) {
        int row = by * 128 + ty * 8 + i;
        if (row >= M) continue;
#pragma unroll
        for (int j = 0; j < 8; j++) {
            int col = bx * 128 + tx * 8 + j;
            float v = acc[i][j];
            if (bias) v += bias[col];
            if (RELU) v = v > 0.f ? v : 0.f;
            C[(size_t)row * ldc + col] = v;
        }
    }
}

// ---- GAT layer 1 input-space gather (fp16 output) ---------------------------
__global__ __launch_bounds__(64) void gat_agg_in64(
    const int* __restrict__ rowptr, const int* __restrict__ csrsrc,
    const float* __restrict__ alS, const float* __restrict__ alD,
    const float* __restrict__ in, __half* __restrict__ agg)
{
    constexpr int NT = 64;
    __shared__ float s_red[8];
    __shared__ float s_bm[4];
    __shared__ float s_binv[4];
    __shared__ float s_al[16][4];
    __shared__ int   s_src[16];

    int d = blockIdx.x;
    int tid = threadIdx.x;
    int lane = tid & 31, w = tid >> 5;
    int beg = rowptr[d], end = rowptr[d + 1];

    float4 ad4 = *(const float4*)(alD + (size_t)d * 4);
    float adv[4] = {ad4.x, ad4.y, ad4.z, ad4.w};

    float mx[4] = {-INFINITY, -INFINITY, -INFINITY, -INFINITY};
    for (int i = beg + tid; i < end; i += NT) {
        int s = csrsrc[i];
        float4 as4 = *(const float4*)(alS + (size_t)s * 4);
        float l[4] = {as4.x + adv[0], as4.y + adv[1], as4.z + adv[2], as4.w + adv[3]};
#pragma unroll
        for (int hh = 0; hh < 4; hh++) {
            float t = l[hh];
            t = t > 0.f ? t : 0.2f * t;
            mx[hh] = fmaxf(mx[hh], t);
        }
    }
#pragma unroll
    for (int hh = 0; hh < 4; hh++)
#pragma unroll
        for (int o = 16; o; o >>= 1)
            mx[hh] = fmaxf(mx[hh], __shfl_xor_sync(0xFFFFFFFFu, mx[hh], o));
    if (lane == 0)
#pragma unroll
        for (int hh = 0; hh < 4; hh++) s_red[w * 4 + hh] = mx[hh];
    __syncthreads();
    if (tid < 4) s_bm[tid] = fmaxf(s_red[tid], s_red[4 + tid]);
    __syncthreads();
    float bm[4] = {s_bm[0], s_bm[1], s_bm[2], s_bm[3]};

    float sme[4] = {0.f, 0.f, 0.f, 0.f};
    for (int i = beg + tid; i < end; i += NT) {
        int s = csrsrc[i];
        float4 as4 = *(const float4*)(alS + (size_t)s * 4);
        float l[4] = {as4.x + adv[0], as4.y + adv[1], as4.z + adv[2], as4.w + adv[3]};
#pragma unroll
        for (int hh = 0; hh < 4; hh++) {
            float t = l[hh];
            t = t > 0.f ? t : 0.2f * t;
            sme[hh] += expf(t - bm[hh]);
        }
    }
#pragma unroll
    for (int hh = 0; hh < 4; hh++)
#pragma unroll
        for (int o = 16; o; o >>= 1)
            sme[hh] += __shfl_xor_sync(0xFFFFFFFFu, sme[hh], o);
    if (lane == 0)
#pragma unroll
        for (int hh = 0; hh < 4; hh++) s_red[w * 4 + hh] = sme[hh];
    __syncthreads();
    if (tid < 4) s_binv[tid] = 1.0f / fmaxf(s_red[tid] + s_red[4 + tid], 1e-16f);
    __syncthreads();

    float acc[4] = {0.f, 0.f, 0.f, 0.f};
    for (int c0 = beg; c0 < end; c0 += 16) {
        int cnt = min(16, end - c0);
        if (tid < cnt * 4) {
            int j = tid >> 2, hh = tid & 3;
            int s = csrsrc[c0 + j];
            if (hh == 0) s_src[j] = s;
            float t = alS[(size_t)s * 4 + hh] + adv[hh];
            t = t > 0.f ? t : 0.2f * t;
            s_al[j][hh] = expf(t - s_bm[hh]) * s_binv[hh];
        }
        __syncthreads();
        int j = 0;
        for (; j + 4 <= cnt; j += 4) {
            float v0 = in[(size_t)s_src[j + 0] * 64 + tid];
            float v1 = in[(size_t)s_src[j + 1] * 64 + tid];
            float v2 = in[(size_t)s_src[j + 2] * 64 + tid];
            float v3 = in[(size_t)s_src[j + 3] * 64 + tid];
#pragma unroll
            for (int hh = 0; hh < 4; hh++) {
                acc[hh] = fmaf(s_al[j + 0][hh], v0, acc[hh]);
                acc[hh] = fmaf(s_al[j + 1][hh], v1, acc[hh]);
                acc[hh] = fmaf(s_al[j + 2][hh], v2, acc[hh]);
                acc[hh] = fmaf(s_al[j + 3][hh], v3, acc[hh]);
            }
        }
        for (; j < cnt; j++) {
            float v = in[(size_t)s_src[j] * 64 + tid];
#pragma unroll
            for (int hh = 0; hh < 4; hh++)
                acc[hh] = fmaf(s_al[j][hh], v, acc[hh]);
        }
        __syncthreads();
    }

#pragma unroll
    for (int hh = 0; hh < 4; hh++)
        agg[(size_t)d * 256 + hh * 64 + tid] = __float2half_rn(acc[hh]);
}

// ---- fused per-destination GAT softmax + gather (fp16 in, fp16 out) ---------
template <int HC, int SPLIT>
__global__ __launch_bounds__(128) void gat_gather_h(
    const int* __restrict__ rowptr, const int* __restrict__ csrsrc,
    const float* __restrict__ alS, const float* __restrict__ alD,
    const __half* __restrict__ h, __half* __restrict__ out)
{
    constexpr int NT = 128;
    constexpr int HCW = HC / SPLIT;
    static_assert(HCW == 4 * NT, "4 channels per thread");
    constexpr int CPH = HC / 4;

    __shared__ float s_red[16];
    __shared__ float s_bm[4];
    __shared__ float s_binv[4];
    __shared__ float s_al[32][4];
    __shared__ int   s_src[32];

    int d = blockIdx.x;
    int half = (SPLIT > 1) ? blockIdx.y : 0;
    int coff = half * HCW;
    int tid = threadIdx.x;
    int lane = tid & 31, w = tid >> 5;
    int beg = rowptr[d], end = rowptr[d + 1];

    float4 ad4 = *(const float4*)(alD + (size_t)d * 4);
    float adv[4] = {ad4.x, ad4.y, ad4.z, ad4.w};

    float mx[4] = {-INFINITY, -INFINITY, -INFINITY, -INFINITY};
    for (int i = beg + tid; i < end; i += NT) {
        int s = csrsrc[i];
        float4 as4 = *(const float4*)(alS + (size_t)s * 4);
        float l[4] = {as4.x + adv[0], as4.y + adv[1], as4.z + adv[2], as4.w + adv[3]};
#pragma unroll
        for (int hh = 0; hh < 4; hh++) {
            float t = l[hh];
            t = t > 0.f ? t : 0.2f * t;
            mx[hh] = fmaxf(mx[hh], t);
        }
    }
#pragma unroll
    for (int hh = 0; hh < 4; hh++)
#pragma unroll
        for (int o = 16; o; o >>= 1)
            mx[hh] = fmaxf(mx[hh], __shfl_xor_sync(0xFFFFFFFFu, mx[hh], o));
    if (lane == 0)
#pragma unroll
        for (int hh = 0; hh < 4; hh++) s_red[w * 4 + hh] = mx[hh];
    __syncthreads();
    if (tid < 4) {
        float r = fmaxf(fmaxf(s_red[tid], s_red[4 + tid]),
                        fmaxf(s_red[8 + tid], s_red[12 + tid]));
        s_bm[tid] = r;
    }
    __syncthreads();
    float bm[4] = {s_bm[0], s_bm[1], s_bm[2], s_bm[3]};

    float sme[4] = {0.f, 0.f, 0.f, 0.f};
    for (int i = beg + tid; i < end; i += NT) {
        int s = csrsrc[i];
        float4 as4 = *(const float4*)(alS + (size_t)s * 4);
        float l[4] = {as4.x + adv[0], as4.y + adv[1], as4.z + adv[2], as4.w + adv[3]};
#pragma unroll
        for (int hh = 0; hh < 4; hh++) {
            float t = l[hh];
            t = t > 0.f ? t : 0.2f * t;
            sme[hh] += expf(t - bm[hh]);
        }
    }
#pragma unroll
    for (int hh = 0; hh < 4; hh++)
#pragma unroll
        for (int o = 16; o; o >>= 1)
            sme[hh] += __shfl_xor_sync(0xFFFFFFFFu, sme[hh], o);
    if (lane == 0)
#pragma unroll
        for (int hh = 0; hh < 4; hh++) s_red[w * 4 + hh] = sme[hh];
    __syncthreads();
    if (tid < 4) {
        float r = s_red[tid] + s_red[4 + tid] + s_red[8 + tid] + s_red[12 + tid];
        s_binv[tid] = 1.0f / fmaxf(r, 1e-16f);
    }
    __syncthreads();

    float4 acc = make_float4(0.f, 0.f, 0.f, 0.f);
    int hof = (coff + tid * 4) / CPH;

    for (int c0 = beg; c0 < end; c0 += 32) {
        int cnt = min(32, end - c0);
        if (tid < cnt * 4) {
            int j = tid >> 2, hh = tid & 3;
            int s = csrsrc[c0 + j];
            if (hh == 0) s_src[j] = s;
            float t = alS[(size_t)s * 4 + hh] + adv[hh];
            t = t > 0.f ? t : 0.2f * t;
            s_al[j][hh] = expf(t - s_bm[hh]) * s_binv[hh];
        }
        __syncthreads();
        int j = 0;
        for (; j + 4 <= cnt; j += 4) {
            const uint2* p0 = (const uint2*)(h + (size_t)s_src[j + 0] * HC + coff) + tid;
            const uint2* p1 = (const uint2*)(h + (size_t)s_src[j + 1] * HC + coff) + tid;
            const uint2* p2 = (const uint2*)(h + (size_t)s_src[j + 2] * HC + coff) + tid;
            const uint2* p3 = (const uint2*)(h + (size_t)s_src[j + 3] * HC + coff) + tid;
            uint2 r0 = *p0, r1 = *p1, r2 = *p2, r3 = *p3;
            float a0 = s_al[j + 0][hof];
            float a1 = s_al[j + 1][hof];
            float a2 = s_al[j + 2][hof];
            float a3 = s_al[j + 3][hof];
            float2 f0a = __half22float2(*(__half2*)&r0.x);
            float2 f0b = __half22float2(*(__half2*)&r0.y);
            float2 f1a = __half22float2(*(__half2*)&r1.x);
            float2 f1b = __half22float2(*(__half2*)&r1.y);
            float2 f2a = __half22float2(*(__half2*)&r2.x);
            float2 f2b = __half22float2(*(__half2*)&r2.y);
            float2 f3a = __half22float2(*(__half2*)&r3.x);
            float2 f3b = __half22float2(*(__half2*)&r3.y);
            acc.x = fmaf(a0, f0a.x, acc.x); acc.y = fmaf(a0, f0a.y, acc.y);
            acc.z = fmaf(a0, f0b.x, acc.z); acc.w = fmaf(a0, f0b.y, acc.w);
            acc.x = fmaf(a1, f1a.x, acc.x); acc.y = fmaf(a1, f1a.y, acc.y);
            acc.z = fmaf(a1, f1b.x, acc.z); acc.w = fmaf(a1, f1b.y, acc.w);
            acc.x = fmaf(a2, f2a.x, acc.x); acc.y = fmaf(a2, f2a.y, acc.y);
            acc.z = fmaf(a2, f2b.x, acc.z); acc.w = fmaf(a2, f2b.y, acc.w);
            acc.x = fmaf(a3, f3a.x, acc.x); acc.y = fmaf(a3, f3a.y, acc.y);
            acc.z = fmaf(a3, f3b.x, acc.z); acc.w = fmaf(a3, f3b.y, acc.w);
        }
        for (; j < cnt; j++) {
            const uint2* p = (const uint2*)(h + (size_t)s_src[j] * HC + coff) + tid;
            uint2 rr = *p;
            float a = s_al[j][hof];
            float2 fa = __half22float2(*(__half2*)&rr.x);
            float2 fb = __half22float2(*(__half2*)&rr.y);
            acc.x = fmaf(a, fa.x, acc.x);
            acc.y = fmaf(a, fa.y, acc.y);
            acc.z = fmaf(a, fb.x, acc.z);
            acc.w = fmaf(a, fb.y, acc.w);
        }
        __syncthreads();
    }

    uint2 ov;
    __half2 o0 = __floats2half2_rn(acc.x, acc.y);
    __half2 o1 = __floats2half2_rn(acc.z, acc.w);
    ov.x = *(uint32_t*)&o0;
    ov.y = *(uint32_t*)&o1;
    *((uint2*)(out + (size_t)d * HC + coff) + tid) = ov;
}

// ---------------- GCN gather (fp16 in, fp32 out) -----------------------------
__global__ __launch_bounds__(64) void gcn_gather_h(
    const int* __restrict__ rowptr, const int* __restrict__ csrsrc,
    const float* __restrict__ dinv, const __half* __restrict__ h,
    float* __restrict__ out)
{
    int d = blockIdx.x;
    int tid = threadIdx.x;
    int beg = rowptr[d], end = rowptr[d + 1];
    float dd = dinv[d];

    float4 acc = make_float4(0.f, 0.f, 0.f, 0.f);
    int i = beg;
    for (; i + 4 <= end; i += 4) {
        int s0 = csrsrc[i + 0], s1 = csrsrc[i + 1];
        int s2 = csrsrc[i + 2], s3 = csrsrc[i + 3];
        float n0 = dinv[s0] * dd, n1 = dinv[s1] * dd;
        float n2 = dinv[s2] * dd, n3 = dinv[s3] * dd;
        uint2 r0 = *((const uint2*)(h + (size_t)s0 * 256) + tid);
        uint2 r1 = *((const uint2*)(h + (size_t)s1 * 256) + tid);
        uint2 r2 = *((const uint2*)(h + (size_t)s2 * 256) + tid);
        uint2 r3 = *((const uint2*)(h + (size_t)s3 * 256) + tid);
        float2 f0a = __half22float2(*(__half2*)&r0.x);
        float2 f0b = __half22float2(*(__half2*)&r0.y);
        float2 f1a = __half22float2(*(__half2*)&r1.x);
        float2 f1b = __half22float2(*(__half2*)&r1.y);
        float2 f2a = __half22float2(*(__half2*)&r2.x);
        float2 f2b = __half22float2(*(__half2*)&r2.y);
        float2 f3a = __half22float2(*(__half2*)&r3.x);
        float2 f3b = __half22float2(*(__half2*)&r3.y);
        acc.x = fmaf(n0, f0a.x, acc.x); acc.y = fmaf(n0, f0a.y, acc.y);
        acc.z = fmaf(n0, f0b.x, acc.z); acc.w = fmaf(n0, f0b.y, acc.w);
        acc.x = fmaf(n1, f1a.x, acc.x); acc.y = fmaf(n1, f1a.y, acc.y);
        acc.z = fmaf(n1, f1b.x, acc.z); acc.w = fmaf(n1, f1b.y, acc.w);
        acc.x = fmaf(n2, f2a.x, acc.x); acc.y = fmaf(n2, f2a.y, acc.y);
        acc.z = fmaf(n2, f2b.x, acc.z); acc.w = fmaf(n2, f2b.y, acc.w);
        acc.x = fmaf(n3, f3a.x, acc.x); acc.y = fmaf(n3, f3a.y, acc.y);
        acc.z = fmaf(n3, f3b.x, acc.z); acc.w = fmaf(n3, f3b.y, acc.w);
    }
    for (; i < end; i++) {
        int s = csrsrc[i];
        float nrm = dinv[s] * dd;
        uint2 rr = *((const uint2*)(h + (size_t)s * 256) + tid);
        float2 fa = __half22float2(*(__half2*)&rr.x);
        float2 fb = __half22float2(*(__half2*)&rr.y);
        acc.x = fmaf(nrm, fa.x, acc.x);
        acc.y = fmaf(nrm, fa.y, acc.y);
        acc.z = fmaf(nrm, fb.x, acc.z);
        acc.w = fmaf(nrm, fb.y, acc.w);
    }
    *(float4*)(out + (size_t)d * 256 + tid * 4) = acc;
}

// ---------------- BatchNorm -------------------------------------------------
__global__ void bn_stats(const float* __restrict__ x, int rows, int K,
                         float* __restrict__ sum, float* __restrict__ sq)
{
    int col = blockIdx.x * blockDim.x + threadIdx.x;
    float s = 0.f, q = 0.f;
    for (int r = blockIdx.y; r < rows; r += gridDim.y) {
        float v = x[(size_t)r * K + col];
        s += v;
        q += v * v;
    }
    atomicAdd(sum + col, s);
    atomicAdd(sq + col, q);
}

__global__ void bn_stats_h(const __half* __restrict__ x, int rows, int K,
                           float* __restrict__ sum, float* __restrict__ sq)
{
    int col = blockIdx.x * blockDim.x + threadIdx.x;
    float s = 0.f, q = 0.f;
    for (int r = blockIdx.y; r < rows; r += gridDim.y) {
        float v = __half2float(x[(size_t)r * K + col]);
        s += v;
        q += v * v;
    }
    atomicAdd(sum + col, s);
    atomicAdd(sq + col, q);
}

__global__ void bn_finalize(const float* __restrict__ sum, const float* __restrict__ sq,
                            const float* __restrict__ g, const float* __restrict__ b,
                            int rows, int K, float* __restrict__ scale,
                            float* __restrict__ shift)
{
    int c = blockIdx.x * blockDim.x + threadIdx.x;
    if (c >= K) return;
    float inv_n = 1.0f / (float)rows;
    float mu = sum[c] * inv_n;
    float var = sq[c] * inv_n - mu * mu;
    float sc = g[c] * rsqrtf(var + 1e-5f);
    scale[c] = sc;
    shift[c] = b[c] - mu * sc;
}

__global__ void bn_apply_relu(float* __restrict__ x, const float* __restrict__ scale,
                              const float* __restrict__ shift, size_t total, int K)
{
    for (size_t i = (size_t)blockIdx.x * blockDim.x + threadIdx.x; i < total;
         i += (size_t)gridDim.x * blockDim.x) {
        int c = (int)(i % K);
        float v = x[i] * scale[c] + shift[c];
        x[i] = v > 0.f ? v : 0.f;
    }
}

// ---------------- Pooling: one block per graph (batch sorted, no atomics) ----
__global__ __launch_bounds__(256) void pool_graph(
    const float* __restrict__ h, const int* __restrict__ gstart,
    const float* __restrict__ scale, const float* __restrict__ shift,
    float* __restrict__ z)
{
    int g = blockIdx.x;
    int c = threadIdx.x;
    int beg = gstart[g], end = gstart[g + 1];
    float sc = scale[c], sh = shift[c];
    float sum = 0.f, mx = 0.f;
    for (int r = beg; r < end; r++) {
        float v = fmaxf(fmaf(h[(size_t)r * 256 + c], sc, sh), 0.f);
        sum += v;
        mx = fmaxf(mx, v);
    }
    float cnt = (float)(end - beg);
    z[(size_t)g * 640 + c] = sum / fmaxf(cnt, 1.0f);
    z[(size_t)g * 640 + 256 + c] = mx;
}

// ---------------- Head -------------------------------------------------------
__global__ void head_final(const float* __restrict__ zf, const float* __restrict__ Wf2,
                           const float* __restrict__ bf2, float* __restrict__ out)
{
    int g = blockIdx.x;
    int t = threadIdx.x;
    float v = zf[(size_t)g * 128 + t] * Wf2[t];
#pragma unroll
    for (int o = 16; o; o >>= 1) v += __shfl_down_sync(0xFFFFFFFFu, v, o);
    __shared__ float sm[4];
    if ((t & 31) == 0) sm[t >> 5] = v;
    __syncthreads();
    if (t == 0) {
        float s = sm[0] + sm[1] + sm[2] + sm[3] + bf2[0];
        out[g] = 1.0f / (1.0f + expf(-s));
    }
}

// ---------------- launch ------------------------------------------------------
extern "C" void kernel_launch(void* const* d_in, const int* in_sizes, int n_in,
                              void* d_out, int out_size)
{
    const float* x    = (const float*)d_in[0];
    const int*   ei   = (const int*)d_in[1];
    const int*   batch= (const int*)d_in[2];
    const float* fp   = (const float*)d_in[3];
    const float* W1   = (const float*)d_in[4];
    const float* a1s  = (const float*)d_in[5];
    const float* a1d  = (const float*)d_in[6];
    const float* bn1g = (const float*)d_in[8];
    const float* bn1b = (const float*)d_in[9];
    const float* W2   = (const float*)d_in[10];
    const float* a2s  = (const float*)d_in[11];
    const float* a2d  = (const float*)d_in[12];
    const float* bn2g = (const float*)d_in[14];
    const float* bn2b = (const float*)d_in[15];
    const float* Wg   = (const float*)d_in[16];
    const float* bn3g = (const float*)d_in[18];
    const float* bn3b = (const float*)d_in[19];
    const float* Ws   = (const float*)d_in[20];
    const float* bs   = (const float*)d_in[21];
    const float* Wf1  = (const float*)d_in[22];
    const float* bnfg = (const float*)d_in[24];
    const float* bnfb = (const float*)d_in[25];
    const float* Wf2  = (const float*)d_in[26];
    const float* bf2  = (const float*)d_in[27];
    float* out = (float*)d_out;

    int n    = in_sizes[0] / 64;
    int E    = in_sizes[1] / 2;
    int Etot = E + n;
    int G    = in_sizes[3] / 128;

    float *bufA, *bufB, *bufC, *alS, *alD, *dinv, *uu, *vv;
    float *bnsum, *bnsq, *bnscale, *bnshift, *z, *zf;
    __half *w1p, *w2p, *wgp;
    int *degi, *incl, *part, *rowptr, *cursor, *csrsrc, *gstart;
    cudaGetSymbolAddress((void**)&bufA, g_bufA);
    cudaGetSymbolAddress((void**)&bufB, g_bufB);
    cudaGetSymbolAddress((void**)&bufC, g_bufC);
    cudaGetSymbolAddress((void**)&w1p, g_w1p);
    cudaGetSymbolAddress((void**)&w2p, g_w2p);
    cudaGetSymbolAddress((void**)&wgp, g_wgp);
    cudaGetSymbolAddress((void**)&alS, g_alS);
    cudaGetSymbolAddress((void**)&alD, g_alD);
    cudaGetSymbolAddress((void**)&uu, g_u);
    cudaGetSymbolAddress((void**)&vv, g_v);
    cudaGetSymbolAddress((void**)&degi, g_degi);
    cudaGetSymbolAddress((void**)&incl, g_incl);
    cudaGetSymbolAddress((void**)&part, g_part);
    cudaGetSymbolAddress((void**)&rowptr, g_rowptr);
    cudaGetSymbolAddress((void**)&cursor, g_cursor);
    cudaGetSymbolAddress((void**)&csrsrc, g_csrsrc);
    cudaGetSymbolAddress((void**)&dinv, g_dinv);
    cudaGetSymbolAddress((void**)&gstart, g_gstart);
    cudaGetSymbolAddress((void**)&bnsum, g_bnsum);
    cudaGetSymbolAddress((void**)&bnsq, g_bnsq);
    cudaGetSymbolAddress((void**)&bnscale, g_bnscale);
    cudaGetSymbolAddress((void**)&bnshift, g_bnshift);
    cudaGetSymbolAddress((void**)&z, g_z);
    cudaGetSymbolAddress((void**)&zf, g_zf);

    __half* bufA_h = (__half*)bufA;
    __half* bufB_h = (__half*)bufB;
    __half* bufC_h = (__half*)bufC;

    size_t tf_smem = SMEM_FLOATS * sizeof(float);
    static bool attr_done = false;
    if (!attr_done) {
        cudaFuncSetAttribute(tf32gemm,
                             cudaFuncAttributeMaxDynamicSharedMemorySize, (int)tf_smem);
        attr_done = true;
    }

    auto bnstats_h = [&](const __half* Xp, int rows, int K, const float* gg,
                         const float* bb) {
        cudaMemsetAsync(bnsum, 0, K * sizeof(float));
        cudaMemsetAsync(bnsq, 0, K * sizeof(float));
        dim3 g1(K / 128, 128);
        bn_stats_h<<<g1, 128>>>(Xp, rows, K, bnsum, bnsq);
        bn_finalize<<<(K + 127) / 128, 128>>>(bnsum, bnsq, gg, bb, rows, K,
                                              bnscale, bnshift);
    };

    // ---- CSR build + graph boundaries + weight packing (independent)
    cudaMemsetAsync(degi, 0, n * sizeof(int));
    deg_build<<<(Etot + 255) / 256, 256>>>(ei, E, Etot, degi);
    int nb = (n + 1023) / 1024;
    scan_partial<<<nb, 1024>>>(degi, n, incl, part);
    scan_roots<<<1, 128>>>(part, nb);
    scan_add<<<(n + 255) / 256, 256>>>(incl, degi, part, n, Etot,
                                       rowptr, cursor, dinv);
    csr_scatter<<<(Etot + 255) / 256, 256>>>(ei, E, Etot, cursor, csrsrc);
    gstart_build<<<(n + 256) / 256, 256>>>(batch, n, G, gstart);
    pack_w<<<(64 * 512 + 255) / 256, 256>>>(W1, 64, 512, w1p);
    pack_w<<<(512 * 1024 + 255) / 256, 256>>>(W2, 512, 1024, w2p);
    pack_w<<<(1024 * 256 + 255) / 256, 256>>>(Wg, 1024, 256, wgp);

    // ---- GAT layer 1 (input-space): exact fp32 alphas; gather x -> fp16; hgemm
    uv_build<<<(64 * 4 * 32 + 255) / 256, 256>>>(W1, a1s, a1d, 64, 128, uu, vv);
    alpha_gemm64<<<(n + 7) / 8, 256>>>(x, n, uu, vv, alS, alD);
    gat_agg_in64<<<n, 64>>>(rowptr, csrsrc, alS, alD, x, bufA_h);
    {
        dim3 grid(4, (n + 127) / 128);
        hgemm<false, false, true, true><<<grid, 256, H_SMEM>>>(
            bufA_h, w1p, bufB_h, n, 512, 64, 256, 512,
            nullptr, nullptr, nullptr, nullptr, 128, nullptr, nullptr);
    }
    bnstats_h(bufB_h, n, 512, bn1g, bn1b);

    // ---- GAT layer 2: bufC_h = relu(bn(bufB_h))@W2 (+ alphas); gather -> bufA_h
    cudaMemsetAsync(alS, 0, (size_t)n * 4 * sizeof(float));
    cudaMemsetAsync(alD, 0, (size_t)n * 4 * sizeof(float));
    {
        dim3 grid(8, (n + 127) / 128);
        hgemm<true, true, false, true><<<grid, 256, H_SMEM>>>(
            bufB_h, w2p, bufC_h, n, 1024, 512, 512, 1024,
            bnscale, bnshift, a2s, a2d, 256, alS, alD);
    }
    {
        dim3 grid(n, 2);
        gat_gather_h<1024, 2><<<grid, 128>>>(rowptr, csrsrc, alS, alD, bufC_h, bufA_h);
    }
    bnstats_h(bufA_h, n, 1024, bn2g, bn2b);

    // ---- GCN: bufB_h = relu(bn(bufA_h))@Wg; gather -> bufC (fp32); BN stats
    {
        dim3 grid(2, (n + 127) / 128);
        hgemm<true, false, false, true><<<grid, 256, H_SMEM>>>(
            bufA_h, wgp, bufB_h, n, 256, 1024, 1024, 256,
            bnscale, bnshift, nullptr, nullptr, 256, nullptr, nullptr);
    }
    gcn_gather_h<<<n, 64>>>(rowptr, csrsrc, dinv, bufB_h, bufC);
    {
        cudaMemsetAsync(bnsum, 0, 256 * sizeof(float));
        cudaMemsetAsync(bnsq, 0, 256 * sizeof(float));
        dim3 g1(2, 128);
        bn_stats<<<g1, 128>>>(bufC, n, 256, bnsum, bnsq);
        bn_finalize<<<2, 128>>>(bnsum, bnsq, bn3g, bn3b, n, 256, bnscale, bnshift);
    }

    // ---- Pooling into z[G,640] (block per graph; BN+relu on the fly)
    pool_graph<<<G, 256>>>(bufC, gstart, bnscale, bnshift, z);

    // ---- solvent MLP: relu(fp @ Ws + bs) -> z[:,512:640]
    {
        dim3 grid(1, (G + 127) / 128);
        sgemm<true><<<grid, 256>>>(fp, Ws, bs, z + 512, G, 128, 128, 128, 640);
    }

    // ---- head: zf = z @ Wf1 via tf32 (bf1 cancels under BN); BN; relu; sigmoid
    {
        dim3 grid(1, (G + 127) / 128);
        tf32gemm<<<grid, 256, tf_smem>>>(z, Wf1, zf, G, 128, 640, 640, 128, 128);
    }
    {
        cudaMemsetAsync(bnsum, 0, 128 * sizeof(float));
        cudaMemsetAsync(bnsq, 0, 128 * sizeof(float));
        dim3 g1(1, 128);
        bn_stats<<<g1, 128>>>(zf, G, 128, bnsum, bnsq);
        bn_finalize<<<1, 128>>>(bnsum, bnsq, bnfg, bnfb, G, 128, bnscale, bnshift);
        bn_apply_relu<<<((size_t)G * 128 + 255) / 256, 256>>>(zf, bnscale, bnshift,
                                                              (size_t)G * 128, 128);
    }
    head_final<<<G, 128>>>(zf, Wf2, bf2, out);
}

// round 13
// speedup vs baseline: 1.3893x; 1.0279x over previous
#include <cuda_runtime.h>
#include <cuda_fp16.h>
#include <math.h>
#include <stdint.h>

// Problem capacities (fixed shapes per reference)
#define NMAXN 50000
#define EMAXE 200000
#define ETOTMAX (EMAXE + NMAXN)
#define GMAXG 1000

// ---------------- scratch (static device memory; no allocations allowed) ----
__device__ float g_bufA[(size_t)NMAXN * 1024];
__device__ float g_bufB[(size_t)NMAXN * 1024];
__device__ float g_bufC[(size_t)NMAXN * 1024];
__device__ __half g_w1p[64 * 512];
__device__ __half g_w2p[512 * 1024];
__device__ __half g_wgp[1024 * 256];
__device__ float g_alS[NMAXN * 4];
__device__ float g_alD[NMAXN * 4];
__device__ float g_u[512 * 4];
__device__ float g_v[512 * 4];
__device__ int   g_degi[NMAXN];
__device__ int   g_incl[NMAXN];
__device__ int   g_part[128];
__device__ int   g_rowptr[NMAXN + 1];
__device__ int   g_cursor[NMAXN];
__device__ int   g_csrsrc[ETOTMAX];
__device__ float g_dinv[NMAXN];
__device__ int   g_gstart[GMAXG + 1];
__device__ float g_bnsum[1024];
__device__ float g_bnsq[1024];
__device__ float g_bnscale[1024];
__device__ float g_bnshift[1024];
__device__ float g_z[GMAXG * 640];
__device__ float g_zf[GMAXG * 128];

// ---------------- CSR build -------------------------------------------------
__global__ void deg_build(const int* __restrict__ ei, int E, int Etot,
                          int* __restrict__ degi)
{
    int e = blockIdx.x * blockDim.x + threadIdx.x;
    if (e >= Etot) return;
    int d = (e < E) ? ei[E + e] : (e - E);
    atomicAdd(degi + d, 1);
}

__global__ __launch_bounds__(1024) void scan_partial(
    const int* __restrict__ degi, int n, int* __restrict__ incl,
    int* __restrict__ part)
{
    __shared__ int sm[32];
    int tid = threadIdx.x;
    int lane = tid & 31, w = tid >> 5;
    int i = blockIdx.x * 1024 + tid;
    int v = (i < n) ? degi[i] : 0;
    int x = v;
#pragma unroll
    for (int o = 1; o < 32; o <<= 1) {
        int y = __shfl_up_sync(0xFFFFFFFFu, x, o);
        if (lane >= o) x += y;
    }
    if (lane == 31) sm[w] = x;
    __syncthreads();
    if (w == 0) {
        int y = sm[lane];
#pragma unroll
        for (int o = 1; o < 32; o <<= 1) {
            int z = __shfl_up_sync(0xFFFFFFFFu, y, o);
            if (lane >= o) y += z;
        }
        sm[lane] = y;
    }
    __syncthreads();
    int inclv = x + (w ? sm[w - 1] : 0);
    if (i < n) incl[i] = inclv;
    if (tid == 1023) part[blockIdx.x] = inclv;
}

__global__ void scan_roots(int* __restrict__ part, int nb)
{
    __shared__ int sm[128];
    int t = threadIdx.x;
    sm[t] = (t < nb) ? part[t] : 0;
    __syncthreads();
    if (t == 0) {
        int run = 0;
        for (int i = 0; i < nb; i++) { int v = sm[i]; sm[i] = run; run += v; }
    }
    __syncthreads();
    if (t < nb) part[t] = sm[t];
}

__global__ void scan_add(const int* __restrict__ incl, const int* __restrict__ degi,
                         const int* __restrict__ part, int n, int Etot,
                         int* __restrict__ rowptr, int* __restrict__ cursor,
                         float* __restrict__ dinv)
{
    int i = blockIdx.x * blockDim.x + threadIdx.x;
    if (i == 0) rowptr[n] = Etot;
    if (i >= n) return;
    int dg = degi[i];
    int exc = incl[i] + part[i >> 10] - dg;
    rowptr[i] = exc;
    cursor[i] = exc;
    dinv[i] = rsqrtf(fmaxf((float)dg, 1.0f));
}

__global__ void csr_scatter(const int* __restrict__ ei, int E, int Etot,
                            int* __restrict__ cursor, int* __restrict__ csrsrc)
{
    int e = blockIdx.x * blockDim.x + threadIdx.x;
    if (e >= Etot) return;
    int s, d;
    if (e < E) { s = ei[e]; d = ei[E + e]; }
    else       { s = e - E; d = e - E; }
    int pos = atomicAdd(cursor + d, 1);
    csrsrc[pos] = s;
}

__global__ void gstart_build(const int* __restrict__ batch, int n, int G,
                             int* __restrict__ gstart)
{
    int i = blockIdx.x * blockDim.x + threadIdx.x;
    if (i < n) {
        int b = batch[i];
        int bp = (i > 0) ? batch[i - 1] : -1;
        for (int g = bp + 1; g <= b; g++) gstart[g] = i;
    } else if (i == n) {
        int bl = batch[n - 1];
        for (int g = bl + 1; g <= G; g++) gstart[g] = n;
    }
}

// ---------------- weight packing (all three weights, one launch) -------------
// Wp[k/2][n][2] fp16
__device__ __forceinline__ void pack_one(const float* __restrict__ W, int Nc, int i,
                                         __half* __restrict__ Wp)
{
    int k = i / Nc, nn = i % Nc;
    Wp[(size_t)(k >> 1) * 2 * Nc + 2 * nn + (k & 1)] = __float2half_rn(W[i]);
}

__global__ void pack_all(const float* __restrict__ W1, const float* __restrict__ W2,
                         const float* __restrict__ Wg,
                         __half* __restrict__ w1p, __half* __restrict__ w2p,
                         __half* __restrict__ wgp)
{
    const int S1 = 64 * 512, S2 = 512 * 1024, S3 = 1024 * 256;
    int i = blockIdx.x * blockDim.x + threadIdx.x;
    if (i < S1) pack_one(W1, 512, i, w1p);
    else if (i < S1 + S2) pack_one(W2, 1024, i - S1, w2p);
    else if (i < S1 + S2 + S3) pack_one(Wg, 256, i - S1 - S2, wgp);
}

// ---------------- u/v vectors: u[k,h] = sum_c W[k,hC+c]*a[h,c] ---------------
__global__ void uv_build(const float* __restrict__ W, const float* __restrict__ aS,
                         const float* __restrict__ aD, int K, int C,
                         float* __restrict__ u, float* __restrict__ v)
{
    int idx = blockIdx.x * blockDim.x + threadIdx.x;
    int warp = idx >> 5, lane = idx & 31;
    if (warp >= K * 4) return;
    int k = warp >> 2, h = warp & 3;
    const float* wrow = W + (size_t)k * (4 * C) + h * C;
    const float* as = aS + h * C;
    const float* ad = aD + h * C;
    float s = 0.f, d = 0.f;
    for (int c = lane; c < C; c += 32) {
        float wv = wrow[c];
        s += wv * as[c];
        d += wv * ad[c];
    }
#pragma unroll
    for (int o = 16; o; o >>= 1) {
        s += __shfl_xor_sync(0xFFFFFFFFu, s, o);
        d += __shfl_xor_sync(0xFFFFFFFFu, d, o);
    }
    if (lane == 0) { u[k * 4 + h] = s; v[k * 4 + h] = d; }
}

// ---------------- skinny alpha GEMM (layer 1, K=64, fp32 exact) --------------
__global__ __launch_bounds__(256) void alpha_gemm64(
    const float* __restrict__ in, int n,
    const float* __restrict__ u, const float* __restrict__ v,
    float* __restrict__ alS, float* __restrict__ alD)
{
    __shared__ float su[64][4];
    __shared__ float sv[64][4];
    int tid = threadIdx.x;
    if (tid < 64 * 4) { su[tid >> 2][tid & 3] = u[tid]; sv[tid >> 2][tid & 3] = v[tid]; }
    __syncthreads();

    int warp = tid >> 5, lane = tid & 31;
    for (int node = blockIdx.x * 8 + warp; node < n; node += gridDim.x * 8) {
        const float* row = in + (size_t)node * 64;
        float x0 = row[lane], x1 = row[lane + 32];
        float as[4], ad[4];
#pragma unroll
        for (int h = 0; h < 4; h++) {
            as[h] = x0 * su[lane][h] + x1 * su[lane + 32][h];
            ad[h] = x0 * sv[lane][h] + x1 * sv[lane + 32][h];
        }
#pragma unroll
        for (int h = 0; h < 4; h++) {
#pragma unroll
            for (int o = 16; o; o >>= 1) {
                as[h] += __shfl_xor_sync(0xFFFFFFFFu, as[h], o);
                ad[h] += __shfl_xor_sync(0xFFFFFFFFu, ad[h], o);
            }
        }
        if (lane == 0) {
            *(float4*)(alS + (size_t)node * 4) = make_float4(as[0], as[1], as[2], as[3]);
            *(float4*)(alD + (size_t)node * 4) = make_float4(ad[0], ad[1], ad[2], ad[3]);
        }
    }
}

// ---------------- FP16 tensor-core GEMM (k-tile 64, double-buffered) ---------
__device__ __forceinline__ void mma_f16(float c[4], const uint32_t a[4],
                                        uint32_t b0, uint32_t b1) {
    asm volatile(
        "mma.sync.aligned.m16n8k16.row.col.f32.f16.f16.f32 "
        "{%0,%1,%2,%3}, {%4,%5,%6,%7}, {%8,%9}, {%0,%1,%2,%3};"
        : "+f"(c[0]), "+f"(c[1]), "+f"(c[2]), "+f"(c[3])
        : "r"(a[0]), "r"(a[1]), "r"(a[2]), "r"(a[3]), "r"(b0), "r"(b1));
}

__device__ __forceinline__ void cp_async16(void* smem_dst, const void* gmem_src,
                                           bool pred) {
    uint32_t saddr = (uint32_t)__cvta_generic_to_shared(smem_dst);
    int sz = pred ? 16 : 0;
    asm volatile("cp.async.cg.shared.global [%0], [%1], 16, %2;\n"
                 :: "r"(saddr), "l"(gmem_src), "r"(sz));
}

__device__ __forceinline__ uint32_t bnrelu_h2(uint32_t v, float2 sc, float2 sh) {
    float2 f = __half22float2(*(__half2*)&v);
    f.x = fmaxf(fmaf(f.x, sc.x, sh.x), 0.f);
    f.y = fmaxf(fmaf(f.y, sc.y, sh.y), 0.f);
    __half2 h = __floats2half2_rn(f.x, f.y);
    return *(uint32_t*)&h;
}

// k-tile 64: A stage = 128 rows x 36 half2 (32 data + 4 pad) = 18432 B
//            B stage = 32 k2-rows x 136 half2 = 17408 B; 2 stages.
#define H_ASTG 18432
#define H_BSTG 17408
#define H_SMEM (2 * (H_ASTG + H_BSTG))

// C[M,Nc] = op(A)[M,K] @ B[K,Nc]; A fp16 [M,K]; Bp fp16 k-pair packed.
// K % 64 == 0. op = relu(bn) if BNRELU. GROUP: A += (blockN/128)*K.
// ALPHA: logit partials. HALFOUT: C written fp16.
template <bool BNRELU, bool ALPHA, bool GROUP, bool HALFOUT>
__global__ __launch_bounds__(256, 2) void hgemm(
    const __half* __restrict__ A, const __half* __restrict__ Bp,
    void* __restrict__ Cout, int M, int Nc, int K, int lda, int ldc,
    const float* __restrict__ scale, const float* __restrict__ shift,
    const float* __restrict__ aS, const float* __restrict__ aD, int Chead,
    float* __restrict__ alS, float* __restrict__ alD)
{
    extern __shared__ char smem[];

    int tid = threadIdx.x;
    int lane = tid & 31;
    int wid = tid >> 5;
    int warpM = (wid >> 2) * 64;
    int warpN = (wid & 3) * 32;
    int r = lane >> 2;
    int cq = lane & 3;

    int blockM = blockIdx.y * 128;
    int blockN = blockIdx.x * 128;

    if (GROUP) A += (size_t)(blockN >> 7) * K;

    float acc[4][4][4];
#pragma unroll
    for (int mt = 0; mt < 4; mt++)
#pragma unroll
        for (int nt = 0; nt < 4; nt++)
#pragma unroll
            for (int i = 0; i < 4; i++) acc[mt][nt][i] = 0.0f;

    int nk = K >> 6;

    auto load_tile = [&](int kt, int buf) {
        char* As = smem + buf * H_ASTG;
        char* Bs = smem + 2 * H_ASTG + buf * H_BSTG;
#pragma unroll
        for (int i = 0; i < 4; i++) {
            int row = (tid >> 3) + i * 32;
            int grow = blockM + row;
            cp_async16(As + (size_t)row * 144 + (tid & 7) * 16,
                       A + (size_t)grow * lda + kt * 64 + (tid & 7) * 8,
                       grow < M);
        }
#pragma unroll
        for (int i = 0; i < 4; i++) {
            int c = tid + i * 256;
            int krow = c >> 5;          // 0..31
            int nc4 = (c & 31) * 4;     // half2 index 0..124
            cp_async16(Bs + ((size_t)krow * 136 + nc4) * 4,
                       Bp + (size_t)(kt * 32 + krow) * 2 * Nc + 2 * blockN + nc4 * 2,
                       true);
        }
        asm volatile("cp.async.commit_group;\n");
    };

    load_tile(0, 0);

    for (int kt = 0; kt < nk; kt++) {
        if (kt + 1 < nk) {
            load_tile(kt + 1, (kt + 1) & 1);
            asm volatile("cp.async.wait_group 1;\n");
        } else {
            asm volatile("cp.async.wait_group 0;\n");
        }
        __syncthreads();

        const uint32_t* As2 = (const uint32_t*)(smem + (kt & 1) * H_ASTG);
        const uint32_t* Bs2 = (const uint32_t*)(smem + 2 * H_ASTG + (kt & 1) * H_BSTG);

#pragma unroll
        for (int ks = 0; ks < 4; ks++) {
            int kb2 = ks * 8;
            float2 sc01, sh01, sc23, sh23;
            if (BNRELU) {
                int kg = kt * 64 + ks * 16 + 2 * cq;
                sc01 = *(const float2*)(scale + kg);
                sh01 = *(const float2*)(shift + kg);
                sc23 = *(const float2*)(scale + kg + 8);
                sh23 = *(const float2*)(shift + kg + 8);
            }
            uint32_t a[4][4], b[4][2];
#pragma unroll
            for (int mt = 0; mt < 4; mt++) {
                int m = warpM + mt * 16 + r;
                uint32_t a0 = As2[m * 36 + kb2 + cq];
                uint32_t a1 = As2[(m + 8) * 36 + kb2 + cq];
                uint32_t a2 = As2[m * 36 + kb2 + cq + 4];
                uint32_t a3 = As2[(m + 8) * 36 + kb2 + cq + 4];
                if (BNRELU) {
                    a0 = bnrelu_h2(a0, sc01, sh01);
                    a1 = bnrelu_h2(a1, sc01, sh01);
                    a2 = bnrelu_h2(a2, sc23, sh23);
                    a3 = bnrelu_h2(a3, sc23, sh23);
                }
                a[mt][0] = a0; a[mt][1] = a1; a[mt][2] = a2; a[mt][3] = a3;
            }
#pragma unroll
            for (int nt = 0; nt < 4; nt++) {
                int nn = warpN + nt * 8 + r;
                b[nt][0] = Bs2[(kb2 + cq) * 136 + nn];
                b[nt][1] = Bs2[(kb2 + cq + 4) * 136 + nn];
            }
#pragma unroll
            for (int mt = 0; mt < 4; mt++)
#pragma unroll
                for (int nt = 0; nt < 4; nt++)
                    mma_f16(acc[mt][nt], a[mt], b[nt][0], b[nt][1]);
        }
        __syncthreads();
    }

#pragma unroll
    for (int mt = 0; mt < 4; mt++) {
        int row0 = blockM + warpM + mt * 16 + r;
#pragma unroll
        for (int nt = 0; nt < 4; nt++) {
            int col = blockN + warpN + nt * 8 + cq * 2;
            if (HALFOUT) {
                __half2* Ch = (__half2*)Cout;
                if (row0 < M)
                    Ch[((size_t)row0 * ldc + col) >> 1] =
                        __floats2half2_rn(acc[mt][nt][0], acc[mt][nt][1]);
                if (row0 + 8 < M)
                    Ch[((size_t)(row0 + 8) * ldc + col) >> 1] =
                        __floats2half2_rn(acc[mt][nt][2], acc[mt][nt][3]);
            } else {
                float* C = (float*)Cout;
                if (row0 < M)
                    *(float2*)(C + (size_t)row0 * ldc + col) =
                        make_float2(acc[mt][nt][0], acc[mt][nt][1]);
                if (row0 + 8 < M)
                    *(float2*)(C + (size_t)(row0 + 8) * ldc + col) =
                        make_float2(acc[mt][nt][2], acc[mt][nt][3]);
            }
        }
    }

    if (ALPHA) {
        int head = blockN / Chead;
        float ws[4][2], wd[4][2];
#pragma unroll
        for (int nt = 0; nt < 4; nt++) {
            int col = blockN + warpN + nt * 8 + cq * 2;
            int c = col - head * Chead;
            ws[nt][0] = aS[head * Chead + c];
            ws[nt][1] = aS[head * Chead + c + 1];
            wd[nt][0] = aD[head * Chead + c];
            wd[nt][1] = aD[head * Chead + c + 1];
        }
#pragma unroll
        for (int mt = 0; mt < 4; mt++) {
            float ps0 = 0.f, pd0 = 0.f, ps1 = 0.f, pd1 = 0.f;
#pragma unroll
            for (int nt = 0; nt < 4; nt++) {
                ps0 += acc[mt][nt][0] * ws[nt][0] + acc[mt][nt][1] * ws[nt][1];
                pd0 += acc[mt][nt][0] * wd[nt][0] + acc[mt][nt][1] * wd[nt][1];
                ps1 += acc[mt][nt][2] * ws[nt][0] + acc[mt][nt][3] * ws[nt][1];
                pd1 += acc[mt][nt][2] * wd[nt][0] + acc[mt][nt][3] * wd[nt][1];
            }
#pragma unroll
            for (int o = 1; o < 4; o <<= 1) {
                ps0 += __shfl_xor_sync(0xFFFFFFFFu, ps0, o);
                pd0 += __shfl_xor_sync(0xFFFFFFFFu, pd0, o);
                ps1 += __shfl_xor_sync(0xFFFFFFFFu, ps1, o);
                pd1 += __shfl_xor_sync(0xFFFFFFFFu, pd1, o);
            }
            if (cq == 0) {
                int row0 = blockM + warpM + mt * 16 + r;
                if (row0 < M) {
                    atomicAdd(alS + (size_t)row0 * 4 + head, ps0);
                    atomicAdd(alD + (size_t)row0 * 4 + head, pd0);
                }
                if (row0 + 8 < M) {
                    atomicAdd(alS + (size_t)(row0 + 8) * 4 + head, ps1);
                    atomicAdd(alD + (size_t)(row0 + 8) * 4 + head, pd1);
                }
            }
        }
    }
}

// ---------------- TF32 tensor-core GEMM (head z@Wf1 only) --------------------
__device__ __forceinline__ void mma_tf32(float c[4], const float a[4], const float b[2]) {
    asm volatile(
        "mma.sync.aligned.m16n8k8.row.col.f32.tf32.tf32.f32 "
        "{%0,%1,%2,%3}, {%4,%5,%6,%7}, {%8,%9}, {%0,%1,%2,%3};"
        : "+f"(c[0]), "+f"(c[1]), "+f"(c[2]), "+f"(c[3])
        : "r"(__float_as_uint(a[0])), "r"(__float_as_uint(a[1])),
          "r"(__float_as_uint(a[2])), "r"(__float_as_uint(a[3])),
          "r"(__float_as_uint(b[0])), "r"(__float_as_uint(b[1])));
}

#define ABUF 4608
#define BBUF 4352
#define SMEM_FLOATS (2 * ABUF + 2 * BBUF)

__global__ __launch_bounds__(256, 2) void tf32gemm(
    const float* __restrict__ A, const float* __restrict__ B,
    float* __restrict__ C, int M, int Nc, int K, int lda, int ldb, int ldc)
{
    extern __shared__ float smemf[];

    int tid = threadIdx.x;
    int lane = tid & 31;
    int wid = tid >> 5;
    int warpM = (wid >> 2) * 64;
    int warpN = (wid & 3) * 32;
    int r = lane >> 2;
    int cq = lane & 3;

    int blockM = blockIdx.y * 128;
    int blockN = blockIdx.x * 128;

    int acol = (tid & 7) * 4;
    int arow0 = tid >> 3;
    int bcol = (tid & 31) * 4;
    int brow0 = tid >> 5;

    float acc[4][4][4];
#pragma unroll
    for (int mt = 0; mt < 4; mt++)
#pragma unroll
        for (int nt = 0; nt < 4; nt++)
#pragma unroll
            for (int i = 0; i < 4; i++) acc[mt][nt][i] = 0.0f;

    int nk = K >> 5;

    auto load_tile = [&](int k0, int buf) {
        float* As = smemf + buf * ABUF;
        float* Bs = smemf + 2 * ABUF + buf * BBUF;
#pragma unroll
        for (int i = 0; i < 4; i++) {
            int row = blockM + arow0 + i * 32;
            cp_async16(&As[(arow0 + i * 32) * 36 + acol],
                       A + (size_t)row * lda + k0 + acol, row < M);
        }
#pragma unroll
        for (int i = 0; i < 4; i++) {
            int kr = brow0 + i * 8;
            cp_async16(&Bs[kr * 136 + bcol],
                       B + (size_t)(k0 + kr) * ldb + blockN + bcol, true);
        }
        asm volatile("cp.async.commit_group;\n");
    };

    load_tile(0, 0);

    for (int kt = 0; kt < nk; kt++) {
        if (kt + 1 < nk) {
            load_tile((kt + 1) << 5, (kt + 1) & 1);
            asm volatile("cp.async.wait_group 1;\n");
        } else {
            asm volatile("cp.async.wait_group 0;\n");
        }
        __syncthreads();

        const float* As = smemf + (kt & 1) * ABUF;
        const float* Bs = smemf + 2 * ABUF + (kt & 1) * BBUF;

#pragma unroll
        for (int kk = 0; kk < 4; kk++) {
            int kb = kk * 8;
            float a[4][4], b[4][2];
#pragma unroll
            for (int mt = 0; mt < 4; mt++) {
                int m = warpM + mt * 16 + r;
                a[mt][0] = As[m * 36 + kb + cq];
                a[mt][1] = As[(m + 8) * 36 + kb + cq];
                a[mt][2] = As[m * 36 + kb + cq + 4];
                a[mt][3] = As[(m + 8) * 36 + kb + cq + 4];
            }
#pragma unroll
            for (int nt = 0; nt < 4; nt++) {
                int nn = warpN + nt * 8 + r;
                b[nt][0] = Bs[(kb + cq) * 136 + nn];
                b[nt][1] = Bs[(kb + cq + 4) * 136 + nn];
            }
#pragma unroll
            for (int mt = 0; mt < 4; mt++)
#pragma unroll
                for (int nt = 0; nt < 4; nt++)
                    mma_tf32(acc[mt][nt], a[mt], b[nt]);
        }
        __syncthreads();
    }

#pragma unroll
    for (int mt = 0; mt < 4; mt++) {
        int row0 = blockM + warpM + mt * 16 + r;
#pragma unroll
        for (int nt = 0; nt < 4; nt++) {
            int col = blockN + warpN + nt * 8 + cq * 2;
            if (row0 < M)
                *(float2*)(C + (size_t)row0 * ldc + col) =
                    make_float2(acc[mt][nt][0], acc[mt][nt][1]);
            if (row0 + 8 < M)
                *(float2*)(C + (size_t)(row0 + 8) * ldc + col) =
                    make_float2(acc[mt][nt][2], acc[mt][nt][3]);
        }
    }
}

// ---------------- fp32 SGEMM (solvent MLP: bias+relu) ------------------------
template <bool RELU>
__global__ __launch_bounds__(256) void sgemm(
    const float* __restrict__ A, const float* __restrict__ B,
    const float* __restrict__ bias, float* __restrict__ C,
    int M, int Nc, int K, int lda, int ldc)
{
    __shared__ float As[8][128];
    __shared__ float Bs[8][128];

    int tid = threadIdx.x;
    int bx = blockIdx.x;
    int by = blockIdx.y;

    int tx = tid % 16;
    int ty = tid / 16;

    int rowA = by * 128 + tid / 2;
    int colA = (tid % 2) * 4;
    int rowB = tid / 32;
    int colB = (tid % 32) * 4;

    float acc[8][8];
#pragma unroll
    for (int i = 0; i < 8; i++)
#pragma unroll
        for (int j = 0; j < 8; j++) acc[i][j] = 0.0f;

    for (int k0 = 0; k0 < K; k0 += 8) {
        float4 av = make_float4(0.f, 0.f, 0.f, 0.f);
        if (rowA < M)
            av = *(const float4*)(A + (size_t)rowA * lda + k0 + colA);
        As[colA + 0][tid / 2] = av.x;
        As[colA + 1][tid / 2] = av.y;
        As[colA + 2][tid / 2] = av.z;
        As[colA + 3][tid / 2] = av.w;

        float4 bv = *(const float4*)(B + (size_t)(k0 + rowB) * Nc + bx * 128 + colB);
        *(float4*)(&Bs[rowB][colB]) = bv;

        __syncthreads();

#pragma unroll
        for (int kk = 0; kk < 8; kk++) {
            float ra[8], rb[8];
#pragma unroll
            for (int i = 0; i < 8; i++) ra[i] = As[kk][ty * 8 + i];
#pragma unroll
            for (int j = 0; j < 8; j++) rb[j] = Bs[kk][tx * 8 + j];
#pragma unroll
            for (int i = 0; i < 8; i++)
#pragma unroll
                for (int j = 0; j < 8; j++) acc[i][j] = fmaf(ra[i], rb[j], acc[i][j]);
        }
        __syncthreads();
    }

#pragma unroll
    for (int i = 0; i < 8; i++) {
        int row = by * 128 + ty * 8 + i;
        if (row >= M) continue;
#pragma unroll
        for (int j = 0; j < 8; j++) {
            int col = bx * 128 + tx * 8 + j;
            float v = acc[i][j];
            if (bias) v += bias[col];
            if (RELU) v = v > 0.f ? v : 0.f;
            C[(size_t)row * ldc + col] = v;
        }
    }
}

// ---- GAT layer 1 input-space gather (fp16 output) ---------------------------
__global__ __launch_bounds__(64) void gat_agg_in64(
    const int* __restrict__ rowptr, const int* __restrict__ csrsrc,
    const float* __restrict__ alS, const float* __restrict__ alD,
    const float* __restrict__ in, __half* __restrict__ agg)
{
    constexpr int NT = 64;
    __shared__ float s_red[8];
    __shared__ float s_bm[4];
    __shared__ float s_binv[4];
    __shared__ float s_al[16][4];
    __shared__ int   s_src[16];

    int d = blockIdx.x;
    int tid = threadIdx.x;
    int lane = tid & 31, w = tid >> 5;
    int beg = rowptr[d], end = rowptr[d + 1];

    float4 ad4 = *(const float4*)(alD + (size_t)d * 4);
    float adv[4] = {ad4.x, ad4.y, ad4.z, ad4.w};

    float mx[4] = {-INFINITY, -INFINITY, -INFINITY, -INFINITY};
    for (int i = beg + tid; i < end; i += NT) {
        int s = csrsrc[i];
        float4 as4 = *(const float4*)(alS + (size_t)s * 4);
        float l[4] = {as4.x + adv[0], as4.y + adv[1], as4.z + adv[2], as4.w + adv[3]};
#pragma unroll
        for (int hh = 0; hh < 4; hh++) {
            float t = l[hh];
            t = t > 0.f ? t : 0.2f * t;
            mx[hh] = fmaxf(mx[hh], t);
        }
    }
#pragma unroll
    for (int hh = 0; hh < 4; hh++)
#pragma unroll
        for (int o = 16; o; o >>= 1)
            mx[hh] = fmaxf(mx[hh], __shfl_xor_sync(0xFFFFFFFFu, mx[hh], o));
    if (lane == 0)
#pragma unroll
        for (int hh = 0; hh < 4; hh++) s_red[w * 4 + hh] = mx[hh];
    __syncthreads();
    if (tid < 4) s_bm[tid] = fmaxf(s_red[tid], s_red[4 + tid]);
    __syncthreads();
    float bm[4] = {s_bm[0], s_bm[1], s_bm[2], s_bm[3]};

    float sme[4] = {0.f, 0.f, 0.f, 0.f};
    for (int i = beg + tid; i < end; i += NT) {
        int s = csrsrc[i];
        float4 as4 = *(const float4*)(alS + (size_t)s * 4);
        float l[4] = {as4.x + adv[0], as4.y + adv[1], as4.z + adv[2], as4.w + adv[3]};
#pragma unroll
        for (int hh = 0; hh < 4; hh++) {
            float t = l[hh];
            t = t > 0.f ? t : 0.2f * t;
            sme[hh] += expf(t - bm[hh]);
        }
    }
#pragma unroll
    for (int hh = 0; hh < 4; hh++)
#pragma unroll
        for (int o = 16; o; o >>= 1)
            sme[hh] += __shfl_xor_sync(0xFFFFFFFFu, sme[hh], o);
    if (lane == 0)
#pragma unroll
        for (int hh = 0; hh < 4; hh++) s_red[w * 4 + hh] = sme[hh];
    __syncthreads();
    if (tid < 4) s_binv[tid] = 1.0f / fmaxf(s_red[tid] + s_red[4 + tid], 1e-16f);
    __syncthreads();

    float acc[4] = {0.f, 0.f, 0.f, 0.f};
    for (int c0 = beg; c0 < end; c0 += 16) {
        int cnt = min(16, end - c0);
        if (tid < cnt * 4) {
            int j = tid >> 2, hh = tid & 3;
            int s = csrsrc[c0 + j];
            if (hh == 0) s_src[j] = s;
            float t = alS[(size_t)s * 4 + hh] + adv[hh];
            t = t > 0.f ? t : 0.2f * t;
            s_al[j][hh] = expf(t - s_bm[hh]) * s_binv[hh];
        }
        __syncthreads();
        int j = 0;
        for (; j + 4 <= cnt; j += 4) {
            float v0 = in[(size_t)s_src[j + 0] * 64 + tid];
            float v1 = in[(size_t)s_src[j + 1] * 64 + tid];
            float v2 = in[(size_t)s_src[j + 2] * 64 + tid];
            float v3 = in[(size_t)s_src[j + 3] * 64 + tid];
#pragma unroll
            for (int hh = 0; hh < 4; hh++) {
                acc[hh] = fmaf(s_al[j + 0][hh], v0, acc[hh]);
                acc[hh] = fmaf(s_al[j + 1][hh], v1, acc[hh]);
                acc[hh] = fmaf(s_al[j + 2][hh], v2, acc[hh]);
                acc[hh] = fmaf(s_al[j + 3][hh], v3, acc[hh]);
            }
        }
        for (; j < cnt; j++) {
            float v = in[(size_t)s_src[j] * 64 + tid];
#pragma unroll
            for (int hh = 0; hh < 4; hh++)
                acc[hh] = fmaf(s_al[j][hh], v, acc[hh]);
        }
        __syncthreads();
    }

#pragma unroll
    for (int hh = 0; hh < 4; hh++)
        agg[(size_t)d * 256 + hh * 64 + tid] = __float2half_rn(acc[hh]);
}

// ---- fused per-destination GAT softmax + gather (fp16 in, fp16 out) ---------
template <int HC, int SPLIT>
__global__ __launch_bounds__(128) void gat_gather_h(
    const int* __restrict__ rowptr, const int* __restrict__ csrsrc,
    const float* __restrict__ alS, const float* __restrict__ alD,
    const __half* __restrict__ h, __half* __restrict__ out)
{
    constexpr int NT = 128;
    constexpr int HCW = HC / SPLIT;
    static_assert(HCW == 4 * NT, "4 channels per thread");
    constexpr int CPH = HC / 4;

    __shared__ float s_red[16];
    __shared__ float s_bm[4];
    __shared__ float s_binv[4];
    __shared__ float s_al[32][4];
    __shared__ int   s_src[32];

    int d = blockIdx.x;
    int half = (SPLIT > 1) ? blockIdx.y : 0;
    int coff = half * HCW;
    int tid = threadIdx.x;
    int lane = tid & 31, w = tid >> 5;
    int beg = rowptr[d], end = rowptr[d + 1];

    float4 ad4 = *(const float4*)(alD + (size_t)d * 4);
    float adv[4] = {ad4.x, ad4.y, ad4.z, ad4.w};

    float mx[4] = {-INFINITY, -INFINITY, -INFINITY, -INFINITY};
    for (int i = beg + tid; i < end; i += NT) {
        int s = csrsrc[i];
        float4 as4 = *(const float4*)(alS + (size_t)s * 4);
        float l[4] = {as4.x + adv[0], as4.y + adv[1], as4.z + adv[2], as4.w + adv[3]};
#pragma unroll
        for (int hh = 0; hh < 4; hh++) {
            float t = l[hh];
            t = t > 0.f ? t : 0.2f * t;
            mx[hh] = fmaxf(mx[hh], t);
        }
    }
#pragma unroll
    for (int hh = 0; hh < 4; hh++)
#pragma unroll
        for (int o = 16; o; o >>= 1)
            mx[hh] = fmaxf(mx[hh], __shfl_xor_sync(0xFFFFFFFFu, mx[hh], o));
    if (lane == 0)
#pragma unroll
        for (int hh = 0; hh < 4; hh++) s_red[w * 4 + hh] = mx[hh];
    __syncthreads();
    if (tid < 4) {
        float r = fmaxf(fmaxf(s_red[tid], s_red[4 + tid]),
                        fmaxf(s_red[8 + tid], s_red[12 + tid]));
        s_bm[tid] = r;
    }
    __syncthreads();
    float bm[4] = {s_bm[0], s_bm[1], s_bm[2], s_bm[3]};

    float sme[4] = {0.f, 0.f, 0.f, 0.f};
    for (int i = beg + tid; i < end; i += NT) {
        int s = csrsrc[i];
        float4 as4 = *(const float4*)(alS + (size_t)s * 4);
        float l[4] = {as4.x + adv[0], as4.y + adv[1], as4.z + adv[2], as4.w + adv[3]};
#pragma unroll
        for (int hh = 0; hh < 4; hh++) {
            float t = l[hh];
            t = t > 0.f ? t : 0.2f * t;
            sme[hh] += expf(t - bm[hh]);
        }
    }
#pragma unroll
    for (int hh = 0; hh < 4; hh++)
#pragma unroll
        for (int o = 16; o; o >>= 1)
            sme[hh] += __shfl_xor_sync(0xFFFFFFFFu, sme[hh], o);
    if (lane == 0)
#pragma unroll
        for (int hh = 0; hh < 4; hh++) s_red[w * 4 + hh] = sme[hh];
    __syncthreads();
    if (tid < 4) {
        float r = s_red[tid] + s_red[4 + tid] + s_red[8 + tid] + s_red[12 + tid];
        s_binv[tid] = 1.0f / fmaxf(r, 1e-16f);
    }
    __syncthreads();

    float4 acc = make_float4(0.f, 0.f, 0.f, 0.f);
    int hof = (coff + tid * 4) / CPH;

    for (int c0 = beg; c0 < end; c0 += 32) {
        int cnt = min(32, end - c0);
        if (tid < cnt * 4) {
            int j = tid >> 2, hh = tid & 3;
            int s = csrsrc[c0 + j];
            if (hh == 0) s_src[j] = s;
            float t = alS[(size_t)s * 4 + hh] + adv[hh];
            t = t > 0.f ? t : 0.2f * t;
            s_al[j][hh] = expf(t - s_bm[hh]) * s_binv[hh];
        }
        __syncthreads();
        int j = 0;
        for (; j + 4 <= cnt; j += 4) {
            const uint2* p0 = (const uint2*)(h + (size_t)s_src[j + 0] * HC + coff) + tid;
            const uint2* p1 = (const uint2*)(h + (size_t)s_src[j + 1] * HC + coff) + tid;
            const uint2* p2 = (const uint2*)(h + (size_t)s_src[j + 2] * HC + coff) + tid;
            const uint2* p3 = (const uint2*)(h + (size_t)s_src[j + 3] * HC + coff) + tid;
            uint2 r0 = *p0, r1 = *p1, r2 = *p2, r3 = *p3;
            float a0 = s_al[j + 0][hof];
            float a1 = s_al[j + 1][hof];
            float a2 = s_al[j + 2][hof];
            float a3 = s_al[j + 3][hof];
            float2 f0a = __half22float2(*(__half2*)&r0.x);
            float2 f0b = __half22float2(*(__half2*)&r0.y);
            float2 f1a = __half22float2(*(__half2*)&r1.x);
            float2 f1b = __half22float2(*(__half2*)&r1.y);
            float2 f2a = __half22float2(*(__half2*)&r2.x);
            float2 f2b = __half22float2(*(__half2*)&r2.y);
            float2 f3a = __half22float2(*(__half2*)&r3.x);
            float2 f3b = __half22float2(*(__half2*)&r3.y);
            acc.x = fmaf(a0, f0a.x, acc.x); acc.y = fmaf(a0, f0a.y, acc.y);
            acc.z = fmaf(a0, f0b.x, acc.z); acc.w = fmaf(a0, f0b.y, acc.w);
            acc.x = fmaf(a1, f1a.x, acc.x); acc.y = fmaf(a1, f1a.y, acc.y);
            acc.z = fmaf(a1, f1b.x, acc.z); acc.w = fmaf(a1, f1b.y, acc.w);
            acc.x = fmaf(a2, f2a.x, acc.x); acc.y = fmaf(a2, f2a.y, acc.y);
            acc.z = fmaf(a2, f2b.x, acc.z); acc.w = fmaf(a2, f2b.y, acc.w);
            acc.x = fmaf(a3, f3a.x, acc.x); acc.y = fmaf(a3, f3a.y, acc.y);
            acc.z = fmaf(a3, f3b.x, acc.z); acc.w = fmaf(a3, f3b.y, acc.w);
        }
        for (; j < cnt; j++) {
            const uint2* p = (const uint2*)(h + (size_t)s_src[j] * HC + coff) + tid;
            uint2 rr = *p;
            float a = s_al[j][hof];
            float2 fa = __half22float2(*(__half2*)&rr.x);
            float2 fb = __half22float2(*(__half2*)&rr.y);
            acc.x = fmaf(a, fa.x, acc.x);
            acc.y = fmaf(a, fa.y, acc.y);
            acc.z = fmaf(a, fb.x, acc.z);
            acc.w = fmaf(a, fb.y, acc.w);
        }
        __syncthreads();
    }

    uint2 ov;
    __half2 o0 = __floats2half2_rn(acc.x, acc.y);
    __half2 o1 = __floats2half2_rn(acc.z, acc.w);
    ov.x = *(uint32_t*)&o0;
    ov.y = *(uint32_t*)&o1;
    *((uint2*)(out + (size_t)d * HC + coff) + tid) = ov;
}

// ---------------- GCN gather (fp16 in, fp32 out) -----------------------------
__global__ __launch_bounds__(64) void gcn_gather_h(
    const int* __restrict__ rowptr, const int* __restrict__ csrsrc,
    const float* __restrict__ dinv, const __half* __restrict__ h,
    float* __restrict__ out)
{
    int d = blockIdx.x;
    int tid = threadIdx.x;
    int beg = rowptr[d], end = rowptr[d + 1];
    float dd = dinv[d];

    float4 acc = make_float4(0.f, 0.f, 0.f, 0.f);
    int i = beg;
    for (; i + 4 <= end; i += 4) {
        int s0 = csrsrc[i + 0], s1 = csrsrc[i + 1];
        int s2 = csrsrc[i + 2], s3 = csrsrc[i + 3];
        float n0 = dinv[s0] * dd, n1 = dinv[s1] * dd;
        float n2 = dinv[s2] * dd, n3 = dinv[s3] * dd;
        uint2 r0 = *((const uint2*)(h + (size_t)s0 * 256) + tid);
        uint2 r1 = *((const uint2*)(h + (size_t)s1 * 256) + tid);
        uint2 r2 = *((const uint2*)(h + (size_t)s2 * 256) + tid);
        uint2 r3 = *((const uint2*)(h + (size_t)s3 * 256) + tid);
        float2 f0a = __half22float2(*(__half2*)&r0.x);
        float2 f0b = __half22float2(*(__half2*)&r0.y);
        float2 f1a = __half22float2(*(__half2*)&r1.x);
        float2 f1b = __half22float2(*(__half2*)&r1.y);
        float2 f2a = __half22float2(*(__half2*)&r2.x);
        float2 f2b = __half22float2(*(__half2*)&r2.y);
        float2 f3a = __half22float2(*(__half2*)&r3.x);
        float2 f3b = __half22float2(*(__half2*)&r3.y);
        acc.x = fmaf(n0, f0a.x, acc.x); acc.y = fmaf(n0, f0a.y, acc.y);
        acc.z = fmaf(n0, f0b.x, acc.z); acc.w = fmaf(n0, f0b.y, acc.w);
        acc.x = fmaf(n1, f1a.x, acc.x); acc.y = fmaf(n1, f1a.y, acc.y);
        acc.z = fmaf(n1, f1b.x, acc.z); acc.w = fmaf(n1, f1b.y, acc.w);
        acc.x = fmaf(n2, f2a.x, acc.x); acc.y = fmaf(n2, f2a.y, acc.y);
        acc.z = fmaf(n2, f2b.x, acc.z); acc.w = fmaf(n2, f2b.y, acc.w);
        acc.x = fmaf(n3, f3a.x, acc.x); acc.y = fmaf(n3, f3a.y, acc.y);
        acc.z = fmaf(n3, f3b.x, acc.z); acc.w = fmaf(n3, f3b.y, acc.w);
    }
    for (; i < end; i++) {
        int s = csrsrc[i];
        float nrm = dinv[s] * dd;
        uint2 rr = *((const uint2*)(h + (size_t)s * 256) + tid);
        float2 fa = __half22float2(*(__half2*)&rr.x);
        float2 fb = __half22float2(*(__half2*)&rr.y);
        acc.x = fmaf(nrm, fa.x, acc.x);
        acc.y = fmaf(nrm, fa.y, acc.y);
        acc.z = fmaf(nrm, fb.x, acc.z);
        acc.w = fmaf(nrm, fb.y, acc.w);
    }
    *(float4*)(out + (size_t)d * 256 + tid * 4) = acc;
}

// ---------------- BatchNorm -------------------------------------------------
__global__ void bn_stats(const float* __restrict__ x, int rows, int K,
                         float* __restrict__ sum, float* __restrict__ sq)
{
    int col = blockIdx.x * blockDim.x + threadIdx.x;
    float s = 0.f, q = 0.f;
    for (int r = blockIdx.y; r < rows; r += gridDim.y) {
        float v = x[(size_t)r * K + col];
        s += v;
        q += v * v;
    }
    atomicAdd(sum + col, s);
    atomicAdd(sq + col, q);
}

// fp16 stats: 4 halves per thread via uint2; grid (K/512, 128), 128 threads
__global__ void bn_stats_h4(const __half* __restrict__ x, int rows, int K,
                            float* __restrict__ sum, float* __restrict__ sq)
{
    int c0 = (blockIdx.x * blockDim.x + threadIdx.x) * 4;
    if (c0 >= K) return;
    float s0 = 0.f, s1 = 0.f, s2 = 0.f, s3 = 0.f;
    float q0 = 0.f, q1 = 0.f, q2 = 0.f, q3 = 0.f;
    for (int r = blockIdx.y; r < rows; r += gridDim.y) {
        uint2 v = *(const uint2*)(x + (size_t)r * K + c0);
        float2 a = __half22float2(*(__half2*)&v.x);
        float2 b = __half22float2(*(__half2*)&v.y);
        s0 += a.x; q0 += a.x * a.x;
        s1 += a.y; q1 += a.y * a.y;
        s2 += b.x; q2 += b.x * b.x;
        s3 += b.y; q3 += b.y * b.y;
    }
    atomicAdd(sum + c0 + 0, s0); atomicAdd(sq + c0 + 0, q0);
    atomicAdd(sum + c0 + 1, s1); atomicAdd(sq + c0 + 1, q1);
    atomicAdd(sum + c0 + 2, s2); atomicAdd(sq + c0 + 2, q2);
    atomicAdd(sum + c0 + 3, s3); atomicAdd(sq + c0 + 3, q3);
}

__global__ void bn_finalize(const float* __restrict__ sum, const float* __restrict__ sq,
                            const float* __restrict__ g, const float* __restrict__ b,
                            int rows, int K, float* __restrict__ scale,
                            float* __restrict__ shift)
{
    int c = blockIdx.x * blockDim.x + threadIdx.x;
    if (c >= K) return;
    float inv_n = 1.0f / (float)rows;
    float mu = sum[c] * inv_n;
    float var = sq[c] * inv_n - mu * mu;
    float sc = g[c] * rsqrtf(var + 1e-5f);
    scale[c] = sc;
    shift[c] = b[c] - mu * sc;
}

__global__ void bn_apply_relu(float* __restrict__ x, const float* __restrict__ scale,
                              const float* __restrict__ shift, size_t total, int K)
{
    for (size_t i = (size_t)blockIdx.x * blockDim.x + threadIdx.x; i < total;
         i += (size_t)gridDim.x * blockDim.x) {
        int c = (int)(i % K);
        float v = x[i] * scale[c] + shift[c];
        x[i] = v > 0.f ? v : 0.f;
    }
}

// ---------------- Pooling: one block per graph (batch sorted, no atomics) ----
__global__ __launch_bounds__(256) void pool_graph(
    const float* __restrict__ h, const int* __restrict__ gstart,
    const float* __restrict__ scale, const float* __restrict__ shift,
    float* __restrict__ z)
{
    int g = blockIdx.x;
    int c = threadIdx.x;
    int beg = gstart[g], end = gstart[g + 1];
    float sc = scale[c], sh = shift[c];
    float sum = 0.f, mx = 0.f;
    for (int r = beg; r < end; r++) {
        float v = fmaxf(fmaf(h[(size_t)r * 256 + c], sc, sh), 0.f);
        sum += v;
        mx = fmaxf(mx, v);
    }
    float cnt = (float)(end - beg);
    z[(size_t)g * 640 + c] = sum / fmaxf(cnt, 1.0f);
    z[(size_t)g * 640 + 256 + c] = mx;
}

// ---------------- Head -------------------------------------------------------
__global__ void head_final(const float* __restrict__ zf, const float* __restrict__ Wf2,
                           const float* __restrict__ bf2, float* __restrict__ out)
{
    int g = blockIdx.x;
    int t = threadIdx.x;
    float v = zf[(size_t)g * 128 + t] * Wf2[t];
#pragma unroll
    for (int o = 16; o; o >>= 1) v += __shfl_down_sync(0xFFFFFFFFu, v, o);
    __shared__ float sm[4];
    if ((t & 31) == 0) sm[t >> 5] = v;
    __syncthreads();
    if (t == 0) {
        float s = sm[0] + sm[1] + sm[2] + sm[3] + bf2[0];
        out[g] = 1.0f / (1.0f + expf(-s));
    }
}

// ---------------- launch ------------------------------------------------------
extern "C" void kernel_launch(void* const* d_in, const int* in_sizes, int n_in,
                              void* d_out, int out_size)
{
    const float* x    = (const float*)d_in[0];
    const int*   ei   = (const int*)d_in[1];
    const int*   batch= (const int*)d_in[2];
    const float* fp   = (const float*)d_in[3];
    const float* W1   = (const float*)d_in[4];
    const float* a1s  = (const float*)d_in[5];
    const float* a1d  = (const float*)d_in[6];
    const float* bn1g = (const float*)d_in[8];
    const float* bn1b = (const float*)d_in[9];
    const float* W2   = (const float*)d_in[10];
    const float* a2s  = (const float*)d_in[11];
    const float* a2d  = (const float*)d_in[12];
    const float* bn2g = (const float*)d_in[14];
    const float* bn2b = (const float*)d_in[15];
    const float* Wg   = (const float*)d_in[16];
    const float* bn3g = (const float*)d_in[18];
    const float* bn3b = (const float*)d_in[19];
    const float* Ws   = (const float*)d_in[20];
    const float* bs   = (const float*)d_in[21];
    const float* Wf1  = (const float*)d_in[22];
    const float* bnfg = (const float*)d_in[24];
    const float* bnfb = (const float*)d_in[25];
    const float* Wf2  = (const float*)d_in[26];
    const float* bf2  = (const float*)d_in[27];
    float* out = (float*)d_out;

    int n    = in_sizes[0] / 64;
    int E    = in_sizes[1] / 2;
    int Etot = E + n;
    int G    = in_sizes[3] / 128;

    float *bufA, *bufB, *bufC, *alS, *alD, *dinv, *uu, *vv;
    float *bnsum, *bnsq, *bnscale, *bnshift, *z, *zf;
    __half *w1p, *w2p, *wgp;
    int *degi, *incl, *part, *rowptr, *cursor, *csrsrc, *gstart;
    cudaGetSymbolAddress((void**)&bufA, g_bufA);
    cudaGetSymbolAddress((void**)&bufB, g_bufB);
    cudaGetSymbolAddress((void**)&bufC, g_bufC);
    cudaGetSymbolAddress((void**)&w1p, g_w1p);
    cudaGetSymbolAddress((void**)&w2p, g_w2p);
    cudaGetSymbolAddress((void**)&wgp, g_wgp);
    cudaGetSymbolAddress((void**)&alS, g_alS);
    cudaGetSymbolAddress((void**)&alD, g_alD);
    cudaGetSymbolAddress((void**)&uu, g_u);
    cudaGetSymbolAddress((void**)&vv, g_v);
    cudaGetSymbolAddress((void**)&degi, g_degi);
    cudaGetSymbolAddress((void**)&incl, g_incl);
    cudaGetSymbolAddress((void**)&part, g_part);
    cudaGetSymbolAddress((void**)&rowptr, g_rowptr);
    cudaGetSymbolAddress((void**)&cursor, g_cursor);
    cudaGetSymbolAddress((void**)&csrsrc, g_csrsrc);
    cudaGetSymbolAddress((void**)&dinv, g_dinv);
    cudaGetSymbolAddress((void**)&gstart, g_gstart);
    cudaGetSymbolAddress((void**)&bnsum, g_bnsum);
    cudaGetSymbolAddress((void**)&bnsq, g_bnsq);
    cudaGetSymbolAddress((void**)&bnscale, g_bnscale);
    cudaGetSymbolAddress((void**)&bnshift, g_bnshift);
    cudaGetSymbolAddress((void**)&z, g_z);
    cudaGetSymbolAddress((void**)&zf, g_zf);

    __half* bufA_h = (__half*)bufA;
    __half* bufB_h = (__half*)bufB;
    __half* bufC_h = (__half*)bufC;

    size_t tf_smem = SMEM_FLOATS * sizeof(float);
    static bool attr_done = false;
    if (!attr_done) {
        cudaFuncSetAttribute(tf32gemm,
                             cudaFuncAttributeMaxDynamicSharedMemorySize, (int)tf_smem);
        cudaFuncSetAttribute(hgemm<false, false, true, true>,
                             cudaFuncAttributeMaxDynamicSharedMemorySize, H_SMEM);
        cudaFuncSetAttribute(hgemm<true, true, false, true>,
                             cudaFuncAttributeMaxDynamicSharedMemorySize, H_SMEM);
        cudaFuncSetAttribute(hgemm<true, false, false, true>,
                             cudaFuncAttributeMaxDynamicSharedMemorySize, H_SMEM);
        attr_done = true;
    }

    auto bnstats_h = [&](const __half* Xp, int rows, int K, const float* gg,
                         const float* bb) {
        cudaMemsetAsync(bnsum, 0, K * sizeof(float));
        cudaMemsetAsync(bnsq, 0, K * sizeof(float));
        dim3 g1(K / 512, 128);
        bn_stats_h4<<<g1, 128>>>(Xp, rows, K, bnsum, bnsq);
        bn_finalize<<<(K + 127) / 128, 128>>>(bnsum, bnsq, gg, bb, rows, K,
                                              bnscale, bnshift);
    };

    // ---- CSR build + graph boundaries + weight packing (independent)
    cudaMemsetAsync(degi, 0, n * sizeof(int));
    deg_build<<<(Etot + 255) / 256, 256>>>(ei, E, Etot, degi);
    int nb = (n + 1023) / 1024;
    scan_partial<<<nb, 1024>>>(degi, n, incl, part);
    scan_roots<<<1, 128>>>(part, nb);
    scan_add<<<(n + 255) / 256, 256>>>(incl, degi, part, n, Etot,
                                       rowptr, cursor, dinv);
    csr_scatter<<<(Etot + 255) / 256, 256>>>(ei, E, Etot, cursor, csrsrc);
    gstart_build<<<(n + 256) / 256, 256>>>(batch, n, G, gstart);
    {
        int total = 64 * 512 + 512 * 1024 + 1024 * 256;
        pack_all<<<(total + 255) / 256, 256>>>(W1, W2, Wg, w1p, w2p, wgp);
    }

    // ---- GAT layer 1 (input-space): exact fp32 alphas; gather x -> fp16; hgemm
    uv_build<<<(64 * 4 * 32 + 255) / 256, 256>>>(W1, a1s, a1d, 64, 128, uu, vv);
    alpha_gemm64<<<(n + 7) / 8, 256>>>(x, n, uu, vv, alS, alD);
    gat_agg_in64<<<n, 64>>>(rowptr, csrsrc, alS, alD, x, bufA_h);
    {
        dim3 grid(4, (n + 127) / 128);
        hgemm<false, false, true, true><<<grid, 256, H_SMEM>>>(
            bufA_h, w1p, bufB_h, n, 512, 64, 256, 512,
            nullptr, nullptr, nullptr, nullptr, 128, nullptr, nullptr);
    }
    bnstats_h(bufB_h, n, 512, bn1g, bn1b);

    // ---- GAT layer 2: bufC_h = relu(bn(bufB_h))@W2 (+ alphas); gather -> bufA_h
    cudaMemsetAsync(alS, 0, (size_t)n * 4 * sizeof(float));
    cudaMemsetAsync(alD, 0, (size_t)n * 4 * sizeof(float));
    {
        dim3 grid(8, (n + 127) / 128);
        hgemm<true, true, false, true><<<grid, 256, H_SMEM>>>(
            bufB_h, w2p, bufC_h, n, 1024, 512, 512, 1024,
            bnscale, bnshift, a2s, a2d, 256, alS, alD);
    }
    {
        dim3 grid(n, 2);
        gat_gather_h<1024, 2><<<grid, 128>>>(rowptr, csrsrc, alS, alD, bufC_h, bufA_h);
    }
    bnstats_h(bufA_h, n, 1024, bn2g, bn2b);

    // ---- GCN: bufB_h = relu(bn(bufA_h))@Wg; gather -> bufC (fp32); BN stats
    {
        dim3 grid(2, (n + 127) / 128);
        hgemm<true, false, false, true><<<grid, 256, H_SMEM>>>(
            bufA_h, wgp, bufB_h, n, 256, 1024, 1024, 256,
            bnscale, bnshift, nullptr, nullptr, 256, nullptr, nullptr);
    }
    gcn_gather_h<<<n, 64>>>(rowptr, csrsrc, dinv, bufB_h, bufC);
    {
        cudaMemsetAsync(bnsum, 0, 256 * sizeof(float));
        cudaMemsetAsync(bnsq, 0, 256 * sizeof(float));
        dim3 g1(2, 128);
        bn_stats<<<g1, 128>>>(bufC, n, 256, bnsum, bnsq);
        bn_finalize<<<2, 128>>>(bnsum, bnsq, bn3g, bn3b, n, 256, bnscale, bnshift);
    }

    // ---- Pooling into z[G,640] (block per graph; BN+relu on the fly)
    pool_graph<<<G, 256>>>(bufC, gstart, bnscale, bnshift, z);

    // ---- solvent MLP: relu(fp @ Ws + bs) -> z[:,512:640]
    {
        dim3 grid(1, (G + 127) / 128);
        sgemm<true><<<grid, 256>>>(fp, Ws, bs, z + 512, G, 128, 128, 128, 640);
    }

    // ---- head: zf = z @ Wf1 via tf32 (bf1 cancels under BN); BN; relu; sigmoid
    {
        dim3 grid(1, (G + 127) / 128);
        tf32gemm<<<grid, 256, tf_smem>>>(z, Wf1, zf, G, 128, 640, 640, 128, 128);
    }
    {
        cudaMemsetAsync(bnsum, 0, 128 * sizeof(float));
        cudaMemsetAsync(bnsq, 0, 128 * sizeof(float));
        dim3 g1(1, 128);
        bn_stats<<<g1, 128>>>(zf, G, 128, bnsum, bnsq);
        bn_finalize<<<1, 128>>>(bnsum, bnsq, bnfg, bnfb, G, 128, bnscale, bnshift);
        bn_apply_relu<<<((size_t)G * 128 + 255) / 256, 256>>>(zf, bnscale, bnshift,
                                                              (size_t)G * 128, 128);
    }
    head_final<<<G, 128>>>(zf, Wf2, bf2, out);
}

// round 14
// speedup vs baseline: 1.4307x; 1.0298x over previous
#include <cuda_runtime.h>
#include <cuda_fp16.h>
#include <math.h>
#include <stdint.h>

// Problem capacities (fixed shapes per reference)
#define NMAXN 50000
#define EMAXE 200000
#define ETOTMAX (EMAXE + NMAXN)
#define GMAXG 1000

// ---------------- scratch (static device memory; no allocations allowed) ----
__device__ float g_bufA[(size_t)NMAXN * 1024];
__device__ float g_bufB[(size_t)NMAXN * 1024];
__device__ float g_bufC[(size_t)NMAXN * 1024];
__device__ __half g_w1p[64 * 512];
__device__ __half g_w2p[512 * 1024];
__device__ __half g_wgp[1024 * 256];
__device__ float g_alS[NMAXN * 4];
__device__ float g_alD[NMAXN * 4];
__device__ float g_alpha[(size_t)ETOTMAX * 4];
__device__ float g_u[512 * 4];
__device__ float g_v[512 * 4];
__device__ int   g_degi[NMAXN];
__device__ int   g_incl[NMAXN];
__device__ int   g_part[128];
__device__ int   g_rowptr[NMAXN + 1];
__device__ int   g_cursor[NMAXN];
__device__ int   g_csrsrc[ETOTMAX];
__device__ float g_dinv[NMAXN];
__device__ int   g_gstart[GMAXG + 1];
__device__ float g_bnsum[1024];
__device__ float g_bnsq[1024];
__device__ float g_bnscale[1024];
__device__ float g_bnshift[1024];
__device__ float g_z[GMAXG * 640];
__device__ float g_zf[GMAXG * 128];

// ---------------- CSR build -------------------------------------------------
__global__ void deg_build(const int* __restrict__ ei, int E, int Etot,
                          int* __restrict__ degi)
{
    int e = blockIdx.x * blockDim.x + threadIdx.x;
    if (e >= Etot) return;
    int d = (e < E) ? ei[E + e] : (e - E);
    atomicAdd(degi + d, 1);
}

__global__ __launch_bounds__(1024) void scan_partial(
    const int* __restrict__ degi, int n, int* __restrict__ incl,
    int* __restrict__ part)
{
    __shared__ int sm[32];
    int tid = threadIdx.x;
    int lane = tid & 31, w = tid >> 5;
    int i = blockIdx.x * 1024 + tid;
    int v = (i < n) ? degi[i] : 0;
    int x = v;
#pragma unroll
    for (int o = 1; o < 32; o <<= 1) {
        int y = __shfl_up_sync(0xFFFFFFFFu, x, o);
        if (lane >= o) x += y;
    }
    if (lane == 31) sm[w] = x;
    __syncthreads();
    if (w == 0) {
        int y = sm[lane];
#pragma unroll
        for (int o = 1; o < 32; o <<= 1) {
            int z = __shfl_up_sync(0xFFFFFFFFu, y, o);
            if (lane >= o) y += z;
        }
        sm[lane] = y;
    }
    __syncthreads();
    int inclv = x + (w ? sm[w - 1] : 0);
    if (i < n) incl[i] = inclv;
    if (tid == 1023) part[blockIdx.x] = inclv;
}

__global__ void scan_roots(int* __restrict__ part, int nb)
{
    __shared__ int sm[128];
    int t = threadIdx.x;
    sm[t] = (t < nb) ? part[t] : 0;
    __syncthreads();
    if (t == 0) {
        int run = 0;
        for (int i = 0; i < nb; i++) { int v = sm[i]; sm[i] = run; run += v; }
    }
    __syncthreads();
    if (t < nb) part[t] = sm[t];
}

__global__ void scan_add(const int* __restrict__ incl, const int* __restrict__ degi,
                         const int* __restrict__ part, int n, int Etot,
                         int* __restrict__ rowptr, int* __restrict__ cursor,
                         float* __restrict__ dinv)
{
    int i = blockIdx.x * blockDim.x + threadIdx.x;
    if (i == 0) rowptr[n] = Etot;
    if (i >= n) return;
    int dg = degi[i];
    int exc = incl[i] + part[i >> 10] - dg;
    rowptr[i] = exc;
    cursor[i] = exc;
    dinv[i] = rsqrtf(fmaxf((float)dg, 1.0f));
}

__global__ void csr_scatter(const int* __restrict__ ei, int E, int Etot,
                            int* __restrict__ cursor, int* __restrict__ csrsrc)
{
    int e = blockIdx.x * blockDim.x + threadIdx.x;
    if (e >= Etot) return;
    int s, d;
    if (e < E) { s = ei[e]; d = ei[E + e]; }
    else       { s = e - E; d = e - E; }
    int pos = atomicAdd(cursor + d, 1);
    csrsrc[pos] = s;
}

__global__ void gstart_build(const int* __restrict__ batch, int n, int G,
                             int* __restrict__ gstart)
{
    int i = blockIdx.x * blockDim.x + threadIdx.x;
    if (i < n) {
        int b = batch[i];
        int bp = (i > 0) ? batch[i - 1] : -1;
        for (int g = bp + 1; g <= b; g++) gstart[g] = i;
    } else if (i == n) {
        int bl = batch[n - 1];
        for (int g = bl + 1; g <= G; g++) gstart[g] = n;
    }
}

// ---------------- weight packing (all three weights, one launch) -------------
__device__ __forceinline__ void pack_one(const float* __restrict__ W, int Nc, int i,
                                         __half* __restrict__ Wp)
{
    int k = i / Nc, nn = i % Nc;
    Wp[(size_t)(k >> 1) * 2 * Nc + 2 * nn + (k & 1)] = __float2half_rn(W[i]);
}

__global__ void pack_all(const float* __restrict__ W1, const float* __restrict__ W2,
                         const float* __restrict__ Wg,
                         __half* __restrict__ w1p, __half* __restrict__ w2p,
                         __half* __restrict__ wgp)
{
    const int S1 = 64 * 512, S2 = 512 * 1024, S3 = 1024 * 256;
    int i = blockIdx.x * blockDim.x + threadIdx.x;
    if (i < S1) pack_one(W1, 512, i, w1p);
    else if (i < S1 + S2) pack_one(W2, 1024, i - S1, w2p);
    else if (i < S1 + S2 + S3) pack_one(Wg, 256, i - S1 - S2, wgp);
}

// ---------------- u/v vectors: u[k,h] = sum_c W[k,hC+c]*a[h,c] ---------------
__global__ void uv_build(const float* __restrict__ W, const float* __restrict__ aS,
                         const float* __restrict__ aD, int K, int C,
                         float* __restrict__ u, float* __restrict__ v)
{
    int idx = blockIdx.x * blockDim.x + threadIdx.x;
    int warp = idx >> 5, lane = idx & 31;
    if (warp >= K * 4) return;
    int k = warp >> 2, h = warp & 3;
    const float* wrow = W + (size_t)k * (4 * C) + h * C;
    const float* as = aS + h * C;
    const float* ad = aD + h * C;
    float s = 0.f, d = 0.f;
    for (int c = lane; c < C; c += 32) {
        float wv = wrow[c];
        s += wv * as[c];
        d += wv * ad[c];
    }
#pragma unroll
    for (int o = 16; o; o >>= 1) {
        s += __shfl_xor_sync(0xFFFFFFFFu, s, o);
        d += __shfl_xor_sync(0xFFFFFFFFu, d, o);
    }
    if (lane == 0) { u[k * 4 + h] = s; v[k * 4 + h] = d; }
}

// ---------------- skinny alpha GEMM (layer 1, K=64, fp32 exact) --------------
__global__ __launch_bounds__(256) void alpha_gemm64(
    const float* __restrict__ in, int n,
    const float* __restrict__ u, const float* __restrict__ v,
    float* __restrict__ alS, float* __restrict__ alD)
{
    __shared__ float su[64][4];
    __shared__ float sv[64][4];
    int tid = threadIdx.x;
    if (tid < 64 * 4) { su[tid >> 2][tid & 3] = u[tid]; sv[tid >> 2][tid & 3] = v[tid]; }
    __syncthreads();

    int warp = tid >> 5, lane = tid & 31;
    for (int node = blockIdx.x * 8 + warp; node < n; node += gridDim.x * 8) {
        const float* row = in + (size_t)node * 64;
        float x0 = row[lane], x1 = row[lane + 32];
        float as[4], ad[4];
#pragma unroll
        for (int h = 0; h < 4; h++) {
            as[h] = x0 * su[lane][h] + x1 * su[lane + 32][h];
            ad[h] = x0 * sv[lane][h] + x1 * sv[lane + 32][h];
        }
#pragma unroll
        for (int h = 0; h < 4; h++) {
#pragma unroll
            for (int o = 16; o; o >>= 1) {
                as[h] += __shfl_xor_sync(0xFFFFFFFFu, as[h], o);
                ad[h] += __shfl_xor_sync(0xFFFFFFFFu, ad[h], o);
            }
        }
        if (lane == 0) {
            *(float4*)(alS + (size_t)node * 4) = make_float4(as[0], as[1], as[2], as[3]);
            *(float4*)(alD + (size_t)node * 4) = make_float4(ad[0], ad[1], ad[2], ad[3]);
        }
    }
}

// ---------------- per-edge softmax weights (one warp per destination) --------
// alpha[i,h] = exp(leaky(alS[src_i]+alD[d]) - max) / sum   (CSR order, coalesced)
__global__ __launch_bounds__(256) void alpha_edges(
    const int* __restrict__ rowptr, const int* __restrict__ csrsrc,
    const float* __restrict__ alS, const float* __restrict__ alD, int n,
    float* __restrict__ alpha)
{
    int warp = (blockIdx.x * blockDim.x + threadIdx.x) >> 5;
    int lane = threadIdx.x & 31;
    if (warp >= n) return;
    int d = warp;
    int beg = rowptr[d], end = rowptr[d + 1];

    float4 ad4 = *(const float4*)(alD + (size_t)d * 4);
    float adv[4] = {ad4.x, ad4.y, ad4.z, ad4.w};

    float mx[4] = {-INFINITY, -INFINITY, -INFINITY, -INFINITY};
    for (int i = beg + lane; i < end; i += 32) {
        int s = csrsrc[i];
        float4 as4 = *(const float4*)(alS + (size_t)s * 4);
        float l[4] = {as4.x + adv[0], as4.y + adv[1], as4.z + adv[2], as4.w + adv[3]};
#pragma unroll
        for (int h = 0; h < 4; h++) {
            float t = l[h];
            t = t > 0.f ? t : 0.2f * t;
            mx[h] = fmaxf(mx[h], t);
        }
    }
#pragma unroll
    for (int h = 0; h < 4; h++)
#pragma unroll
        for (int o = 16; o; o >>= 1)
            mx[h] = fmaxf(mx[h], __shfl_xor_sync(0xFFFFFFFFu, mx[h], o));

    float sme[4] = {0.f, 0.f, 0.f, 0.f};
    for (int i = beg + lane; i < end; i += 32) {
        int s = csrsrc[i];
        float4 as4 = *(const float4*)(alS + (size_t)s * 4);
        float l[4] = {as4.x + adv[0], as4.y + adv[1], as4.z + adv[2], as4.w + adv[3]};
#pragma unroll
        for (int h = 0; h < 4; h++) {
            float t = l[h];
            t = t > 0.f ? t : 0.2f * t;
            sme[h] += expf(t - mx[h]);
        }
    }
#pragma unroll
    for (int h = 0; h < 4; h++)
#pragma unroll
        for (int o = 16; o; o >>= 1)
            sme[h] += __shfl_xor_sync(0xFFFFFFFFu, sme[h], o);

    float binv[4];
#pragma unroll
    for (int h = 0; h < 4; h++) binv[h] = 1.0f / fmaxf(sme[h], 1e-16f);

    for (int i = beg + lane; i < end; i += 32) {
        int s = csrsrc[i];
        float4 as4 = *(const float4*)(alS + (size_t)s * 4);
        float l[4] = {as4.x + adv[0], as4.y + adv[1], as4.z + adv[2], as4.w + adv[3]};
        float4 av;
        float t0 = l[0] > 0.f ? l[0] : 0.2f * l[0];
        float t1 = l[1] > 0.f ? l[1] : 0.2f * l[1];
        float t2 = l[2] > 0.f ? l[2] : 0.2f * l[2];
        float t3 = l[3] > 0.f ? l[3] : 0.2f * l[3];
        av.x = expf(t0 - mx[0]) * binv[0];
        av.y = expf(t1 - mx[1]) * binv[1];
        av.z = expf(t2 - mx[2]) * binv[2];
        av.w = expf(t3 - mx[3]) * binv[3];
        *(float4*)(alpha + (size_t)i * 4) = av;
    }
}

// ---------------- FP16 tensor-core GEMM (k-tile 64, double-buffered) ---------
__device__ __forceinline__ void mma_f16(float c[4], const uint32_t a[4],
                                        uint32_t b0, uint32_t b1) {
    asm volatile(
        "mma.sync.aligned.m16n8k16.row.col.f32.f16.f16.f32 "
        "{%0,%1,%2,%3}, {%4,%5,%6,%7}, {%8,%9}, {%0,%1,%2,%3};"
        : "+f"(c[0]), "+f"(c[1]), "+f"(c[2]), "+f"(c[3])
        : "r"(a[0]), "r"(a[1]), "r"(a[2]), "r"(a[3]), "r"(b0), "r"(b1));
}

__device__ __forceinline__ void cp_async16(void* smem_dst, const void* gmem_src,
                                           bool pred) {
    uint32_t saddr = (uint32_t)__cvta_generic_to_shared(smem_dst);
    int sz = pred ? 16 : 0;
    asm volatile("cp.async.cg.shared.global [%0], [%1], 16, %2;\n"
                 :: "r"(saddr), "l"(gmem_src), "r"(sz));
}

__device__ __forceinline__ uint32_t bnrelu_h2(uint32_t v, float2 sc, float2 sh) {
    float2 f = __half22float2(*(__half2*)&v);
    f.x = fmaxf(fmaf(f.x, sc.x, sh.x), 0.f);
    f.y = fmaxf(fmaf(f.y, sc.y, sh.y), 0.f);
    __half2 h = __floats2half2_rn(f.x, f.y);
    return *(uint32_t*)&h;
}

#define H_ASTG 18432
#define H_BSTG 17408
#define H_SMEM (2 * (H_ASTG + H_BSTG))

template <bool BNRELU, bool ALPHA, bool GROUP, bool HALFOUT>
__global__ __launch_bounds__(256, 2) void hgemm(
    const __half* __restrict__ A, const __half* __restrict__ Bp,
    void* __restrict__ Cout, int M, int Nc, int K, int lda, int ldc,
    const float* __restrict__ scale, const float* __restrict__ shift,
    const float* __restrict__ aS, const float* __restrict__ aD, int Chead,
    float* __restrict__ alS, float* __restrict__ alD)
{
    extern __shared__ char smem[];

    int tid = threadIdx.x;
    int lane = tid & 31;
    int wid = tid >> 5;
    int warpM = (wid >> 2) * 64;
    int warpN = (wid & 3) * 32;
    int r = lane >> 2;
    int cq = lane & 3;

    int blockM = blockIdx.y * 128;
    int blockN = blockIdx.x * 128;

    if (GROUP) A += (size_t)(blockN >> 7) * K;

    float acc[4][4][4];
#pragma unroll
    for (int mt = 0; mt < 4; mt++)
#pragma unroll
        for (int nt = 0; nt < 4; nt++)
#pragma unroll
            for (int i = 0; i < 4; i++) acc[mt][nt][i] = 0.0f;

    int nk = K >> 6;

    auto load_tile = [&](int kt, int buf) {
        char* As = smem + buf * H_ASTG;
        char* Bs = smem + 2 * H_ASTG + buf * H_BSTG;
#pragma unroll
        for (int i = 0; i < 4; i++) {
            int row = (tid >> 3) + i * 32;
            int grow = blockM + row;
            cp_async16(As + (size_t)row * 144 + (tid & 7) * 16,
                       A + (size_t)grow * lda + kt * 64 + (tid & 7) * 8,
                       grow < M);
        }
#pragma unroll
        for (int i = 0; i < 4; i++) {
            int c = tid + i * 256;
            int krow = c >> 5;
            int nc4 = (c & 31) * 4;
            cp_async16(Bs + ((size_t)krow * 136 + nc4) * 4,
                       Bp + (size_t)(kt * 32 + krow) * 2 * Nc + 2 * blockN + nc4 * 2,
                       true);
        }
        asm volatile("cp.async.commit_group;\n");
    };

    load_tile(0, 0);

    for (int kt = 0; kt < nk; kt++) {
        if (kt + 1 < nk) {
            load_tile(kt + 1, (kt + 1) & 1);
            asm volatile("cp.async.wait_group 1;\n");
        } else {
            asm volatile("cp.async.wait_group 0;\n");
        }
        __syncthreads();

        const uint32_t* As2 = (const uint32_t*)(smem + (kt & 1) * H_ASTG);
        const uint32_t* Bs2 = (const uint32_t*)(smem + 2 * H_ASTG + (kt & 1) * H_BSTG);

#pragma unroll
        for (int ks = 0; ks < 4; ks++) {
            int kb2 = ks * 8;
            float2 sc01, sh01, sc23, sh23;
            if (BNRELU) {
                int kg = kt * 64 + ks * 16 + 2 * cq;
                sc01 = *(const float2*)(scale + kg);
                sh01 = *(const float2*)(shift + kg);
                sc23 = *(const float2*)(scale + kg + 8);
                sh23 = *(const float2*)(shift + kg + 8);
            }
            uint32_t a[4][4], b[4][2];
#pragma unroll
            for (int mt = 0; mt < 4; mt++) {
                int m = warpM + mt * 16 + r;
                uint32_t a0 = As2[m * 36 + kb2 + cq];
                uint32_t a1 = As2[(m + 8) * 36 + kb2 + cq];
                uint32_t a2 = As2[m * 36 + kb2 + cq + 4];
                uint32_t a3 = As2[(m + 8) * 36 + kb2 + cq + 4];
                if (BNRELU) {
                    a0 = bnrelu_h2(a0, sc01, sh01);
                    a1 = bnrelu_h2(a1, sc01, sh01);
                    a2 = bnrelu_h2(a2, sc23, sh23);
                    a3 = bnrelu_h2(a3, sc23, sh23);
                }
                a[mt][0] = a0; a[mt][1] = a1; a[mt][2] = a2; a[mt][3] = a3;
            }
#pragma unroll
            for (int nt = 0; nt < 4; nt++) {
                int nn = warpN + nt * 8 + r;
                b[nt][0] = Bs2[(kb2 + cq) * 136 + nn];
                b[nt][1] = Bs2[(kb2 + cq + 4) * 136 + nn];
            }
#pragma unroll
            for (int mt = 0; mt < 4; mt++)
#pragma unroll
                for (int nt = 0; nt < 4; nt++)
                    mma_f16(acc[mt][nt], a[mt], b[nt][0], b[nt][1]);
        }
        __syncthreads();
    }

#pragma unroll
    for (int mt = 0; mt < 4; mt++) {
        int row0 = blockM + warpM + mt * 16 + r;
#pragma unroll
        for (int nt = 0; nt < 4; nt++) {
            int col = blockN + warpN + nt * 8 + cq * 2;
            if (HALFOUT) {
                __half2* Ch = (__half2*)Cout;
                if (row0 < M)
                    Ch[((size_t)row0 * ldc + col) >> 1] =
                        __floats2half2_rn(acc[mt][nt][0], acc[mt][nt][1]);
                if (row0 + 8 < M)
                    Ch[((size_t)(row0 + 8) * ldc + col) >> 1] =
                        __floats2half2_rn(acc[mt][nt][2], acc[mt][nt][3]);
            } else {
                float* C = (float*)Cout;
                if (row0 < M)
                    *(float2*)(C + (size_t)row0 * ldc + col) =
                        make_float2(acc[mt][nt][0], acc[mt][nt][1]);
                if (row0 + 8 < M)
                    *(float2*)(C + (size_t)(row0 + 8) * ldc + col) =
                        make_float2(acc[mt][nt][2], acc[mt][nt][3]);
            }
        }
    }

    if (ALPHA) {
        int head = blockN / Chead;
        float ws[4][2], wd[4][2];
#pragma unroll
        for (int nt = 0; nt < 4; nt++) {
            int col = blockN + warpN + nt * 8 + cq * 2;
            int c = col - head * Chead;
            ws[nt][0] = aS[head * Chead + c];
            ws[nt][1] = aS[head * Chead + c + 1];
            wd[nt][0] = aD[head * Chead + c];
            wd[nt][1] = aD[head * Chead + c + 1];
        }
#pragma unroll
        for (int mt = 0; mt < 4; mt++) {
            float ps0 = 0.f, pd0 = 0.f, ps1 = 0.f, pd1 = 0.f;
#pragma unroll
            for (int nt = 0; nt < 4; nt++) {
                ps0 += acc[mt][nt][0] * ws[nt][0] + acc[mt][nt][1] * ws[nt][1];
                pd0 += acc[mt][nt][0] * wd[nt][0] + acc[mt][nt][1] * wd[nt][1];
                ps1 += acc[mt][nt][2] * ws[nt][0] + acc[mt][nt][3] * ws[nt][1];
                pd1 += acc[mt][nt][2] * wd[nt][0] + acc[mt][nt][3] * wd[nt][1];
            }
#pragma unroll
            for (int o = 1; o < 4; o <<= 1) {
                ps0 += __shfl_xor_sync(0xFFFFFFFFu, ps0, o);
                pd0 += __shfl_xor_sync(0xFFFFFFFFu, pd0, o);
                ps1 += __shfl_xor_sync(0xFFFFFFFFu, ps1, o);
                pd1 += __shfl_xor_sync(0xFFFFFFFFu, pd1, o);
            }
            if (cq == 0) {
                int row0 = blockM + warpM + mt * 16 + r;
                if (row0 < M) {
                    atomicAdd(alS + (size_t)row0 * 4 + head, ps0);
                    atomicAdd(alD + (size_t)row0 * 4 + head, pd0);
                }
                if (row0 + 8 < M) {
                    atomicAdd(alS + (size_t)(row0 + 8) * 4 + head, ps1);
                    atomicAdd(alD + (size_t)(row0 + 8) * 4 + head, pd1);
                }
            }
        }
    }
}

// ---------------- TF32 tensor-core GEMM (head z@Wf1 only) --------------------
__device__ __forceinline__ void mma_tf32(float c[4], const float a[4], const float b[2]) {
    asm volatile(
        "mma.sync.aligned.m16n8k8.row.col.f32.tf32.tf32.f32 "
        "{%0,%1,%2,%3}, {%4,%5,%6,%7}, {%8,%9}, {%0,%1,%2,%3};"
        : "+f"(c[0]), "+f"(c[1]), "+f"(c[2]), "+f"(c[3])
        : "r"(__float_as_uint(a[0])), "r"(__float_as_uint(a[1])),
          "r"(__float_as_uint(a[2])), "r"(__float_as_uint(a[3])),
          "r"(__float_as_uint(b[0])), "r"(__float_as_uint(b[1])));
}

#define ABUF 4608
#define BBUF 4352
#define SMEM_FLOATS (2 * ABUF + 2 * BBUF)

__global__ __launch_bounds__(256, 2) void tf32gemm(
    const float* __restrict__ A, const float* __restrict__ B,
    float* __restrict__ C, int M, int Nc, int K, int lda, int ldb, int ldc)
{
    extern __shared__ float smemf[];

    int tid = threadIdx.x;
    int lane = tid & 31;
    int wid = tid >> 5;
    int warpM = (wid >> 2) * 64;
    int warpN = (wid & 3) * 32;
    int r = lane >> 2;
    int cq = lane & 3;

    int blockM = blockIdx.y * 128;
    int blockN = blockIdx.x * 128;

    int acol = (tid & 7) * 4;
    int arow0 = tid >> 3;
    int bcol = (tid & 31) * 4;
    int brow0 = tid >> 5;

    float acc[4][4][4];
#pragma unroll
    for (int mt = 0; mt < 4; mt++)
#pragma unroll
        for (int nt = 0; nt < 4; nt++)
#pragma unroll
            for (int i = 0; i < 4; i++) acc[mt][nt][i] = 0.0f;

    int nk = K >> 5;

    auto load_tile = [&](int k0, int buf) {
        float* As = smemf + buf * ABUF;
        float* Bs = smemf + 2 * ABUF + buf * BBUF;
#pragma unroll
        for (int i = 0; i < 4; i++) {
            int row = blockM + arow0 + i * 32;
            cp_async16(&As[(arow0 + i * 32) * 36 + acol],
                       A + (size_t)row * lda + k0 + acol, row < M);
        }
#pragma unroll
        for (int i = 0; i < 4; i++) {
            int kr = brow0 + i * 8;
            cp_async16(&Bs[kr * 136 + bcol],
                       B + (size_t)(k0 + kr) * ldb + blockN + bcol, true);
        }
        asm volatile("cp.async.commit_group;\n");
    };

    load_tile(0, 0);

    for (int kt = 0; kt < nk; kt++) {
        if (kt + 1 < nk) {
            load_tile((kt + 1) << 5, (kt + 1) & 1);
            asm volatile("cp.async.wait_group 1;\n");
        } else {
            asm volatile("cp.async.wait_group 0;\n");
        }
        __syncthreads();

        const float* As = smemf + (kt & 1) * ABUF;
        const float* Bs = smemf + 2 * ABUF + (kt & 1) * BBUF;

#pragma unroll
        for (int kk = 0; kk < 4; kk++) {
            int kb = kk * 8;
            float a[4][4], b[4][2];
#pragma unroll
            for (int mt = 0; mt < 4; mt++) {
                int m = warpM + mt * 16 + r;
                a[mt][0] = As[m * 36 + kb + cq];
                a[mt][1] = As[(m + 8) * 36 + kb + cq];
                a[mt][2] = As[m * 36 + kb + cq + 4];
                a[mt][3] = As[(m + 8) * 36 + kb + cq + 4];
            }
#pragma unroll
            for (int nt = 0; nt < 4; nt++) {
                int nn = warpN + nt * 8 + r;
                b[nt][0] = Bs[(kb + cq) * 136 + nn];
                b[nt][1] = Bs[(kb + cq + 4) * 136 + nn];
            }
#pragma unroll
            for (int mt = 0; mt < 4; mt++)
#pragma unroll
                for (int nt = 0; nt < 4; nt++)
                    mma_tf32(acc[mt][nt], a[mt], b[nt]);
        }
        __syncthreads();
    }

#pragma unroll
    for (int mt = 0; mt < 4; mt++) {
        int row0 = blockM + warpM + mt * 16 + r;
#pragma unroll
        for (int nt = 0; nt < 4; nt++) {
            int col = blockN + warpN + nt * 8 + cq * 2;
            if (row0 < M)
                *(float2*)(C + (size_t)row0 * ldc + col) =
                    make_float2(acc[mt][nt][0], acc[mt][nt][1]);
            if (row0 + 8 < M)
                *(float2*)(C + (size_t)(row0 + 8) * ldc + col) =
                    make_float2(acc[mt][nt][2], acc[mt][nt][3]);
        }
    }
}

// ---------------- fp32 SGEMM (solvent MLP: bias+relu) ------------------------
template <bool RELU>
__global__ __launch_bounds__(256) void sgemm(
    const float* __restrict__ A, const float* __restrict__ B,
    const float* __restrict__ bias, float* __restrict__ C,
    int M, int Nc, int K, int lda, int ldc)
{
    __shared__ float As[8][128];
    __shared__ float Bs[8][128];

    int tid = threadIdx.x;
    int bx = blockIdx.x;
    int by = blockIdx.y;

    int tx = tid % 16;
    int ty = tid / 16;

    int rowA = by * 128 + tid / 2;
    int colA = (tid % 2) * 4;
    int rowB = tid / 32;
    int colB = (tid % 32) * 4;

    float acc[8][8];
#pragma unroll
    for (int i = 0; i < 8; i++)
#pragma unroll
        for (int j = 0; j < 8; j++) acc[i][j] = 0.0f;

    for (int k0 = 0; k0 < K; k0 += 8) {
        float4 av = make_float4(0.f, 0.f, 0.f, 0.f);
        if (rowA < M)
            av = *(const float4*)(A + (size_t)rowA * lda + k0 + colA);
        As[colA + 0][tid / 2] = av.x;
        As[colA + 1][tid / 2] = av.y;
        As[colA + 2][tid / 2] = av.z;
        As[colA + 3][tid / 2] = av.w;

        float4 bv = *(const float4*)(B + (size_t)(k0 + rowB) * Nc + bx * 128 + colB);
        *(float4*)(&Bs[rowB][colB]) = bv;

        __syncthreads();

#pragma unroll
        for (int kk = 0; kk < 8; kk++) {
            float ra[8], rb[8];
#pragma unroll
            for (int i = 0; i < 8; i++) ra[i] = As[kk][ty * 8 + i];
#pragma unroll
            for (int j = 0; j < 8; j++) rb[j] = Bs[kk][tx * 8 + j];
#pragma unroll
            for (int i = 0; i < 8; i++)
#pragma unroll
                for (int j = 0; j < 8; j++) acc[i][j] = fmaf(ra[i], rb[j], acc[i][j]);
        }
        __syncthreads();
    }

#pragma unroll
    for (int i = 0; i < 8; i++) {
        int row = by * 128 + ty * 8 + i;
        if (row >= M) continue;
#pragma unroll
        for (int j = 0; j < 8; j++) {
            int col = bx * 128 + tx * 8 + j;
            float v = acc[i][j];
            if (bias) v += bias[col];
            if (RELU) v = v > 0.f ? v : 0.f;
            C[(size_t)row * ldc + col] = v;
        }
    }
}

// ---- GAT layer 1 input-space gather (precomputed alphas, fp16 output) -------
__global__ __launch_bounds__(64) void gat_agg_in64(
    const int* __restrict__ rowptr, const int* __restrict__ csrsrc,
    const float* __restrict__ alpha,
    const float* __restrict__ in, __half* __restrict__ agg)
{
    __shared__ float s_al[16][4];
    __shared__ int   s_src[16];

    int d = blockIdx.x;
    int tid = threadIdx.x;
    int beg = rowptr[d], end = rowptr[d + 1];

    float acc[4] = {0.f, 0.f, 0.f, 0.f};
    for (int c0 = beg; c0 < end; c0 += 16) {
        int cnt = min(16, end - c0);
        if (tid < cnt) s_src[tid] = csrsrc[c0 + tid];
        if (tid < cnt * 4) ((float*)s_al)[tid] = alpha[(size_t)c0 * 4 + tid];
        __syncthreads();
        int j = 0;
        for (; j + 4 <= cnt; j += 4) {
            float v0 = in[(size_t)s_src[j + 0] * 64 + tid];
            float v1 = in[(size_t)s_src[j + 1] * 64 + tid];
            float v2 = in[(size_t)s_src[j + 2] * 64 + tid];
            float v3 = in[(size_t)s_src[j + 3] * 64 + tid];
#pragma unroll
            for (int hh = 0; hh < 4; hh++) {
                acc[hh] = fmaf(s_al[j + 0][hh], v0, acc[hh]);
                acc[hh] = fmaf(s_al[j + 1][hh], v1, acc[hh]);
                acc[hh] = fmaf(s_al[j + 2][hh], v2, acc[hh]);
                acc[hh] = fmaf(s_al[j + 3][hh], v3, acc[hh]);
            }
        }
        for (; j < cnt; j++) {
            float v = in[(size_t)s_src[j] * 64 + tid];
#pragma unroll
            for (int hh = 0; hh < 4; hh++)
                acc[hh] = fmaf(s_al[j][hh], v, acc[hh]);
        }
        __syncthreads();
    }

#pragma unroll
    for (int hh = 0; hh < 4; hh++)
        agg[(size_t)d * 256 + hh * 64 + tid] = __float2half_rn(acc[hh]);
}

// ---- GAT2 gather (precomputed alphas; fp16 in, fp16 out; 2 blocks/node) -----
template <int HC, int SPLIT>
__global__ __launch_bounds__(128) void gat_gather_h(
    const int* __restrict__ rowptr, const int* __restrict__ csrsrc,
    const float* __restrict__ alpha,
    const __half* __restrict__ h, __half* __restrict__ out)
{
    constexpr int NT = 128;
    constexpr int HCW = HC / SPLIT;
    static_assert(HCW == 4 * NT, "4 channels per thread");
    constexpr int CPH = HC / 4;

    __shared__ float s_al[32][4];
    __shared__ int   s_src[32];

    int d = blockIdx.x;
    int half = (SPLIT > 1) ? blockIdx.y : 0;
    int coff = half * HCW;
    int tid = threadIdx.x;
    int beg = rowptr[d], end = rowptr[d + 1];

    float4 acc = make_float4(0.f, 0.f, 0.f, 0.f);
    int hof = (coff + tid * 4) / CPH;

    for (int c0 = beg; c0 < end; c0 += 32) {
        int cnt = min(32, end - c0);
        if (tid < cnt) s_src[tid] = csrsrc[c0 + tid];
        if (tid < cnt * 4) ((float*)s_al)[tid] = alpha[(size_t)c0 * 4 + tid];
        __syncthreads();
        int j = 0;
        for (; j + 4 <= cnt; j += 4) {
            const uint2* p0 = (const uint2*)(h + (size_t)s_src[j + 0] * HC + coff) + tid;
            const uint2* p1 = (const uint2*)(h + (size_t)s_src[j + 1] * HC + coff) + tid;
            const uint2* p2 = (const uint2*)(h + (size_t)s_src[j + 2] * HC + coff) + tid;
            const uint2* p3 = (const uint2*)(h + (size_t)s_src[j + 3] * HC + coff) + tid;
            uint2 r0 = *p0, r1 = *p1, r2 = *p2, r3 = *p3;
            float a0 = s_al[j + 0][hof];
            float a1 = s_al[j + 1][hof];
            float a2 = s_al[j + 2][hof];
            float a3 = s_al[j + 3][hof];
            float2 f0a = __half22float2(*(__half2*)&r0.x);
            float2 f0b = __half22float2(*(__half2*)&r0.y);
            float2 f1a = __half22float2(*(__half2*)&r1.x);
            float2 f1b = __half22float2(*(__half2*)&r1.y);
            float2 f2a = __half22float2(*(__half2*)&r2.x);
            float2 f2b = __half22float2(*(__half2*)&r2.y);
            float2 f3a = __half22float2(*(__half2*)&r3.x);
            float2 f3b = __half22float2(*(__half2*)&r3.y);
            acc.x = fmaf(a0, f0a.x, acc.x); acc.y = fmaf(a0, f0a.y, acc.y);
            acc.z = fmaf(a0, f0b.x, acc.z); acc.w = fmaf(a0, f0b.y, acc.w);
            acc.x = fmaf(a1, f1a.x, acc.x); acc.y = fmaf(a1, f1a.y, acc.y);
            acc.z = fmaf(a1, f1b.x, acc.z); acc.w = fmaf(a1, f1b.y, acc.w);
            acc.x = fmaf(a2, f2a.x, acc.x); acc.y = fmaf(a2, f2a.y, acc.y);
            acc.z = fmaf(a2, f2b.x, acc.z); acc.w = fmaf(a2, f2b.y, acc.w);
            acc.x = fmaf(a3, f3a.x, acc.x); acc.y = fmaf(a3, f3a.y, acc.y);
            acc.z = fmaf(a3, f3b.x, acc.z); acc.w = fmaf(a3, f3b.y, acc.w);
        }
        for (; j < cnt; j++) {
            const uint2* p = (const uint2*)(h + (size_t)s_src[j] * HC + coff) + tid;
            uint2 rr = *p;
            float a = s_al[j][hof];
            float2 fa = __half22float2(*(__half2*)&rr.x);
            float2 fb = __half22float2(*(__half2*)&rr.y);
            acc.x = fmaf(a, fa.x, acc.x);
            acc.y = fmaf(a, fa.y, acc.y);
            acc.z = fmaf(a, fb.x, acc.z);
            acc.w = fmaf(a, fb.y, acc.w);
        }
        __syncthreads();
    }

    uint2 ov;
    __half2 o0 = __floats2half2_rn(acc.x, acc.y);
    __half2 o1 = __floats2half2_rn(acc.z, acc.w);
    ov.x = *(uint32_t*)&o0;
    ov.y = *(uint32_t*)&o1;
    *((uint2*)(out + (size_t)d * HC + coff) + tid) = ov;
}

// ---------------- GCN gather (fp16 in, fp32 out) -----------------------------
__global__ __launch_bounds__(64) void gcn_gather_h(
    const int* __restrict__ rowptr, const int* __restrict__ csrsrc,
    const float* __restrict__ dinv, const __half* __restrict__ h,
    float* __restrict__ out)
{
    int d = blockIdx.x;
    int tid = threadIdx.x;
    int beg = rowptr[d], end = rowptr[d + 1];
    float dd = dinv[d];

    float4 acc = make_float4(0.f, 0.f, 0.f, 0.f);
    int i = beg;
    for (; i + 4 <= end; i += 4) {
        int s0 = csrsrc[i + 0], s1 = csrsrc[i + 1];
        int s2 = csrsrc[i + 2], s3 = csrsrc[i + 3];
        float n0 = dinv[s0] * dd, n1 = dinv[s1] * dd;
        float n2 = dinv[s2] * dd, n3 = dinv[s3] * dd;
        uint2 r0 = *((const uint2*)(h + (size_t)s0 * 256) + tid);
        uint2 r1 = *((const uint2*)(h + (size_t)s1 * 256) + tid);
        uint2 r2 = *((const uint2*)(h + (size_t)s2 * 256) + tid);
        uint2 r3 = *((const uint2*)(h + (size_t)s3 * 256) + tid);
        float2 f0a = __half22float2(*(__half2*)&r0.x);
        float2 f0b = __half22float2(*(__half2*)&r0.y);
        float2 f1a = __half22float2(*(__half2*)&r1.x);
        float2 f1b = __half22float2(*(__half2*)&r1.y);
        float2 f2a = __half22float2(*(__half2*)&r2.x);
        float2 f2b = __half22float2(*(__half2*)&r2.y);
        float2 f3a = __half22float2(*(__half2*)&r3.x);
        float2 f3b = __half22float2(*(__half2*)&r3.y);
        acc.x = fmaf(n0, f0a.x, acc.x); acc.y = fmaf(n0, f0a.y, acc.y);
        acc.z = fmaf(n0, f0b.x, acc.z); acc.w = fmaf(n0, f0b.y, acc.w);
        acc.x = fmaf(n1, f1a.x, acc.x); acc.y = fmaf(n1, f1a.y, acc.y);
        acc.z = fmaf(n1, f1b.x, acc.z); acc.w = fmaf(n1, f1b.y, acc.w);
        acc.x = fmaf(n2, f2a.x, acc.x); acc.y = fmaf(n2, f2a.y, acc.y);
        acc.z = fmaf(n2, f2b.x, acc.z); acc.w = fmaf(n2, f2b.y, acc.w);
        acc.x = fmaf(n3, f3a.x, acc.x); acc.y = fmaf(n3, f3a.y, acc.y);
        acc.z = fmaf(n3, f3b.x, acc.z); acc.w = fmaf(n3, f3b.y, acc.w);
    }
    for (; i < end; i++) {
        int s = csrsrc[i];
        float nrm = dinv[s] * dd;
        uint2 rr = *((const uint2*)(h + (size_t)s * 256) + tid);
        float2 fa = __half22float2(*(__half2*)&rr.x);
        float2 fb = __half22float2(*(__half2*)&rr.y);
        acc.x = fmaf(nrm, fa.x, acc.x);
        acc.y = fmaf(nrm, fa.y, acc.y);
        acc.z = fmaf(nrm, fb.x, acc.z);
        acc.w = fmaf(nrm, fb.y, acc.w);
    }
    *(float4*)(out + (size_t)d * 256 + tid * 4) = acc;
}

// ---------------- BatchNorm -------------------------------------------------
__global__ void bn_stats(const float* __restrict__ x, int rows, int K,
                         float* __restrict__ sum, float* __restrict__ sq)
{
    int col = blockIdx.x * blockDim.x + threadIdx.x;
    float s = 0.f, q = 0.f;
    for (int r = blockIdx.y; r < rows; r += gridDim.y) {
        float v = x[(size_t)r * K + col];
        s += v;
        q += v * v;
    }
    atomicAdd(sum + col, s);
    atomicAdd(sq + col, q);
}

__global__ void bn_stats_h4(const __half* __restrict__ x, int rows, int K,
                            float* __restrict__ sum, float* __restrict__ sq)
{
    int c0 = (blockIdx.x * blockDim.x + threadIdx.x) * 4;
    if (c0 >= K) return;
    float s0 = 0.f, s1 = 0.f, s2 = 0.f, s3 = 0.f;
    float q0 = 0.f, q1 = 0.f, q2 = 0.f, q3 = 0.f;
    for (int r = blockIdx.y; r < rows; r += gridDim.y) {
        uint2 v = *(const uint2*)(x + (size_t)r * K + c0);
        float2 a = __half22float2(*(__half2*)&v.x);
        float2 b = __half22float2(*(__half2*)&v.y);
        s0 += a.x; q0 += a.x * a.x;
        s1 += a.y; q1 += a.y * a.y;
        s2 += b.x; q2 += b.x * b.x;
        s3 += b.y; q3 += b.y * b.y;
    }
    atomicAdd(sum + c0 + 0, s0); atomicAdd(sq + c0 + 0, q0);
    atomicAdd(sum + c0 + 1, s1); atomicAdd(sq + c0 + 1, q1);
    atomicAdd(sum + c0 + 2, s2); atomicAdd(sq + c0 + 2, q2);
    atomicAdd(sum + c0 + 3, s3); atomicAdd(sq + c0 + 3, q3);
}

__global__ void bn_finalize(const float* __restrict__ sum, const float* __restrict__ sq,
                            const float* __restrict__ g, const float* __restrict__ b,
                            int rows, int K, float* __restrict__ scale,
                            float* __restrict__ shift)
{
    int c = blockIdx.x * blockDim.x + threadIdx.x;
    if (c >= K) return;
    float inv_n = 1.0f / (float)rows;
    float mu = sum[c] * inv_n;
    float var = sq[c] * inv_n - mu * mu;
    float sc = g[c] * rsqrtf(var + 1e-5f);
    scale[c] = sc;
    shift[c] = b[c] - mu * sc;
}

__global__ void bn_apply_relu(float* __restrict__ x, const float* __restrict__ scale,
                              const float* __restrict__ shift, size_t total, int K)
{
    for (size_t i = (size_t)blockIdx.x * blockDim.x + threadIdx.x; i < total;
         i += (size_t)gridDim.x * blockDim.x) {
        int c = (int)(i % K);
        float v = x[i] * scale[c] + shift[c];
        x[i] = v > 0.f ? v : 0.f;
    }
}

// ---------------- Pooling: one block per graph (batch sorted, no atomics) ----
__global__ __launch_bounds__(256) void pool_graph(
    const float* __restrict__ h, const int* __restrict__ gstart,
    const float* __restrict__ scale, const float* __restrict__ shift,
    float* __restrict__ z)
{
    int g = blockIdx.x;
    int c = threadIdx.x;
    int beg = gstart[g], end = gstart[g + 1];
    float sc = scale[c], sh = shift[c];
    float sum = 0.f, mx = 0.f;
    for (int r = beg; r < end; r++) {
        float v = fmaxf(fmaf(h[(size_t)r * 256 + c], sc, sh), 0.f);
        sum += v;
        mx = fmaxf(mx, v);
    }
    float cnt = (float)(end - beg);
    z[(size_t)g * 640 + c] = sum / fmaxf(cnt, 1.0f);
    z[(size_t)g * 640 + 256 + c] = mx;
}

// ---------------- Head -------------------------------------------------------
__global__ void head_final(const float* __restrict__ zf, const float* __restrict__ Wf2,
                           const float* __restrict__ bf2, float* __restrict__ out)
{
    int g = blockIdx.x;
    int t = threadIdx.x;
    float v = zf[(size_t)g * 128 + t] * Wf2[t];
#pragma unroll
    for (int o = 16; o; o >>= 1) v += __shfl_down_sync(0xFFFFFFFFu, v, o);
    __shared__ float sm[4];
    if ((t & 31) == 0) sm[t >> 5] = v;
    __syncthreads();
    if (t == 0) {
        float s = sm[0] + sm[1] + sm[2] + sm[3] + bf2[0];
        out[g] = 1.0f / (1.0f + expf(-s));
    }
}

// ---------------- launch ------------------------------------------------------
extern "C" void kernel_launch(void* const* d_in, const int* in_sizes, int n_in,
                              void* d_out, int out_size)
{
    const float* x    = (const float*)d_in[0];
    const int*   ei   = (const int*)d_in[1];
    const int*   batch= (const int*)d_in[2];
    const float* fp   = (const float*)d_in[3];
    const float* W1   = (const float*)d_in[4];
    const float* a1s  = (const float*)d_in[5];
    const float* a1d  = (const float*)d_in[6];
    const float* bn1g = (const float*)d_in[8];
    const float* bn1b = (const float*)d_in[9];
    const float* W2   = (const float*)d_in[10];
    const float* a2s  = (const float*)d_in[11];
    const float* a2d  = (const float*)d_in[12];
    const float* bn2g = (const float*)d_in[14];
    const float* bn2b = (const float*)d_in[15];
    const float* Wg   = (const float*)d_in[16];
    const float* bn3g = (const float*)d_in[18];
    const float* bn3b = (const float*)d_in[19];
    const float* Ws   = (const float*)d_in[20];
    const float* bs   = (const float*)d_in[21];
    const float* Wf1  = (const float*)d_in[22];
    const float* bnfg = (const float*)d_in[24];
    const float* bnfb = (const float*)d_in[25];
    const float* Wf2  = (const float*)d_in[26];
    const float* bf2  = (const float*)d_in[27];
    float* out = (float*)d_out;

    int n    = in_sizes[0] / 64;
    int E    = in_sizes[1] / 2;
    int Etot = E + n;
    int G    = in_sizes[3] / 128;

    float *bufA, *bufB, *bufC, *alS, *alD, *alpha, *dinv, *uu, *vv;
    float *bnsum, *bnsq, *bnscale, *bnshift, *z, *zf;
    __half *w1p, *w2p, *wgp;
    int *degi, *incl, *part, *rowptr, *cursor, *csrsrc, *gstart;
    cudaGetSymbolAddress((void**)&bufA, g_bufA);
    cudaGetSymbolAddress((void**)&bufB, g_bufB);
    cudaGetSymbolAddress((void**)&bufC, g_bufC);
    cudaGetSymbolAddress((void**)&w1p, g_w1p);
    cudaGetSymbolAddress((void**)&w2p, g_w2p);
    cudaGetSymbolAddress((void**)&wgp, g_wgp);
    cudaGetSymbolAddress((void**)&alS, g_alS);
    cudaGetSymbolAddress((void**)&alD, g_alD);
    cudaGetSymbolAddress((void**)&alpha, g_alpha);
    cudaGetSymbolAddress((void**)&uu, g_u);
    cudaGetSymbolAddress((void**)&vv, g_v);
    cudaGetSymbolAddress((void**)&degi, g_degi);
    cudaGetSymbolAddress((void**)&incl, g_incl);
    cudaGetSymbolAddress((void**)&part, g_part);
    cudaGetSymbolAddress((void**)&rowptr, g_rowptr);
    cudaGetSymbolAddress((void**)&cursor, g_cursor);
    cudaGetSymbolAddress((void**)&csrsrc, g_csrsrc);
    cudaGetSymbolAddress((void**)&dinv, g_dinv);
    cudaGetSymbolAddress((void**)&gstart, g_gstart);
    cudaGetSymbolAddress((void**)&bnsum, g_bnsum);
    cudaGetSymbolAddress((void**)&bnsq, g_bnsq);
    cudaGetSymbolAddress((void**)&bnscale, g_bnscale);
    cudaGetSymbolAddress((void**)&bnshift, g_bnshift);
    cudaGetSymbolAddress((void**)&z, g_z);
    cudaGetSymbolAddress((void**)&zf, g_zf);

    __half* bufA_h = (__half*)bufA;
    __half* bufB_h = (__half*)bufB;
    __half* bufC_h = (__half*)bufC;

    size_t tf_smem = SMEM_FLOATS * sizeof(float);
    static bool attr_done = false;
    if (!attr_done) {
        cudaFuncSetAttribute(tf32gemm,
                             cudaFuncAttributeMaxDynamicSharedMemorySize, (int)tf_smem);
        cudaFuncSetAttribute(hgemm<false, false, true, true>,
                             cudaFuncAttributeMaxDynamicSharedMemorySize, H_SMEM);
        cudaFuncSetAttribute(hgemm<true, true, false, true>,
                             cudaFuncAttributeMaxDynamicSharedMemorySize, H_SMEM);
        cudaFuncSetAttribute(hgemm<true, false, false, true>,
                             cudaFuncAttributeMaxDynamicSharedMemorySize, H_SMEM);
        attr_done = true;
    }

    auto bnstats_h = [&](const __half* Xp, int rows, int K, const float* gg,
                         const float* bb) {
        cudaMemsetAsync(bnsum, 0, K * sizeof(float));
        cudaMemsetAsync(bnsq, 0, K * sizeof(float));
        dim3 g1(K / 512, 128);
        bn_stats_h4<<<g1, 128>>>(Xp, rows, K, bnsum, bnsq);
        bn_finalize<<<(K + 127) / 128, 128>>>(bnsum, bnsq, gg, bb, rows, K,
                                              bnscale, bnshift);
    };

    // ---- CSR build + graph boundaries + weight packing (independent)
    cudaMemsetAsync(degi, 0, n * sizeof(int));
    deg_build<<<(Etot + 255) / 256, 256>>>(ei, E, Etot, degi);
    int nb = (n + 1023) / 1024;
    scan_partial<<<nb, 1024>>>(degi, n, incl, part);
    scan_roots<<<1, 128>>>(part, nb);
    scan_add<<<(n + 255) / 256, 256>>>(incl, degi, part, n, Etot,
                                       rowptr, cursor, dinv);
    csr_scatter<<<(Etot + 255) / 256, 256>>>(ei, E, Etot, cursor, csrsrc);
    gstart_build<<<(n + 256) / 256, 256>>>(batch, n, G, gstart);
    {
        int total = 64 * 512 + 512 * 1024 + 1024 * 256;
        pack_all<<<(total + 255) / 256, 256>>>(W1, W2, Wg, w1p, w2p, wgp);
    }

    // ---- GAT layer 1 (input-space): exact fp32 alphas; per-edge softmax;
    //      gather x -> fp16; hgemm
    uv_build<<<(64 * 4 * 32 + 255) / 256, 256>>>(W1, a1s, a1d, 64, 128, uu, vv);
    alpha_gemm64<<<(n + 7) / 8, 256>>>(x, n, uu, vv, alS, alD);
    alpha_edges<<<(n + 7) / 8, 256>>>(rowptr, csrsrc, alS, alD, n, alpha);
    gat_agg_in64<<<n, 64>>>(rowptr, csrsrc, alpha, x, bufA_h);
    {
        dim3 grid(4, (n + 127) / 128);
        hgemm<false, false, true, true><<<grid, 256, H_SMEM>>>(
            bufA_h, w1p, bufB_h, n, 512, 64, 256, 512,
            nullptr, nullptr, nullptr, nullptr, 128, nullptr, nullptr);
    }
    bnstats_h(bufB_h, n, 512, bn1g, bn1b);

    // ---- GAT layer 2: bufC_h = relu(bn(bufB_h))@W2 (+ fused logit partials);
    //      per-edge softmax; gather -> bufA_h
    cudaMemsetAsync(alS, 0, (size_t)n * 4 * sizeof(float));
    cudaMemsetAsync(alD, 0, (size_t)n * 4 * sizeof(float));
    {
        dim3 grid(8, (n + 127) / 128);
        hgemm<true, true, false, true><<<grid, 256, H_SMEM>>>(
            bufB_h, w2p, bufC_h, n, 1024, 512, 512, 1024,
            bnscale, bnshift, a2s, a2d, 256, alS, alD);
    }
    alpha_edges<<<(n + 7) / 8, 256>>>(rowptr, csrsrc, alS, alD, n, alpha);
    {
        dim3 grid(n, 2);
        gat_gather_h<1024, 2><<<grid, 128>>>(rowptr, csrsrc, alpha, bufC_h, bufA_h);
    }
    bnstats_h(bufA_h, n, 1024, bn2g, bn2b);

    // ---- GCN: bufB_h = relu(bn(bufA_h))@Wg; gather -> bufC (fp32); BN stats
    {
        dim3 grid(2, (n + 127) / 128);
        hgemm<true, false, false, true><<<grid, 256, H_SMEM>>>(
            bufA_h, wgp, bufB_h, n, 256, 1024, 1024, 256,
            bnscale, bnshift, nullptr, nullptr, 256, nullptr, nullptr);
    }
    gcn_gather_h<<<n, 64>>>(rowptr, csrsrc, dinv, bufB_h, bufC);
    {
        cudaMemsetAsync(bnsum, 0, 256 * sizeof(float));
        cudaMemsetAsync(bnsq, 0, 256 * sizeof(float));
        dim3 g1(2, 128);
        bn_stats<<<g1, 128>>>(bufC, n, 256, bnsum, bnsq);
        bn_finalize<<<2, 128>>>(bnsum, bnsq, bn3g, bn3b, n, 256, bnscale, bnshift);
    }

    // ---- Pooling into z[G,640] (block per graph; BN+relu on the fly)
    pool_graph<<<G, 256>>>(bufC, gstart, bnscale, bnshift, z);

    // ---- solvent MLP: relu(fp @ Ws + bs) -> z[:,512:640]
    {
        dim3 grid(1, (G + 127) / 128);
        sgemm<true><<<grid, 256>>>(fp, Ws, bs, z + 512, G, 128, 128, 128, 640);
    }

    // ---- head: zf = z @ Wf1 via tf32 (bf1 cancels under BN); BN; relu; sigmoid
    {
        dim3 grid(1, (G + 127) / 128);
        tf32gemm<<<grid, 256, tf_smem>>>(z, Wf1, zf, G, 128, 640, 640, 128, 128);
    }
    {
        cudaMemsetAsync(bnsum, 0, 128 * sizeof(float));
        cudaMemsetAsync(bnsq, 0, 128 * sizeof(float));
        dim3 g1(1, 128);
        bn_stats<<<g1, 128>>>(zf, G, 128, bnsum, bnsq);
        bn_finalize<<<1, 128>>>(bnsum, bnsq, bnfg, bnfb, G, 128, bnscale, bnshift);
        bn_apply_relu<<<((size_t)G * 128 + 255) / 256, 256>>>(zf, bnscale, bnshift,
                                                              (size_t)G * 128, 128);
    }
    head_final<<<G, 128>>>(zf, Wf2, bf2, out);
}

// round 15
// speedup vs baseline: 1.4472x; 1.0115x over previous
#include <cuda_runtime.h>
#include <cuda_fp16.h>
#include <math.h>
#include <stdint.h>

// Problem capacities (fixed shapes per reference)
#define NMAXN 50000
#define EMAXE 200000
#define ETOTMAX (EMAXE + NMAXN)
#define GMAXG 1000

// ---------------- scratch (static device memory; no allocations allowed) ----
__device__ float g_bufA[(size_t)NMAXN * 1024];
__device__ float g_bufB[(size_t)NMAXN * 1024];
__device__ float g_bufC[(size_t)NMAXN * 1024];
__device__ __half g_w1p[64 * 512];
__device__ __half g_w2p[512 * 1024];
__device__ __half g_wgp[1024 * 256];
__device__ float g_alS[NMAXN * 4];
__device__ float g_alD[NMAXN * 4];
__device__ float g_alpha[(size_t)ETOTMAX * 4];
__device__ float g_u[512 * 4];
__device__ float g_v[512 * 4];
__device__ int   g_degi[NMAXN];
__device__ int   g_incl[NMAXN];
__device__ int   g_part[128];
__device__ int   g_rowptr[NMAXN + 1];
__device__ int   g_cursor[NMAXN];
__device__ int   g_csrsrc[ETOTMAX];
__device__ float g_dinv[NMAXN];
__device__ int   g_gstart[GMAXG + 1];
__device__ float g_bnsum[1024];
__device__ float g_bnsq[1024];
__device__ float g_bnscale[1024];
__device__ float g_bnshift[1024];
__device__ float g_z[GMAXG * 640];
__device__ float g_zf[GMAXG * 128];

// ---------------- CSR build -------------------------------------------------
__global__ void deg_build(const int* __restrict__ ei, int E, int Etot,
                          int* __restrict__ degi)
{
    int e = blockIdx.x * blockDim.x + threadIdx.x;
    if (e >= Etot) return;
    int d = (e < E) ? ei[E + e] : (e - E);
    atomicAdd(degi + d, 1);
}

__global__ __launch_bounds__(1024) void scan_partial(
    const int* __restrict__ degi, int n, int* __restrict__ incl,
    int* __restrict__ part)
{
    __shared__ int sm[32];
    int tid = threadIdx.x;
    int lane = tid & 31, w = tid >> 5;
    int i = blockIdx.x * 1024 + tid;
    int v = (i < n) ? degi[i] : 0;
    int x = v;
#pragma unroll
    for (int o = 1; o < 32; o <<= 1) {
        int y = __shfl_up_sync(0xFFFFFFFFu, x, o);
        if (lane >= o) x += y;
    }
    if (lane == 31) sm[w] = x;
    __syncthreads();
    if (w == 0) {
        int y = sm[lane];
#pragma unroll
        for (int o = 1; o < 32; o <<= 1) {
            int z = __shfl_up_sync(0xFFFFFFFFu, y, o);
            if (lane >= o) y += z;
        }
        sm[lane] = y;
    }
    __syncthreads();
    int inclv = x + (w ? sm[w - 1] : 0);
    if (i < n) incl[i] = inclv;
    if (tid == 1023) part[blockIdx.x] = inclv;
}

__global__ void scan_roots(int* __restrict__ part, int nb)
{
    __shared__ int sm[128];
    int t = threadIdx.x;
    sm[t] = (t < nb) ? part[t] : 0;
    __syncthreads();
    if (t == 0) {
        int run = 0;
        for (int i = 0; i < nb; i++) { int v = sm[i]; sm[i] = run; run += v; }
    }
    __syncthreads();
    if (t < nb) part[t] = sm[t];
}

__global__ void scan_add(const int* __restrict__ incl, const int* __restrict__ degi,
                         const int* __restrict__ part, int n, int Etot,
                         int* __restrict__ rowptr, int* __restrict__ cursor,
                         float* __restrict__ dinv)
{
    int i = blockIdx.x * blockDim.x + threadIdx.x;
    if (i == 0) rowptr[n] = Etot;
    if (i >= n) return;
    int dg = degi[i];
    int exc = incl[i] + part[i >> 10] - dg;
    rowptr[i] = exc;
    cursor[i] = exc;
    dinv[i] = rsqrtf(fmaxf((float)dg, 1.0f));
}

__global__ void csr_scatter(const int* __restrict__ ei, int E, int Etot,
                            int* __restrict__ cursor, int* __restrict__ csrsrc)
{
    int e = blockIdx.x * blockDim.x + threadIdx.x;
    if (e >= Etot) return;
    int s, d;
    if (e < E) { s = ei[e]; d = ei[E + e]; }
    else       { s = e - E; d = e - E; }
    int pos = atomicAdd(cursor + d, 1);
    csrsrc[pos] = s;
}

__global__ void gstart_build(const int* __restrict__ batch, int n, int G,
                             int* __restrict__ gstart)
{
    int i = blockIdx.x * blockDim.x + threadIdx.x;
    if (i < n) {
        int b = batch[i];
        int bp = (i > 0) ? batch[i - 1] : -1;
        for (int g = bp + 1; g <= b; g++) gstart[g] = i;
    } else if (i == n) {
        int bl = batch[n - 1];
        for (int g = bl + 1; g <= G; g++) gstart[g] = n;
    }
}

// ---------------- weight packing (all three weights, one launch) -------------
__device__ __forceinline__ void pack_one(const float* __restrict__ W, int Nc, int i,
                                         __half* __restrict__ Wp)
{
    int k = i / Nc, nn = i % Nc;
    Wp[(size_t)(k >> 1) * 2 * Nc + 2 * nn + (k & 1)] = __float2half_rn(W[i]);
}

__global__ void pack_all(const float* __restrict__ W1, const float* __restrict__ W2,
                         const float* __restrict__ Wg,
                         __half* __restrict__ w1p, __half* __restrict__ w2p,
                         __half* __restrict__ wgp)
{
    const int S1 = 64 * 512, S2 = 512 * 1024, S3 = 1024 * 256;
    int i = blockIdx.x * blockDim.x + threadIdx.x;
    if (i < S1) pack_one(W1, 512, i, w1p);
    else if (i < S1 + S2) pack_one(W2, 1024, i - S1, w2p);
    else if (i < S1 + S2 + S3) pack_one(Wg, 256, i - S1 - S2, wgp);
}

// ---------------- u/v vectors: u[k,h] = sum_c W[k,hC+c]*a[h,c] ---------------
__global__ void uv_build(const float* __restrict__ W, const float* __restrict__ aS,
                         const float* __restrict__ aD, int K, int C,
                         float* __restrict__ u, float* __restrict__ v)
{
    int idx = blockIdx.x * blockDim.x + threadIdx.x;
    int warp = idx >> 5, lane = idx & 31;
    if (warp >= K * 4) return;
    int k = warp >> 2, h = warp & 3;
    const float* wrow = W + (size_t)k * (4 * C) + h * C;
    const float* as = aS + h * C;
    const float* ad = aD + h * C;
    float s = 0.f, d = 0.f;
    for (int c = lane; c < C; c += 32) {
        float wv = wrow[c];
        s += wv * as[c];
        d += wv * ad[c];
    }
#pragma unroll
    for (int o = 16; o; o >>= 1) {
        s += __shfl_xor_sync(0xFFFFFFFFu, s, o);
        d += __shfl_xor_sync(0xFFFFFFFFu, d, o);
    }
    if (lane == 0) { u[k * 4 + h] = s; v[k * 4 + h] = d; }
}

// ---------------- skinny alpha GEMM (layer 1, K=64, fp32 exact) --------------
__global__ __launch_bounds__(256) void alpha_gemm64(
    const float* __restrict__ in, int n,
    const float* __restrict__ u, const float* __restrict__ v,
    float* __restrict__ alS, float* __restrict__ alD)
{
    __shared__ float su[64][4];
    __shared__ float sv[64][4];
    int tid = threadIdx.x;
    if (tid < 64 * 4) { su[tid >> 2][tid & 3] = u[tid]; sv[tid >> 2][tid & 3] = v[tid]; }
    __syncthreads();

    int warp = tid >> 5, lane = tid & 31;
    for (int node = blockIdx.x * 8 + warp; node < n; node += gridDim.x * 8) {
        const float* row = in + (size_t)node * 64;
        float x0 = row[lane], x1 = row[lane + 32];
        float as[4], ad[4];
#pragma unroll
        for (int h = 0; h < 4; h++) {
            as[h] = x0 * su[lane][h] + x1 * su[lane + 32][h];
            ad[h] = x0 * sv[lane][h] + x1 * sv[lane + 32][h];
        }
#pragma unroll
        for (int h = 0; h < 4; h++) {
#pragma unroll
            for (int o = 16; o; o >>= 1) {
                as[h] += __shfl_xor_sync(0xFFFFFFFFu, as[h], o);
                ad[h] += __shfl_xor_sync(0xFFFFFFFFu, ad[h], o);
            }
        }
        if (lane == 0) {
            *(float4*)(alS + (size_t)node * 4) = make_float4(as[0], as[1], as[2], as[3]);
            *(float4*)(alD + (size_t)node * 4) = make_float4(ad[0], ad[1], ad[2], ad[3]);
        }
    }
}

// ---------------- per-edge softmax weights (one warp per destination) --------
__global__ __launch_bounds__(256) void alpha_edges(
    const int* __restrict__ rowptr, const int* __restrict__ csrsrc,
    const float* __restrict__ alS, const float* __restrict__ alD, int n,
    float* __restrict__ alpha)
{
    int warp = (blockIdx.x * blockDim.x + threadIdx.x) >> 5;
    int lane = threadIdx.x & 31;
    if (warp >= n) return;
    int d = warp;
    int beg = rowptr[d], end = rowptr[d + 1];

    float4 ad4 = *(const float4*)(alD + (size_t)d * 4);
    float adv[4] = {ad4.x, ad4.y, ad4.z, ad4.w};

    float mx[4] = {-INFINITY, -INFINITY, -INFINITY, -INFINITY};
    for (int i = beg + lane; i < end; i += 32) {
        int s = csrsrc[i];
        float4 as4 = *(const float4*)(alS + (size_t)s * 4);
        float l[4] = {as4.x + adv[0], as4.y + adv[1], as4.z + adv[2], as4.w + adv[3]};
#pragma unroll
        for (int h = 0; h < 4; h++) {
            float t = l[h];
            t = t > 0.f ? t : 0.2f * t;
            mx[h] = fmaxf(mx[h], t);
        }
    }
#pragma unroll
    for (int h = 0; h < 4; h++)
#pragma unroll
        for (int o = 16; o; o >>= 1)
            mx[h] = fmaxf(mx[h], __shfl_xor_sync(0xFFFFFFFFu, mx[h], o));

    float sme[4] = {0.f, 0.f, 0.f, 0.f};
    for (int i = beg + lane; i < end; i += 32) {
        int s = csrsrc[i];
        float4 as4 = *(const float4*)(alS + (size_t)s * 4);
        float l[4] = {as4.x + adv[0], as4.y + adv[1], as4.z + adv[2], as4.w + adv[3]};
#pragma unroll
        for (int h = 0; h < 4; h++) {
            float t = l[h];
            t = t > 0.f ? t : 0.2f * t;
            sme[h] += expf(t - mx[h]);
        }
    }
#pragma unroll
    for (int h = 0; h < 4; h++)
#pragma unroll
        for (int o = 16; o; o >>= 1)
            sme[h] += __shfl_xor_sync(0xFFFFFFFFu, sme[h], o);

    float binv[4];
#pragma unroll
    for (int h = 0; h < 4; h++) binv[h] = 1.0f / fmaxf(sme[h], 1e-16f);

    for (int i = beg + lane; i < end; i += 32) {
        int s = csrsrc[i];
        float4 as4 = *(const float4*)(alS + (size_t)s * 4);
        float l[4] = {as4.x + adv[0], as4.y + adv[1], as4.z + adv[2], as4.w + adv[3]};
        float4 av;
        float t0 = l[0] > 0.f ? l[0] : 0.2f * l[0];
        float t1 = l[1] > 0.f ? l[1] : 0.2f * l[1];
        float t2 = l[2] > 0.f ? l[2] : 0.2f * l[2];
        float t3 = l[3] > 0.f ? l[3] : 0.2f * l[3];
        av.x = expf(t0 - mx[0]) * binv[0];
        av.y = expf(t1 - mx[1]) * binv[1];
        av.z = expf(t2 - mx[2]) * binv[2];
        av.w = expf(t3 - mx[3]) * binv[3];
        *(float4*)(alpha + (size_t)i * 4) = av;
    }
}

// ---------------- FP16 tensor-core GEMM (ldmatrix A, k-tile 64) --------------
__device__ __forceinline__ void mma_f16(float c[4], const uint32_t a[4],
                                        uint32_t b0, uint32_t b1) {
    asm volatile(
        "mma.sync.aligned.m16n8k16.row.col.f32.f16.f16.f32 "
        "{%0,%1,%2,%3}, {%4,%5,%6,%7}, {%8,%9}, {%0,%1,%2,%3};"
        : "+f"(c[0]), "+f"(c[1]), "+f"(c[2]), "+f"(c[3])
        : "r"(a[0]), "r"(a[1]), "r"(a[2]), "r"(a[3]), "r"(b0), "r"(b1));
}

__device__ __forceinline__ void ldmatrix_x4(uint32_t a[4], uint32_t saddr) {
    asm volatile(
        "ldmatrix.sync.aligned.m8n8.x4.shared.b16 {%0,%1,%2,%3}, [%4];"
        : "=r"(a[0]), "=r"(a[1]), "=r"(a[2]), "=r"(a[3]) : "r"(saddr));
}

__device__ __forceinline__ void cp_async16(void* smem_dst, const void* gmem_src,
                                           bool pred) {
    uint32_t saddr = (uint32_t)__cvta_generic_to_shared(smem_dst);
    int sz = pred ? 16 : 0;
    asm volatile("cp.async.cg.shared.global [%0], [%1], 16, %2;\n"
                 :: "r"(saddr), "l"(gmem_src), "r"(sz));
}

__device__ __forceinline__ uint32_t bnrelu_h2(uint32_t v, float2 sc, float2 sh) {
    float2 f = __half22float2(*(__half2*)&v);
    f.x = fmaxf(fmaf(f.x, sc.x, sh.x), 0.f);
    f.y = fmaxf(fmaf(f.y, sc.y, sh.y), 0.f);
    __half2 h = __floats2half2_rn(f.x, f.y);
    return *(uint32_t*)&h;
}

#define H_ASTG 18432
#define H_BSTG 17408
#define H_SMEM (2 * (H_ASTG + H_BSTG))

template <bool BNRELU, bool ALPHA, bool GROUP, bool HALFOUT>
__global__ __launch_bounds__(256, 2) void hgemm(
    const __half* __restrict__ A, const __half* __restrict__ Bp,
    void* __restrict__ Cout, int M, int Nc, int K, int lda, int ldc,
    const float* __restrict__ scale, const float* __restrict__ shift,
    const float* __restrict__ aS, const float* __restrict__ aD, int Chead,
    float* __restrict__ alS, float* __restrict__ alD)
{
    extern __shared__ char smem[];

    int tid = threadIdx.x;
    int lane = tid & 31;
    int wid = tid >> 5;
    int warpM = (wid >> 2) * 64;
    int warpN = (wid & 3) * 32;
    int r = lane >> 2;
    int cq = lane & 3;

    int blockM = blockIdx.y * 128;
    int blockN = blockIdx.x * 128;

    if (GROUP) A += (size_t)(blockN >> 7) * K;

    float acc[4][4][4];
#pragma unroll
    for (int mt = 0; mt < 4; mt++)
#pragma unroll
        for (int nt = 0; nt < 4; nt++)
#pragma unroll
            for (int i = 0; i < 4; i++) acc[mt][nt][i] = 0.0f;

    int nk = K >> 6;

    // per-lane ldmatrix base offset within an A stage:
    // rows (warpM + mt*16 + (lane&15)), col-half (lane>>4)*16 bytes
    uint32_t aoff = (uint32_t)(warpM + (lane & 15)) * 144 + (uint32_t)(lane >> 4) * 16;

    auto load_tile = [&](int kt, int buf) {
        char* As = smem + buf * H_ASTG;
        char* Bs = smem + 2 * H_ASTG + buf * H_BSTG;
#pragma unroll
        for (int i = 0; i < 4; i++) {
            int row = (tid >> 3) + i * 32;
            int grow = blockM + row;
            cp_async16(As + (size_t)row * 144 + (tid & 7) * 16,
                       A + (size_t)grow * lda + kt * 64 + (tid & 7) * 8,
                       grow < M);
        }
#pragma unroll
        for (int i = 0; i < 4; i++) {
            int c = tid + i * 256;
            int krow = c >> 5;
            int nc4 = (c & 31) * 4;
            cp_async16(Bs + ((size_t)krow * 136 + nc4) * 4,
                       Bp + (size_t)(kt * 32 + krow) * 2 * Nc + 2 * blockN + nc4 * 2,
                       true);
        }
        asm volatile("cp.async.commit_group;\n");
    };

    load_tile(0, 0);

    for (int kt = 0; kt < nk; kt++) {
        if (kt + 1 < nk) {
            load_tile(kt + 1, (kt + 1) & 1);
            asm volatile("cp.async.wait_group 1;\n");
        } else {
            asm volatile("cp.async.wait_group 0;\n");
        }
        __syncthreads();

        const char* Asb = smem + (kt & 1) * H_ASTG;
        uint32_t abase = (uint32_t)__cvta_generic_to_shared(Asb) + aoff;
        const uint32_t* Bs2 = (const uint32_t*)(smem + 2 * H_ASTG + (kt & 1) * H_BSTG);

#pragma unroll
        for (int ks = 0; ks < 4; ks++) {
            int kb2 = ks * 8;
            float2 sc01, sh01, sc23, sh23;
            if (BNRELU) {
                int kg = kt * 64 + ks * 16 + 2 * cq;
                sc01 = *(const float2*)(scale + kg);
                sh01 = *(const float2*)(shift + kg);
                sc23 = *(const float2*)(scale + kg + 8);
                sh23 = *(const float2*)(shift + kg + 8);
            }
            uint32_t a[4][4], b[4][2];
#pragma unroll
            for (int mt = 0; mt < 4; mt++) {
                ldmatrix_x4(a[mt], abase + (uint32_t)mt * 16 * 144 + (uint32_t)ks * 32);
                if (BNRELU) {
                    a[mt][0] = bnrelu_h2(a[mt][0], sc01, sh01);
                    a[mt][1] = bnrelu_h2(a[mt][1], sc01, sh01);
                    a[mt][2] = bnrelu_h2(a[mt][2], sc23, sh23);
                    a[mt][3] = bnrelu_h2(a[mt][3], sc23, sh23);
                }
            }
#pragma unroll
            for (int nt = 0; nt < 4; nt++) {
                int nn = warpN + nt * 8 + r;
                b[nt][0] = Bs2[(kb2 + cq) * 136 + nn];
                b[nt][1] = Bs2[(kb2 + cq + 4) * 136 + nn];
            }
#pragma unroll
            for (int mt = 0; mt < 4; mt++)
#pragma unroll
                for (int nt = 0; nt < 4; nt++)
                    mma_f16(acc[mt][nt], a[mt], b[nt][0], b[nt][1]);
        }
        __syncthreads();
    }

#pragma unroll
    for (int mt = 0; mt < 4; mt++) {
        int row0 = blockM + warpM + mt * 16 + r;
#pragma unroll
        for (int nt = 0; nt < 4; nt++) {
            int col = blockN + warpN + nt * 8 + cq * 2;
            if (HALFOUT) {
                __half2* Ch = (__half2*)Cout;
                if (row0 < M)
                    Ch[((size_t)row0 * ldc + col) >> 1] =
                        __floats2half2_rn(acc[mt][nt][0], acc[mt][nt][1]);
                if (row0 + 8 < M)
                    Ch[((size_t)(row0 + 8) * ldc + col) >> 1] =
                        __floats2half2_rn(acc[mt][nt][2], acc[mt][nt][3]);
            } else {
                float* C = (float*)Cout;
                if (row0 < M)
                    *(float2*)(C + (size_t)row0 * ldc + col) =
                        make_float2(acc[mt][nt][0], acc[mt][nt][1]);
                if (row0 + 8 < M)
                    *(float2*)(C + (size_t)(row0 + 8) * ldc + col) =
                        make_float2(acc[mt][nt][2], acc[mt][nt][3]);
            }
        }
    }

    if (ALPHA) {
        int head = blockN / Chead;
        float ws[4][2], wd[4][2];
#pragma unroll
        for (int nt = 0; nt < 4; nt++) {
            int col = blockN + warpN + nt * 8 + cq * 2;
            int c = col - head * Chead;
            ws[nt][0] = aS[head * Chead + c];
            ws[nt][1] = aS[head * Chead + c + 1];
            wd[nt][0] = aD[head * Chead + c];
            wd[nt][1] = aD[head * Chead + c + 1];
        }
#pragma unroll
        for (int mt = 0; mt < 4; mt++) {
            float ps0 = 0.f, pd0 = 0.f, ps1 = 0.f, pd1 = 0.f;
#pragma unroll
            for (int nt = 0; nt < 4; nt++) {
                ps0 += acc[mt][nt][0] * ws[nt][0] + acc[mt][nt][1] * ws[nt][1];
                pd0 += acc[mt][nt][0] * wd[nt][0] + acc[mt][nt][1] * wd[nt][1];
                ps1 += acc[mt][nt][2] * ws[nt][0] + acc[mt][nt][3] * ws[nt][1];
                pd1 += acc[mt][nt][2] * wd[nt][0] + acc[mt][nt][3] * wd[nt][1];
            }
#pragma unroll
            for (int o = 1; o < 4; o <<= 1) {
                ps0 += __shfl_xor_sync(0xFFFFFFFFu, ps0, o);
                pd0 += __shfl_xor_sync(0xFFFFFFFFu, pd0, o);
                ps1 += __shfl_xor_sync(0xFFFFFFFFu, ps1, o);
                pd1 += __shfl_xor_sync(0xFFFFFFFFu, pd1, o);
            }
            if (cq == 0) {
                int row0 = blockM + warpM + mt * 16 + r;
                if (row0 < M) {
                    atomicAdd(alS + (size_t)row0 * 4 + head, ps0);
                    atomicAdd(alD + (size_t)row0 * 4 + head, pd0);
                }
                if (row0 + 8 < M) {
                    atomicAdd(alS + (size_t)(row0 + 8) * 4 + head, ps1);
                    atomicAdd(alD + (size_t)(row0 + 8) * 4 + head, pd1);
                }
            }
        }
    }
}

// ---------------- TF32 tensor-core GEMM (head z@Wf1 only) --------------------
__device__ __forceinline__ void mma_tf32(float c[4], const float a[4], const float b[2]) {
    asm volatile(
        "mma.sync.aligned.m16n8k8.row.col.f32.tf32.tf32.f32 "
        "{%0,%1,%2,%3}, {%4,%5,%6,%7}, {%8,%9}, {%0,%1,%2,%3};"
        : "+f"(c[0]), "+f"(c[1]), "+f"(c[2]), "+f"(c[3])
        : "r"(__float_as_uint(a[0])), "r"(__float_as_uint(a[1])),
          "r"(__float_as_uint(a[2])), "r"(__float_as_uint(a[3])),
          "r"(__float_as_uint(b[0])), "r"(__float_as_uint(b[1])));
}

#define ABUF 4608
#define BBUF 4352
#define SMEM_FLOATS (2 * ABUF + 2 * BBUF)

__global__ __launch_bounds__(256, 2) void tf32gemm(
    const float* __restrict__ A, const float* __restrict__ B,
    float* __restrict__ C, int M, int Nc, int K, int lda, int ldb, int ldc)
{
    extern __shared__ float smemf[];

    int tid = threadIdx.x;
    int lane = tid & 31;
    int wid = tid >> 5;
    int warpM = (wid >> 2) * 64;
    int warpN = (wid & 3) * 32;
    int r = lane >> 2;
    int cq = lane & 3;

    int blockM = blockIdx.y * 128;
    int blockN = blockIdx.x * 128;

    int acol = (tid & 7) * 4;
    int arow0 = tid >> 3;
    int bcol = (tid & 31) * 4;
    int brow0 = tid >> 5;

    float acc[4][4][4];
#pragma unroll
    for (int mt = 0; mt < 4; mt++)
#pragma unroll
        for (int nt = 0; nt < 4; nt++)
#pragma unroll
            for (int i = 0; i < 4; i++) acc[mt][nt][i] = 0.0f;

    int nk = K >> 5;

    auto load_tile = [&](int k0, int buf) {
        float* As = smemf + buf * ABUF;
        float* Bs = smemf + 2 * ABUF + buf * BBUF;
#pragma unroll
        for (int i = 0; i < 4; i++) {
            int row = blockM + arow0 + i * 32;
            cp_async16(&As[(arow0 + i * 32) * 36 + acol],
                       A + (size_t)row * lda + k0 + acol, row < M);
        }
#pragma unroll
        for (int i = 0; i < 4; i++) {
            int kr = brow0 + i * 8;
            cp_async16(&Bs[kr * 136 + bcol],
                       B + (size_t)(k0 + kr) * ldb + blockN + bcol, true);
        }
        asm volatile("cp.async.commit_group;\n");
    };

    load_tile(0, 0);

    for (int kt = 0; kt < nk; kt++) {
        if (kt + 1 < nk) {
            load_tile((kt + 1) << 5, (kt + 1) & 1);
            asm volatile("cp.async.wait_group 1;\n");
        } else {
            asm volatile("cp.async.wait_group 0;\n");
        }
        __syncthreads();

        const float* As = smemf + (kt & 1) * ABUF;
        const float* Bs = smemf + 2 * ABUF + (kt & 1) * BBUF;

#pragma unroll
        for (int kk = 0; kk < 4; kk++) {
            int kb = kk * 8;
            float a[4][4], b[4][2];
#pragma unroll
            for (int mt = 0; mt < 4; mt++) {
                int m = warpM + mt * 16 + r;
                a[mt][0] = As[m * 36 + kb + cq];
                a[mt][1] = As[(m + 8) * 36 + kb + cq];
                a[mt][2] = As[m * 36 + kb + cq + 4];
                a[mt][3] = As[(m + 8) * 36 + kb + cq + 4];
            }
#pragma unroll
            for (int nt = 0; nt < 4; nt++) {
                int nn = warpN + nt * 8 + r;
                b[nt][0] = Bs[(kb + cq) * 136 + nn];
                b[nt][1] = Bs[(kb + cq + 4) * 136 + nn];
            }
#pragma unroll
            for (int mt = 0; mt < 4; mt++)
#pragma unroll
                for (int nt = 0; nt < 4; nt++)
                    mma_tf32(acc[mt][nt], a[mt], b[nt]);
        }
        __syncthreads();
    }

#pragma unroll
    for (int mt = 0; mt < 4; mt++) {
        int row0 = blockM + warpM + mt * 16 + r;
#pragma unroll
        for (int nt = 0; nt < 4; nt++) {
            int col = blockN + warpN + nt * 8 + cq * 2;
            if (row0 < M)
                *(float2*)(C + (size_t)row0 * ldc + col) =
                    make_float2(acc[mt][nt][0], acc[mt][nt][1]);
            if (row0 + 8 < M)
                *(float2*)(C + (size_t)(row0 + 8) * ldc + col) =
                    make_float2(acc[mt][nt][2], acc[mt][nt][3]);
        }
    }
}

// ---------------- fp32 SGEMM (solvent MLP: bias+relu) ------------------------
template <bool RELU>
__global__ __launch_bounds__(256) void sgemm(
    const float* __restrict__ A, const float* __restrict__ B,
    const float* __restrict__ bias, float* __restrict__ C,
    int M, int Nc, int K, int lda, int ldc)
{
    __shared__ float As[8][128];
    __shared__ float Bs[8][128];

    int tid = threadIdx.x;
    int bx = blockIdx.x;
    int by = blockIdx.y;

    int tx = tid % 16;
    int ty = tid / 16;

    int rowA = by * 128 + tid / 2;
    int colA = (tid % 2) * 4;
    int rowB = tid / 32;
    int colB = (tid % 32) * 4;

    float acc[8][8];
#pragma unroll
    for (int i = 0; i < 8; i++)
#pragma unroll
        for (int j = 0; j < 8; j++) acc[i][j] = 0.0f;

    for (int k0 = 0; k0 < K; k0 += 8) {
        float4 av = make_float4(0.f, 0.f, 0.f, 0.f);
        if (rowA < M)
            av = *(const float4*)(A + (size_t)rowA * lda + k0 + colA);
        As[colA + 0][tid / 2] = av.x;
        As[colA + 1][tid / 2] = av.y;
        As[colA + 2][tid / 2] = av.z;
        As[colA + 3][tid / 2] = av.w;

        float4 bv = *(const float4*)(B + (size_t)(k0 + rowB) * Nc + bx * 128 + colB);
        *(float4*)(&Bs[rowB][colB]) = bv;

        __syncthreads();

#pragma unroll
        for (int kk = 0; kk < 8; kk++) {
            float ra[8], rb[8];
#pragma unroll
            for (int i = 0; i < 8; i++) ra[i] = As[kk][ty * 8 + i];
#pragma unroll
            for (int j = 0; j < 8; j++) rb[j] = Bs[kk][tx * 8 + j];
#pragma unroll
            for (int i = 0; i < 8; i++)
#pragma unroll
                for (int j = 0; j < 8; j++) acc[i][j] = fmaf(ra[i], rb[j], acc[i][j]);
        }
        __syncthreads();
    }

#pragma unroll
    for (int i = 0; i < 8; i++) {
        int row = by * 128 + ty * 8 + i;
        if (row >= M) continue;
#pragma unroll
        for (int j = 0; j < 8; j++) {
            int col = bx * 128 + tx * 8 + j;
            float v = acc[i][j];
            if (bias) v += bias[col];
            if (RELU) v = v > 0.f ? v : 0.f;
            C[(size_t)row * ldc + col] = v;
        }
    }
}

// ---- GAT layer 1 input-space gather (precomputed alphas, fp16 output) -------
__global__ __launch_bounds__(64) void gat_agg_in64(
    const int* __restrict__ rowptr, const int* __restrict__ csrsrc,
    const float* __restrict__ alpha,
    const float* __restrict__ in, __half* __restrict__ agg)
{
    __shared__ float s_al[16][4];
    __shared__ int   s_src[16];

    int d = blockIdx.x;
    int tid = threadIdx.x;
    int beg = rowptr[d], end = rowptr[d + 1];

    float acc[4] = {0.f, 0.f, 0.f, 0.f};
    for (int c0 = beg; c0 < end; c0 += 16) {
        int cnt = min(16, end - c0);
        if (tid < cnt) s_src[tid] = csrsrc[c0 + tid];
        if (tid < cnt * 4) ((float*)s_al)[tid] = alpha[(size_t)c0 * 4 + tid];
        __syncthreads();
        int j = 0;
        for (; j + 4 <= cnt; j += 4) {
            float v0 = in[(size_t)s_src[j + 0] * 64 + tid];
            float v1 = in[(size_t)s_src[j + 1] * 64 + tid];
            float v2 = in[(size_t)s_src[j + 2] * 64 + tid];
            float v3 = in[(size_t)s_src[j + 3] * 64 + tid];
#pragma unroll
            for (int hh = 0; hh < 4; hh++) {
                acc[hh] = fmaf(s_al[j + 0][hh], v0, acc[hh]);
                acc[hh] = fmaf(s_al[j + 1][hh], v1, acc[hh]);
                acc[hh] = fmaf(s_al[j + 2][hh], v2, acc[hh]);
                acc[hh] = fmaf(s_al[j + 3][hh], v3, acc[hh]);
            }
        }
        for (; j < cnt; j++) {
            float v = in[(size_t)s_src[j] * 64 + tid];
#pragma unroll
            for (int hh = 0; hh < 4; hh++)
                acc[hh] = fmaf(s_al[j][hh], v, acc[hh]);
        }
        __syncthreads();
    }

#pragma unroll
    for (int hh = 0; hh < 4; hh++)
        agg[(size_t)d * 256 + hh * 64 + tid] = __float2half_rn(acc[hh]);
}

// ---- GAT2 gather (precomputed alphas; fp16 in, fp16 out; 2 blocks/node) -----
template <int HC, int SPLIT>
__global__ __launch_bounds__(128) void gat_gather_h(
    const int* __restrict__ rowptr, const int* __restrict__ csrsrc,
    const float* __restrict__ alpha,
    const __half* __restrict__ h, __half* __restrict__ out)
{
    constexpr int NT = 128;
    constexpr int HCW = HC / SPLIT;
    static_assert(HCW == 4 * NT, "4 channels per thread");
    constexpr int CPH = HC / 4;

    __shared__ float s_al[32][4];
    __shared__ int   s_src[32];

    int d = blockIdx.x;
    int half = (SPLIT > 1) ? blockIdx.y : 0;
    int coff = half * HCW;
    int tid = threadIdx.x;
    int beg = rowptr[d], end = rowptr[d + 1];

    float4 acc = make_float4(0.f, 0.f, 0.f, 0.f);
    int hof = (coff + tid * 4) / CPH;

    for (int c0 = beg; c0 < end; c0 += 32) {
        int cnt = min(32, end - c0);
        if (tid < cnt) s_src[tid] = csrsrc[c0 + tid];
        if (tid < cnt * 4) ((float*)s_al)[tid] = alpha[(size_t)c0 * 4 + tid];
        __syncthreads();
        int j = 0;
        for (; j + 4 <= cnt; j += 4) {
            const uint2* p0 = (const uint2*)(h + (size_t)s_src[j + 0] * HC + coff) + tid;
            const uint2* p1 = (const uint2*)(h + (size_t)s_src[j + 1] * HC + coff) + tid;
            const uint2* p2 = (const uint2*)(h + (size_t)s_src[j + 2] * HC + coff) + tid;
            const uint2* p3 = (const uint2*)(h + (size_t)s_src[j + 3] * HC + coff) + tid;
            uint2 r0 = *p0, r1 = *p1, r2 = *p2, r3 = *p3;
            float a0 = s_al[j + 0][hof];
            float a1 = s_al[j + 1][hof];
            float a2 = s_al[j + 2][hof];
            float a3 = s_al[j + 3][hof];
            float2 f0a = __half22float2(*(__half2*)&r0.x);
            float2 f0b = __half22float2(*(__half2*)&r0.y);
            float2 f1a = __half22float2(*(__half2*)&r1.x);
            float2 f1b = __half22float2(*(__half2*)&r1.y);
            float2 f2a = __half22float2(*(__half2*)&r2.x);
            float2 f2b = __half22float2(*(__half2*)&r2.y);
            float2 f3a = __half22float2(*(__half2*)&r3.x);
            float2 f3b = __half22float2(*(__half2*)&r3.y);
            acc.x = fmaf(a0, f0a.x, acc.x); acc.y = fmaf(a0, f0a.y, acc.y);
            acc.z = fmaf(a0, f0b.x, acc.z); acc.w = fmaf(a0, f0b.y, acc.w);
            acc.x = fmaf(a1, f1a.x, acc.x); acc.y = fmaf(a1, f1a.y, acc.y);
            acc.z = fmaf(a1, f1b.x, acc.z); acc.w = fmaf(a1, f1b.y, acc.w);
            acc.x = fmaf(a2, f2a.x, acc.x); acc.y = fmaf(a2, f2a.y, acc.y);
            acc.z = fmaf(a2, f2b.x, acc.z); acc.w = fmaf(a2, f2b.y, acc.w);
            acc.x = fmaf(a3, f3a.x, acc.x); acc.y = fmaf(a3, f3a.y, acc.y);
            acc.z = fmaf(a3, f3b.x, acc.z); acc.w = fmaf(a3, f3b.y, acc.w);
        }
        for (; j < cnt; j++) {
            const uint2* p = (const uint2*)(h + (size_t)s_src[j] * HC + coff) + tid;
            uint2 rr = *p;
            float a = s_al[j][hof];
            float2 fa = __half22float2(*(__half2*)&rr.x);
            float2 fb = __half22float2(*(__half2*)&rr.y);
            acc.x = fmaf(a, fa.x, acc.x);
            acc.y = fmaf(a, fa.y, acc.y);
            acc.z = fmaf(a, fb.x, acc.z);
            acc.w = fmaf(a, fb.y, acc.w);
        }
        __syncthreads();
    }

    uint2 ov;
    __half2 o0 = __floats2half2_rn(acc.x, acc.y);
    __half2 o1 = __floats2half2_rn(acc.z, acc.w);
    ov.x = *(uint32_t*)&o0;
    ov.y = *(uint32_t*)&o1;
    *((uint2*)(out + (size_t)d * HC + coff) + tid) = ov;
}

// ---------------- GCN gather (fp16 in, fp16 out) -----------------------------
__global__ __launch_bounds__(64) void gcn_gather_h(
    const int* __restrict__ rowptr, const int* __restrict__ csrsrc,
    const float* __restrict__ dinv, const __half* __restrict__ h,
    __half* __restrict__ out)
{
    int d = blockIdx.x;
    int tid = threadIdx.x;
    int beg = rowptr[d], end = rowptr[d + 1];
    float dd = dinv[d];

    float4 acc = make_float4(0.f, 0.f, 0.f, 0.f);
    int i = beg;
    for (; i + 4 <= end; i += 4) {
        int s0 = csrsrc[i + 0], s1 = csrsrc[i + 1];
        int s2 = csrsrc[i + 2], s3 = csrsrc[i + 3];
        float n0 = dinv[s0] * dd, n1 = dinv[s1] * dd;
        float n2 = dinv[s2] * dd, n3 = dinv[s3] * dd;
        uint2 r0 = *((const uint2*)(h + (size_t)s0 * 256) + tid);
        uint2 r1 = *((const uint2*)(h + (size_t)s1 * 256) + tid);
        uint2 r2 = *((const uint2*)(h + (size_t)s2 * 256) + tid);
        uint2 r3 = *((const uint2*)(h + (size_t)s3 * 256) + tid);
        float2 f0a = __half22float2(*(__half2*)&r0.x);
        float2 f0b = __half22float2(*(__half2*)&r0.y);
        float2 f1a = __half22float2(*(__half2*)&r1.x);
        float2 f1b = __half22float2(*(__half2*)&r1.y);
        float2 f2a = __half22float2(*(__half2*)&r2.x);
        float2 f2b = __half22float2(*(__half2*)&r2.y);
        float2 f3a = __half22float2(*(__half2*)&r3.x);
        float2 f3b = __half22float2(*(__half2*)&r3.y);
        acc.x = fmaf(n0, f0a.x, acc.x); acc.y = fmaf(n0, f0a.y, acc.y);
        acc.z = fmaf(n0, f0b.x, acc.z); acc.w = fmaf(n0, f0b.y, acc.w);
        acc.x = fmaf(n1, f1a.x, acc.x); acc.y = fmaf(n1, f1a.y, acc.y);
        acc.z = fmaf(n1, f1b.x, acc.z); acc.w = fmaf(n1, f1b.y, acc.w);
        acc.x = fmaf(n2, f2a.x, acc.x); acc.y = fmaf(n2, f2a.y, acc.y);
        acc.z = fmaf(n2, f2b.x, acc.z); acc.w = fmaf(n2, f2b.y, acc.w);
        acc.x = fmaf(n3, f3a.x, acc.x); acc.y = fmaf(n3, f3a.y, acc.y);
        acc.z = fmaf(n3, f3b.x, acc.z); acc.w = fmaf(n3, f3b.y, acc.w);
    }
    for (; i < end; i++) {
        int s = csrsrc[i];
        float nrm = dinv[s] * dd;
        uint2 rr = *((const uint2*)(h + (size_t)s * 256) + tid);
        float2 fa = __half22float2(*(__half2*)&rr.x);
        float2 fb = __half22float2(*(__half2*)&rr.y);
        acc.x = fmaf(nrm, fa.x, acc.x);
        acc.y = fmaf(nrm, fa.y, acc.y);
        acc.z = fmaf(nrm, fb.x, acc.z);
        acc.w = fmaf(nrm, fb.y, acc.w);
    }
    uint2 ov;
    __half2 o0 = __floats2half2_rn(acc.x, acc.y);
    __half2 o1 = __floats2half2_rn(acc.z, acc.w);
    ov.x = *(uint32_t*)&o0;
    ov.y = *(uint32_t*)&o1;
    *((uint2*)(out + (size_t)d * 256) + tid) = ov;
}

// ---------------- BatchNorm -------------------------------------------------
__global__ void bn_stats(const float* __restrict__ x, int rows, int K,
                         float* __restrict__ sum, float* __restrict__ sq)
{
    int col = blockIdx.x * blockDim.x + threadIdx.x;
    float s = 0.f, q = 0.f;
    for (int r = blockIdx.y; r < rows; r += gridDim.y) {
        float v = x[(size_t)r * K + col];
        s += v;
        q += v * v;
    }
    atomicAdd(sum + col, s);
    atomicAdd(sq + col, q);
}

__global__ void bn_stats_h4(const __half* __restrict__ x, int rows, int K,
                            float* __restrict__ sum, float* __restrict__ sq)
{
    int c0 = (blockIdx.x * blockDim.x + threadIdx.x) * 4;
    if (c0 >= K) return;
    float s0 = 0.f, s1 = 0.f, s2 = 0.f, s3 = 0.f;
    float q0 = 0.f, q1 = 0.f, q2 = 0.f, q3 = 0.f;
    for (int r = blockIdx.y; r < rows; r += gridDim.y) {
        uint2 v = *(const uint2*)(x + (size_t)r * K + c0);
        float2 a = __half22float2(*(__half2*)&v.x);
        float2 b = __half22float2(*(__half2*)&v.y);
        s0 += a.x; q0 += a.x * a.x;
        s1 += a.y; q1 += a.y * a.y;
        s2 += b.x; q2 += b.x * b.x;
        s3 += b.y; q3 += b.y * b.y;
    }
    atomicAdd(sum + c0 + 0, s0); atomicAdd(sq + c0 + 0, q0);
    atomicAdd(sum + c0 + 1, s1); atomicAdd(sq + c0 + 1, q1);
    atomicAdd(sum + c0 + 2, s2); atomicAdd(sq + c0 + 2, q2);
    atomicAdd(sum + c0 + 3, s3); atomicAdd(sq + c0 + 3, q3);
}

__global__ void bn_finalize(const float* __restrict__ sum, const float* __restrict__ sq,
                            const float* __restrict__ g, const float* __restrict__ b,
                            int rows, int K, float* __restrict__ scale,
                            float* __restrict__ shift)
{
    int c = blockIdx.x * blockDim.x + threadIdx.x;
    if (c >= K) return;
    float inv_n = 1.0f / (float)rows;
    float mu = sum[c] * inv_n;
    float var = sq[c] * inv_n - mu * mu;
    float sc = g[c] * rsqrtf(var + 1e-5f);
    scale[c] = sc;
    shift[c] = b[c] - mu * sc;
}

__global__ void bn_apply_relu(float* __restrict__ x, const float* __restrict__ scale,
                              const float* __restrict__ shift, size_t total, int K)
{
    for (size_t i = (size_t)blockIdx.x * blockDim.x + threadIdx.x; i < total;
         i += (size_t)gridDim.x * blockDim.x) {
        int c = (int)(i % K);
        float v = x[i] * scale[c] + shift[c];
        x[i] = v > 0.f ? v : 0.f;
    }
}

// ---------------- Pooling (fp16 input; batch sorted, no atomics) -------------
__global__ __launch_bounds__(256) void pool_graph_h(
    const __half* __restrict__ h, const int* __restrict__ gstart,
    const float* __restrict__ scale, const float* __restrict__ shift,
    float* __restrict__ z)
{
    int g = blockIdx.x;
    int c = threadIdx.x;
    int beg = gstart[g], end = gstart[g + 1];
    float sc = scale[c], sh = shift[c];
    float sum = 0.f, mx = 0.f;
    for (int r = beg; r < end; r++) {
        float hv = __half2float(h[(size_t)r * 256 + c]);
        float v = fmaxf(fmaf(hv, sc, sh), 0.f);
        sum += v;
        mx = fmaxf(mx, v);
    }
    float cnt = (float)(end - beg);
    z[(size_t)g * 640 + c] = sum / fmaxf(cnt, 1.0f);
    z[(size_t)g * 640 + 256 + c] = mx;
}

// ---------------- Head -------------------------------------------------------
__global__ void head_final(const float* __restrict__ zf, const float* __restrict__ Wf2,
                           const float* __restrict__ bf2, float* __restrict__ out)
{
    int g = blockIdx.x;
    int t = threadIdx.x;
    float v = zf[(size_t)g * 128 + t] * Wf2[t];
#pragma unroll
    for (int o = 16; o; o >>= 1) v += __shfl_down_sync(0xFFFFFFFFu, v, o);
    __shared__ float sm[4];
    if ((t & 31) == 0) sm[t >> 5] = v;
    __syncthreads();
    if (t == 0) {
        float s = sm[0] + sm[1] + sm[2] + sm[3] + bf2[0];
        out[g] = 1.0f / (1.0f + expf(-s));
    }
}

// ---------------- launch ------------------------------------------------------
extern "C" void kernel_launch(void* const* d_in, const int* in_sizes, int n_in,
                              void* d_out, int out_size)
{
    const float* x    = (const float*)d_in[0];
    const int*   ei   = (const int*)d_in[1];
    const int*   batch= (const int*)d_in[2];
    const float* fp   = (const float*)d_in[3];
    const float* W1   = (const float*)d_in[4];
    const float* a1s  = (const float*)d_in[5];
    const float* a1d  = (const float*)d_in[6];
    const float* bn1g = (const float*)d_in[8];
    const float* bn1b = (const float*)d_in[9];
    const float* W2   = (const float*)d_in[10];
    const float* a2s  = (const float*)d_in[11];
    const float* a2d  = (const float*)d_in[12];
    const float* bn2g = (const float*)d_in[14];
    const float* bn2b = (const float*)d_in[15];
    const float* Wg   = (const float*)d_in[16];
    const float* bn3g = (const float*)d_in[18];
    const float* bn3b = (const float*)d_in[19];
    const float* Ws   = (const float*)d_in[20];
    const float* bs   = (const float*)d_in[21];
    const float* Wf1  = (const float*)d_in[22];
    const float* bnfg = (const float*)d_in[24];
    const float* bnfb = (const float*)d_in[25];
    const float* Wf2  = (const float*)d_in[26];
    const float* bf2  = (const float*)d_in[27];
    float* out = (float*)d_out;

    int n    = in_sizes[0] / 64;
    int E    = in_sizes[1] / 2;
    int Etot = E + n;
    int G    = in_sizes[3] / 128;

    float *bufA, *bufB, *bufC, *alS, *alD, *alpha, *dinv, *uu, *vv;
    float *bnsum, *bnsq, *bnscale, *bnshift, *z, *zf;
    __half *w1p, *w2p, *wgp;
    int *degi, *incl, *part, *rowptr, *cursor, *csrsrc, *gstart;
    cudaGetSymbolAddress((void**)&bufA, g_bufA);
    cudaGetSymbolAddress((void**)&bufB, g_bufB);
    cudaGetSymbolAddress((void**)&bufC, g_bufC);
    cudaGetSymbolAddress((void**)&w1p, g_w1p);
    cudaGetSymbolAddress((void**)&w2p, g_w2p);
    cudaGetSymbolAddress((void**)&wgp, g_wgp);
    cudaGetSymbolAddress((void**)&alS, g_alS);
    cudaGetSymbolAddress((void**)&alD, g_alD);
    cudaGetSymbolAddress((void**)&alpha, g_alpha);
    cudaGetSymbolAddress((void**)&uu, g_u);
    cudaGetSymbolAddress((void**)&vv, g_v);
    cudaGetSymbolAddress((void**)&degi, g_degi);
    cudaGetSymbolAddress((void**)&incl, g_incl);
    cudaGetSymbolAddress((void**)&part, g_part);
    cudaGetSymbolAddress((void**)&rowptr, g_rowptr);
    cudaGetSymbolAddress((void**)&cursor, g_cursor);
    cudaGetSymbolAddress((void**)&csrsrc, g_csrsrc);
    cudaGetSymbolAddress((void**)&dinv, g_dinv);
    cudaGetSymbolAddress((void**)&gstart, g_gstart);
    cudaGetSymbolAddress((void**)&bnsum, g_bnsum);
    cudaGetSymbolAddress((void**)&bnsq, g_bnsq);
    cudaGetSymbolAddress((void**)&bnscale, g_bnscale);
    cudaGetSymbolAddress((void**)&bnshift, g_bnshift);
    cudaGetSymbolAddress((void**)&z, g_z);
    cudaGetSymbolAddress((void**)&zf, g_zf);

    __half* bufA_h = (__half*)bufA;
    __half* bufB_h = (__half*)bufB;
    __half* bufC_h = (__half*)bufC;

    size_t tf_smem = SMEM_FLOATS * sizeof(float);
    static bool attr_done = false;
    if (!attr_done) {
        cudaFuncSetAttribute(tf32gemm,
                             cudaFuncAttributeMaxDynamicSharedMemorySize, (int)tf_smem);
        cudaFuncSetAttribute(hgemm<false, false, true, true>,
                             cudaFuncAttributeMaxDynamicSharedMemorySize, H_SMEM);
        cudaFuncSetAttribute(hgemm<true, true, false, true>,
                             cudaFuncAttributeMaxDynamicSharedMemorySize, H_SMEM);
        cudaFuncSetAttribute(hgemm<true, false, false, true>,
                             cudaFuncAttributeMaxDynamicSharedMemorySize, H_SMEM);
        attr_done = true;
    }

    auto bnstats_h = [&](const __half* Xp, int rows, int K, const float* gg,
                         const float* bb) {
        cudaMemsetAsync(bnsum, 0, K * sizeof(float));
        cudaMemsetAsync(bnsq, 0, K * sizeof(float));
        dim3 g1((K / 4 + 127) / 128, 128);
        bn_stats_h4<<<g1, 128>>>(Xp, rows, K, bnsum, bnsq);
        bn_finalize<<<(K + 127) / 128, 128>>>(bnsum, bnsq, gg, bb, rows, K,
                                              bnscale, bnshift);
    };

    // ---- CSR build + graph boundaries + weight packing (independent)
    cudaMemsetAsync(degi, 0, n * sizeof(int));
    deg_build<<<(Etot + 255) / 256, 256>>>(ei, E, Etot, degi);
    int nb = (n + 1023) / 1024;
    scan_partial<<<nb, 1024>>>(degi, n, incl, part);
    scan_roots<<<1, 128>>>(part, nb);
    scan_add<<<(n + 255) / 256, 256>>>(incl, degi, part, n, Etot,
                                       rowptr, cursor, dinv);
    csr_scatter<<<(Etot + 255) / 256, 256>>>(ei, E, Etot, cursor, csrsrc);
    gstart_build<<<(n + 256) / 256, 256>>>(batch, n, G, gstart);
    {
        int total = 64 * 512 + 512 * 1024 + 1024 * 256;
        pack_all<<<(total + 255) / 256, 256>>>(W1, W2, Wg, w1p, w2p, wgp);
    }

    // ---- GAT layer 1 (input-space): exact fp32 alphas; per-edge softmax;
    //      gather x -> fp16; hgemm
    uv_build<<<(64 * 4 * 32 + 255) / 256, 256>>>(W1, a1s, a1d, 64, 128, uu, vv);
    alpha_gemm64<<<(n + 7) / 8, 256>>>(x, n, uu, vv, alS, alD);
    alpha_edges<<<(n + 7) / 8, 256>>>(rowptr, csrsrc, alS, alD, n, alpha);
    gat_agg_in64<<<n, 64>>>(rowptr, csrsrc, alpha, x, bufA_h);
    {
        dim3 grid(4, (n + 127) / 128);
        hgemm<false, false, true, true><<<grid, 256, H_SMEM>>>(
            bufA_h, w1p, bufB_h, n, 512, 64, 256, 512,
            nullptr, nullptr, nullptr, nullptr, 128, nullptr, nullptr);
    }
    bnstats_h(bufB_h, n, 512, bn1g, bn1b);

    // ---- GAT layer 2: bufC_h = relu(bn(bufB_h))@W2 (+ fused logit partials);
    //      per-edge softmax; gather -> bufA_h
    cudaMemsetAsync(alS, 0, (size_t)n * 4 * sizeof(float));
    cudaMemsetAsync(alD, 0, (size_t)n * 4 * sizeof(float));
    {
        dim3 grid(8, (n + 127) / 128);
        hgemm<true, true, false, true><<<grid, 256, H_SMEM>>>(
            bufB_h, w2p, bufC_h, n, 1024, 512, 512, 1024,
            bnscale, bnshift, a2s, a2d, 256, alS, alD);
    }
    alpha_edges<<<(n + 7) / 8, 256>>>(rowptr, csrsrc, alS, alD, n, alpha);
    {
        dim3 grid(n, 2);
        gat_gather_h<1024, 2><<<grid, 128>>>(rowptr, csrsrc, alpha, bufC_h, bufA_h);
    }
    bnstats_h(bufA_h, n, 1024, bn2g, bn2b);

    // ---- GCN: bufB_h = relu(bn(bufA_h))@Wg; gather -> bufC_h (fp16); BN stats
    {
        dim3 grid(2, (n + 127) / 128);
        hgemm<true, false, false, true><<<grid, 256, H_SMEM>>>(
            bufA_h, wgp, bufB_h, n, 256, 1024, 1024, 256,
            bnscale, bnshift, nullptr, nullptr, 256, nullptr, nullptr);
    }
    gcn_gather_h<<<n, 64>>>(rowptr, csrsrc, dinv, bufB_h, bufC_h);
    bnstats_h(bufC_h, n, 256, bn3g, bn3b);

    // ---- Pooling into z[G,640] (block per graph; BN+relu on the fly)
    pool_graph_h<<<G, 256>>>(bufC_h, gstart, bnscale, bnshift, z);

    // ---- solvent MLP: relu(fp @ Ws + bs) -> z[:,512:640]
    {
        dim3 grid(1, (G + 127) / 128);
        sgemm<true><<<grid, 256>>>(fp, Ws, bs, z + 512, G, 128, 128, 128, 640);
    }

    // ---- head: zf = z @ Wf1 via tf32 (bf1 cancels under BN); BN; relu; sigmoid
    {
        dim3 grid(1, (G + 127) / 128);
        tf32gemm<<<grid, 256, tf_smem>>>(z, Wf1, zf, G, 128, 640, 640, 128, 128);
    }
    {
        cudaMemsetAsync(bnsum, 0, 128 * sizeof(float));
        cudaMemsetAsync(bnsq, 0, 128 * sizeof(float));
        dim3 g1(1, 128);
        bn_stats<<<g1, 128>>>(zf, G, 128, bnsum, bnsq);
        bn_finalize<<<1, 128>>>(bnsum, bnsq, bnfg, bnfb, G, 128, bnscale, bnshift);
        bn_apply_relu<<<((size_t)G * 128 + 255) / 256, 256>>>(zf, bnscale, bnshift,
                                                              (size_t)G * 128, 128);
    }
    head_final<<<G, 128>>>(zf, Wf2, bf2, out);
}

// round 16
// speedup vs baseline: 1.6736x; 1.1564x over previous
#include <cuda_runtime.h>
#include <cuda_fp16.h>
#include <math.h>
#include <stdint.h>

// Problem capacities (fixed shapes per reference)
#define NMAXN 50000
#define EMAXE 200000
#define ETOTMAX (EMAXE + NMAXN)
#define GMAXG 1000

// ---------------- scratch (static device memory; no allocations allowed) ----
__device__ float g_bufA[(size_t)NMAXN * 1024];
__device__ float g_bufB[(size_t)NMAXN * 1024];
__device__ float g_bufC[(size_t)NMAXN * 1024];
__device__ __half g_w1p[64 * 512];
__device__ __half g_w2p[512 * 1024];
__device__ __half g_wgp[1024 * 256];
__device__ float g_al2[2 * NMAXN * 4];          // alS | alD (contiguous)
__device__ float g_alpha[(size_t)ETOTMAX * 4];
__device__ float g_u[512 * 4];
__device__ float g_v[512 * 4];
__device__ int   g_degi[NMAXN];
__device__ int   g_incl[NMAXN];
__device__ int   g_part[128];
__device__ int   g_rowptr[NMAXN + 1];
__device__ int   g_cursor[NMAXN];
__device__ int   g_csrsrc[ETOTMAX];
__device__ float g_dinv[NMAXN];
__device__ int   g_gstart[GMAXG + 1];
__device__ float g_bnacc[2048];                 // sum[0:1024) | sq[1024:2048)
__device__ float g_bnscale[1024];
__device__ float g_bnshift[1024];
__device__ float g_z[GMAXG * 640];
__device__ float g_zf[GMAXG * 128];

// ---------------- CSR build -------------------------------------------------
__global__ void deg_build(const int* __restrict__ ei, int E, int Etot,
                          int* __restrict__ degi)
{
    int e = blockIdx.x * blockDim.x + threadIdx.x;
    if (e >= Etot) return;
    int d = (e < E) ? ei[E + e] : (e - E);
    atomicAdd(degi + d, 1);
}

__global__ __launch_bounds__(1024) void scan_partial(
    const int* __restrict__ degi, int n, int* __restrict__ incl,
    int* __restrict__ part)
{
    __shared__ int sm[32];
    int tid = threadIdx.x;
    int lane = tid & 31, w = tid >> 5;
    int i = blockIdx.x * 1024 + tid;
    int v = (i < n) ? degi[i] : 0;
    int x = v;
#pragma unroll
    for (int o = 1; o < 32; o <<= 1) {
        int y = __shfl_up_sync(0xFFFFFFFFu, x, o);
        if (lane >= o) x += y;
    }
    if (lane == 31) sm[w] = x;
    __syncthreads();
    if (w == 0) {
        int y = sm[lane];
#pragma unroll
        for (int o = 1; o < 32; o <<= 1) {
            int z = __shfl_up_sync(0xFFFFFFFFu, y, o);
            if (lane >= o) y += z;
        }
        sm[lane] = y;
    }
    __syncthreads();
    int inclv = x + (w ? sm[w - 1] : 0);
    if (i < n) incl[i] = inclv;
    if (tid == 1023) part[blockIdx.x] = inclv;
}

__global__ void scan_roots(int* __restrict__ part, int nb)
{
    __shared__ int sm[128];
    int t = threadIdx.x;
    sm[t] = (t < nb) ? part[t] : 0;
    __syncthreads();
    if (t == 0) {
        int run = 0;
        for (int i = 0; i < nb; i++) { int v = sm[i]; sm[i] = run; run += v; }
    }
    __syncthreads();
    if (t < nb) part[t] = sm[t];
}

__global__ void scan_add(const int* __restrict__ incl, const int* __restrict__ degi,
                         const int* __restrict__ part, int n, int Etot,
                         int* __restrict__ rowptr, int* __restrict__ cursor,
                         float* __restrict__ dinv)
{
    int i = blockIdx.x * blockDim.x + threadIdx.x;
    if (i == 0) rowptr[n] = Etot;
    if (i >= n) return;
    int dg = degi[i];
    int exc = incl[i] + part[i >> 10] - dg;
    rowptr[i] = exc;
    cursor[i] = exc;
    dinv[i] = rsqrtf(fmaxf((float)dg, 1.0f));
}

__global__ void csr_scatter(const int* __restrict__ ei, int E, int Etot,
                            int* __restrict__ cursor, int* __restrict__ csrsrc)
{
    int e = blockIdx.x * blockDim.x + threadIdx.x;
    if (e >= Etot) return;
    int s, d;
    if (e < E) { s = ei[e]; d = ei[E + e]; }
    else       { s = e - E; d = e - E; }
    int pos = atomicAdd(cursor + d, 1);
    csrsrc[pos] = s;
}

__global__ void gstart_build(const int* __restrict__ batch, int n, int G,
                             int* __restrict__ gstart)
{
    int i = blockIdx.x * blockDim.x + threadIdx.x;
    if (i < n) {
        int b = batch[i];
        int bp = (i > 0) ? batch[i - 1] : -1;
        for (int g = bp + 1; g <= b; g++) gstart[g] = i;
    } else if (i == n) {
        int bl = batch[n - 1];
        for (int g = bl + 1; g <= G; g++) gstart[g] = n;
    }
}

// ---------------- weight packing (all three weights, one launch) -------------
__device__ __forceinline__ void pack_one(const float* __restrict__ W, int Nc, int i,
                                         __half* __restrict__ Wp)
{
    int k = i / Nc, nn = i % Nc;
    Wp[(size_t)(k >> 1) * 2 * Nc + 2 * nn + (k & 1)] = __float2half_rn(W[i]);
}

__global__ void pack_all(const float* __restrict__ W1, const float* __restrict__ W2,
                         const float* __restrict__ Wg,
                         __half* __restrict__ w1p, __half* __restrict__ w2p,
                         __half* __restrict__ wgp)
{
    const int S1 = 64 * 512, S2 = 512 * 1024, S3 = 1024 * 256;
    int i = blockIdx.x * blockDim.x + threadIdx.x;
    if (i < S1) pack_one(W1, 512, i, w1p);
    else if (i < S1 + S2) pack_one(W2, 1024, i - S1, w2p);
    else if (i < S1 + S2 + S3) pack_one(Wg, 256, i - S1 - S2, wgp);
}

// ---------------- u/v vectors: u[k,h] = sum_c W[k,hC+c]*a[h,c] ---------------
__global__ void uv_build(const float* __restrict__ W, const float* __restrict__ aS,
                         const float* __restrict__ aD, int K, int C,
                         float* __restrict__ u, float* __restrict__ v)
{
    int idx = blockIdx.x * blockDim.x + threadIdx.x;
    int warp = idx >> 5, lane = idx & 31;
    if (warp >= K * 4) return;
    int k = warp >> 2, h = warp & 3;
    const float* wrow = W + (size_t)k * (4 * C) + h * C;
    const float* as = aS + h * C;
    const float* ad = aD + h * C;
    float s = 0.f, d = 0.f;
    for (int c = lane; c < C; c += 32) {
        float wv = wrow[c];
        s += wv * as[c];
        d += wv * ad[c];
    }
#pragma unroll
    for (int o = 16; o; o >>= 1) {
        s += __shfl_xor_sync(0xFFFFFFFFu, s, o);
        d += __shfl_xor_sync(0xFFFFFFFFu, d, o);
    }
    if (lane == 0) { u[k * 4 + h] = s; v[k * 4 + h] = d; }
}

// ---------------- skinny alpha GEMM (layer 1, K=64, fp32 exact) --------------
__global__ __launch_bounds__(256) void alpha_gemm64(
    const float* __restrict__ in, int n,
    const float* __restrict__ u, const float* __restrict__ v,
    float* __restrict__ alS, float* __restrict__ alD)
{
    __shared__ float su[64][4];
    __shared__ float sv[64][4];
    int tid = threadIdx.x;
    if (tid < 64 * 4) { su[tid >> 2][tid & 3] = u[tid]; sv[tid >> 2][tid & 3] = v[tid]; }
    __syncthreads();

    int warp = tid >> 5, lane = tid & 31;
    for (int node = blockIdx.x * 8 + warp; node < n; node += gridDim.x * 8) {
        const float* row = in + (size_t)node * 64;
        float x0 = row[lane], x1 = row[lane + 32];
        float as[4], ad[4];
#pragma unroll
        for (int h = 0; h < 4; h++) {
            as[h] = x0 * su[lane][h] + x1 * su[lane + 32][h];
            ad[h] = x0 * sv[lane][h] + x1 * sv[lane + 32][h];
        }
#pragma unroll
        for (int h = 0; h < 4; h++) {
#pragma unroll
            for (int o = 16; o; o >>= 1) {
                as[h] += __shfl_xor_sync(0xFFFFFFFFu, as[h], o);
                ad[h] += __shfl_xor_sync(0xFFFFFFFFu, ad[h], o);
            }
        }
        if (lane == 0) {
            *(float4*)(alS + (size_t)node * 4) = make_float4(as[0], as[1], as[2], as[3]);
            *(float4*)(alD + (size_t)node * 4) = make_float4(ad[0], ad[1], ad[2], ad[3]);
        }
    }
}

// ---------------- per-edge softmax weights (one warp per destination) --------
__global__ __launch_bounds__(256) void alpha_edges(
    const int* __restrict__ rowptr, const int* __restrict__ csrsrc,
    const float* __restrict__ alS, const float* __restrict__ alD, int n,
    float* __restrict__ alpha)
{
    int warp = (blockIdx.x * blockDim.x + threadIdx.x) >> 5;
    int lane = threadIdx.x & 31;
    if (warp >= n) return;
    int d = warp;
    int beg = rowptr[d], end = rowptr[d + 1];

    float4 ad4 = *(const float4*)(alD + (size_t)d * 4);
    float adv[4] = {ad4.x, ad4.y, ad4.z, ad4.w};

    float mx[4] = {-INFINITY, -INFINITY, -INFINITY, -INFINITY};
    for (int i = beg + lane; i < end; i += 32) {
        int s = csrsrc[i];
        float4 as4 = *(const float4*)(alS + (size_t)s * 4);
        float l[4] = {as4.x + adv[0], as4.y + adv[1], as4.z + adv[2], as4.w + adv[3]};
#pragma unroll
        for (int h = 0; h < 4; h++) {
            float t = l[h];
            t = t > 0.f ? t : 0.2f * t;
            mx[h] = fmaxf(mx[h], t);
        }
    }
#pragma unroll
    for (int h = 0; h < 4; h++)
#pragma unroll
        for (int o = 16; o; o >>= 1)
            mx[h] = fmaxf(mx[h], __shfl_xor_sync(0xFFFFFFFFu, mx[h], o));

    float sme[4] = {0.f, 0.f, 0.f, 0.f};
    for (int i = beg + lane; i < end; i += 32) {
        int s = csrsrc[i];
        float4 as4 = *(const float4*)(alS + (size_t)s * 4);
        float l[4] = {as4.x + adv[0], as4.y + adv[1], as4.z + adv[2], as4.w + adv[3]};
#pragma unroll
        for (int h = 0; h < 4; h++) {
            float t = l[h];
            t = t > 0.f ? t : 0.2f * t;
            sme[h] += expf(t - mx[h]);
        }
    }
#pragma unroll
    for (int h = 0; h < 4; h++)
#pragma unroll
        for (int o = 16; o; o >>= 1)
            sme[h] += __shfl_xor_sync(0xFFFFFFFFu, sme[h], o);

    float binv[4];
#pragma unroll
    for (int h = 0; h < 4; h++) binv[h] = 1.0f / fmaxf(sme[h], 1e-16f);

    for (int i = beg + lane; i < end; i += 32) {
        int s = csrsrc[i];
        float4 as4 = *(const float4*)(alS + (size_t)s * 4);
        float l[4] = {as4.x + adv[0], as4.y + adv[1], as4.z + adv[2], as4.w + adv[3]};
        float4 av;
        float t0 = l[0] > 0.f ? l[0] : 0.2f * l[0];
        float t1 = l[1] > 0.f ? l[1] : 0.2f * l[1];
        float t2 = l[2] > 0.f ? l[2] : 0.2f * l[2];
        float t3 = l[3] > 0.f ? l[3] : 0.2f * l[3];
        av.x = expf(t0 - mx[0]) * binv[0];
        av.y = expf(t1 - mx[1]) * binv[1];
        av.z = expf(t2 - mx[2]) * binv[2];
        av.w = expf(t3 - mx[3]) * binv[3];
        *(float4*)(alpha + (size_t)i * 4) = av;
    }
}

// ---------------- FP16 tensor-core GEMM (ldmatrix A, k-tile 64) --------------
// Templated block width BN in {128, 256}. 128: 256 thr, 2 blk/SM. 256: 512 thr.
__device__ __forceinline__ void mma_f16(float c[4], const uint32_t a[4],
                                        uint32_t b0, uint32_t b1) {
    asm volatile(
        "mma.sync.aligned.m16n8k16.row.col.f32.f16.f16.f32 "
        "{%0,%1,%2,%3}, {%4,%5,%6,%7}, {%8,%9}, {%0,%1,%2,%3};"
        : "+f"(c[0]), "+f"(c[1]), "+f"(c[2]), "+f"(c[3])
        : "r"(a[0]), "r"(a[1]), "r"(a[2]), "r"(a[3]), "r"(b0), "r"(b1));
}

__device__ __forceinline__ void ldmatrix_x4(uint32_t a[4], uint32_t saddr) {
    asm volatile(
        "ldmatrix.sync.aligned.m8n8.x4.shared.b16 {%0,%1,%2,%3}, [%4];"
        : "=r"(a[0]), "=r"(a[1]), "=r"(a[2]), "=r"(a[3]) : "r"(saddr));
}

__device__ __forceinline__ void cp_async16(void* smem_dst, const void* gmem_src,
                                           bool pred) {
    uint32_t saddr = (uint32_t)__cvta_generic_to_shared(smem_dst);
    int sz = pred ? 16 : 0;
    asm volatile("cp.async.cg.shared.global [%0], [%1], 16, %2;\n"
                 :: "r"(saddr), "l"(gmem_src), "r"(sz));
}

__device__ __forceinline__ uint32_t bnrelu_h2(uint32_t v, float2 sc, float2 sh) {
    float2 f = __half22float2(*(__half2*)&v);
    f.x = fmaxf(fmaf(f.x, sc.x, sh.x), 0.f);
    f.y = fmaxf(fmaf(f.y, sc.y, sh.y), 0.f);
    __half2 h = __floats2half2_rn(f.x, f.y);
    return *(uint32_t*)&h;
}

#define H_ASTG 18432
// per-BN B stage bytes: 32 k2-rows * (BN+8) half2 * 4
#define H_BSTG(BN) (32 * ((BN) + 8) * 4)
#define H_SMEM(BN) (2 * (H_ASTG + H_BSTG(BN)))

template <bool BNRELU, bool ALPHA, bool GROUP, bool HALFOUT, int BN>
__global__ __launch_bounds__(BN * 2, (BN == 128) ? 2 : 1) void hgemm(
    const __half* __restrict__ A, const __half* __restrict__ Bp,
    void* __restrict__ Cout, int M, int Nc, int K, int lda, int ldc,
    const float* __restrict__ scale, const float* __restrict__ shift,
    const float* __restrict__ aS, const float* __restrict__ aD, int Chead,
    float* __restrict__ alS, float* __restrict__ alD)
{
    extern __shared__ char smem[];
    constexpr int THREADS = BN * 2;
    constexpr int NWN = BN / 32;         // warps along N
    constexpr int P2 = BN + 8;           // B pitch in half2
    constexpr int BSTG = H_BSTG(BN);
    constexpr int CHROW = BN / 4;        // cp16 chunks per B k2-row

    int tid = threadIdx.x;
    int lane = tid & 31;
    int wid = tid >> 5;
    int warpM = (wid / NWN) * 64;
    int warpN = (wid % NWN) * 32;
    int r = lane >> 2;
    int cq = lane & 3;

    int blockM = blockIdx.y * 128;
    int blockN = blockIdx.x * BN;

    if (GROUP) A += (size_t)(blockN >> 7) * K;

    float acc[4][4][4];
#pragma unroll
    for (int mt = 0; mt < 4; mt++)
#pragma unroll
        for (int nt = 0; nt < 4; nt++)
#pragma unroll
            for (int i = 0; i < 4; i++) acc[mt][nt][i] = 0.0f;

    int nk = K >> 6;

    uint32_t aoff = (uint32_t)(warpM + (lane & 15)) * 144 + (uint32_t)(lane >> 4) * 16;

    auto load_tile = [&](int kt, int buf) {
        char* As = smem + buf * H_ASTG;
        char* Bs = smem + 2 * H_ASTG + buf * BSTG;
#pragma unroll
        for (int i = 0; i < 1024 / THREADS; i++) {
            int row = (tid >> 3) + i * (THREADS / 8);
            int grow = blockM + row;
            cp_async16(As + (size_t)row * 144 + (tid & 7) * 16,
                       A + (size_t)grow * lda + kt * 64 + (tid & 7) * 8,
                       grow < M);
        }
#pragma unroll
        for (int i = 0; i < 4; i++) {
            int c = tid + i * THREADS;
            int krow = c / CHROW;
            int ncd = (c % CHROW) * 4;   // half2 index within row
            cp_async16(Bs + ((size_t)krow * P2 + ncd) * 4,
                       Bp + (size_t)(kt * 32 + krow) * 2 * Nc + 2 * blockN + ncd * 2,
                       true);
        }
        asm volatile("cp.async.commit_group;\n");
    };

    load_tile(0, 0);

    for (int kt = 0; kt < nk; kt++) {
        if (kt + 1 < nk) {
            load_tile(kt + 1, (kt + 1) & 1);
            asm volatile("cp.async.wait_group 1;\n");
        } else {
            asm volatile("cp.async.wait_group 0;\n");
        }
        __syncthreads();

        const char* Asb = smem + (kt & 1) * H_ASTG;
        uint32_t abase = (uint32_t)__cvta_generic_to_shared(Asb) + aoff;
        const uint32_t* Bs2 = (const uint32_t*)(smem + 2 * H_ASTG + (kt & 1) * BSTG);

#pragma unroll
        for (int ks = 0; ks < 4; ks++) {
            int kb2 = ks * 8;
            float2 sc01, sh01, sc23, sh23;
            if (BNRELU) {
                int kg = kt * 64 + ks * 16 + 2 * cq;
                sc01 = *(const float2*)(scale + kg);
                sh01 = *(const float2*)(shift + kg);
                sc23 = *(const float2*)(scale + kg + 8);
                sh23 = *(const float2*)(shift + kg + 8);
            }
            uint32_t a[4][4], b[4][2];
#pragma unroll
            for (int mt = 0; mt < 4; mt++) {
                ldmatrix_x4(a[mt], abase + (uint32_t)mt * 16 * 144 + (uint32_t)ks * 32);
                if (BNRELU) {
                    a[mt][0] = bnrelu_h2(a[mt][0], sc01, sh01);
                    a[mt][1] = bnrelu_h2(a[mt][1], sc01, sh01);
                    a[mt][2] = bnrelu_h2(a[mt][2], sc23, sh23);
                    a[mt][3] = bnrelu_h2(a[mt][3], sc23, sh23);
                }
            }
#pragma unroll
            for (int nt = 0; nt < 4; nt++) {
                int nn = warpN + nt * 8 + r;
                b[nt][0] = Bs2[(kb2 + cq) * P2 + nn];
                b[nt][1] = Bs2[(kb2 + cq + 4) * P2 + nn];
            }
#pragma unroll
            for (int mt = 0; mt < 4; mt++)
#pragma unroll
                for (int nt = 0; nt < 4; nt++)
                    mma_f16(acc[mt][nt], a[mt], b[nt][0], b[nt][1]);
        }
        __syncthreads();
    }

#pragma unroll
    for (int mt = 0; mt < 4; mt++) {
        int row0 = blockM + warpM + mt * 16 + r;
#pragma unroll
        for (int nt = 0; nt < 4; nt++) {
            int col = blockN + warpN + nt * 8 + cq * 2;
            if (HALFOUT) {
                __half2* Ch = (__half2*)Cout;
                if (row0 < M)
                    Ch[((size_t)row0 * ldc + col) >> 1] =
                        __floats2half2_rn(acc[mt][nt][0], acc[mt][nt][1]);
                if (row0 + 8 < M)
                    Ch[((size_t)(row0 + 8) * ldc + col) >> 1] =
                        __floats2half2_rn(acc[mt][nt][2], acc[mt][nt][3]);
            } else {
                float* C = (float*)Cout;
                if (row0 < M)
                    *(float2*)(C + (size_t)row0 * ldc + col) =
                        make_float2(acc[mt][nt][0], acc[mt][nt][1]);
                if (row0 + 8 < M)
                    *(float2*)(C + (size_t)(row0 + 8) * ldc + col) =
                        make_float2(acc[mt][nt][2], acc[mt][nt][3]);
            }
        }
    }

    if (ALPHA) {
        int head = blockN / Chead;
        float ws[4][2], wd[4][2];
#pragma unroll
        for (int nt = 0; nt < 4; nt++) {
            int col = blockN + warpN + nt * 8 + cq * 2;
            int c = col - head * Chead;
            ws[nt][0] = aS[head * Chead + c];
            ws[nt][1] = aS[head * Chead + c + 1];
            wd[nt][0] = aD[head * Chead + c];
            wd[nt][1] = aD[head * Chead + c + 1];
        }
#pragma unroll
        for (int mt = 0; mt < 4; mt++) {
            float ps0 = 0.f, pd0 = 0.f, ps1 = 0.f, pd1 = 0.f;
#pragma unroll
            for (int nt = 0; nt < 4; nt++) {
                ps0 += acc[mt][nt][0] * ws[nt][0] + acc[mt][nt][1] * ws[nt][1];
                pd0 += acc[mt][nt][0] * wd[nt][0] + acc[mt][nt][1] * wd[nt][1];
                ps1 += acc[mt][nt][2] * ws[nt][0] + acc[mt][nt][3] * ws[nt][1];
                pd1 += acc[mt][nt][2] * wd[nt][0] + acc[mt][nt][3] * wd[nt][1];
            }
#pragma unroll
            for (int o = 1; o < 4; o <<= 1) {
                ps0 += __shfl_xor_sync(0xFFFFFFFFu, ps0, o);
                pd0 += __shfl_xor_sync(0xFFFFFFFFu, pd0, o);
                ps1 += __shfl_xor_sync(0xFFFFFFFFu, ps1, o);
                pd1 += __shfl_xor_sync(0xFFFFFFFFu, pd1, o);
            }
            if (cq == 0) {
                int row0 = blockM + warpM + mt * 16 + r;
                if (row0 < M) {
                    atomicAdd(alS + (size_t)row0 * 4 + head, ps0);
                    atomicAdd(alD + (size_t)row0 * 4 + head, pd0);
                }
                if (row0 + 8 < M) {
                    atomicAdd(alS + (size_t)(row0 + 8) * 4 + head, ps1);
                    atomicAdd(alD + (size_t)(row0 + 8) * 4 + head, pd1);
                }
            }
        }
    }
}

// ---------------- TF32 tensor-core GEMM (head z@Wf1 only) --------------------
__device__ __forceinline__ void mma_tf32(float c[4], const float a[4], const float b[2]) {
    asm volatile(
        "mma.sync.aligned.m16n8k8.row.col.f32.tf32.tf32.f32 "
        "{%0,%1,%2,%3}, {%4,%5,%6,%7}, {%8,%9}, {%0,%1,%2,%3};"
        : "+f"(c[0]), "+f"(c[1]), "+f"(c[2]), "+f"(c[3])
        : "r"(__float_as_uint(a[0])), "r"(__float_as_uint(a[1])),
          "r"(__float_as_uint(a[2])), "r"(__float_as_uint(a[3])),
          "r"(__float_as_uint(b[0])), "r"(__float_as_uint(b[1])));
}

#define ABUF 4608
#define BBUF 4352
#define SMEM_FLOATS (2 * ABUF + 2 * BBUF)

__global__ __launch_bounds__(256, 2) void tf32gemm(
    const float* __restrict__ A, const float* __restrict__ B,
    float* __restrict__ C, int M, int Nc, int K, int lda, int ldb, int ldc)
{
    extern __shared__ float smemf[];

    int tid = threadIdx.x;
    int lane = tid & 31;
    int wid = tid >> 5;
    int warpM = (wid >> 2) * 64;
    int warpN = (wid & 3) * 32;
    int r = lane >> 2;
    int cq = lane & 3;

    int blockM = blockIdx.y * 128;
    int blockN = blockIdx.x * 128;

    int acol = (tid & 7) * 4;
    int arow0 = tid >> 3;
    int bcol = (tid & 31) * 4;
    int brow0 = tid >> 5;

    float acc[4][4][4];
#pragma unroll
    for (int mt = 0; mt < 4; mt++)
#pragma unroll
        for (int nt = 0; nt < 4; nt++)
#pragma unroll
            for (int i = 0; i < 4; i++) acc[mt][nt][i] = 0.0f;

    int nk = K >> 5;

    auto load_tile = [&](int k0, int buf) {
        float* As = smemf + buf * ABUF;
        float* Bs = smemf + 2 * ABUF + buf * BBUF;
#pragma unroll
        for (int i = 0; i < 4; i++) {
            int row = blockM + arow0 + i * 32;
            cp_async16(&As[(arow0 + i * 32) * 36 + acol],
                       A + (size_t)row * lda + k0 + acol, row < M);
        }
#pragma unroll
        for (int i = 0; i < 4; i++) {
            int kr = brow0 + i * 8;
            cp_async16(&Bs[kr * 136 + bcol],
                       B + (size_t)(k0 + kr) * ldb + blockN + bcol, true);
        }
        asm volatile("cp.async.commit_group;\n");
    };

    load_tile(0, 0);

    for (int kt = 0; kt < nk; kt++) {
        if (kt + 1 < nk) {
            load_tile((kt + 1) << 5, (kt + 1) & 1);
            asm volatile("cp.async.wait_group 1;\n");
        } else {
            asm volatile("cp.async.wait_group 0;\n");
        }
        __syncthreads();

        const float* As = smemf + (kt & 1) * ABUF;
        const float* Bs = smemf + 2 * ABUF + (kt & 1) * BBUF;

#pragma unroll
        for (int kk = 0; kk < 4; kk++) {
            int kb = kk * 8;
            float a[4][4], b[4][2];
#pragma unroll
            for (int mt = 0; mt < 4; mt++) {
                int m = warpM + mt * 16 + r;
                a[mt][0] = As[m * 36 + kb + cq];
                a[mt][1] = As[(m + 8) * 36 + kb + cq];
                a[mt][2] = As[m * 36 + kb + cq + 4];
                a[mt][3] = As[(m + 8) * 36 + kb + cq + 4];
            }
#pragma unroll
            for (int nt = 0; nt < 4; nt++) {
                int nn = warpN + nt * 8 + r;
                b[nt][0] = Bs[(kb + cq) * 136 + nn];
                b[nt][1] = Bs[(kb + cq + 4) * 136 + nn];
            }
#pragma unroll
            for (int mt = 0; mt < 4; mt++)
#pragma unroll
                for (int nt = 0; nt < 4; nt++)
                    mma_tf32(acc[mt][nt], a[mt], b[nt]);
        }
        __syncthreads();
    }

#pragma unroll
    for (int mt = 0; mt < 4; mt++) {
        int row0 = blockM + warpM + mt * 16 + r;
#pragma unroll
        for (int nt = 0; nt < 4; nt++) {
            int col = blockN + warpN + nt * 8 + cq * 2;
            if (row0 < M)
                *(float2*)(C + (size_t)row0 * ldc + col) =
                    make_float2(acc[mt][nt][0], acc[mt][nt][1]);
            if (row0 + 8 < M)
                *(float2*)(C + (size_t)(row0 + 8) * ldc + col) =
                    make_float2(acc[mt][nt][2], acc[mt][nt][3]);
        }
    }
}

// ---------------- fp32 SGEMM (solvent MLP: bias+relu) ------------------------
template <bool RELU>
__global__ __launch_bounds__(256) void sgemm(
    const float* __restrict__ A, const float* __restrict__ B,
    const float* __restrict__ bias, float* __restrict__ C,
    int M, int Nc, int K, int lda, int ldc)
{
    __shared__ float As[8][128];
    __shared__ float Bs[8][128];

    int tid = threadIdx.x;
    int bx = blockIdx.x;
    int by = blockIdx.y;

    int tx = tid % 16;
    int ty = tid / 16;

    int rowA = by * 128 + tid / 2;
    int colA = (tid % 2) * 4;
    int rowB = tid / 32;
    int colB = (tid % 32) * 4;

    float acc[8][8];
#pragma unroll
    for (int i = 0; i < 8; i++)
#pragma unroll
        for (int j = 0; j < 8; j++) acc[i][j] = 0.0f;

    for (int k0 = 0; k0 < K; k0 += 8) {
        float4 av = make_float4(0.f, 0.f, 0.f, 0.f);
        if (rowA < M)
            av = *(const float4*)(A + (size_t)rowA * lda + k0 + colA);
        As[colA + 0][tid / 2] = av.x;
        As[colA + 1][tid / 2] = av.y;
        As[colA + 2][tid / 2] = av.z;
        As[colA + 3][tid / 2] = av.w;

        float4 bv = *(const float4*)(B + (size_t)(k0 + rowB) * Nc + bx * 128 + colB);
        *(float4*)(&Bs[rowB][colB]) = bv;

        __syncthreads();

#pragma unroll
        for (int kk = 0; kk < 8; kk++) {
            float ra[8], rb[8];
#pragma unroll
            for (int i = 0; i < 8; i++) ra[i] = As[kk][ty * 8 + i];
#pragma unroll
            for (int j = 0; j < 8; j++) rb[j] = Bs[kk][tx * 8 + j];
#pragma unroll
            for (int i = 0; i < 8; i++)
#pragma unroll
                for (int j = 0; j < 8; j++) acc[i][j] = fmaf(ra[i], rb[j], acc[i][j]);
        }
        __syncthreads();
    }

#pragma unroll
    for (int i = 0; i < 8; i++) {
        int row = by * 128 + ty * 8 + i;
        if (row >= M) continue;
#pragma unroll
        for (int j = 0; j < 8; j++) {
            int col = bx * 128 + tx * 8 + j;
            float v = acc[i][j];
            if (bias) v += bias[col];
            if (RELU) v = v > 0.f ? v : 0.f;
            C[(size_t)row * ldc + col] = v;
        }
    }
}

// ---- GAT layer 1 input-space gather (precomputed alphas, fp16 output) -------
__global__ __launch_bounds__(64) void gat_agg_in64(
    const int* __restrict__ rowptr, const int* __restrict__ csrsrc,
    const float* __restrict__ alpha,
    const float* __restrict__ in, __half* __restrict__ agg)
{
    __shared__ float s_al[16][4];
    __shared__ int   s_src[16];

    int d = blockIdx.x;
    int tid = threadIdx.x;
    int beg = rowptr[d], end = rowptr[d + 1];

    float acc[4] = {0.f, 0.f, 0.f, 0.f};
    for (int c0 = beg; c0 < end; c0 += 16) {
        int cnt = min(16, end - c0);
        if (tid < cnt) s_src[tid] = csrsrc[c0 + tid];
        if (tid < cnt * 4) ((float*)s_al)[tid] = alpha[(size_t)c0 * 4 + tid];
        __syncthreads();
        int j = 0;
        for (; j + 4 <= cnt; j += 4) {
            float v0 = in[(size_t)s_src[j + 0] * 64 + tid];
            float v1 = in[(size_t)s_src[j + 1] * 64 + tid];
            float v2 = in[(size_t)s_src[j + 2] * 64 + tid];
            float v3 = in[(size_t)s_src[j + 3] * 64 + tid];
#pragma unroll
            for (int hh = 0; hh < 4; hh++) {
                acc[hh] = fmaf(s_al[j + 0][hh], v0, acc[hh]);
                acc[hh] = fmaf(s_al[j + 1][hh], v1, acc[hh]);
                acc[hh] = fmaf(s_al[j + 2][hh], v2, acc[hh]);
                acc[hh] = fmaf(s_al[j + 3][hh], v3, acc[hh]);
            }
        }
        for (; j < cnt; j++) {
            float v = in[(size_t)s_src[j] * 64 + tid];
#pragma unroll
            for (int hh = 0; hh < 4; hh++)
                acc[hh] = fmaf(s_al[j][hh], v, acc[hh]);
        }
        __syncthreads();
    }

#pragma unroll
    for (int hh = 0; hh < 4; hh++)
        agg[(size_t)d * 256 + hh * 64 + tid] = __float2half_rn(acc[hh]);
}

// ---- GAT2 gather (precomputed alphas; fp16 in, fp16 out; 2 blocks/node) -----
template <int HC, int SPLIT>
__global__ __launch_bounds__(128) void gat_gather_h(
    const int* __restrict__ rowptr, const int* __restrict__ csrsrc,
    const float* __restrict__ alpha,
    const __half* __restrict__ h, __half* __restrict__ out)
{
    constexpr int NT = 128;
    constexpr int HCW = HC / SPLIT;
    static_assert(HCW == 4 * NT, "4 channels per thread");
    constexpr int CPH = HC / 4;

    __shared__ float s_al[32][4];
    __shared__ int   s_src[32];

    int d = blockIdx.x;
    int half = (SPLIT > 1) ? blockIdx.y : 0;
    int coff = half * HCW;
    int tid = threadIdx.x;
    int beg = rowptr[d], end = rowptr[d + 1];

    float4 acc = make_float4(0.f, 0.f, 0.f, 0.f);
    int hof = (coff + tid * 4) / CPH;

    for (int c0 = beg; c0 < end; c0 += 32) {
        int cnt = min(32, end - c0);
        if (tid < cnt) s_src[tid] = csrsrc[c0 + tid];
        if (tid < cnt * 4) ((float*)s_al)[tid] = alpha[(size_t)c0 * 4 + tid];
        __syncthreads();
        int j = 0;
        for (; j + 4 <= cnt; j += 4) {
            const uint2* p0 = (const uint2*)(h + (size_t)s_src[j + 0] * HC + coff) + tid;
            const uint2* p1 = (const uint2*)(h + (size_t)s_src[j + 1] * HC + coff) + tid;
            const uint2* p2 = (const uint2*)(h + (size_t)s_src[j + 2] * HC + coff) + tid;
            const uint2* p3 = (const uint2*)(h + (size_t)s_src[j + 3] * HC + coff) + tid;
            uint2 r0 = *p0, r1 = *p1, r2 = *p2, r3 = *p3;
            float a0 = s_al[j + 0][hof];
            float a1 = s_al[j + 1][hof];
            float a2 = s_al[j + 2][hof];
            float a3 = s_al[j + 3][hof];
            float2 f0a = __half22float2(*(__half2*)&r0.x);
            float2 f0b = __half22float2(*(__half2*)&r0.y);
            float2 f1a = __half22float2(*(__half2*)&r1.x);
            float2 f1b = __half22float2(*(__half2*)&r1.y);
            float2 f2a = __half22float2(*(__half2*)&r2.x);
            float2 f2b = __half22float2(*(__half2*)&r2.y);
            float2 f3a = __half22float2(*(__half2*)&r3.x);
            float2 f3b = __half22float2(*(__half2*)&r3.y);
            acc.x = fmaf(a0, f0a.x, acc.x); acc.y = fmaf(a0, f0a.y, acc.y);
            acc.z = fmaf(a0, f0b.x, acc.z); acc.w = fmaf(a0, f0b.y, acc.w);
            acc.x = fmaf(a1, f1a.x, acc.x); acc.y = fmaf(a1, f1a.y, acc.y);
            acc.z = fmaf(a1, f1b.x, acc.z); acc.w = fmaf(a1, f1b.y, acc.w);
            acc.x = fmaf(a2, f2a.x, acc.x); acc.y = fmaf(a2, f2a.y, acc.y);
            acc.z = fmaf(a2, f2b.x, acc.z); acc.w = fmaf(a2, f2b.y, acc.w);
            acc.x = fmaf(a3, f3a.x, acc.x); acc.y = fmaf(a3, f3a.y, acc.y);
            acc.z = fmaf(a3, f3b.x, acc.z); acc.w = fmaf(a3, f3b.y, acc.w);
        }
        for (; j < cnt; j++) {
            const uint2* p = (const uint2*)(h + (size_t)s_src[j] * HC + coff) + tid;
            uint2 rr = *p;
            float a = s_al[j][hof];
            float2 fa = __half22float2(*(__half2*)&rr.x);
            float2 fb = __half22float2(*(__half2*)&rr.y);
            acc.x = fmaf(a, fa.x, acc.x);
            acc.y = fmaf(a, fa.y, acc.y);
            acc.z = fmaf(a, fb.x, acc.z);
            acc.w = fmaf(a, fb.y, acc.w);
        }
        __syncthreads();
    }

    uint2 ov;
    __half2 o0 = __floats2half2_rn(acc.x, acc.y);
    __half2 o1 = __floats2half2_rn(acc.z, acc.w);
    ov.x = *(uint32_t*)&o0;
    ov.y = *(uint32_t*)&o1;
    *((uint2*)(out + (size_t)d * HC + coff) + tid) = ov;
}

// ---------------- GCN gather (fp16 in, fp16 out) -----------------------------
__global__ __launch_bounds__(64) void gcn_gather_h(
    const int* __restrict__ rowptr, const int* __restrict__ csrsrc,
    const float* __restrict__ dinv, const __half* __restrict__ h,
    __half* __restrict__ out)
{
    int d = blockIdx.x;
    int tid = threadIdx.x;
    int beg = rowptr[d], end = rowptr[d + 1];
    float dd = dinv[d];

    float4 acc = make_float4(0.f, 0.f, 0.f, 0.f);
    int i = beg;
    for (; i + 4 <= end; i += 4) {
        int s0 = csrsrc[i + 0], s1 = csrsrc[i + 1];
        int s2 = csrsrc[i + 2], s3 = csrsrc[i + 3];
        float n0 = dinv[s0] * dd, n1 = dinv[s1] * dd;
        float n2 = dinv[s2] * dd, n3 = dinv[s3] * dd;
        uint2 r0 = *((const uint2*)(h + (size_t)s0 * 256) + tid);
        uint2 r1 = *((const uint2*)(h + (size_t)s1 * 256) + tid);
        uint2 r2 = *((const uint2*)(h + (size_t)s2 * 256) + tid);
        uint2 r3 = *((const uint2*)(h + (size_t)s3 * 256) + tid);
        float2 f0a = __half22float2(*(__half2*)&r0.x);
        float2 f0b = __half22float2(*(__half2*)&r0.y);
        float2 f1a = __half22float2(*(__half2*)&r1.x);
        float2 f1b = __half22float2(*(__half2*)&r1.y);
        float2 f2a = __half22float2(*(__half2*)&r2.x);
        float2 f2b = __half22float2(*(__half2*)&r2.y);
        float2 f3a = __half22float2(*(__half2*)&r3.x);
        float2 f3b = __half22float2(*(__half2*)&r3.y);
        acc.x = fmaf(n0, f0a.x, acc.x); acc.y = fmaf(n0, f0a.y, acc.y);
        acc.z = fmaf(n0, f0b.x, acc.z); acc.w = fmaf(n0, f0b.y, acc.w);
        acc.x = fmaf(n1, f1a.x, acc.x); acc.y = fmaf(n1, f1a.y, acc.y);
        acc.z = fmaf(n1, f1b.x, acc.z); acc.w = fmaf(n1, f1b.y, acc.w);
        acc.x = fmaf(n2, f2a.x, acc.x); acc.y = fmaf(n2, f2a.y, acc.y);
        acc.z = fmaf(n2, f2b.x, acc.z); acc.w = fmaf(n2, f2b.y, acc.w);
        acc.x = fmaf(n3, f3a.x, acc.x); acc.y = fmaf(n3, f3a.y, acc.y);
        acc.z = fmaf(n3, f3b.x, acc.z); acc.w = fmaf(n3, f3b.y, acc.w);
    }
    for (; i < end; i++) {
        int s = csrsrc[i];
        float nrm = dinv[s] * dd;
        uint2 rr = *((const uint2*)(h + (size_t)s * 256) + tid);
        float2 fa = __half22float2(*(__half2*)&rr.x);
        float2 fb = __half22float2(*(__half2*)&rr.y);
        acc.x = fmaf(nrm, fa.x, acc.x);
        acc.y = fmaf(nrm, fa.y, acc.y);
        acc.z = fmaf(nrm, fb.x, acc.z);
        acc.w = fmaf(nrm, fb.y, acc.w);
    }
    uint2 ov;
    __half2 o0 = __floats2half2_rn(acc.x, acc.y);
    __half2 o1 = __floats2half2_rn(acc.z, acc.w);
    ov.x = *(uint32_t*)&o0;
    ov.y = *(uint32_t*)&o1;
    *((uint2*)(out + (size_t)d * 256) + tid) = ov;
}

// ---------------- BatchNorm -------------------------------------------------
__global__ void bn_stats(const float* __restrict__ x, int rows, int K,
                         float* __restrict__ sum, float* __restrict__ sq)
{
    int col = blockIdx.x * blockDim.x + threadIdx.x;
    float s = 0.f, q = 0.f;
    for (int r = blockIdx.y; r < rows; r += gridDim.y) {
        float v = x[(size_t)r * K + col];
        s += v;
        q += v * v;
    }
    atomicAdd(sum + col, s);
    atomicAdd(sq + col, q);
}

__global__ void bn_stats_h4(const __half* __restrict__ x, int rows, int K,
                            float* __restrict__ sum, float* __restrict__ sq)
{
    int c0 = (blockIdx.x * blockDim.x + threadIdx.x) * 4;
    if (c0 >= K) return;
    float s0 = 0.f, s1 = 0.f, s2 = 0.f, s3 = 0.f;
    float q0 = 0.f, q1 = 0.f, q2 = 0.f, q3 = 0.f;
    for (int r = blockIdx.y; r < rows; r += gridDim.y) {
        uint2 v = *(const uint2*)(x + (size_t)r * K + c0);
        float2 a = __half22float2(*(__half2*)&v.x);
        float2 b = __half22float2(*(__half2*)&v.y);
        s0 += a.x; q0 += a.x * a.x;
        s1 += a.y; q1 += a.y * a.y;
        s2 += b.x; q2 += b.x * b.x;
        s3 += b.y; q3 += b.y * b.y;
    }
    atomicAdd(sum + c0 + 0, s0); atomicAdd(sq + c0 + 0, q0);
    atomicAdd(sum + c0 + 1, s1); atomicAdd(sq + c0 + 1, q1);
    atomicAdd(sum + c0 + 2, s2); atomicAdd(sq + c0 + 2, q2);
    atomicAdd(sum + c0 + 3, s3); atomicAdd(sq + c0 + 3, q3);
}

__global__ void bn_finalize(const float* __restrict__ sum, const float* __restrict__ sq,
                            const float* __restrict__ g, const float* __restrict__ b,
                            int rows, int K, float* __restrict__ scale,
                            float* __restrict__ shift)
{
    int c = blockIdx.x * blockDim.x + threadIdx.x;
    if (c >= K) return;
    float inv_n = 1.0f / (float)rows;
    float mu = sum[c] * inv_n;
    float var = sq[c] * inv_n - mu * mu;
    float sc = g[c] * rsqrtf(var + 1e-5f);
    scale[c] = sc;
    shift[c] = b[c] - mu * sc;
}

// ---------------- Pooling (fp16 input; batch sorted, no atomics) -------------
__global__ __launch_bounds__(256) void pool_graph_h(
    const __half* __restrict__ h, const int* __restrict__ gstart,
    const float* __restrict__ scale, const float* __restrict__ shift,
    float* __restrict__ z)
{
    int g = blockIdx.x;
    int c = threadIdx.x;
    int beg = gstart[g], end = gstart[g + 1];
    float sc = scale[c], sh = shift[c];
    float sum = 0.f, mx = 0.f;
    for (int r = beg; r < end; r++) {
        float hv = __half2float(h[(size_t)r * 256 + c]);
        float v = fmaxf(fmaf(hv, sc, sh), 0.f);
        sum += v;
        mx = fmaxf(mx, v);
    }
    float cnt = (float)(end - beg);
    z[(size_t)g * 640 + c] = sum / fmaxf(cnt, 1.0f);
    z[(size_t)g * 640 + 256 + c] = mx;
}

// ---------------- Head (BN+relu fused in) ------------------------------------
__global__ void head_final(const float* __restrict__ zf,
                           const float* __restrict__ scale,
                           const float* __restrict__ shift,
                           const float* __restrict__ Wf2,
                           const float* __restrict__ bf2, float* __restrict__ out)
{
    int g = blockIdx.x;
    int t = threadIdx.x;
    float v = fmaxf(fmaf(zf[(size_t)g * 128 + t], scale[t], shift[t]), 0.f) * Wf2[t];
#pragma unroll
    for (int o = 16; o; o >>= 1) v += __shfl_down_sync(0xFFFFFFFFu, v, o);
    __shared__ float sm[4];
    if ((t & 31) == 0) sm[t >> 5] = v;
    __syncthreads();
    if (t == 0) {
        float s = sm[0] + sm[1] + sm[2] + sm[3] + bf2[0];
        out[g] = 1.0f / (1.0f + expf(-s));
    }
}

// ---------------- launch ------------------------------------------------------
extern "C" void kernel_launch(void* const* d_in, const int* in_sizes, int n_in,
                              void* d_out, int out_size)
{
    const float* x    = (const float*)d_in[0];
    const int*   ei   = (const int*)d_in[1];
    const int*   batch= (const int*)d_in[2];
    const float* fp   = (const float*)d_in[3];
    const float* W1   = (const float*)d_in[4];
    const float* a1s  = (const float*)d_in[5];
    const float* a1d  = (const float*)d_in[6];
    const float* bn1g = (const float*)d_in[8];
    const float* bn1b = (const float*)d_in[9];
    const float* W2   = (const float*)d_in[10];
    const float* a2s  = (const float*)d_in[11];
    const float* a2d  = (const float*)d_in[12];
    const float* bn2g = (const float*)d_in[14];
    const float* bn2b = (const float*)d_in[15];
    const float* Wg   = (const float*)d_in[16];
    const float* bn3g = (const float*)d_in[18];
    const float* bn3b = (const float*)d_in[19];
    const float* Ws   = (const float*)d_in[20];
    const float* bs   = (const float*)d_in[21];
    const float* Wf1  = (const float*)d_in[22];
    const float* bnfg = (const float*)d_in[24];
    const float* bnfb = (const float*)d_in[25];
    const float* Wf2  = (const float*)d_in[26];
    const float* bf2  = (const float*)d_in[27];
    float* out = (float*)d_out;

    int n    = in_sizes[0] / 64;
    int E    = in_sizes[1] / 2;
    int Etot = E + n;
    int G    = in_sizes[3] / 128;

    float *bufA, *bufB, *bufC, *al2, *alpha, *dinv, *uu, *vv;
    float *bnacc, *bnscale, *bnshift, *z, *zf;
    __half *w1p, *w2p, *wgp;
    int *degi, *incl, *part, *rowptr, *cursor, *csrsrc, *gstart;
    cudaGetSymbolAddress((void**)&bufA, g_bufA);
    cudaGetSymbolAddress((void**)&bufB, g_bufB);
    cudaGetSymbolAddress((void**)&bufC, g_bufC);
    cudaGetSymbolAddress((void**)&w1p, g_w1p);
    cudaGetSymbolAddress((void**)&w2p, g_w2p);
    cudaGetSymbolAddress((void**)&wgp, g_wgp);
    cudaGetSymbolAddress((void**)&al2, g_al2);
    cudaGetSymbolAddress((void**)&alpha, g_alpha);
    cudaGetSymbolAddress((void**)&uu, g_u);
    cudaGetSymbolAddress((void**)&vv, g_v);
    cudaGetSymbolAddress((void**)&degi, g_degi);
    cudaGetSymbolAddress((void**)&incl, g_incl);
    cudaGetSymbolAddress((void**)&part, g_part);
    cudaGetSymbolAddress((void**)&rowptr, g_rowptr);
    cudaGetSymbolAddress((void**)&cursor, g_cursor);
    cudaGetSymbolAddress((void**)&csrsrc, g_csrsrc);
    cudaGetSymbolAddress((void**)&dinv, g_dinv);
    cudaGetSymbolAddress((void**)&gstart, g_gstart);
    cudaGetSymbolAddress((void**)&bnacc, g_bnacc);
    cudaGetSymbolAddress((void**)&bnscale, g_bnscale);
    cudaGetSymbolAddress((void**)&bnshift, g_bnshift);
    cudaGetSymbolAddress((void**)&z, g_z);
    cudaGetSymbolAddress((void**)&zf, g_zf);

    float* alS = al2;
    float* alD = al2 + (size_t)NMAXN * 4;
    float* bnsum = bnacc;
    float* bnsq  = bnacc + 1024;

    __half* bufA_h = (__half*)bufA;
    __half* bufB_h = (__half*)bufB;
    __half* bufC_h = (__half*)bufC;

    size_t tf_smem = SMEM_FLOATS * sizeof(float);
    static bool attr_done = false;
    if (!attr_done) {
        cudaFuncSetAttribute(tf32gemm,
                             cudaFuncAttributeMaxDynamicSharedMemorySize, (int)tf_smem);
        cudaFuncSetAttribute(hgemm<false, false, true, true, 128>,
                             cudaFuncAttributeMaxDynamicSharedMemorySize, H_SMEM(128));
        cudaFuncSetAttribute(hgemm<true, true, false, true, 256>,
                             cudaFuncAttributeMaxDynamicSharedMemorySize, H_SMEM(256));
        cudaFuncSetAttribute(hgemm<true, false, false, true, 256>,
                             cudaFuncAttributeMaxDynamicSharedMemorySize, H_SMEM(256));
        attr_done = true;
    }

    auto bnstats_h = [&](const __half* Xp, int rows, int K, const float* gg,
                         const float* bb) {
        cudaMemsetAsync(bnacc, 0, 2048 * sizeof(float));
        dim3 g1((K / 4 + 127) / 128, 256);
        bn_stats_h4<<<g1, 128>>>(Xp, rows, K, bnsum, bnsq);
        bn_finalize<<<(K + 127) / 128, 128>>>(bnsum, bnsq, gg, bb, rows, K,
                                              bnscale, bnshift);
    };

    // ---- CSR build + graph boundaries + weight packing (independent)
    cudaMemsetAsync(degi, 0, n * sizeof(int));
    deg_build<<<(Etot + 255) / 256, 256>>>(ei, E, Etot, degi);
    int nb = (n + 1023) / 1024;
    scan_partial<<<nb, 1024>>>(degi, n, incl, part);
    scan_roots<<<1, 128>>>(part, nb);
    scan_add<<<(n + 255) / 256, 256>>>(incl, degi, part, n, Etot,
                                       rowptr, cursor, dinv);
    csr_scatter<<<(Etot + 255) / 256, 256>>>(ei, E, Etot, cursor, csrsrc);
    gstart_build<<<(n + 256) / 256, 256>>>(batch, n, G, gstart);
    {
        int total = 64 * 512 + 512 * 1024 + 1024 * 256;
        pack_all<<<(total + 255) / 256, 256>>>(W1, W2, Wg, w1p, w2p, wgp);
    }

    // ---- GAT layer 1 (input-space): exact fp32 alphas; per-edge softmax;
    //      gather x -> fp16; hgemm (head-grouped, BN=128 tiles)
    uv_build<<<(64 * 4 * 32 + 255) / 256, 256>>>(W1, a1s, a1d, 64, 128, uu, vv);
    alpha_gemm64<<<(n + 7) / 8, 256>>>(x, n, uu, vv, alS, alD);
    alpha_edges<<<(n + 7) / 8, 256>>>(rowptr, csrsrc, alS, alD, n, alpha);
    gat_agg_in64<<<n, 64>>>(rowptr, csrsrc, alpha, x, bufA_h);
    {
        dim3 grid(4, (n + 127) / 128);
        hgemm<false, false, true, true, 128><<<grid, 256, H_SMEM(128)>>>(
            bufA_h, w1p, bufB_h, n, 512, 64, 256, 512,
            nullptr, nullptr, nullptr, nullptr, 128, nullptr, nullptr);
    }
    bnstats_h(bufB_h, n, 512, bn1g, bn1b);

    // ---- GAT layer 2: bufC_h = relu(bn(bufB_h))@W2 (+ fused logit partials,
    //      wide 256 tiles); per-edge softmax; gather -> bufA_h
    cudaMemsetAsync(al2, 0, (size_t)2 * NMAXN * 4 * sizeof(float));
    {
        dim3 grid(4, (n + 127) / 128);
        hgemm<true, true, false, true, 256><<<grid, 512, H_SMEM(256)>>>(
            bufB_h, w2p, bufC_h, n, 1024, 512, 512, 1024,
            bnscale, bnshift, a2s, a2d, 256, alS, alD);
    }
    alpha_edges<<<(n + 7) / 8, 256>>>(rowptr, csrsrc, alS, alD, n, alpha);
    {
        dim3 grid(n, 2);
        gat_gather_h<1024, 2><<<grid, 128>>>(rowptr, csrsrc, alpha, bufC_h, bufA_h);
    }
    bnstats_h(bufA_h, n, 1024, bn2g, bn2b);

    // ---- GCN: bufB_h = relu(bn(bufA_h))@Wg (wide); gather -> bufC_h; BN stats
    {
        dim3 grid(1, (n + 127) / 128);
        hgemm<true, false, false, true, 256><<<grid, 512, H_SMEM(256)>>>(
            bufA_h, wgp, bufB_h, n, 256, 1024, 1024, 256,
            bnscale, bnshift, nullptr, nullptr, 256, nullptr, nullptr);
    }
    gcn_gather_h<<<n, 64>>>(rowptr, csrsrc, dinv, bufB_h, bufC_h);
    bnstats_h(bufC_h, n, 256, bn3g, bn3b);

    // ---- Pooling into z[G,640] (block per graph; BN+relu on the fly)
    pool_graph_h<<<G, 256>>>(bufC_h, gstart, bnscale, bnshift, z);

    // ---- solvent MLP: relu(fp @ Ws + bs) -> z[:,512:640]
    {
        dim3 grid(1, (G + 127) / 128);
        sgemm<true><<<grid, 256>>>(fp, Ws, bs, z + 512, G, 128, 128, 128, 640);
    }

    // ---- head: zf = z @ Wf1 via tf32 (bf1 cancels under BN); BN stats;
    //      BN+relu fused into final dot+sigmoid
    {
        dim3 grid(1, (G + 127) / 128);
        tf32gemm<<<grid, 256, tf_smem>>>(z, Wf1, zf, G, 128, 640, 640, 128, 128);
    }
    {
        cudaMemsetAsync(bnacc, 0, 2048 * sizeof(float));
        dim3 g1(1, 128);
        bn_stats<<<g1, 128>>>(zf, G, 128, bnsum, bnsq);
        bn_finalize<<<1, 128>>>(bnsum, bnsq, bnfg, bnfb, G, 128, bnscale, bnshift);
    }
    head_final<<<G, 128>>>(zf, bnscale, bnshift, Wf2, bf2, out);
}

// round 17
// speedup vs baseline: 1.6792x; 1.0034x over previous
#include <cuda_runtime.h>
#include <cuda_fp16.h>
#include <math.h>
#include <stdint.h>

// Problem capacities (fixed shapes per reference)
#define NMAXN 50000
#define EMAXE 200000
#define ETOTMAX (EMAXE + NMAXN)
#define GMAXG 1000

// ---------------- scratch (static device memory; no allocations allowed) ----
__device__ float g_bufA[(size_t)NMAXN * 1024];
__device__ float g_bufB[(size_t)NMAXN * 1024];
__device__ float g_bufC[(size_t)NMAXN * 1024];
__device__ __half g_w1p[64 * 512];
__device__ __half g_w2p[512 * 1024];
__device__ __half g_wgp[1024 * 256];
__device__ float g_al2[2 * NMAXN * 4];          // alS | alD (contiguous)
__device__ float g_alpha[(size_t)ETOTMAX * 4];
__device__ float g_u[512 * 4];
__device__ float g_v[512 * 4];
__device__ int   g_degi[NMAXN];
__device__ int   g_incl[NMAXN];
__device__ int   g_part[128];
__device__ int   g_rowptr[NMAXN + 1];
__device__ int   g_cursor[NMAXN];
__device__ int   g_csrsrc[ETOTMAX];
__device__ float g_dinv[NMAXN];
__device__ int   g_gstart[GMAXG + 1];
__device__ float g_bnacc[2048];                 // sum[0:1024) | sq[1024:2048)
__device__ float g_bnscale[1024];
__device__ float g_bnshift[1024];
__device__ float g_z[GMAXG * 640];
__device__ float g_zf[GMAXG * 128];

// ---------------- CSR build -------------------------------------------------
__global__ void deg_build(const int* __restrict__ ei, int E, int Etot,
                          int* __restrict__ degi)
{
    int e = blockIdx.x * blockDim.x + threadIdx.x;
    if (e >= Etot) return;
    int d = (e < E) ? ei[E + e] : (e - E);
    atomicAdd(degi + d, 1);
}

__global__ __launch_bounds__(1024) void scan_partial(
    const int* __restrict__ degi, int n, int* __restrict__ incl,
    int* __restrict__ part)
{
    __shared__ int sm[32];
    int tid = threadIdx.x;
    int lane = tid & 31, w = tid >> 5;
    int i = blockIdx.x * 1024 + tid;
    int v = (i < n) ? degi[i] : 0;
    int x = v;
#pragma unroll
    for (int o = 1; o < 32; o <<= 1) {
        int y = __shfl_up_sync(0xFFFFFFFFu, x, o);
        if (lane >= o) x += y;
    }
    if (lane == 31) sm[w] = x;
    __syncthreads();
    if (w == 0) {
        int y = sm[lane];
#pragma unroll
        for (int o = 1; o < 32; o <<= 1) {
            int z = __shfl_up_sync(0xFFFFFFFFu, y, o);
            if (lane >= o) y += z;
        }
        sm[lane] = y;
    }
    __syncthreads();
    int inclv = x + (w ? sm[w - 1] : 0);
    if (i < n) incl[i] = inclv;
    if (tid == 1023) part[blockIdx.x] = inclv;
}

__global__ void scan_roots(int* __restrict__ part, int nb)
{
    __shared__ int sm[128];
    int t = threadIdx.x;
    sm[t] = (t < nb) ? part[t] : 0;
    __syncthreads();
    if (t == 0) {
        int run = 0;
        for (int i = 0; i < nb; i++) { int v = sm[i]; sm[i] = run; run += v; }
    }
    __syncthreads();
    if (t < nb) part[t] = sm[t];
}

__global__ void scan_add(const int* __restrict__ incl, const int* __restrict__ degi,
                         const int* __restrict__ part, int n, int Etot,
                         int* __restrict__ rowptr, int* __restrict__ cursor,
                         float* __restrict__ dinv)
{
    int i = blockIdx.x * blockDim.x + threadIdx.x;
    if (i == 0) rowptr[n] = Etot;
    if (i >= n) return;
    int dg = degi[i];
    int exc = incl[i] + part[i >> 10] - dg;
    rowptr[i] = exc;
    cursor[i] = exc;
    dinv[i] = rsqrtf(fmaxf((float)dg, 1.0f));
}

__global__ void csr_scatter(const int* __restrict__ ei, int E, int Etot,
                            int* __restrict__ cursor, int* __restrict__ csrsrc)
{
    int e = blockIdx.x * blockDim.x + threadIdx.x;
    if (e >= Etot) return;
    int s, d;
    if (e < E) { s = ei[e]; d = ei[E + e]; }
    else       { s = e - E; d = e - E; }
    int pos = atomicAdd(cursor + d, 1);
    csrsrc[pos] = s;
}

__global__ void gstart_build(const int* __restrict__ batch, int n, int G,
                             int* __restrict__ gstart)
{
    int i = blockIdx.x * blockDim.x + threadIdx.x;
    if (i < n) {
        int b = batch[i];
        int bp = (i > 0) ? batch[i - 1] : -1;
        for (int g = bp + 1; g <= b; g++) gstart[g] = i;
    } else if (i == n) {
        int bl = batch[n - 1];
        for (int g = bl + 1; g <= G; g++) gstart[g] = n;
    }
}

// ---------------- weight packing (all three weights, one launch) -------------
__device__ __forceinline__ void pack_one(const float* __restrict__ W, int Nc, int i,
                                         __half* __restrict__ Wp)
{
    int k = i / Nc, nn = i % Nc;
    Wp[(size_t)(k >> 1) * 2 * Nc + 2 * nn + (k & 1)] = __float2half_rn(W[i]);
}

__global__ void pack_all(const float* __restrict__ W1, const float* __restrict__ W2,
                         const float* __restrict__ Wg,
                         __half* __restrict__ w1p, __half* __restrict__ w2p,
                         __half* __restrict__ wgp)
{
    const int S1 = 64 * 512, S2 = 512 * 1024, S3 = 1024 * 256;
    int i = blockIdx.x * blockDim.x + threadIdx.x;
    if (i < S1) pack_one(W1, 512, i, w1p);
    else if (i < S1 + S2) pack_one(W2, 1024, i - S1, w2p);
    else if (i < S1 + S2 + S3) pack_one(Wg, 256, i - S1 - S2, wgp);
}

// ---------------- u/v vectors: u[k,h] = sum_c W[k,hC+c]*a[h,c] ---------------
__global__ void uv_build(const float* __restrict__ W, const float* __restrict__ aS,
                         const float* __restrict__ aD, int K, int C,
                         float* __restrict__ u, float* __restrict__ v)
{
    int idx = blockIdx.x * blockDim.x + threadIdx.x;
    int warp = idx >> 5, lane = idx & 31;
    if (warp >= K * 4) return;
    int k = warp >> 2, h = warp & 3;
    const float* wrow = W + (size_t)k * (4 * C) + h * C;
    const float* as = aS + h * C;
    const float* ad = aD + h * C;
    float s = 0.f, d = 0.f;
    for (int c = lane; c < C; c += 32) {
        float wv = wrow[c];
        s += wv * as[c];
        d += wv * ad[c];
    }
#pragma unroll
    for (int o = 16; o; o >>= 1) {
        s += __shfl_xor_sync(0xFFFFFFFFu, s, o);
        d += __shfl_xor_sync(0xFFFFFFFFu, d, o);
    }
    if (lane == 0) { u[k * 4 + h] = s; v[k * 4 + h] = d; }
}

// ---------------- skinny alpha GEMM (layer 1, K=64, fp32 exact) --------------
__global__ __launch_bounds__(256) void alpha_gemm64(
    const float* __restrict__ in, int n,
    const float* __restrict__ u, const float* __restrict__ v,
    float* __restrict__ alS, float* __restrict__ alD)
{
    __shared__ float su[64][4];
    __shared__ float sv[64][4];
    int tid = threadIdx.x;
    if (tid < 64 * 4) { su[tid >> 2][tid & 3] = u[tid]; sv[tid >> 2][tid & 3] = v[tid]; }
    __syncthreads();

    int warp = tid >> 5, lane = tid & 31;
    for (int node = blockIdx.x * 8 + warp; node < n; node += gridDim.x * 8) {
        const float* row = in + (size_t)node * 64;
        float x0 = row[lane], x1 = row[lane + 32];
        float as[4], ad[4];
#pragma unroll
        for (int h = 0; h < 4; h++) {
            as[h] = x0 * su[lane][h] + x1 * su[lane + 32][h];
            ad[h] = x0 * sv[lane][h] + x1 * sv[lane + 32][h];
        }
#pragma unroll
        for (int h = 0; h < 4; h++) {
#pragma unroll
            for (int o = 16; o; o >>= 1) {
                as[h] += __shfl_xor_sync(0xFFFFFFFFu, as[h], o);
                ad[h] += __shfl_xor_sync(0xFFFFFFFFu, ad[h], o);
            }
        }
        if (lane == 0) {
            *(float4*)(alS + (size_t)node * 4) = make_float4(as[0], as[1], as[2], as[3]);
            *(float4*)(alD + (size_t)node * 4) = make_float4(ad[0], ad[1], ad[2], ad[3]);
        }
    }
}

// ---------------- per-edge softmax weights (one warp per destination) --------
__global__ __launch_bounds__(256) void alpha_edges(
    const int* __restrict__ rowptr, const int* __restrict__ csrsrc,
    const float* __restrict__ alS, const float* __restrict__ alD, int n,
    float* __restrict__ alpha)
{
    int warp = (blockIdx.x * blockDim.x + threadIdx.x) >> 5;
    int lane = threadIdx.x & 31;
    if (warp >= n) return;
    int d = warp;
    int beg = rowptr[d], end = rowptr[d + 1];

    float4 ad4 = *(const float4*)(alD + (size_t)d * 4);
    float adv[4] = {ad4.x, ad4.y, ad4.z, ad4.w};

    float mx[4] = {-INFINITY, -INFINITY, -INFINITY, -INFINITY};
    for (int i = beg + lane; i < end; i += 32) {
        int s = csrsrc[i];
        float4 as4 = *(const float4*)(alS + (size_t)s * 4);
        float l[4] = {as4.x + adv[0], as4.y + adv[1], as4.z + adv[2], as4.w + adv[3]};
#pragma unroll
        for (int h = 0; h < 4; h++) {
            float t = l[h];
            t = t > 0.f ? t : 0.2f * t;
            mx[h] = fmaxf(mx[h], t);
        }
    }
#pragma unroll
    for (int h = 0; h < 4; h++)
#pragma unroll
        for (int o = 16; o; o >>= 1)
            mx[h] = fmaxf(mx[h], __shfl_xor_sync(0xFFFFFFFFu, mx[h], o));

    float sme[4] = {0.f, 0.f, 0.f, 0.f};
    for (int i = beg + lane; i < end; i += 32) {
        int s = csrsrc[i];
        float4 as4 = *(const float4*)(alS + (size_t)s * 4);
        float l[4] = {as4.x + adv[0], as4.y + adv[1], as4.z + adv[2], as4.w + adv[3]};
#pragma unroll
        for (int h = 0; h < 4; h++) {
            float t = l[h];
            t = t > 0.f ? t : 0.2f * t;
            sme[h] += expf(t - mx[h]);
        }
    }
#pragma unroll
    for (int h = 0; h < 4; h++)
#pragma unroll
        for (int o = 16; o; o >>= 1)
            sme[h] += __shfl_xor_sync(0xFFFFFFFFu, sme[h], o);

    float binv[4];
#pragma unroll
    for (int h = 0; h < 4; h++) binv[h] = 1.0f / fmaxf(sme[h], 1e-16f);

    for (int i = beg + lane; i < end; i += 32) {
        int s = csrsrc[i];
        float4 as4 = *(const float4*)(alS + (size_t)s * 4);
        float l[4] = {as4.x + adv[0], as4.y + adv[1], as4.z + adv[2], as4.w + adv[3]};
        float4 av;
        float t0 = l[0] > 0.f ? l[0] : 0.2f * l[0];
        float t1 = l[1] > 0.f ? l[1] : 0.2f * l[1];
        float t2 = l[2] > 0.f ? l[2] : 0.2f * l[2];
        float t3 = l[3] > 0.f ? l[3] : 0.2f * l[3];
        av.x = expf(t0 - mx[0]) * binv[0];
        av.y = expf(t1 - mx[1]) * binv[1];
        av.z = expf(t2 - mx[2]) * binv[2];
        av.w = expf(t3 - mx[3]) * binv[3];
        *(float4*)(alpha + (size_t)i * 4) = av;
    }
}

// ---------------- FP16 tensor-core GEMM (ldmatrix A, k-tile 64) --------------
// BN in {128, 256}; NSTAGE in {2, 3}. 128: 256 thr, 2 blk/SM. 256: 512 thr, 1 blk/SM.
__device__ __forceinline__ void mma_f16(float c[4], const uint32_t a[4],
                                        uint32_t b0, uint32_t b1) {
    asm volatile(
        "mma.sync.aligned.m16n8k16.row.col.f32.f16.f16.f32 "
        "{%0,%1,%2,%3}, {%4,%5,%6,%7}, {%8,%9}, {%0,%1,%2,%3};"
        : "+f"(c[0]), "+f"(c[1]), "+f"(c[2]), "+f"(c[3])
        : "r"(a[0]), "r"(a[1]), "r"(a[2]), "r"(a[3]), "r"(b0), "r"(b1));
}

__device__ __forceinline__ void ldmatrix_x4(uint32_t a[4], uint32_t saddr) {
    asm volatile(
        "ldmatrix.sync.aligned.m8n8.x4.shared.b16 {%0,%1,%2,%3}, [%4];"
        : "=r"(a[0]), "=r"(a[1]), "=r"(a[2]), "=r"(a[3]) : "r"(saddr));
}

__device__ __forceinline__ void cp_async16(void* smem_dst, const void* gmem_src,
                                           bool pred) {
    uint32_t saddr = (uint32_t)__cvta_generic_to_shared(smem_dst);
    int sz = pred ? 16 : 0;
    asm volatile("cp.async.cg.shared.global [%0], [%1], 16, %2;\n"
                 :: "r"(saddr), "l"(gmem_src), "r"(sz));
}

__device__ __forceinline__ uint32_t bnrelu_h2(uint32_t v, float2 sc, float2 sh) {
    float2 f = __half22float2(*(__half2*)&v);
    f.x = fmaxf(fmaf(f.x, sc.x, sh.x), 0.f);
    f.y = fmaxf(fmaf(f.y, sc.y, sh.y), 0.f);
    __half2 h = __floats2half2_rn(f.x, f.y);
    return *(uint32_t*)&h;
}

#define H_ASTG 18432
#define H_BSTG(BN) (32 * ((BN) + 8) * 4)
#define H_STG(BN) (H_ASTG + H_BSTG(BN))
#define H_SMEM(BN, NS) ((NS) * H_STG(BN))

template <bool BNRELU, bool ALPHA, bool GROUP, bool HALFOUT, int BN, int NSTAGE>
__global__ __launch_bounds__(BN * 2, (BN == 128) ? 2 : 1) void hgemm(
    const __half* __restrict__ A, const __half* __restrict__ Bp,
    void* __restrict__ Cout, int M, int Nc, int K, int lda, int ldc,
    const float* __restrict__ scale, const float* __restrict__ shift,
    const float* __restrict__ aS, const float* __restrict__ aD, int Chead,
    float* __restrict__ alS, float* __restrict__ alD)
{
    extern __shared__ char smem[];
    constexpr int THREADS = BN * 2;
    constexpr int NWN = BN / 32;
    constexpr int P2 = BN + 8;
    constexpr int STG = H_STG(BN);
    constexpr int CHROW = BN / 4;

    int tid = threadIdx.x;
    int lane = tid & 31;
    int wid = tid >> 5;
    int warpM = (wid / NWN) * 64;
    int warpN = (wid % NWN) * 32;
    int r = lane >> 2;
    int cq = lane & 3;

    int blockM = blockIdx.y * 128;
    int blockN = blockIdx.x * BN;

    if (GROUP) A += (size_t)(blockN >> 7) * K;

    float acc[4][4][4];
#pragma unroll
    for (int mt = 0; mt < 4; mt++)
#pragma unroll
        for (int nt = 0; nt < 4; nt++)
#pragma unroll
            for (int i = 0; i < 4; i++) acc[mt][nt][i] = 0.0f;

    int nk = K >> 6;

    uint32_t aoff = (uint32_t)(warpM + (lane & 15)) * 144 + (uint32_t)(lane >> 4) * 16;

    auto load_tile = [&](int kt, int buf) {
        char* As = smem + (size_t)buf * STG;
        char* Bs = As + H_ASTG;
#pragma unroll
        for (int i = 0; i < 1024 / THREADS; i++) {
            int row = (tid >> 3) + i * (THREADS / 8);
            int grow = blockM + row;
            cp_async16(As + (size_t)row * 144 + (tid & 7) * 16,
                       A + (size_t)grow * lda + kt * 64 + (tid & 7) * 8,
                       grow < M);
        }
#pragma unroll
        for (int i = 0; i < 4; i++) {
            int c = tid + i * THREADS;
            int krow = c / CHROW;
            int ncd = (c % CHROW) * 4;
            cp_async16(Bs + ((size_t)krow * P2 + ncd) * 4,
                       Bp + (size_t)(kt * 32 + krow) * 2 * Nc + 2 * blockN + ncd * 2,
                       true);
        }
        asm volatile("cp.async.commit_group;\n");
    };

    load_tile(0, 0);
    if (NSTAGE >= 3 && nk > 1) load_tile(1, 1);

    for (int kt = 0; kt < nk; kt++) {
        if (NSTAGE == 2) {
            if (kt + 1 < nk) {
                load_tile(kt + 1, (kt + 1) % NSTAGE);
                asm volatile("cp.async.wait_group 1;\n");
            } else {
                asm volatile("cp.async.wait_group 0;\n");
            }
            __syncthreads();
        } else {
            if (kt + 1 < nk) asm volatile("cp.async.wait_group 1;\n");
            else             asm volatile("cp.async.wait_group 0;\n");
            __syncthreads();
            if (kt + 2 < nk) load_tile(kt + 2, (kt + 2) % NSTAGE);
        }

        const char* Asb = smem + (size_t)(kt % NSTAGE) * STG;
        uint32_t abase = (uint32_t)__cvta_generic_to_shared(Asb) + aoff;
        const uint32_t* Bs2 = (const uint32_t*)(Asb + H_ASTG);

#pragma unroll
        for (int ks = 0; ks < 4; ks++) {
            int kb2 = ks * 8;
            float2 sc01, sh01, sc23, sh23;
            if (BNRELU) {
                int kg = kt * 64 + ks * 16 + 2 * cq;
                sc01 = *(const float2*)(scale + kg);
                sh01 = *(const float2*)(shift + kg);
                sc23 = *(const float2*)(scale + kg + 8);
                sh23 = *(const float2*)(shift + kg + 8);
            }
            uint32_t a[4][4], b[4][2];
#pragma unroll
            for (int mt = 0; mt < 4; mt++) {
                ldmatrix_x4(a[mt], abase + (uint32_t)mt * 16 * 144 + (uint32_t)ks * 32);
                if (BNRELU) {
                    a[mt][0] = bnrelu_h2(a[mt][0], sc01, sh01);
                    a[mt][1] = bnrelu_h2(a[mt][1], sc01, sh01);
                    a[mt][2] = bnrelu_h2(a[mt][2], sc23, sh23);
                    a[mt][3] = bnrelu_h2(a[mt][3], sc23, sh23);
                }
            }
#pragma unroll
            for (int nt = 0; nt < 4; nt++) {
                int nn = warpN + nt * 8 + r;
                b[nt][0] = Bs2[(kb2 + cq) * P2 + nn];
                b[nt][1] = Bs2[(kb2 + cq + 4) * P2 + nn];
            }
#pragma unroll
            for (int mt = 0; mt < 4; mt++)
#pragma unroll
                for (int nt = 0; nt < 4; nt++)
                    mma_f16(acc[mt][nt], a[mt], b[nt][0], b[nt][1]);
        }
        if (NSTAGE == 2 || kt + 1 < nk) __syncthreads();
    }

#pragma unroll
    for (int mt = 0; mt < 4; mt++) {
        int row0 = blockM + warpM + mt * 16 + r;
#pragma unroll
        for (int nt = 0; nt < 4; nt++) {
            int col = blockN + warpN + nt * 8 + cq * 2;
            if (HALFOUT) {
                __half2* Ch = (__half2*)Cout;
                if (row0 < M)
                    Ch[((size_t)row0 * ldc + col) >> 1] =
                        __floats2half2_rn(acc[mt][nt][0], acc[mt][nt][1]);
                if (row0 + 8 < M)
                    Ch[((size_t)(row0 + 8) * ldc + col) >> 1] =
                        __floats2half2_rn(acc[mt][nt][2], acc[mt][nt][3]);
            } else {
                float* C = (float*)Cout;
                if (row0 < M)
                    *(float2*)(C + (size_t)row0 * ldc + col) =
                        make_float2(acc[mt][nt][0], acc[mt][nt][1]);
                if (row0 + 8 < M)
                    *(float2*)(C + (size_t)(row0 + 8) * ldc + col) =
                        make_float2(acc[mt][nt][2], acc[mt][nt][3]);
            }
        }
    }

    if (ALPHA) {
        int head = blockN / Chead;
        float ws[4][2], wd[4][2];
#pragma unroll
        for (int nt = 0; nt < 4; nt++) {
            int col = blockN + warpN + nt * 8 + cq * 2;
            int c = col - head * Chead;
            ws[nt][0] = aS[head * Chead + c];
            ws[nt][1] = aS[head * Chead + c + 1];
            wd[nt][0] = aD[head * Chead + c];
            wd[nt][1] = aD[head * Chead + c + 1];
        }
#pragma unroll
        for (int mt = 0; mt < 4; mt++) {
            float ps0 = 0.f, pd0 = 0.f, ps1 = 0.f, pd1 = 0.f;
#pragma unroll
            for (int nt = 0; nt < 4; nt++) {
                ps0 += acc[mt][nt][0] * ws[nt][0] + acc[mt][nt][1] * ws[nt][1];
                pd0 += acc[mt][nt][0] * wd[nt][0] + acc[mt][nt][1] * wd[nt][1];
                ps1 += acc[mt][nt][2] * ws[nt][0] + acc[mt][nt][3] * ws[nt][1];
                pd1 += acc[mt][nt][2] * wd[nt][0] + acc[mt][nt][3] * wd[nt][1];
            }
#pragma unroll
            for (int o = 1; o < 4; o <<= 1) {
                ps0 += __shfl_xor_sync(0xFFFFFFFFu, ps0, o);
                pd0 += __shfl_xor_sync(0xFFFFFFFFu, pd0, o);
                ps1 += __shfl_xor_sync(0xFFFFFFFFu, ps1, o);
                pd1 += __shfl_xor_sync(0xFFFFFFFFu, pd1, o);
            }
            if (cq == 0) {
                int row0 = blockM + warpM + mt * 16 + r;
                if (row0 < M) {
                    atomicAdd(alS + (size_t)row0 * 4 + head, ps0);
                    atomicAdd(alD + (size_t)row0 * 4 + head, pd0);
                }
                if (row0 + 8 < M) {
                    atomicAdd(alS + (size_t)(row0 + 8) * 4 + head, ps1);
                    atomicAdd(alD + (size_t)(row0 + 8) * 4 + head, pd1);
                }
            }
        }
    }
}

// ---------------- TF32 tensor-core GEMM (head z@Wf1 only) --------------------
__device__ __forceinline__ void mma_tf32(float c[4], const float a[4], const float b[2]) {
    asm volatile(
        "mma.sync.aligned.m16n8k8.row.col.f32.tf32.tf32.f32 "
        "{%0,%1,%2,%3}, {%4,%5,%6,%7}, {%8,%9}, {%0,%1,%2,%3};"
        : "+f"(c[0]), "+f"(c[1]), "+f"(c[2]), "+f"(c[3])
        : "r"(__float_as_uint(a[0])), "r"(__float_as_uint(a[1])),
          "r"(__float_as_uint(a[2])), "r"(__float_as_uint(a[3])),
          "r"(__float_as_uint(b[0])), "r"(__float_as_uint(b[1])));
}

#define ABUF 4608
#define BBUF 4352
#define SMEM_FLOATS (2 * ABUF + 2 * BBUF)

__global__ __launch_bounds__(256, 2) void tf32gemm(
    const float* __restrict__ A, const float* __restrict__ B,
    float* __restrict__ C, int M, int Nc, int K, int lda, int ldb, int ldc)
{
    extern __shared__ float smemf[];

    int tid = threadIdx.x;
    int lane = tid & 31;
    int wid = tid >> 5;
    int warpM = (wid >> 2) * 64;
    int warpN = (wid & 3) * 32;
    int r = lane >> 2;
    int cq = lane & 3;

    int blockM = blockIdx.y * 128;
    int blockN = blockIdx.x * 128;

    int acol = (tid & 7) * 4;
    int arow0 = tid >> 3;
    int bcol = (tid & 31) * 4;
    int brow0 = tid >> 5;

    float acc[4][4][4];
#pragma unroll
    for (int mt = 0; mt < 4; mt++)
#pragma unroll
        for (int nt = 0; nt < 4; nt++)
#pragma unroll
            for (int i = 0; i < 4; i++) acc[mt][nt][i] = 0.0f;

    int nk = K >> 5;

    auto load_tile = [&](int k0, int buf) {
        float* As = smemf + buf * ABUF;
        float* Bs = smemf + 2 * ABUF + buf * BBUF;
#pragma unroll
        for (int i = 0; i < 4; i++) {
            int row = blockM + arow0 + i * 32;
            cp_async16(&As[(arow0 + i * 32) * 36 + acol],
                       A + (size_t)row * lda + k0 + acol, row < M);
        }
#pragma unroll
        for (int i = 0; i < 4; i++) {
            int kr = brow0 + i * 8;
            cp_async16(&Bs[kr * 136 + bcol],
                       B + (size_t)(k0 + kr) * ldb + blockN + bcol, true);
        }
        asm volatile("cp.async.commit_group;\n");
    };

    load_tile(0, 0);

    for (int kt = 0; kt < nk; kt++) {
        if (kt + 1 < nk) {
            load_tile((kt + 1) << 5, (kt + 1) & 1);
            asm volatile("cp.async.wait_group 1;\n");
        } else {
            asm volatile("cp.async.wait_group 0;\n");
        }
        __syncthreads();

        const float* As = smemf + (kt & 1) * ABUF;
        const float* Bs = smemf + 2 * ABUF + (kt & 1) * BBUF;

#pragma unroll
        for (int kk = 0; kk < 4; kk++) {
            int kb = kk * 8;
            float a[4][4], b[4][2];
#pragma unroll
            for (int mt = 0; mt < 4; mt++) {
                int m = warpM + mt * 16 + r;
                a[mt][0] = As[m * 36 + kb + cq];
                a[mt][1] = As[(m + 8) * 36 + kb + cq];
                a[mt][2] = As[m * 36 + kb + cq + 4];
                a[mt][3] = As[(m + 8) * 36 + kb + cq + 4];
            }
#pragma unroll
            for (int nt = 0; nt < 4; nt++) {
                int nn = warpN + nt * 8 + r;
                b[nt][0] = Bs[(kb + cq) * 136 + nn];
                b[nt][1] = Bs[(kb + cq + 4) * 136 + nn];
            }
#pragma unroll
            for (int mt = 0; mt < 4; mt++)
#pragma unroll
                for (int nt = 0; nt < 4; nt++)
                    mma_tf32(acc[mt][nt], a[mt], b[nt]);
        }
        __syncthreads();
    }

#pragma unroll
    for (int mt = 0; mt < 4; mt++) {
        int row0 = blockM + warpM + mt * 16 + r;
#pragma unroll
        for (int nt = 0; nt < 4; nt++) {
            int col = blockN + warpN + nt * 8 + cq * 2;
            if (row0 < M)
                *(float2*)(C + (size_t)row0 * ldc + col) =
                    make_float2(acc[mt][nt][0], acc[mt][nt][1]);
            if (row0 + 8 < M)
                *(float2*)(C + (size_t)(row0 + 8) * ldc + col) =
                    make_float2(acc[mt][nt][2], acc[mt][nt][3]);
        }
    }
}

// ---------------- fp32 SGEMM (solvent MLP: bias+relu) ------------------------
template <bool RELU>
__global__ __launch_bounds__(256) void sgemm(
    const float* __restrict__ A, const float* __restrict__ B,
    const float* __restrict__ bias, float* __restrict__ C,
    int M, int Nc, int K, int lda, int ldc)
{
    __shared__ float As[8][128];
    __shared__ float Bs[8][128];

    int tid = threadIdx.x;
    int bx = blockIdx.x;
    int by = blockIdx.y;

    int tx = tid % 16;
    int ty = tid / 16;

    int rowA = by * 128 + tid / 2;
    int colA = (tid % 2) * 4;
    int rowB = tid / 32;
    int colB = (tid % 32) * 4;

    float acc[8][8];
#pragma unroll
    for (int i = 0; i < 8; i++)
#pragma unroll
        for (int j = 0; j < 8; j++) acc[i][j] = 0.0f;

    for (int k0 = 0; k0 < K; k0 += 8) {
        float4 av = make_float4(0.f, 0.f, 0.f, 0.f);
        if (rowA < M)
            av = *(const float4*)(A + (size_t)rowA * lda + k0 + colA);
        As[colA + 0][tid / 2] = av.x;
        As[colA + 1][tid / 2] = av.y;
        As[colA + 2][tid / 2] = av.z;
        As[colA + 3][tid / 2] = av.w;

        float4 bv = *(const float4*)(B + (size_t)(k0 + rowB) * Nc + bx * 128 + colB);
        *(float4*)(&Bs[rowB][colB]) = bv;

        __syncthreads();

#pragma unroll
        for (int kk = 0; kk < 8; kk++) {
            float ra[8], rb[8];
#pragma unroll
            for (int i = 0; i < 8; i++) ra[i] = As[kk][ty * 8 + i];
#pragma unroll
            for (int j = 0; j < 8; j++) rb[j] = Bs[kk][tx * 8 + j];
#pragma unroll
            for (int i = 0; i < 8; i++)
#pragma unroll
                for (int j = 0; j < 8; j++) acc[i][j] = fmaf(ra[i], rb[j], acc[i][j]);
        }
        __syncthreads();
    }

#pragma unroll
    for (int i = 0; i < 8; i++) {
        int row = by * 128 + ty * 8 + i;
        if (row >= M) continue;
#pragma unroll
        for (int j = 0; j < 8; j++) {
            int col = bx * 128 + tx * 8 + j;
            float v = acc[i][j];
            if (bias) v += bias[col];
            if (RELU) v = v > 0.f ? v : 0.f;
            C[(size_t)row * ldc + col] = v;
        }
    }
}

// ---- GAT layer 1 input-space gather (precomputed alphas, fp16 output) -------
__global__ __launch_bounds__(64) void gat_agg_in64(
    const int* __restrict__ rowptr, const int* __restrict__ csrsrc,
    const float* __restrict__ alpha,
    const float* __restrict__ in, __half* __restrict__ agg)
{
    __shared__ float s_al[16][4];
    __shared__ int   s_src[16];

    int d = blockIdx.x;
    int tid = threadIdx.x;
    int beg = rowptr[d], end = rowptr[d + 1];

    float acc[4] = {0.f, 0.f, 0.f, 0.f};
    for (int c0 = beg; c0 < end; c0 += 16) {
        int cnt = min(16, end - c0);
        if (tid < cnt) s_src[tid] = csrsrc[c0 + tid];
        if (tid < cnt * 4) ((float*)s_al)[tid] = alpha[(size_t)c0 * 4 + tid];
        __syncthreads();
        int j = 0;
        for (; j + 4 <= cnt; j += 4) {
            float v0 = in[(size_t)s_src[j + 0] * 64 + tid];
            float v1 = in[(size_t)s_src[j + 1] * 64 + tid];
            float v2 = in[(size_t)s_src[j + 2] * 64 + tid];
            float v3 = in[(size_t)s_src[j + 3] * 64 + tid];
#pragma unroll
            for (int hh = 0; hh < 4; hh++) {
                acc[hh] = fmaf(s_al[j + 0][hh], v0, acc[hh]);
                acc[hh] = fmaf(s_al[j + 1][hh], v1, acc[hh]);
                acc[hh] = fmaf(s_al[j + 2][hh], v2, acc[hh]);
                acc[hh] = fmaf(s_al[j + 3][hh], v3, acc[hh]);
            }
        }
        for (; j < cnt; j++) {
            float v = in[(size_t)s_src[j] * 64 + tid];
#pragma unroll
            for (int hh = 0; hh < 4; hh++)
                acc[hh] = fmaf(s_al[j][hh], v, acc[hh]);
        }
        __syncthreads();
    }

#pragma unroll
    for (int hh = 0; hh < 4; hh++)
        agg[(size_t)d * 256 + hh * 64 + tid] = __float2half_rn(acc[hh]);
}

// ---- GAT2 gather (precomputed alphas; fp16 in, fp16 out; 2 blocks/node) -----
template <int HC, int SPLIT>
__global__ __launch_bounds__(128) void gat_gather_h(
    const int* __restrict__ rowptr, const int* __restrict__ csrsrc,
    const float* __restrict__ alpha,
    const __half* __restrict__ h, __half* __restrict__ out)
{
    constexpr int NT = 128;
    constexpr int HCW = HC / SPLIT;
    static_assert(HCW == 4 * NT, "4 channels per thread");
    constexpr int CPH = HC / 4;

    __shared__ float s_al[32][4];
    __shared__ int   s_src[32];

    int d = blockIdx.x;
    int half = (SPLIT > 1) ? blockIdx.y : 0;
    int coff = half * HCW;
    int tid = threadIdx.x;
    int beg = rowptr[d], end = rowptr[d + 1];

    float4 acc = make_float4(0.f, 0.f, 0.f, 0.f);
    int hof = (coff + tid * 4) / CPH;

    for (int c0 = beg; c0 < end; c0 += 32) {
        int cnt = min(32, end - c0);
        if (tid < cnt) s_src[tid] = csrsrc[c0 + tid];
        if (tid < cnt * 4) ((float*)s_al)[tid] = alpha[(size_t)c0 * 4 + tid];
        __syncthreads();
        int j = 0;
        for (; j + 4 <= cnt; j += 4) {
            const uint2* p0 = (const uint2*)(h + (size_t)s_src[j + 0] * HC + coff) + tid;
            const uint2* p1 = (const uint2*)(h + (size_t)s_src[j + 1] * HC + coff) + tid;
            const uint2* p2 = (const uint2*)(h + (size_t)s_src[j + 2] * HC + coff) + tid;
            const uint2* p3 = (const uint2*)(h + (size_t)s_src[j + 3] * HC + coff) + tid;
            uint2 r0 = *p0, r1 = *p1, r2 = *p2, r3 = *p3;
            float a0 = s_al[j + 0][hof];
            float a1 = s_al[j + 1][hof];
            float a2 = s_al[j + 2][hof];
            float a3 = s_al[j + 3][hof];
            float2 f0a = __half22float2(*(__half2*)&r0.x);
            float2 f0b = __half22float2(*(__half2*)&r0.y);
            float2 f1a = __half22float2(*(__half2*)&r1.x);
            float2 f1b = __half22float2(*(__half2*)&r1.y);
            float2 f2a = __half22float2(*(__half2*)&r2.x);
            float2 f2b = __half22float2(*(__half2*)&r2.y);
            float2 f3a = __half22float2(*(__half2*)&r3.x);
            float2 f3b = __half22float2(*(__half2*)&r3.y);
            acc.x = fmaf(a0, f0a.x, acc.x); acc.y = fmaf(a0, f0a.y, acc.y);
            acc.z = fmaf(a0, f0b.x, acc.z); acc.w = fmaf(a0, f0b.y, acc.w);
            acc.x = fmaf(a1, f1a.x, acc.x); acc.y = fmaf(a1, f1a.y, acc.y);
            acc.z = fmaf(a1, f1b.x, acc.z); acc.w = fmaf(a1, f1b.y, acc.w);
            acc.x = fmaf(a2, f2a.x, acc.x); acc.y = fmaf(a2, f2a.y, acc.y);
            acc.z = fmaf(a2, f2b.x, acc.z); acc.w = fmaf(a2, f2b.y, acc.w);
            acc.x = fmaf(a3, f3a.x, acc.x); acc.y = fmaf(a3, f3a.y, acc.y);
            acc.z = fmaf(a3, f3b.x, acc.z); acc.w = fmaf(a3, f3b.y, acc.w);
        }
        for (; j < cnt; j++) {
            const uint2* p = (const uint2*)(h + (size_t)s_src[j] * HC + coff) + tid;
            uint2 rr = *p;
            float a = s_al[j][hof];
            float2 fa = __half22float2(*(__half2*)&rr.x);
            float2 fb = __half22float2(*(__half2*)&rr.y);
            acc.x = fmaf(a, fa.x, acc.x);
            acc.y = fmaf(a, fa.y, acc.y);
            acc.z = fmaf(a, fb.x, acc.z);
            acc.w = fmaf(a, fb.y, acc.w);
        }
        __syncthreads();
    }

    uint2 ov;
    __half2 o0 = __floats2half2_rn(acc.x, acc.y);
    __half2 o1 = __floats2half2_rn(acc.z, acc.w);
    ov.x = *(uint32_t*)&o0;
    ov.y = *(uint32_t*)&o1;
    *((uint2*)(out + (size_t)d * HC + coff) + tid) = ov;
}

// ---------------- GCN gather (fp16 in, fp16 out) -----------------------------
__global__ __launch_bounds__(64) void gcn_gather_h(
    const int* __restrict__ rowptr, const int* __restrict__ csrsrc,
    const float* __restrict__ dinv, const __half* __restrict__ h,
    __half* __restrict__ out)
{
    int d = blockIdx.x;
    int tid = threadIdx.x;
    int beg = rowptr[d], end = rowptr[d + 1];
    float dd = dinv[d];

    float4 acc = make_float4(0.f, 0.f, 0.f, 0.f);
    int i = beg;
    for (; i + 4 <= end; i += 4) {
        int s0 = csrsrc[i + 0], s1 = csrsrc[i + 1];
        int s2 = csrsrc[i + 2], s3 = csrsrc[i + 3];
        float n0 = dinv[s0] * dd, n1 = dinv[s1] * dd;
        float n2 = dinv[s2] * dd, n3 = dinv[s3] * dd;
        uint2 r0 = *((const uint2*)(h + (size_t)s0 * 256) + tid);
        uint2 r1 = *((const uint2*)(h + (size_t)s1 * 256) + tid);
        uint2 r2 = *((const uint2*)(h + (size_t)s2 * 256) + tid);
        uint2 r3 = *((const uint2*)(h + (size_t)s3 * 256) + tid);
        float2 f0a = __half22float2(*(__half2*)&r0.x);
        float2 f0b = __half22float2(*(__half2*)&r0.y);
        float2 f1a = __half22float2(*(__half2*)&r1.x);
        float2 f1b = __half22float2(*(__half2*)&r1.y);
        float2 f2a = __half22float2(*(__half2*)&r2.x);
        float2 f2b = __half22float2(*(__half2*)&r2.y);
        float2 f3a = __half22float2(*(__half2*)&r3.x);
        float2 f3b = __half22float2(*(__half2*)&r3.y);
        acc.x = fmaf(n0, f0a.x, acc.x); acc.y = fmaf(n0, f0a.y, acc.y);
        acc.z = fmaf(n0, f0b.x, acc.z); acc.w = fmaf(n0, f0b.y, acc.w);
        acc.x = fmaf(n1, f1a.x, acc.x); acc.y = fmaf(n1, f1a.y, acc.y);
        acc.z = fmaf(n1, f1b.x, acc.z); acc.w = fmaf(n1, f1b.y, acc.w);
        acc.x = fmaf(n2, f2a.x, acc.x); acc.y = fmaf(n2, f2a.y, acc.y);
        acc.z = fmaf(n2, f2b.x, acc.z); acc.w = fmaf(n2, f2b.y, acc.w);
        acc.x = fmaf(n3, f3a.x, acc.x); acc.y = fmaf(n3, f3a.y, acc.y);
        acc.z = fmaf(n3, f3b.x, acc.z); acc.w = fmaf(n3, f3b.y, acc.w);
    }
    for (; i < end; i++) {
        int s = csrsrc[i];
        float nrm = dinv[s] * dd;
        uint2 rr = *((const uint2*)(h + (size_t)s * 256) + tid);
        float2 fa = __half22float2(*(__half2*)&rr.x);
        float2 fb = __half22float2(*(__half2*)&rr.y);
        acc.x = fmaf(nrm, fa.x, acc.x);
        acc.y = fmaf(nrm, fa.y, acc.y);
        acc.z = fmaf(nrm, fb.x, acc.z);
        acc.w = fmaf(nrm, fb.y, acc.w);
    }
    uint2 ov;
    __half2 o0 = __floats2half2_rn(acc.x, acc.y);
    __half2 o1 = __floats2half2_rn(acc.z, acc.w);
    ov.x = *(uint32_t*)&o0;
    ov.y = *(uint32_t*)&o1;
    *((uint2*)(out + (size_t)d * 256) + tid) = ov;
}

// ---------------- BatchNorm -------------------------------------------------
__global__ void bn_stats(const float* __restrict__ x, int rows, int K,
                         float* __restrict__ sum, float* __restrict__ sq)
{
    int col = blockIdx.x * blockDim.x + threadIdx.x;
    float s = 0.f, q = 0.f;
    for (int r = blockIdx.y; r < rows; r += gridDim.y) {
        float v = x[(size_t)r * K + col];
        s += v;
        q += v * v;
    }
    atomicAdd(sum + col, s);
    atomicAdd(sq + col, q);
}

__global__ void bn_stats_h4(const __half* __restrict__ x, int rows, int K,
                            float* __restrict__ sum, float* __restrict__ sq)
{
    int c0 = (blockIdx.x * blockDim.x + threadIdx.x) * 4;
    if (c0 >= K) return;
    float s0 = 0.f, s1 = 0.f, s2 = 0.f, s3 = 0.f;
    float q0 = 0.f, q1 = 0.f, q2 = 0.f, q3 = 0.f;
    for (int r = blockIdx.y; r < rows; r += gridDim.y) {
        uint2 v = *(const uint2*)(x + (size_t)r * K + c0);
        float2 a = __half22float2(*(__half2*)&v.x);
        float2 b = __half22float2(*(__half2*)&v.y);
        s0 += a.x; q0 += a.x * a.x;
        s1 += a.y; q1 += a.y * a.y;
        s2 += b.x; q2 += b.x * b.x;
        s3 += b.y; q3 += b.y * b.y;
    }
    atomicAdd(sum + c0 + 0, s0); atomicAdd(sq + c0 + 0, q0);
    atomicAdd(sum + c0 + 1, s1); atomicAdd(sq + c0 + 1, q1);
    atomicAdd(sum + c0 + 2, s2); atomicAdd(sq + c0 + 2, q2);
    atomicAdd(sum + c0 + 3, s3); atomicAdd(sq + c0 + 3, q3);
}

__global__ void bn_finalize(const float* __restrict__ sum, const float* __restrict__ sq,
                            const float* __restrict__ g, const float* __restrict__ b,
                            int rows, int K, float* __restrict__ scale,
                            float* __restrict__ shift)
{
    int c = blockIdx.x * blockDim.x + threadIdx.x;
    if (c >= K) return;
    float inv_n = 1.0f / (float)rows;
    float mu = sum[c] * inv_n;
    float var = sq[c] * inv_n - mu * mu;
    float sc = g[c] * rsqrtf(var + 1e-5f);
    scale[c] = sc;
    shift[c] = b[c] - mu * sc;
}

// ---------------- Pooling (fp16 input; batch sorted, no atomics) -------------
__global__ __launch_bounds__(256) void pool_graph_h(
    const __half* __restrict__ h, const int* __restrict__ gstart,
    const float* __restrict__ scale, const float* __restrict__ shift,
    float* __restrict__ z)
{
    int g = blockIdx.x;
    int c = threadIdx.x;
    int beg = gstart[g], end = gstart[g + 1];
    float sc = scale[c], sh = shift[c];
    float sum = 0.f, mx = 0.f;
    for (int r = beg; r < end; r++) {
        float hv = __half2float(h[(size_t)r * 256 + c]);
        float v = fmaxf(fmaf(hv, sc, sh), 0.f);
        sum += v;
        mx = fmaxf(mx, v);
    }
    float cnt = (float)(end - beg);
    z[(size_t)g * 640 + c] = sum / fmaxf(cnt, 1.0f);
    z[(size_t)g * 640 + 256 + c] = mx;
}

// ---------------- Head (BN+relu fused in) ------------------------------------
__global__ void head_final(const float* __restrict__ zf,
                           const float* __restrict__ scale,
                           const float* __restrict__ shift,
                           const float* __restrict__ Wf2,
                           const float* __restrict__ bf2, float* __restrict__ out)
{
    int g = blockIdx.x;
    int t = threadIdx.x;
    float v = fmaxf(fmaf(zf[(size_t)g * 128 + t], scale[t], shift[t]), 0.f) * Wf2[t];
#pragma unroll
    for (int o = 16; o; o >>= 1) v += __shfl_down_sync(0xFFFFFFFFu, v, o);
    __shared__ float sm[4];
    if ((t & 31) == 0) sm[t >> 5] = v;
    __syncthreads();
    if (t == 0) {
        float s = sm[0] + sm[1] + sm[2] + sm[3] + bf2[0];
        out[g] = 1.0f / (1.0f + expf(-s));
    }
}

// ---------------- launch ------------------------------------------------------
extern "C" void kernel_launch(void* const* d_in, const int* in_sizes, int n_in,
                              void* d_out, int out_size)
{
    const float* x    = (const float*)d_in[0];
    const int*   ei   = (const int*)d_in[1];
    const int*   batch= (const int*)d_in[2];
    const float* fp   = (const float*)d_in[3];
    const float* W1   = (const float*)d_in[4];
    const float* a1s  = (const float*)d_in[5];
    const float* a1d  = (const float*)d_in[6];
    const float* bn1g = (const float*)d_in[8];
    const float* bn1b = (const float*)d_in[9];
    const float* W2   = (const float*)d_in[10];
    const float* a2s  = (const float*)d_in[11];
    const float* a2d  = (const float*)d_in[12];
    const float* bn2g = (const float*)d_in[14];
    const float* bn2b = (const float*)d_in[15];
    const float* Wg   = (const float*)d_in[16];
    const float* bn3g = (const float*)d_in[18];
    const float* bn3b = (const float*)d_in[19];
    const float* Ws   = (const float*)d_in[20];
    const float* bs   = (const float*)d_in[21];
    const float* Wf1  = (const float*)d_in[22];
    const float* bnfg = (const float*)d_in[24];
    const float* bnfb = (const float*)d_in[25];
    const float* Wf2  = (const float*)d_in[26];
    const float* bf2  = (const float*)d_in[27];
    float* out = (float*)d_out;

    int n    = in_sizes[0] / 64;
    int E    = in_sizes[1] / 2;
    int Etot = E + n;
    int G    = in_sizes[3] / 128;

    float *bufA, *bufB, *bufC, *al2, *alpha, *dinv, *uu, *vv;
    float *bnacc, *bnscale, *bnshift, *z, *zf;
    __half *w1p, *w2p, *wgp;
    int *degi, *incl, *part, *rowptr, *cursor, *csrsrc, *gstart;
    cudaGetSymbolAddress((void**)&bufA, g_bufA);
    cudaGetSymbolAddress((void**)&bufB, g_bufB);
    cudaGetSymbolAddress((void**)&bufC, g_bufC);
    cudaGetSymbolAddress((void**)&w1p, g_w1p);
    cudaGetSymbolAddress((void**)&w2p, g_w2p);
    cudaGetSymbolAddress((void**)&wgp, g_wgp);
    cudaGetSymbolAddress((void**)&al2, g_al2);
    cudaGetSymbolAddress((void**)&alpha, g_alpha);
    cudaGetSymbolAddress((void**)&uu, g_u);
    cudaGetSymbolAddress((void**)&vv, g_v);
    cudaGetSymbolAddress((void**)&degi, g_degi);
    cudaGetSymbolAddress((void**)&incl, g_incl);
    cudaGetSymbolAddress((void**)&part, g_part);
    cudaGetSymbolAddress((void**)&rowptr, g_rowptr);
    cudaGetSymbolAddress((void**)&cursor, g_cursor);
    cudaGetSymbolAddress((void**)&csrsrc, g_csrsrc);
    cudaGetSymbolAddress((void**)&dinv, g_dinv);
    cudaGetSymbolAddress((void**)&gstart, g_gstart);
    cudaGetSymbolAddress((void**)&bnacc, g_bnacc);
    cudaGetSymbolAddress((void**)&bnscale, g_bnscale);
    cudaGetSymbolAddress((void**)&bnshift, g_bnshift);
    cudaGetSymbolAddress((void**)&z, g_z);
    cudaGetSymbolAddress((void**)&zf, g_zf);

    float* alS = al2;
    float* alD = al2 + (size_t)NMAXN * 4;
    float* bnsum = bnacc;
    float* bnsq  = bnacc + 1024;

    __half* bufA_h = (__half*)bufA;
    __half* bufB_h = (__half*)bufB;
    __half* bufC_h = (__half*)bufC;

    size_t tf_smem = SMEM_FLOATS * sizeof(float);
    static bool attr_done = false;
    if (!attr_done) {
        cudaFuncSetAttribute(tf32gemm,
                             cudaFuncAttributeMaxDynamicSharedMemorySize, (int)tf_smem);
        cudaFuncSetAttribute(hgemm<false, false, true, true, 128, 2>,
                             cudaFuncAttributeMaxDynamicSharedMemorySize, H_SMEM(128, 2));
        cudaFuncSetAttribute(hgemm<true, true, false, true, 256, 3>,
                             cudaFuncAttributeMaxDynamicSharedMemorySize, H_SMEM(256, 3));
        cudaFuncSetAttribute(hgemm<true, false, false, true, 256, 3>,
                             cudaFuncAttributeMaxDynamicSharedMemorySize, H_SMEM(256, 3));
        attr_done = true;
    }

    auto bnstats_h = [&](const __half* Xp, int rows, int K, const float* gg,
                         const float* bb) {
        cudaMemsetAsync(bnacc, 0, 2048 * sizeof(float));
        dim3 g1((K / 4 + 127) / 128, 256);
        bn_stats_h4<<<g1, 128>>>(Xp, rows, K, bnsum, bnsq);
        bn_finalize<<<(K + 127) / 128, 128>>>(bnsum, bnsq, gg, bb, rows, K,
                                              bnscale, bnshift);
    };

    // ---- CSR build + graph boundaries + weight packing (independent)
    cudaMemsetAsync(degi, 0, n * sizeof(int));
    deg_build<<<(Etot + 255) / 256, 256>>>(ei, E, Etot, degi);
    int nb = (n + 1023) / 1024;
    scan_partial<<<nb, 1024>>>(degi, n, incl, part);
    scan_roots<<<1, 128>>>(part, nb);
    scan_add<<<(n + 255) / 256, 256>>>(incl, degi, part, n, Etot,
                                       rowptr, cursor, dinv);
    csr_scatter<<<(Etot + 255) / 256, 256>>>(ei, E, Etot, cursor, csrsrc);
    gstart_build<<<(n + 256) / 256, 256>>>(batch, n, G, gstart);
    {
        int total = 64 * 512 + 512 * 1024 + 1024 * 256;
        pack_all<<<(total + 255) / 256, 256>>>(W1, W2, Wg, w1p, w2p, wgp);
    }

    // ---- GAT layer 1 (input-space): exact fp32 alphas; per-edge softmax;
    //      gather x -> fp16; hgemm (head-grouped, BN=128, 2-stage)
    uv_build<<<(64 * 4 * 32 + 255) / 256, 256>>>(W1, a1s, a1d, 64, 128, uu, vv);
    alpha_gemm64<<<(n + 7) / 8, 256>>>(x, n, uu, vv, alS, alD);
    alpha_edges<<<(n + 7) / 8, 256>>>(rowptr, csrsrc, alS, alD, n, alpha);
    gat_agg_in64<<<n, 64>>>(rowptr, csrsrc, alpha, x, bufA_h);
    {
        dim3 grid(4, (n + 127) / 128);
        hgemm<false, false, true, true, 128, 2><<<grid, 256, H_SMEM(128, 2)>>>(
            bufA_h, w1p, bufB_h, n, 512, 64, 256, 512,
            nullptr, nullptr, nullptr, nullptr, 128, nullptr, nullptr);
    }
    bnstats_h(bufB_h, n, 512, bn1g, bn1b);

    // ---- GAT layer 2: bufC_h = relu(bn(bufB_h))@W2 (+ fused logit partials,
    //      wide 256 tiles, 3-stage); per-edge softmax; gather -> bufA_h
    cudaMemsetAsync(al2, 0, (size_t)2 * NMAXN * 4 * sizeof(float));
    {
        dim3 grid(4, (n + 127) / 128);
        hgemm<true, true, false, true, 256, 3><<<grid, 512, H_SMEM(256, 3)>>>(
            bufB_h, w2p, bufC_h, n, 1024, 512, 512, 1024,
            bnscale, bnshift, a2s, a2d, 256, alS, alD);
    }
    alpha_edges<<<(n + 7) / 8, 256>>>(rowptr, csrsrc, alS, alD, n, alpha);
    {
        dim3 grid(n, 2);
        gat_gather_h<1024, 2><<<grid, 128>>>(rowptr, csrsrc, alpha, bufC_h, bufA_h);
    }
    bnstats_h(bufA_h, n, 1024, bn2g, bn2b);

    // ---- GCN: bufB_h = relu(bn(bufA_h))@Wg (wide, 3-stage); gather; BN stats
    {
        dim3 grid(1, (n + 127) / 128);
        hgemm<true, false, false, true, 256, 3><<<grid, 512, H_SMEM(256, 3)>>>(
            bufA_h, wgp, bufB_h, n, 256, 1024, 1024, 256,
            bnscale, bnshift, nullptr, nullptr, 256, nullptr, nullptr);
    }
    gcn_gather_h<<<n, 64>>>(rowptr, csrsrc, dinv, bufB_h, bufC_h);
    bnstats_h(bufC_h, n, 256, bn3g, bn3b);

    // ---- Pooling into z[G,640] (block per graph; BN+relu on the fly)
    pool_graph_h<<<G, 256>>>(bufC_h, gstart, bnscale, bnshift, z);

    // ---- solvent MLP: relu(fp @ Ws + bs) -> z[:,512:640]
    {
        dim3 grid(1, (G + 127) / 128);
        sgemm<true><<<grid, 256>>>(fp, Ws, bs, z + 512, G, 128, 128, 128, 640);
    }

    // ---- head: zf = z @ Wf1 via tf32 (bf1 cancels under BN); BN stats;
    //      BN+relu fused into final dot+sigmoid
    {
        dim3 grid(1, (G + 127) / 128);
        tf32gemm<<<grid, 256, tf_smem>>>(z, Wf1, zf, G, 128, 640, 640, 128, 128);
    }
    {
        cudaMemsetAsync(bnacc, 0, 2048 * sizeof(float));
        dim3 g1(1, 128);
        bn_stats<<<g1, 128>>>(zf, G, 128, bnsum, bnsq);
        bn_finalize<<<1, 128>>>(bnsum, bnsq, bnfg, bnfb, G, 128, bnscale, bnshift);
    }
    head_final<<<G, 128>>>(zf, bnscale, bnshift, Wf2, bf2, out);
}